// round 3
// baseline (speedup 1.0000x reference)
#include <cuda_runtime.h>
#include <math.h>

#define BATCH 2
#define CH    256
#define HH    128
#define WW    128
#define HWSZ  16384          // HH*WW
#define PTOT  32768          // BATCH*HWSZ
#define LN_EPS 1e-6f

// ---------------- scratch (module-static; no runtime allocation) ----------------
__device__ float g_xT  [(size_t)PTOT * CH];      // x in NHWC
__device__ float g_acc [(size_t)PTOT * CH];      // branch accumulator (NHWC)
__device__ float g_out1[(size_t)PTOT * CH];      // after LN1
__device__ float g_h   [(size_t)PTOT * 512];     // MLP hidden
__device__ float g_t2  [(size_t)PTOT * CH];      // MLP out + residual
__device__ float g_offp[(size_t)4 * BATCH * 18 * HWSZ];  // offset-conv partials (4 c-chunks)

__device__ __forceinline__ float gelu_f(float v) {
    return 0.5f * v * (1.0f + erff(v * 0.70710678118654752440f));
}

// ---------------- NCHW -> NHWC transpose ----------------
__global__ void k_nchw2nhwc(const float* __restrict__ x) {
    __shared__ float t[32][33];
    int b  = blockIdx.z;
    int p0 = blockIdx.x * 32, c0 = blockIdx.y * 32;
    int tx = threadIdx.x, ty = threadIdx.y;
    const float* xb = x + (size_t)b * CH * HWSZ;
#pragma unroll
    for (int i = 0; i < 4; i++)
        t[ty + 8 * i][tx] = xb[(size_t)(c0 + ty + 8 * i) * HWSZ + p0 + tx];
    __syncthreads();
    float* o = g_xT + (size_t)b * HWSZ * CH;
#pragma unroll
    for (int i = 0; i < 4; i++)
        o[(size_t)(p0 + ty + 8 * i) * CH + c0 + tx] = t[tx][ty + 8 * i];
}

// ---------------- NHWC -> NCHW transpose (reads g_xT reused as final LN output) ----------------
__global__ void k_nhwc2nchw(float* __restrict__ out) {
    __shared__ float t[32][33];
    int b  = blockIdx.z;
    int p0 = blockIdx.x * 32, c0 = blockIdx.y * 32;
    int tx = threadIdx.x, ty = threadIdx.y;
    const float* in = g_xT + (size_t)b * HWSZ * CH;
#pragma unroll
    for (int i = 0; i < 4; i++)
        t[ty + 8 * i][tx] = in[(size_t)(p0 + ty + 8 * i) * CH + c0 + tx];
    __syncthreads();
    float* ob = out + (size_t)b * CH * HWSZ;
#pragma unroll
    for (int i = 0; i < 4; i++)
        ob[(size_t)(c0 + ty + 8 * i) * HWSZ + p0 + tx] = t[tx][ty + 8 * i];
}

// ---------------- offset conv: 3x3 dilated, 18 out channels ----------------
// block = 128 threads (one per col), handles 4 image rows; grid (H/4, B, 4 c-chunks)
template <int D>
__global__ void k_offconv(const float* __restrict__ x, const float* __restrict__ wt) {
    __shared__ float sx[12][WW];
    __shared__ float sw[162];
    int t  = threadIdx.x;
    int h0 = blockIdx.x * 4;
    int b  = blockIdx.y;
    int cz = blockIdx.z;
    const float* xb = x + (size_t)b * CH * HWSZ;

    float acc[4][18];
#pragma unroll
    for (int r = 0; r < 4; r++)
#pragma unroll
        for (int o = 0; o < 18; o++) acc[r][o] = 0.f;

    for (int c = cz * 64; c < cz * 64 + 64; c++) {
        // FIX (R2): 162 weights, 128 threads -> strided loop (was `if (t<162)`,
        // leaving sw[128..161] uninitialized garbage)
        for (int i = t; i < 162; i += 128) {
            int o = i / 9, k = i % 9;
            sw[i] = wt[(size_t)o * CH * 9 + (size_t)c * 9 + k];
        }
        const float* xc = xb + (size_t)c * HWSZ;
#pragma unroll
        for (int rr = 0; rr < 12; rr++) {
            int g = rr >> 2, r = rr & 3;
            int row = h0 + r + (g - 1) * D;
            sx[rr][t] = (row >= 0 && row < HH) ? xc[row * WW + t] : 0.f;
        }
        __syncthreads();
#pragma unroll
        for (int ky = 0; ky < 3; ky++) {
#pragma unroll
            for (int kx = 0; kx < 3; kx++) {
                int col = t + (kx - 1) * D;
                float xr[4];
                bool ok = (col >= 0 && col < WW);
#pragma unroll
                for (int r = 0; r < 4; r++)
                    xr[r] = ok ? sx[ky * 4 + r][col] : 0.f;
#pragma unroll
                for (int o = 0; o < 18; o++) {
                    float wv = sw[o * 9 + ky * 3 + kx];
#pragma unroll
                    for (int r = 0; r < 4; r++) acc[r][o] += wv * xr[r];
                }
            }
        }
        __syncthreads();
    }
    float* op = g_offp + (size_t)(cz * BATCH + b) * 18 * HWSZ;
#pragma unroll
    for (int o = 0; o < 18; o++)
#pragma unroll
        for (int r = 0; r < 4; r++)
            op[(size_t)o * HWSZ + (h0 + r) * WW + t] = acc[r][o];
}

// ---------------- deformable depthwise + LN + GELU + accumulate ----------------
// one 64-thread block per pixel; thread handles 4 channels
template <int D>
__global__ void k_deform(const float* __restrict__ defw,
                         const float* __restrict__ lnw, const float* __restrict__ lnb) {
    __shared__ int   sidx[36];
    __shared__ float swgt[36];
    __shared__ float sdefT[9 * CH];
    __shared__ float red[4];
    int tid = threadIdx.x;
    int p = blockIdx.x & (HWSZ - 1);
    int b = blockIdx.x >> 14;
    int h = p >> 7, w = p & 127;

    for (int i = tid; i < 9 * CH; i += 64) {
        int c = i / 9, k = i % 9;
        sdefT[k * CH + c] = defw[i];
    }
    if (tid < 9) {
        int k = tid, ky = k / 3, kx = k % 3;
        float oy = 0.f, ox = 0.f;
#pragma unroll
        for (int z = 0; z < 4; z++) {
            const float* op = g_offp + (size_t)(z * BATCH + b) * 18 * HWSZ;
            oy += op[(size_t)(2 * k) * HWSZ + p];
            ox += op[(size_t)(2 * k + 1) * HWSZ + p];
        }
        float py = (float)h + (float)((ky - 1) * D) + oy;
        float px = (float)w + (float)((kx - 1) * D) + ox;
        float y0 = floorf(py), x0 = floorf(px);
#pragma unroll
        for (int dy = 0; dy < 2; dy++) {
#pragma unroll
            for (int dx = 0; dx < 2; dx++) {
                float yc = y0 + dy, xc = x0 + dx;
                float wq = (1.f - fabsf(py - yc)) * (1.f - fabsf(px - xc));
                bool valid = (yc >= 0.f) && (yc < 128.f) && (xc >= 0.f) && (xc < 128.f);
                int iy = min(max((int)yc, 0), 127);
                int ix = min(max((int)xc, 0), 127);
                sidx[k * 4 + dy * 2 + dx] = iy * WW + ix;
                swgt[k * 4 + dy * 2 + dx] = valid ? wq : 0.f;
            }
        }
    }
    __syncthreads();

    int c0 = tid * 4;
    float4 wk[9];
#pragma unroll
    for (int k = 0; k < 9; k++)
        wk[k] = *(const float4*)(sdefT + k * CH + c0);

    float4 acc = make_float4(0.f, 0.f, 0.f, 0.f);
    const float* xrow = g_xT + (size_t)b * HWSZ * CH;
#pragma unroll
    for (int k = 0; k < 9; k++) {
        float4 s = make_float4(0.f, 0.f, 0.f, 0.f);
#pragma unroll
        for (int j = 0; j < 4; j++) {
            float wq = swgt[k * 4 + j];
            if (wq != 0.f) {   // uniform across block
                float4 v = *(const float4*)(xrow + (size_t)sidx[k * 4 + j] * CH + c0);
                s.x += wq * v.x; s.y += wq * v.y; s.z += wq * v.z; s.w += wq * v.w;
            }
        }
        acc.x += wk[k].x * s.x; acc.y += wk[k].y * s.y;
        acc.z += wk[k].z * s.z; acc.w += wk[k].w * s.w;
    }

    // LN over 256 channels (2-warp reduce)
    float sum = acc.x + acc.y + acc.z + acc.w;
    float sq  = acc.x * acc.x + acc.y * acc.y + acc.z * acc.z + acc.w * acc.w;
#pragma unroll
    for (int o = 16; o; o >>= 1) {
        sum += __shfl_xor_sync(0xffffffffu, sum, o);
        sq  += __shfl_xor_sync(0xffffffffu, sq, o);
    }
    if ((tid & 31) == 0) { red[(tid >> 5) * 2] = sum; red[(tid >> 5) * 2 + 1] = sq; }
    __syncthreads();
    sum = red[0] + red[2]; sq = red[1] + red[3];
    float mean = sum * (1.f / 256.f);
    float var  = sq * (1.f / 256.f) - mean * mean;
    float rstd = rsqrtf(var + LN_EPS);

    float4 g;
    g.x = gelu_f(lnw[c0 + 0] * ((acc.x - mean) * rstd) + lnb[c0 + 0]);
    g.y = gelu_f(lnw[c0 + 1] * ((acc.y - mean) * rstd) + lnb[c0 + 1]);
    g.z = gelu_f(lnw[c0 + 2] * ((acc.z - mean) * rstd) + lnb[c0 + 2]);
    g.w = gelu_f(lnw[c0 + 3] * ((acc.w - mean) * rstd) + lnb[c0 + 3]);

    float4* dst = (float4*)(g_acc + ((size_t)b * HWSZ + p) * CH + c0);
    float4 cur = *dst;
    cur.x += g.x; cur.y += g.y; cur.z += g.z; cur.w += g.w;
    *dst = cur;
}

// ---------------- FFMA GEMM: C[M,N] = act(A[M,K] @ Bw[N,K]^T + bias) (+res) ----------------
// 128x128 tile, BK=8, 256 threads, 8x8 per thread
template <int ACT, bool RES>
__global__ void k_gemm(const float* __restrict__ A, const float* __restrict__ Bw,
                       const float* __restrict__ bias, const float* __restrict__ res,
                       float* __restrict__ Cm, int N, int K) {
    __shared__ float As[8][128];
    __shared__ float Bs[8][128];
    int tid = threadIdx.x;
    int m0 = blockIdx.x * 128, n0 = blockIdx.y * 128;
    int lr = tid >> 1, lc = (tid & 1) * 4;
    int tx = tid & 15, ty = tid >> 4;

    float acc[8][8];
#pragma unroll
    for (int i = 0; i < 8; i++)
#pragma unroll
        for (int j = 0; j < 8; j++) acc[i][j] = 0.f;

    for (int k0 = 0; k0 < K; k0 += 8) {
        float4 av = *(const float4*)(A  + (size_t)(m0 + lr) * K + k0 + lc);
        float4 bv = *(const float4*)(Bw + (size_t)(n0 + lr) * K + k0 + lc);
        As[lc + 0][lr] = av.x; As[lc + 1][lr] = av.y;
        As[lc + 2][lr] = av.z; As[lc + 3][lr] = av.w;
        Bs[lc + 0][lr] = bv.x; Bs[lc + 1][lr] = bv.y;
        Bs[lc + 2][lr] = bv.z; Bs[lc + 3][lr] = bv.w;
        __syncthreads();
#pragma unroll
        for (int k = 0; k < 8; k++) {
            float4 a0 = *(const float4*)(&As[k][ty * 8]);
            float4 a1 = *(const float4*)(&As[k][ty * 8 + 4]);
            float4 b0 = *(const float4*)(&Bs[k][tx * 8]);
            float4 b1 = *(const float4*)(&Bs[k][tx * 8 + 4]);
            float am[8] = {a0.x, a0.y, a0.z, a0.w, a1.x, a1.y, a1.z, a1.w};
            float bn[8] = {b0.x, b0.y, b0.z, b0.w, b1.x, b1.y, b1.z, b1.w};
#pragma unroll
            for (int i = 0; i < 8; i++)
#pragma unroll
                for (int j = 0; j < 8; j++) acc[i][j] += am[i] * bn[j];
        }
        __syncthreads();
    }
#pragma unroll
    for (int i = 0; i < 8; i++) {
        int m = m0 + ty * 8 + i;
#pragma unroll
        for (int j = 0; j < 8; j++) {
            int n = n0 + tx * 8 + j;
            float v = acc[i][j] + bias[n];
            if (ACT == 1) v = gelu_f(v);
            if (RES) v += res[(size_t)m * N + n];
            acc[i][j] = v;
        }
        float4* d = (float4*)(Cm + (size_t)m * N + n0 + tx * 8);
        d[0] = make_float4(acc[i][0], acc[i][1], acc[i][2], acc[i][3]);
        d[1] = make_float4(acc[i][4], acc[i][5], acc[i][6], acc[i][7]);
    }
}

// ---------------- per-pixel LayerNorm over channels (warp per pixel) ----------------
__global__ void k_ln(const float* __restrict__ in, float* __restrict__ out,
                     const float* __restrict__ gw, const float* __restrict__ gb) {
    int lane = threadIdx.x & 31;
    size_t pix = (size_t)blockIdx.x * 8 + (threadIdx.x >> 5);
    const float4* r = (const float4*)(in + pix * CH) + lane * 2;
    float4 v0 = r[0], v1 = r[1];
    float s = v0.x + v0.y + v0.z + v0.w + v1.x + v1.y + v1.z + v1.w;
    float q = v0.x * v0.x + v0.y * v0.y + v0.z * v0.z + v0.w * v0.w +
              v1.x * v1.x + v1.y * v1.y + v1.z * v1.z + v1.w * v1.w;
#pragma unroll
    for (int o = 16; o; o >>= 1) {
        s += __shfl_xor_sync(0xffffffffu, s, o);
        q += __shfl_xor_sync(0xffffffffu, q, o);
    }
    float mean = s * (1.f / 256.f);
    float var  = q * (1.f / 256.f) - mean * mean;
    float rstd = rsqrtf(var + LN_EPS);
    int c = lane * 8;
    float4 o0, o1;
    o0.x = gw[c + 0] * ((v0.x - mean) * rstd) + gb[c + 0];
    o0.y = gw[c + 1] * ((v0.y - mean) * rstd) + gb[c + 1];
    o0.z = gw[c + 2] * ((v0.z - mean) * rstd) + gb[c + 2];
    o0.w = gw[c + 3] * ((v0.w - mean) * rstd) + gb[c + 3];
    o1.x = gw[c + 4] * ((v1.x - mean) * rstd) + gb[c + 4];
    o1.y = gw[c + 5] * ((v1.y - mean) * rstd) + gb[c + 5];
    o1.z = gw[c + 6] * ((v1.z - mean) * rstd) + gb[c + 6];
    o1.w = gw[c + 7] * ((v1.w - mean) * rstd) + gb[c + 7];
    float4* wptr = (float4*)(out + pix * CH) + lane * 2;
    wptr[0] = o0; wptr[1] = o1;
}

// ---------------- launch ----------------
extern "C" void kernel_launch(void* const* d_in, const int* in_sizes, int n_in,
                              void* d_out, int out_size) {
    const float* x       = (const float*)d_in[0];
    const float* off_w1  = (const float*)d_in[1];
    const float* def_w1  = (const float*)d_in[2];
    const float* bw1     = (const float*)d_in[3];
    const float* bb1     = (const float*)d_in[4];
    const float* off_w2  = (const float*)d_in[5];
    const float* def_w2  = (const float*)d_in[6];
    const float* bw2     = (const float*)d_in[7];
    const float* bb2     = (const float*)d_in[8];
    const float* off_w3  = (const float*)d_in[9];
    const float* def_w3  = (const float*)d_in[10];
    const float* bw3     = (const float*)d_in[11];
    const float* bb3     = (const float*)d_in[12];
    const float* conv_w  = (const float*)d_in[13];
    const float* conv_b  = (const float*)d_in[14];
    const float* n1_w    = (const float*)d_in[15];
    const float* n1_b    = (const float*)d_in[16];
    const float* n2_w    = (const float*)d_in[17];
    const float* n2_b    = (const float*)d_in[18];
    const float* mlp_w1  = (const float*)d_in[19];
    const float* mlp_b1  = (const float*)d_in[20];
    const float* mlp_w2  = (const float*)d_in[21];
    const float* mlp_b2  = (const float*)d_in[22];

    float *pxT, *pacc, *pout1, *ph, *pt2;
    cudaGetSymbolAddress((void**)&pxT,   g_xT);
    cudaGetSymbolAddress((void**)&pacc,  g_acc);
    cudaGetSymbolAddress((void**)&pout1, g_out1);
    cudaGetSymbolAddress((void**)&ph,    g_h);
    cudaGetSymbolAddress((void**)&pt2,   g_t2);

    // 1. x -> NHWC
    k_nchw2nhwc<<<dim3(HWSZ / 32, CH / 32, BATCH), dim3(32, 8)>>>(x);
    // 2. acc = x @ conv_w^T + conv_b
    k_gemm<0, false><<<dim3(PTOT / 128, CH / 128), 256>>>(pxT, conv_w, conv_b, nullptr, pacc, CH, CH);
    // 3. three deformable branches, accumulated sequentially
    k_offconv<1><<<dim3(HH / 4, BATCH, 4), 128>>>(x, off_w1);
    k_deform<1><<<PTOT, 64>>>(def_w1, bw1, bb1);
    k_offconv<9><<<dim3(HH / 4, BATCH, 4), 128>>>(x, off_w2);
    k_deform<9><<<PTOT, 64>>>(def_w2, bw2, bb2);
    k_offconv<12><<<dim3(HH / 4, BATCH, 4), 128>>>(x, off_w3);
    k_deform<12><<<PTOT, 64>>>(def_w3, bw3, bb3);
    // 4. LN1
    k_ln<<<PTOT / 8, 256>>>(pacc, pout1, n1_w, n1_b);
    // 5. MLP
    k_gemm<1, false><<<dim3(PTOT / 128, 512 / 128), 256>>>(pout1, mlp_w1, mlp_b1, nullptr, ph, 512, CH);
    k_gemm<0, true ><<<dim3(PTOT / 128, CH / 128), 256>>>(ph, mlp_w2, mlp_b2, pout1, pt2, CH, 512);
    // 6. LN2 (into g_xT, reused) + transpose to NCHW output
    k_ln<<<PTOT / 8, 256>>>(pt2, pxT, n2_w, n2_b);
    k_nhwc2nchw<<<dim3(HWSZ / 32, CH / 32, BATCH), dim3(32, 8)>>>((float*)d_out);
}

// round 5
// speedup vs baseline: 1.2406x; 1.2406x over previous
#include <cuda_runtime.h>
#include <cuda_bf16.h>
#include <math.h>
#include <stdint.h>

#define BATCH 2
#define CH    256
#define HH    128
#define WW    128
#define HWSZ  16384
#define PTOT  32768
#define LN_EPS 1e-6f

// ---------------- scratch ----------------
__device__ float g_xT  [(size_t)PTOT * CH];
__device__ float g_acc [(size_t)PTOT * CH];
__device__ float g_out1[(size_t)PTOT * CH];
__device__ float g_t2  [(size_t)PTOT * CH];
__device__ float g_offp[(size_t)4 * BATCH * 18 * HWSZ];
__device__ __nv_bfloat16 g_xTh[(size_t)PTOT * CH];
__device__ __nv_bfloat16 g_xTl[(size_t)PTOT * CH];
__device__ __nv_bfloat16 g_o1h[(size_t)PTOT * CH];
__device__ __nv_bfloat16 g_o1l[(size_t)PTOT * CH];
__device__ __nv_bfloat16 g_hh [(size_t)PTOT * 512];
__device__ __nv_bfloat16 g_hl [(size_t)PTOT * 512];
// weight splits: conv_w(65536) | mlp_w1(131072) | mlp_w2(131072)
__device__ __nv_bfloat16 g_wh[327680];
__device__ __nv_bfloat16 g_wl[327680];

__device__ __forceinline__ float gelu_f(float v) {
    return 0.5f * v * (1.0f + erff(v * 0.70710678118654752440f));
}
__device__ __forceinline__ void split_bf16(float v, __nv_bfloat16& h, __nv_bfloat16& l) {
    h = __float2bfloat16(v);
    l = __float2bfloat16(v - __bfloat162float(h));
}
__device__ __forceinline__ uint32_t smem_u32(const void* p) {
    uint32_t a;
    asm("{ .reg .u64 t; cvta.to.shared.u64 t, %1; cvt.u32.u64 %0, t; }" : "=r"(a) : "l"(p));
    return a;
}
__device__ __forceinline__ void ldmx4(uint32_t* r, uint32_t addr) {
    asm volatile("ldmatrix.sync.aligned.m8n8.x4.shared.b16 {%0,%1,%2,%3}, [%4];"
                 : "=r"(r[0]), "=r"(r[1]), "=r"(r[2]), "=r"(r[3]) : "r"(addr));
}
__device__ __forceinline__ void mma16816(float* c, const uint32_t* a, const uint32_t* b) {
    asm volatile("mma.sync.aligned.m16n8k16.row.col.f32.bf16.bf16.f32 "
                 "{%0,%1,%2,%3}, {%4,%5,%6,%7}, {%8,%9}, {%0,%1,%2,%3};"
                 : "+f"(c[0]), "+f"(c[1]), "+f"(c[2]), "+f"(c[3])
                 : "r"(a[0]), "r"(a[1]), "r"(a[2]), "r"(a[3]), "r"(b[0]), "r"(b[1]));
}

// ---------------- NCHW -> NHWC transpose (+ bf16 hi/lo split) ----------------
__global__ void k_nchw2nhwc(const float* __restrict__ x) {
    __shared__ float t[32][33];
    int b  = blockIdx.z;
    int p0 = blockIdx.x * 32, c0 = blockIdx.y * 32;
    int tx = threadIdx.x, ty = threadIdx.y;
    const float* xb = x + (size_t)b * CH * HWSZ;
#pragma unroll
    for (int i = 0; i < 4; i++)
        t[ty + 8 * i][tx] = xb[(size_t)(c0 + ty + 8 * i) * HWSZ + p0 + tx];
    __syncthreads();
    size_t base = (size_t)b * HWSZ * CH;
#pragma unroll
    for (int i = 0; i < 4; i++) {
        float v = t[tx][ty + 8 * i];
        size_t idx = base + (size_t)(p0 + ty + 8 * i) * CH + c0 + tx;
        g_xT[idx] = v;
        __nv_bfloat16 h, l; split_bf16(v, h, l);
        g_xTh[idx] = h; g_xTl[idx] = l;
    }
}

// ---------------- NHWC -> NCHW transpose ----------------
__global__ void k_nhwc2nchw(float* __restrict__ out) {
    __shared__ float t[32][33];
    int b  = blockIdx.z;
    int p0 = blockIdx.x * 32, c0 = blockIdx.y * 32;
    int tx = threadIdx.x, ty = threadIdx.y;
    const float* in = g_xT + (size_t)b * HWSZ * CH;
#pragma unroll
    for (int i = 0; i < 4; i++)
        t[ty + 8 * i][tx] = in[(size_t)(p0 + ty + 8 * i) * CH + c0 + tx];
    __syncthreads();
    float* ob = out + (size_t)b * CH * HWSZ;
#pragma unroll
    for (int i = 0; i < 4; i++)
        ob[(size_t)(c0 + ty + 8 * i) * HWSZ + p0 + tx] = t[tx][ty + 8 * i];
}

// ---------------- fp32 -> bf16 hi/lo split ----------------
__global__ void k_split(const float* __restrict__ s, __nv_bfloat16* __restrict__ h,
                        __nv_bfloat16* __restrict__ l, int n4) {
    int i = blockIdx.x * blockDim.x + threadIdx.x;
    if (i >= n4) return;
    float4 v = ((const float4*)s)[i];
    __nv_bfloat16 ha, la, hb, lb, hc, lc, hd, ld;
    split_bf16(v.x, ha, la); split_bf16(v.y, hb, lb);
    split_bf16(v.z, hc, lc); split_bf16(v.w, hd, ld);
    ((__nv_bfloat162*)h)[2 * i + 0] = __nv_bfloat162(ha, hb);
    ((__nv_bfloat162*)h)[2 * i + 1] = __nv_bfloat162(hc, hd);
    ((__nv_bfloat162*)l)[2 * i + 0] = __nv_bfloat162(la, lb);
    ((__nv_bfloat162*)l)[2 * i + 1] = __nv_bfloat162(lc, ld);
}

// ---------------- offset conv (unchanged) ----------------
template <int D>
__global__ void k_offconv(const float* __restrict__ x, const float* __restrict__ wt) {
    __shared__ float sx[12][WW];
    __shared__ float sw[162];
    int t  = threadIdx.x;
    int h0 = blockIdx.x * 4;
    int b  = blockIdx.y;
    int cz = blockIdx.z;
    const float* xb = x + (size_t)b * CH * HWSZ;

    float acc[4][18];
#pragma unroll
    for (int r = 0; r < 4; r++)
#pragma unroll
        for (int o = 0; o < 18; o++) acc[r][o] = 0.f;

    for (int c = cz * 64; c < cz * 64 + 64; c++) {
        for (int i = t; i < 162; i += 128) {
            int o = i / 9, k = i % 9;
            sw[i] = wt[(size_t)o * CH * 9 + (size_t)c * 9 + k];
        }
        const float* xc = xb + (size_t)c * HWSZ;
#pragma unroll
        for (int rr = 0; rr < 12; rr++) {
            int g = rr >> 2, r = rr & 3;
            int row = h0 + r + (g - 1) * D;
            sx[rr][t] = (row >= 0 && row < HH) ? xc[row * WW + t] : 0.f;
        }
        __syncthreads();
#pragma unroll
        for (int ky = 0; ky < 3; ky++) {
#pragma unroll
            for (int kx = 0; kx < 3; kx++) {
                int col = t + (kx - 1) * D;
                float xr[4];
                bool ok = (col >= 0 && col < WW);
#pragma unroll
                for (int r = 0; r < 4; r++)
                    xr[r] = ok ? sx[ky * 4 + r][col] : 0.f;
#pragma unroll
                for (int o = 0; o < 18; o++) {
                    float wv = sw[o * 9 + ky * 3 + kx];
#pragma unroll
                    for (int r = 0; r < 4; r++) acc[r][o] += wv * xr[r];
                }
            }
        }
        __syncthreads();
    }
    float* op = g_offp + (size_t)(cz * BATCH + b) * 18 * HWSZ;
#pragma unroll
    for (int o = 0; o < 18; o++)
#pragma unroll
        for (int r = 0; r < 4; r++)
            op[(size_t)o * HWSZ + (h0 + r) * WW + t] = acc[r][o];
}

// ---------------- deformable depthwise + LN + GELU + accumulate (unchanged) ----------------
template <int D>
__global__ void k_deform(const float* __restrict__ defw,
                         const float* __restrict__ lnw, const float* __restrict__ lnb) {
    __shared__ int   sidx[36];
    __shared__ float swgt[36];
    __shared__ float sdefT[9 * CH];
    __shared__ float red[4];
    int tid = threadIdx.x;
    int p = blockIdx.x & (HWSZ - 1);
    int b = blockIdx.x >> 14;
    int h = p >> 7, w = p & 127;

    for (int i = tid; i < 9 * CH; i += 64) {
        int c = i / 9, k = i % 9;
        sdefT[k * CH + c] = defw[i];
    }
    if (tid < 9) {
        int k = tid, ky = k / 3, kx = k % 3;
        float oy = 0.f, ox = 0.f;
#pragma unroll
        for (int z = 0; z < 4; z++) {
            const float* op = g_offp + (size_t)(z * BATCH + b) * 18 * HWSZ;
            oy += op[(size_t)(2 * k) * HWSZ + p];
            ox += op[(size_t)(2 * k + 1) * HWSZ + p];
        }
        float py = (float)h + (float)((ky - 1) * D) + oy;
        float px = (float)w + (float)((kx - 1) * D) + ox;
        float y0 = floorf(py), x0 = floorf(px);
#pragma unroll
        for (int dy = 0; dy < 2; dy++) {
#pragma unroll
            for (int dx = 0; dx < 2; dx++) {
                float yc = y0 + dy, xc = x0 + dx;
                float wq = (1.f - fabsf(py - yc)) * (1.f - fabsf(px - xc));
                bool valid = (yc >= 0.f) && (yc < 128.f) && (xc >= 0.f) && (xc < 128.f);
                int iy = min(max((int)yc, 0), 127);
                int ix = min(max((int)xc, 0), 127);
                sidx[k * 4 + dy * 2 + dx] = iy * WW + ix;
                swgt[k * 4 + dy * 2 + dx] = valid ? wq : 0.f;
            }
        }
    }
    __syncthreads();

    int c0 = tid * 4;
    float4 wk[9];
#pragma unroll
    for (int k = 0; k < 9; k++)
        wk[k] = *(const float4*)(sdefT + k * CH + c0);

    float4 acc = make_float4(0.f, 0.f, 0.f, 0.f);
    const float* xrow = g_xT + (size_t)b * HWSZ * CH;
#pragma unroll
    for (int k = 0; k < 9; k++) {
        float4 s = make_float4(0.f, 0.f, 0.f, 0.f);
#pragma unroll
        for (int j = 0; j < 4; j++) {
            float wq = swgt[k * 4 + j];
            if (wq != 0.f) {
                float4 v = *(const float4*)(xrow + (size_t)sidx[k * 4 + j] * CH + c0);
                s.x += wq * v.x; s.y += wq * v.y; s.z += wq * v.z; s.w += wq * v.w;
            }
        }
        acc.x += wk[k].x * s.x; acc.y += wk[k].y * s.y;
        acc.z += wk[k].z * s.z; acc.w += wk[k].w * s.w;
    }

    float sum = acc.x + acc.y + acc.z + acc.w;
    float sq  = acc.x * acc.x + acc.y * acc.y + acc.z * acc.z + acc.w * acc.w;
#pragma unroll
    for (int o = 16; o; o >>= 1) {
        sum += __shfl_xor_sync(0xffffffffu, sum, o);
        sq  += __shfl_xor_sync(0xffffffffu, sq, o);
    }
    if ((tid & 31) == 0) { red[(tid >> 5) * 2] = sum; red[(tid >> 5) * 2 + 1] = sq; }
    __syncthreads();
    sum = red[0] + red[2]; sq = red[1] + red[3];
    float mean = sum * (1.f / 256.f);
    float var  = sq * (1.f / 256.f) - mean * mean;
    float rstd = rsqrtf(var + LN_EPS);

    float4 g;
    g.x = gelu_f(lnw[c0 + 0] * ((acc.x - mean) * rstd) + lnb[c0 + 0]);
    g.y = gelu_f(lnw[c0 + 1] * ((acc.y - mean) * rstd) + lnb[c0 + 1]);
    g.z = gelu_f(lnw[c0 + 2] * ((acc.z - mean) * rstd) + lnb[c0 + 2]);
    g.w = gelu_f(lnw[c0 + 3] * ((acc.w - mean) * rstd) + lnb[c0 + 3]);

    float4* dst = (float4*)(g_acc + ((size_t)b * HWSZ + p) * CH + c0);
    float4 cur = *dst;
    cur.x += g.x; cur.y += g.y; cur.z += g.z; cur.w += g.w;
    *dst = cur;
}

// ---------------- split-bf16 GEMM via mma.sync (HMMA) ----------------
// C[M,N] = act(sum_k (Ah+Al)[m,k]*(Bh+Bl)[n,k] + bias[n]) (+res)
// block tile 128x128, BK=32, 256 threads = 8 warps (4M x 2N), warp tile 32x64
template <int ACT, bool RES, bool BF16OUT>
__global__ void __launch_bounds__(256)
k_mmagemm(const __nv_bfloat16* __restrict__ Ah, const __nv_bfloat16* __restrict__ Al,
          const __nv_bfloat16* __restrict__ Bh, const __nv_bfloat16* __restrict__ Bl,
          const float* __restrict__ bias, const float* __restrict__ res,
          float* __restrict__ Cf, __nv_bfloat16* __restrict__ Chi,
          __nv_bfloat16* __restrict__ Clo, int N, int K) {
    __shared__ __nv_bfloat16 sA[2][128][40];   // [hi/lo][row][BK(32)+pad]
    __shared__ __nv_bfloat16 sB[2][128][40];

    int tid  = threadIdx.x;
    int wid  = tid >> 5, lane = tid & 31;
    int m0   = blockIdx.x * 128, n0 = blockIdx.y * 128;
    int wm   = (wid & 3) * 32;         // warp M offset in tile
    int wn   = (wid >> 2) * 64;        // warp N offset in tile

    float acc[2][8][4];
#pragma unroll
    for (int i = 0; i < 2; i++)
#pragma unroll
        for (int j = 0; j < 8; j++)
#pragma unroll
            for (int q = 0; q < 4; q++) acc[i][j][q] = 0.f;

    const __nv_bfloat16* srcs[4] = {Ah + (size_t)m0 * K, Al + (size_t)m0 * K,
                                    Bh + (size_t)n0 * K, Bl + (size_t)n0 * K};
    __nv_bfloat16* dsts[4] = {&sA[0][0][0], &sA[1][0][0], &sB[0][0][0], &sB[1][0][0]};

    // ldmatrix lane->row/col decomposition (see fragment layout of m16n8k16)
    int a_row8 = ((lane >> 3) & 1) * 8 + (lane & 7);
    int a_col8 = ((lane >> 4) & 1) * 8;
    int b_row8 = ((lane >> 4) & 1) * 8 + (lane & 7);
    int b_col8 = ((lane >> 3) & 1) * 8;

    int nk = K >> 5;
    for (int kc = 0; kc < nk; kc++) {
        // stage 4 tiles of 128x32 bf16
#pragma unroll
        for (int t = 0; t < 4; t++) {
            const __nv_bfloat16* s = srcs[t] + kc * 32;
#pragma unroll
            for (int u = 0; u < 2; u++) {
                int idx = u * 256 + tid;
                int row = idx >> 2, ch = idx & 3;
                uint4 v = *(const uint4*)(s + (size_t)row * K + ch * 8);
                *(uint4*)(dsts[t] + row * 40 + ch * 8) = v;
            }
        }
        __syncthreads();
#pragma unroll
        for (int ks = 0; ks < 2; ks++) {
            uint32_t af[2][2][4];   // [hl][mi][reg]
#pragma unroll
            for (int hl = 0; hl < 2; hl++)
#pragma unroll
                for (int mi = 0; mi < 2; mi++) {
                    uint32_t ad = smem_u32(&sA[hl][wm + mi * 16 + a_row8][ks * 16 + a_col8]);
                    ldmx4(af[hl][mi], ad);
                }
            uint32_t bf[2][4][4];   // [hl][jp][reg]; jp covers n-tiles 2jp,2jp+1
#pragma unroll
            for (int hl = 0; hl < 2; hl++)
#pragma unroll
                for (int jp = 0; jp < 4; jp++) {
                    uint32_t ad = smem_u32(&sB[hl][wn + jp * 16 + b_row8][ks * 16 + b_col8]);
                    ldmx4(bf[hl][jp], ad);
                }
#pragma unroll
            for (int mi = 0; mi < 2; mi++)
#pragma unroll
                for (int j = 0; j < 8; j++) {
                    int jp = j >> 1, hB = (j & 1) * 2;
                    uint32_t bh2[2] = {bf[0][jp][hB], bf[0][jp][hB + 1]};
                    uint32_t bl2[2] = {bf[1][jp][hB], bf[1][jp][hB + 1]};
                    mma16816(acc[mi][j], af[0][mi], bh2);   // Ah*Bh
                    mma16816(acc[mi][j], af[0][mi], bl2);   // Ah*Bl
                    mma16816(acc[mi][j], af[1][mi], bh2);   // Al*Bh
                }
        }
        __syncthreads();
    }

    // epilogue: thread holds rows (wm+mi*16+g, +8), cols (wn+j*8+q*2, +1)
    int g = lane >> 2, q = lane & 3;
#pragma unroll
    for (int mi = 0; mi < 2; mi++) {
#pragma unroll
        for (int half = 0; half < 2; half++) {      // half 0: row g, regs 0,1; half 1: row g+8, regs 2,3
            int m = m0 + wm + mi * 16 + g + half * 8;
#pragma unroll
            for (int j = 0; j < 8; j++) {
                int n = n0 + wn + j * 8 + q * 2;
                float v0 = acc[mi][j][half * 2 + 0] + __ldg(bias + n);
                float v1 = acc[mi][j][half * 2 + 1] + __ldg(bias + n + 1);
                if (ACT == 1) { v0 = gelu_f(v0); v1 = gelu_f(v1); }
                if (RES) {
                    const float2 rv = *(const float2*)(res + (size_t)m * N + n);
                    v0 += rv.x; v1 += rv.y;
                }
                if (BF16OUT) {
                    __nv_bfloat16 h0, l0, h1, l1;
                    split_bf16(v0, h0, l0); split_bf16(v1, h1, l1);
                    *(__nv_bfloat162*)(Chi + (size_t)m * N + n) = __nv_bfloat162(h0, h1);
                    *(__nv_bfloat162*)(Clo + (size_t)m * N + n) = __nv_bfloat162(l0, l1);
                } else {
                    *(float2*)(Cf + (size_t)m * N + n) = make_float2(v0, v1);
                }
            }
        }
    }
}

// ---------------- per-pixel LayerNorm over channels ----------------
__global__ void k_ln(const float* __restrict__ in, float* __restrict__ out,
                     const float* __restrict__ gw, const float* __restrict__ gb) {
    int lane = threadIdx.x & 31;
    size_t pix = (size_t)blockIdx.x * 8 + (threadIdx.x >> 5);
    const float4* r = (const float4*)(in + pix * CH) + lane * 2;
    float4 v0 = r[0], v1 = r[1];
    float s = v0.x + v0.y + v0.z + v0.w + v1.x + v1.y + v1.z + v1.w;
    float q = v0.x * v0.x + v0.y * v0.y + v0.z * v0.z + v0.w * v0.w +
              v1.x * v1.x + v1.y * v1.y + v1.z * v1.z + v1.w * v1.w;
#pragma unroll
    for (int o = 16; o; o >>= 1) {
        s += __shfl_xor_sync(0xffffffffu, s, o);
        q += __shfl_xor_sync(0xffffffffu, q, o);
    }
    float mean = s * (1.f / 256.f);
    float var  = q * (1.f / 256.f) - mean * mean;
    float rstd = rsqrtf(var + LN_EPS);
    int c = lane * 8;
    float4 o0, o1;
    o0.x = gw[c + 0] * ((v0.x - mean) * rstd) + gb[c + 0];
    o0.y = gw[c + 1] * ((v0.y - mean) * rstd) + gb[c + 1];
    o0.z = gw[c + 2] * ((v0.z - mean) * rstd) + gb[c + 2];
    o0.w = gw[c + 3] * ((v0.w - mean) * rstd) + gb[c + 3];
    o1.x = gw[c + 4] * ((v1.x - mean) * rstd) + gb[c + 4];
    o1.y = gw[c + 5] * ((v1.y - mean) * rstd) + gb[c + 5];
    o1.z = gw[c + 6] * ((v1.z - mean) * rstd) + gb[c + 6];
    o1.w = gw[c + 7] * ((v1.w - mean) * rstd) + gb[c + 7];
    float4* wptr = (float4*)(out + pix * CH) + lane * 2;
    wptr[0] = o0; wptr[1] = o1;
}

// ---------------- launch ----------------
extern "C" void kernel_launch(void* const* d_in, const int* in_sizes, int n_in,
                              void* d_out, int out_size) {
    const float* x       = (const float*)d_in[0];
    const float* off_w1  = (const float*)d_in[1];
    const float* def_w1  = (const float*)d_in[2];
    const float* bw1     = (const float*)d_in[3];
    const float* bb1     = (const float*)d_in[4];
    const float* off_w2  = (const float*)d_in[5];
    const float* def_w2  = (const float*)d_in[6];
    const float* bw2     = (const float*)d_in[7];
    const float* bb2     = (const float*)d_in[8];
    const float* off_w3  = (const float*)d_in[9];
    const float* def_w3  = (const float*)d_in[10];
    const float* bw3     = (const float*)d_in[11];
    const float* bb3     = (const float*)d_in[12];
    const float* conv_w  = (const float*)d_in[13];
    const float* conv_b  = (const float*)d_in[14];
    const float* n1_w    = (const float*)d_in[15];
    const float* n1_b    = (const float*)d_in[16];
    const float* n2_w    = (const float*)d_in[17];
    const float* n2_b    = (const float*)d_in[18];
    const float* mlp_w1  = (const float*)d_in[19];
    const float* mlp_b1  = (const float*)d_in[20];
    const float* mlp_w2  = (const float*)d_in[21];
    const float* mlp_b2  = (const float*)d_in[22];

    float *pxT, *pacc, *pout1, *pt2;
    __nv_bfloat16 *pxTh, *pxTl, *po1h, *po1l, *phh, *phl, *pwh, *pwl;
    cudaGetSymbolAddress((void**)&pxT,   g_xT);
    cudaGetSymbolAddress((void**)&pacc,  g_acc);
    cudaGetSymbolAddress((void**)&pout1, g_out1);
    cudaGetSymbolAddress((void**)&pt2,   g_t2);
    cudaGetSymbolAddress((void**)&pxTh,  g_xTh);
    cudaGetSymbolAddress((void**)&pxTl,  g_xTl);
    cudaGetSymbolAddress((void**)&po1h,  g_o1h);
    cudaGetSymbolAddress((void**)&po1l,  g_o1l);
    cudaGetSymbolAddress((void**)&phh,   g_hh);
    cudaGetSymbolAddress((void**)&phl,   g_hl);
    cudaGetSymbolAddress((void**)&pwh,   g_wh);
    cudaGetSymbolAddress((void**)&pwl,   g_wl);

    // 1. x -> NHWC (+ hi/lo split)
    k_nchw2nhwc<<<dim3(HWSZ / 32, CH / 32, BATCH), dim3(32, 8)>>>(x);
    // 2. weight splits
    k_split<<<(65536 / 4 + 255) / 256, 256>>>(conv_w, pwh, pwl, 65536 / 4);
    k_split<<<(131072 / 4 + 255) / 256, 256>>>(mlp_w1, pwh + 65536, pwl + 65536, 131072 / 4);
    k_split<<<(131072 / 4 + 255) / 256, 256>>>(mlp_w2, pwh + 196608, pwl + 196608, 131072 / 4);
    // 3. conv1x1: acc = xT @ conv_w^T + conv_b
    k_mmagemm<0, false, false><<<dim3(PTOT / 128, CH / 128), 256>>>(
        pxTh, pxTl, pwh, pwl, conv_b, nullptr, pacc, nullptr, nullptr, CH, CH);
    // 4. three deformable branches
    k_offconv<1><<<dim3(HH / 4, BATCH, 4), 128>>>(x, off_w1);
    k_deform<1><<<PTOT, 64>>>(def_w1, bw1, bb1);
    k_offconv<9><<<dim3(HH / 4, BATCH, 4), 128>>>(x, off_w2);
    k_deform<9><<<PTOT, 64>>>(def_w2, bw2, bb2);
    k_offconv<12><<<dim3(HH / 4, BATCH, 4), 128>>>(x, off_w3);
    k_deform<12><<<PTOT, 64>>>(def_w3, bw3, bb3);
    // 5. LN1 -> out1 (fp32) + hi/lo split
    k_ln<<<PTOT / 8, 256>>>(pacc, pout1, n1_w, n1_b);
    k_split<<<((PTOT * CH) / 4 + 255) / 256, 256>>>(pout1, po1h, po1l, (PTOT * CH) / 4);
    // 6. MLP1 (bias+GELU, bf16 hi/lo out)
    k_mmagemm<1, false, true><<<dim3(PTOT / 128, 512 / 128), 256>>>(
        po1h, po1l, pwh + 65536, pwl + 65536, mlp_b1, nullptr,
        nullptr, phh, phl, 512, CH);
    // 7. MLP2 (bias + residual out1)
    k_mmagemm<0, true, false><<<dim3(PTOT / 128, CH / 128), 256>>>(
        phh, phl, pwh + 196608, pwl + 196608, mlp_b2, pout1,
        pt2, nullptr, nullptr, CH, 512);
    // 8. LN2 -> g_xT (reuse), transpose out
    k_ln<<<PTOT / 8, 256>>>(pt2, pxT, n2_w, n2_b);
    k_nhwc2nchw<<<dim3(HWSZ / 32, CH / 32, BATCH), dim3(32, 8)>>>((float*)d_out);
}

// round 6
// speedup vs baseline: 1.5242x; 1.2287x over previous
#include <cuda_runtime.h>
#include <cuda_bf16.h>
#include <math.h>
#include <stdint.h>

#define BATCH 2
#define CH    256
#define HH    128
#define WW    128
#define HWSZ  16384
#define PTOT  32768
#define LN_EPS 1e-6f

// ---------------- scratch ----------------
__device__ float g_xT  [(size_t)PTOT * CH];
__device__ float g_acc [(size_t)PTOT * CH];
__device__ float g_out1[(size_t)PTOT * CH];
__device__ float g_t2  [(size_t)PTOT * CH];
__device__ float g_offp[(size_t)3 * 4 * BATCH * 18 * HWSZ];   // [branch][chunk][b][18][HW]
__device__ __nv_bfloat16 g_xTh[(size_t)PTOT * CH];
__device__ __nv_bfloat16 g_xTl[(size_t)PTOT * CH];
__device__ __nv_bfloat16 g_o1h[(size_t)PTOT * CH];
__device__ __nv_bfloat16 g_o1l[(size_t)PTOT * CH];
__device__ __nv_bfloat16 g_hh [(size_t)PTOT * 512];
__device__ __nv_bfloat16 g_hl [(size_t)PTOT * 512];
__device__ __nv_bfloat16 g_wh[327680];
__device__ __nv_bfloat16 g_wl[327680];

__device__ __forceinline__ float gelu_f(float v) {
    return 0.5f * v * (1.0f + erff(v * 0.70710678118654752440f));
}
__device__ __forceinline__ void split_bf16(float v, __nv_bfloat16& h, __nv_bfloat16& l) {
    h = __float2bfloat16(v);
    l = __float2bfloat16(v - __bfloat162float(h));
}
__device__ __forceinline__ uint32_t smem_u32(const void* p) {
    uint32_t a;
    asm("{ .reg .u64 t; cvta.to.shared.u64 t, %1; cvt.u32.u64 %0, t; }" : "=r"(a) : "l"(p));
    return a;
}
__device__ __forceinline__ void ldmx4(uint32_t* r, uint32_t addr) {
    asm volatile("ldmatrix.sync.aligned.m8n8.x4.shared.b16 {%0,%1,%2,%3}, [%4];"
                 : "=r"(r[0]), "=r"(r[1]), "=r"(r[2]), "=r"(r[3]) : "r"(addr));
}
__device__ __forceinline__ void mma16816(float* c, const uint32_t* a, const uint32_t* b) {
    asm volatile("mma.sync.aligned.m16n8k16.row.col.f32.bf16.bf16.f32 "
                 "{%0,%1,%2,%3}, {%4,%5,%6,%7}, {%8,%9}, {%0,%1,%2,%3};"
                 : "+f"(c[0]), "+f"(c[1]), "+f"(c[2]), "+f"(c[3])
                 : "r"(a[0]), "r"(a[1]), "r"(a[2]), "r"(a[3]), "r"(b[0]), "r"(b[1]));
}

// ---------------- NCHW -> NHWC transpose (+ bf16 hi/lo split) ----------------
__global__ void k_nchw2nhwc(const float* __restrict__ x) {
    __shared__ float t[32][33];
    int b  = blockIdx.z;
    int p0 = blockIdx.x * 32, c0 = blockIdx.y * 32;
    int tx = threadIdx.x, ty = threadIdx.y;
    const float* xb = x + (size_t)b * CH * HWSZ;
#pragma unroll
    for (int i = 0; i < 4; i++)
        t[ty + 8 * i][tx] = xb[(size_t)(c0 + ty + 8 * i) * HWSZ + p0 + tx];
    __syncthreads();
    size_t base = (size_t)b * HWSZ * CH;
#pragma unroll
    for (int i = 0; i < 4; i++) {
        float v = t[tx][ty + 8 * i];
        size_t idx = base + (size_t)(p0 + ty + 8 * i) * CH + c0 + tx;
        g_xT[idx] = v;
        __nv_bfloat16 h, l; split_bf16(v, h, l);
        g_xTh[idx] = h; g_xTl[idx] = l;
    }
}

// ---------------- NHWC -> NCHW transpose ----------------
__global__ void k_nhwc2nchw(float* __restrict__ out) {
    __shared__ float t[32][33];
    int b  = blockIdx.z;
    int p0 = blockIdx.x * 32, c0 = blockIdx.y * 32;
    int tx = threadIdx.x, ty = threadIdx.y;
    const float* in = g_xT + (size_t)b * HWSZ * CH;
#pragma unroll
    for (int i = 0; i < 4; i++)
        t[ty + 8 * i][tx] = in[(size_t)(p0 + ty + 8 * i) * CH + c0 + tx];
    __syncthreads();
    float* ob = out + (size_t)b * CH * HWSZ;
#pragma unroll
    for (int i = 0; i < 4; i++)
        ob[(size_t)(c0 + ty + 8 * i) * HWSZ + p0 + tx] = t[tx][ty + 8 * i];
}

// ---------------- fp32 -> bf16 hi/lo split (weights only now) ----------------
__global__ void k_split(const float* __restrict__ s, __nv_bfloat16* __restrict__ h,
                        __nv_bfloat16* __restrict__ l, int n4) {
    int i = blockIdx.x * blockDim.x + threadIdx.x;
    if (i >= n4) return;
    float4 v = ((const float4*)s)[i];
    __nv_bfloat16 ha, la, hb, lb, hc, lc, hd, ld;
    split_bf16(v.x, ha, la); split_bf16(v.y, hb, lb);
    split_bf16(v.z, hc, lc); split_bf16(v.w, hd, ld);
    ((__nv_bfloat162*)h)[2 * i + 0] = __nv_bfloat162(ha, hb);
    ((__nv_bfloat162*)h)[2 * i + 1] = __nv_bfloat162(hc, hd);
    ((__nv_bfloat162*)l)[2 * i + 0] = __nv_bfloat162(la, lb);
    ((__nv_bfloat162*)l)[2 * i + 1] = __nv_bfloat162(lc, ld);
}

// ---------------- offset conv: 3x3 dilated, 18 out channels ----------------
template <int D>
__global__ void k_offconv(const float* __restrict__ x, const float* __restrict__ wt,
                          float* __restrict__ op_base) {
    __shared__ float sx[12][WW];
    __shared__ float sw[162];
    int t  = threadIdx.x;
    int h0 = blockIdx.x * 4;
    int b  = blockIdx.y;
    int cz = blockIdx.z;
    const float* xb = x + (size_t)b * CH * HWSZ;

    float acc[4][18];
#pragma unroll
    for (int r = 0; r < 4; r++)
#pragma unroll
        for (int o = 0; o < 18; o++) acc[r][o] = 0.f;

    for (int c = cz * 64; c < cz * 64 + 64; c++) {
        for (int i = t; i < 162; i += 128) {
            int o = i / 9, k = i % 9;
            sw[i] = wt[(size_t)o * CH * 9 + (size_t)c * 9 + k];
        }
        const float* xc = xb + (size_t)c * HWSZ;
#pragma unroll
        for (int rr = 0; rr < 12; rr++) {
            int g = rr >> 2, r = rr & 3;
            int row = h0 + r + (g - 1) * D;
            sx[rr][t] = (row >= 0 && row < HH) ? xc[row * WW + t] : 0.f;
        }
        __syncthreads();
#pragma unroll
        for (int ky = 0; ky < 3; ky++) {
#pragma unroll
            for (int kx = 0; kx < 3; kx++) {
                int col = t + (kx - 1) * D;
                float xr[4];
                bool ok = (col >= 0 && col < WW);
#pragma unroll
                for (int r = 0; r < 4; r++)
                    xr[r] = ok ? sx[ky * 4 + r][col] : 0.f;
#pragma unroll
                for (int o = 0; o < 18; o++) {
                    float wv = sw[o * 9 + ky * 3 + kx];
#pragma unroll
                    for (int r = 0; r < 4; r++) acc[r][o] += wv * xr[r];
                }
            }
        }
        __syncthreads();
    }
    float* op = op_base + (size_t)(cz * BATCH + b) * 18 * HWSZ;
#pragma unroll
    for (int o = 0; o < 18; o++)
#pragma unroll
        for (int r = 0; r < 4; r++)
            op[(size_t)o * HWSZ + (h0 + r) * WW + t] = acc[r][o];
}

// ---------------- fused: 3 deform branches + conv-acc + LN1 + bf16 split ----------------
// 256 threads = 8 warps; warp = one pixel (32 lanes x 8 channels)
__global__ void __launch_bounds__(256)
k_deform3(const float* __restrict__ dw0, const float* __restrict__ dw1,
          const float* __restrict__ dw2,
          const float* __restrict__ lw0, const float* __restrict__ lb0,
          const float* __restrict__ lw1, const float* __restrict__ lb1,
          const float* __restrict__ lw2, const float* __restrict__ lb2,
          const float* __restrict__ n1w, const float* __restrict__ n1b) {
    __shared__ float sdefT[3][9 * CH];   // [branch][k*CH + c]
    __shared__ int   sidx[8][36];
    __shared__ float swgt[8][36];

    int tid = threadIdx.x, wid = tid >> 5, lane = tid & 31;
    {
        const float* dws[3] = {dw0, dw1, dw2};
#pragma unroll
        for (int br = 0; br < 3; br++)
            for (int i = tid; i < 9 * CH; i += 256) {
                int c = i / 9, k = i % 9;
                sdefT[br][k * CH + c] = dws[br][i];
            }
    }
    __syncthreads();

    int pix = blockIdx.x * 8 + wid;
    int p = pix & (HWSZ - 1);
    int b = pix >> 14;
    int h = p >> 7, w = p & 127;
    int c0 = lane * 8;
    const float* xrow = g_xT + (size_t)b * HWSZ * CH;

    // seed with 1x1-conv result
    float sum[8];
    {
        const float4* ap = (const float4*)(g_acc + (size_t)pix * CH + c0);
        float4 a0 = ap[0], a1 = ap[1];
        sum[0] = a0.x; sum[1] = a0.y; sum[2] = a0.z; sum[3] = a0.w;
        sum[4] = a1.x; sum[5] = a1.y; sum[6] = a1.z; sum[7] = a1.w;
    }

    const int DS[3] = {1, 9, 12};
    const float* lws[3] = {lw0, lw1, lw2};
    const float* lbs[3] = {lb0, lb1, lb2};

#pragma unroll
    for (int br = 0; br < 3; br++) {
        int D = DS[br];
        if (lane < 9) {
            int k = lane, ky = k / 3, kx = k % 3;
            float oy = 0.f, ox = 0.f;
#pragma unroll
            for (int z = 0; z < 4; z++) {
                const float* op = g_offp + ((size_t)(br * 4 + z) * BATCH + b) * 18 * HWSZ;
                oy += op[(size_t)(2 * k) * HWSZ + p];
                ox += op[(size_t)(2 * k + 1) * HWSZ + p];
            }
            float py = (float)h + (float)((ky - 1) * D) + oy;
            float px = (float)w + (float)((kx - 1) * D) + ox;
            float y0 = floorf(py), x0 = floorf(px);
#pragma unroll
            for (int dy = 0; dy < 2; dy++)
#pragma unroll
                for (int dx = 0; dx < 2; dx++) {
                    float yc = y0 + dy, xc = x0 + dx;
                    float wq = (1.f - fabsf(py - yc)) * (1.f - fabsf(px - xc));
                    bool valid = (yc >= 0.f) && (yc < 128.f) && (xc >= 0.f) && (xc < 128.f);
                    int iy = min(max((int)yc, 0), 127);
                    int ix = min(max((int)xc, 0), 127);
                    sidx[wid][k * 4 + dy * 2 + dx] = iy * WW + ix;
                    swgt[wid][k * 4 + dy * 2 + dx] = valid ? wq : 0.f;
                }
        }
        __syncwarp();

        float facc[8];
#pragma unroll
        for (int r = 0; r < 8; r++) facc[r] = 0.f;
#pragma unroll
        for (int k = 0; k < 9; k++) {
            float4 wk0 = *(const float4*)&sdefT[br][k * CH + c0];
            float4 wk1 = *(const float4*)&sdefT[br][k * CH + c0 + 4];
            float s[8];
#pragma unroll
            for (int r = 0; r < 8; r++) s[r] = 0.f;
#pragma unroll
            for (int j = 0; j < 4; j++) {
                float wq = swgt[wid][k * 4 + j];
                if (wq != 0.f) {   // uniform across warp
                    const float4* vp = (const float4*)(xrow + (size_t)sidx[wid][k * 4 + j] * CH + c0);
                    float4 v0 = vp[0], v1 = vp[1];
                    s[0] += wq * v0.x; s[1] += wq * v0.y; s[2] += wq * v0.z; s[3] += wq * v0.w;
                    s[4] += wq * v1.x; s[5] += wq * v1.y; s[6] += wq * v1.z; s[7] += wq * v1.w;
                }
            }
            facc[0] += wk0.x * s[0]; facc[1] += wk0.y * s[1];
            facc[2] += wk0.z * s[2]; facc[3] += wk0.w * s[3];
            facc[4] += wk1.x * s[4]; facc[5] += wk1.y * s[5];
            facc[6] += wk1.z * s[6]; facc[7] += wk1.w * s[7];
        }

        // per-branch LN over 256 channels (in-warp)
        float ls = 0.f, lq = 0.f;
#pragma unroll
        for (int r = 0; r < 8; r++) { ls += facc[r]; lq += facc[r] * facc[r]; }
#pragma unroll
        for (int o = 16; o; o >>= 1) {
            ls += __shfl_xor_sync(0xffffffffu, ls, o);
            lq += __shfl_xor_sync(0xffffffffu, lq, o);
        }
        float mean = ls * (1.f / 256.f);
        float var  = lq * (1.f / 256.f) - mean * mean;
        float rstd = rsqrtf(var + LN_EPS);

        const float4* lwp = (const float4*)(lws[br] + c0);
        const float4* lbp = (const float4*)(lbs[br] + c0);
        float4 lw0v = lwp[0], lw1v = lwp[1], lb0v = lbp[0], lb1v = lbp[1];
        float lw[8] = {lw0v.x, lw0v.y, lw0v.z, lw0v.w, lw1v.x, lw1v.y, lw1v.z, lw1v.w};
        float lb[8] = {lb0v.x, lb0v.y, lb0v.z, lb0v.w, lb1v.x, lb1v.y, lb1v.z, lb1v.w};
#pragma unroll
        for (int r = 0; r < 8; r++)
            sum[r] += gelu_f(lw[r] * ((facc[r] - mean) * rstd) + lb[r]);
        __syncwarp();   // protect sidx/swgt reuse
    }

    // LN1 (in-warp) + fp32 + bf16 hi/lo outputs
    float ls = 0.f, lq = 0.f;
#pragma unroll
    for (int r = 0; r < 8; r++) { ls += sum[r]; lq += sum[r] * sum[r]; }
#pragma unroll
    for (int o = 16; o; o >>= 1) {
        ls += __shfl_xor_sync(0xffffffffu, ls, o);
        lq += __shfl_xor_sync(0xffffffffu, lq, o);
    }
    float mean = ls * (1.f / 256.f);
    float var  = lq * (1.f / 256.f) - mean * mean;
    float rstd = rsqrtf(var + LN_EPS);

    const float4* wp = (const float4*)(n1w + c0);
    const float4* bp = (const float4*)(n1b + c0);
    float4 w0v = wp[0], w1v = wp[1], b0v = bp[0], b1v = bp[1];
    float gw[8] = {w0v.x, w0v.y, w0v.z, w0v.w, w1v.x, w1v.y, w1v.z, w1v.w};
    float gb[8] = {b0v.x, b0v.y, b0v.z, b0v.w, b1v.x, b1v.y, b1v.z, b1v.w};

    float o[8];
    uint32_t hp[4], lp[4];
#pragma unroll
    for (int r = 0; r < 8; r++) o[r] = gw[r] * ((sum[r] - mean) * rstd) + gb[r];
#pragma unroll
    for (int r = 0; r < 8; r += 2) {
        __nv_bfloat16 h0, l0, h1, l1;
        split_bf16(o[r], h0, l0); split_bf16(o[r + 1], h1, l1);
        hp[r >> 1] = (uint32_t)__bfloat16_as_ushort(h0) | ((uint32_t)__bfloat16_as_ushort(h1) << 16);
        lp[r >> 1] = (uint32_t)__bfloat16_as_ushort(l0) | ((uint32_t)__bfloat16_as_ushort(l1) << 16);
    }
    float4* fo = (float4*)(g_out1 + (size_t)pix * CH + c0);
    fo[0] = make_float4(o[0], o[1], o[2], o[3]);
    fo[1] = make_float4(o[4], o[5], o[6], o[7]);
    *(uint4*)(g_o1h + (size_t)pix * CH + c0) = make_uint4(hp[0], hp[1], hp[2], hp[3]);
    *(uint4*)(g_o1l + (size_t)pix * CH + c0) = make_uint4(lp[0], lp[1], lp[2], lp[3]);
}

// ---------------- split-bf16 GEMM via mma.sync (HMMA) ----------------
template <int ACT, bool RES, bool BF16OUT>
__global__ void __launch_bounds__(256)
k_mmagemm(const __nv_bfloat16* __restrict__ Ah, const __nv_bfloat16* __restrict__ Al,
          const __nv_bfloat16* __restrict__ Bh, const __nv_bfloat16* __restrict__ Bl,
          const float* __restrict__ bias, const float* __restrict__ res,
          float* __restrict__ Cf, __nv_bfloat16* __restrict__ Chi,
          __nv_bfloat16* __restrict__ Clo, int N, int K) {
    __shared__ __nv_bfloat16 sA[2][128][40];
    __shared__ __nv_bfloat16 sB[2][128][40];

    int tid  = threadIdx.x;
    int wid  = tid >> 5, lane = tid & 31;
    int m0   = blockIdx.x * 128, n0 = blockIdx.y * 128;
    int wm   = (wid & 3) * 32;
    int wn   = (wid >> 2) * 64;

    float acc[2][8][4];
#pragma unroll
    for (int i = 0; i < 2; i++)
#pragma unroll
        for (int j = 0; j < 8; j++)
#pragma unroll
            for (int q = 0; q < 4; q++) acc[i][j][q] = 0.f;

    const __nv_bfloat16* srcs[4] = {Ah + (size_t)m0 * K, Al + (size_t)m0 * K,
                                    Bh + (size_t)n0 * K, Bl + (size_t)n0 * K};
    __nv_bfloat16* dsts[4] = {&sA[0][0][0], &sA[1][0][0], &sB[0][0][0], &sB[1][0][0]};

    int a_row8 = ((lane >> 3) & 1) * 8 + (lane & 7);
    int a_col8 = ((lane >> 4) & 1) * 8;
    int b_row8 = ((lane >> 4) & 1) * 8 + (lane & 7);
    int b_col8 = ((lane >> 3) & 1) * 8;

    int nk = K >> 5;
    for (int kc = 0; kc < nk; kc++) {
#pragma unroll
        for (int t = 0; t < 4; t++) {
            const __nv_bfloat16* s = srcs[t] + kc * 32;
#pragma unroll
            for (int u = 0; u < 2; u++) {
                int idx = u * 256 + tid;
                int row = idx >> 2, ch = idx & 3;
                uint4 v = *(const uint4*)(s + (size_t)row * K + ch * 8);
                *(uint4*)(dsts[t] + row * 40 + ch * 8) = v;
            }
        }
        __syncthreads();
#pragma unroll
        for (int ks = 0; ks < 2; ks++) {
            uint32_t af[2][2][4];
#pragma unroll
            for (int hl = 0; hl < 2; hl++)
#pragma unroll
                for (int mi = 0; mi < 2; mi++) {
                    uint32_t ad = smem_u32(&sA[hl][wm + mi * 16 + a_row8][ks * 16 + a_col8]);
                    ldmx4(af[hl][mi], ad);
                }
            uint32_t bf[2][4][4];
#pragma unroll
            for (int hl = 0; hl < 2; hl++)
#pragma unroll
                for (int jp = 0; jp < 4; jp++) {
                    uint32_t ad = smem_u32(&sB[hl][wn + jp * 16 + b_row8][ks * 16 + b_col8]);
                    ldmx4(bf[hl][jp], ad);
                }
#pragma unroll
            for (int mi = 0; mi < 2; mi++)
#pragma unroll
                for (int j = 0; j < 8; j++) {
                    int jp = j >> 1, hB = (j & 1) * 2;
                    uint32_t bh2[2] = {bf[0][jp][hB], bf[0][jp][hB + 1]};
                    uint32_t bl2[2] = {bf[1][jp][hB], bf[1][jp][hB + 1]};
                    mma16816(acc[mi][j], af[0][mi], bh2);
                    mma16816(acc[mi][j], af[0][mi], bl2);
                    mma16816(acc[mi][j], af[1][mi], bh2);
                }
        }
        __syncthreads();
    }

    int g = lane >> 2, q = lane & 3;
#pragma unroll
    for (int mi = 0; mi < 2; mi++) {
#pragma unroll
        for (int half = 0; half < 2; half++) {
            int m = m0 + wm + mi * 16 + g + half * 8;
#pragma unroll
            for (int j = 0; j < 8; j++) {
                int n = n0 + wn + j * 8 + q * 2;
                float v0 = acc[mi][j][half * 2 + 0] + __ldg(bias + n);
                float v1 = acc[mi][j][half * 2 + 1] + __ldg(bias + n + 1);
                if (ACT == 1) { v0 = gelu_f(v0); v1 = gelu_f(v1); }
                if (RES) {
                    const float2 rv = *(const float2*)(res + (size_t)m * N + n);
                    v0 += rv.x; v1 += rv.y;
                }
                if (BF16OUT) {
                    __nv_bfloat16 h0, l0, h1, l1;
                    split_bf16(v0, h0, l0); split_bf16(v1, h1, l1);
                    *(__nv_bfloat162*)(Chi + (size_t)m * N + n) = __nv_bfloat162(h0, h1);
                    *(__nv_bfloat162*)(Clo + (size_t)m * N + n) = __nv_bfloat162(l0, l1);
                } else {
                    *(float2*)(Cf + (size_t)m * N + n) = make_float2(v0, v1);
                }
            }
        }
    }
}

// ---------------- per-pixel LayerNorm (LN2) ----------------
__global__ void k_ln(const float* __restrict__ in, float* __restrict__ out,
                     const float* __restrict__ gw, const float* __restrict__ gb) {
    int lane = threadIdx.x & 31;
    size_t pix = (size_t)blockIdx.x * 8 + (threadIdx.x >> 5);
    const float4* r = (const float4*)(in + pix * CH) + lane * 2;
    float4 v0 = r[0], v1 = r[1];
    float s = v0.x + v0.y + v0.z + v0.w + v1.x + v1.y + v1.z + v1.w;
    float q = v0.x * v0.x + v0.y * v0.y + v0.z * v0.z + v0.w * v0.w +
              v1.x * v1.x + v1.y * v1.y + v1.z * v1.z + v1.w * v1.w;
#pragma unroll
    for (int o = 16; o; o >>= 1) {
        s += __shfl_xor_sync(0xffffffffu, s, o);
        q += __shfl_xor_sync(0xffffffffu, q, o);
    }
    float mean = s * (1.f / 256.f);
    float var  = q * (1.f / 256.f) - mean * mean;
    float rstd = rsqrtf(var + LN_EPS);
    int c = lane * 8;
    float4 o0, o1;
    o0.x = gw[c + 0] * ((v0.x - mean) * rstd) + gb[c + 0];
    o0.y = gw[c + 1] * ((v0.y - mean) * rstd) + gb[c + 1];
    o0.z = gw[c + 2] * ((v0.z - mean) * rstd) + gb[c + 2];
    o0.w = gw[c + 3] * ((v0.w - mean) * rstd) + gb[c + 3];
    o1.x = gw[c + 4] * ((v1.x - mean) * rstd) + gb[c + 4];
    o1.y = gw[c + 5] * ((v1.y - mean) * rstd) + gb[c + 5];
    o1.z = gw[c + 6] * ((v1.z - mean) * rstd) + gb[c + 6];
    o1.w = gw[c + 7] * ((v1.w - mean) * rstd) + gb[c + 7];
    float4* wptr = (float4*)(out + pix * CH) + lane * 2;
    wptr[0] = o0; wptr[1] = o1;
}

// ---------------- launch ----------------
extern "C" void kernel_launch(void* const* d_in, const int* in_sizes, int n_in,
                              void* d_out, int out_size) {
    const float* x       = (const float*)d_in[0];
    const float* off_w1  = (const float*)d_in[1];
    const float* def_w1  = (const float*)d_in[2];
    const float* bw1     = (const float*)d_in[3];
    const float* bb1     = (const float*)d_in[4];
    const float* off_w2  = (const float*)d_in[5];
    const float* def_w2  = (const float*)d_in[6];
    const float* bw2     = (const float*)d_in[7];
    const float* bb2     = (const float*)d_in[8];
    const float* off_w3  = (const float*)d_in[9];
    const float* def_w3  = (const float*)d_in[10];
    const float* bw3     = (const float*)d_in[11];
    const float* bb3     = (const float*)d_in[12];
    const float* conv_w  = (const float*)d_in[13];
    const float* conv_b  = (const float*)d_in[14];
    const float* n1_w    = (const float*)d_in[15];
    const float* n1_b    = (const float*)d_in[16];
    const float* n2_w    = (const float*)d_in[17];
    const float* n2_b    = (const float*)d_in[18];
    const float* mlp_w1  = (const float*)d_in[19];
    const float* mlp_b1  = (const float*)d_in[20];
    const float* mlp_w2  = (const float*)d_in[21];
    const float* mlp_b2  = (const float*)d_in[22];

    float *pxT, *pacc, *pout1, *pt2, *poffp;
    __nv_bfloat16 *pxTh, *pxTl, *po1h, *po1l, *phh, *phl, *pwh, *pwl;
    cudaGetSymbolAddress((void**)&pxT,   g_xT);
    cudaGetSymbolAddress((void**)&pacc,  g_acc);
    cudaGetSymbolAddress((void**)&pout1, g_out1);
    cudaGetSymbolAddress((void**)&pt2,   g_t2);
    cudaGetSymbolAddress((void**)&poffp, g_offp);
    cudaGetSymbolAddress((void**)&pxTh,  g_xTh);
    cudaGetSymbolAddress((void**)&pxTl,  g_xTl);
    cudaGetSymbolAddress((void**)&po1h,  g_o1h);
    cudaGetSymbolAddress((void**)&po1l,  g_o1l);
    cudaGetSymbolAddress((void**)&phh,   g_hh);
    cudaGetSymbolAddress((void**)&phl,   g_hl);
    cudaGetSymbolAddress((void**)&pwh,   g_wh);
    cudaGetSymbolAddress((void**)&pwl,   g_wl);

    const size_t OFFB = (size_t)4 * BATCH * 18 * HWSZ;   // per-branch offp stride

    // 1. x -> NHWC (+ hi/lo split)
    k_nchw2nhwc<<<dim3(HWSZ / 32, CH / 32, BATCH), dim3(32, 8)>>>(x);
    // 2. weight splits
    k_split<<<(65536 / 4 + 255) / 256, 256>>>(conv_w, pwh, pwl, 65536 / 4);
    k_split<<<(131072 / 4 + 255) / 256, 256>>>(mlp_w1, pwh + 65536, pwl + 65536, 131072 / 4);
    k_split<<<(131072 / 4 + 255) / 256, 256>>>(mlp_w2, pwh + 196608, pwl + 196608, 131072 / 4);
    // 3. conv1x1: acc = xT @ conv_w^T + conv_b
    k_mmagemm<0, false, false><<<dim3(PTOT / 128, CH / 128), 256>>>(
        pxTh, pxTl, pwh, pwl, conv_b, nullptr, pacc, nullptr, nullptr, CH, CH);
    // 4. offset convs (all three, then single fused deform)
    k_offconv<1><<<dim3(HH / 4, BATCH, 4), 128>>>(x, off_w1, poffp + 0 * OFFB);
    k_offconv<9><<<dim3(HH / 4, BATCH, 4), 128>>>(x, off_w2, poffp + 1 * OFFB);
    k_offconv<12><<<dim3(HH / 4, BATCH, 4), 128>>>(x, off_w3, poffp + 2 * OFFB);
    // 5. fused deform x3 + LN1 + split
    k_deform3<<<PTOT / 8, 256>>>(def_w1, def_w2, def_w3,
                                 bw1, bb1, bw2, bb2, bw3, bb3, n1_w, n1_b);
    // 6. MLP1 (bias+GELU, bf16 hi/lo out)
    k_mmagemm<1, false, true><<<dim3(PTOT / 128, 512 / 128), 256>>>(
        po1h, po1l, pwh + 65536, pwl + 65536, mlp_b1, nullptr,
        nullptr, phh, phl, 512, CH);
    // 7. MLP2 (bias + residual out1)
    k_mmagemm<0, true, false><<<dim3(PTOT / 128, CH / 128), 256>>>(
        phh, phl, pwh + 196608, pwl + 196608, mlp_b2, pout1,
        pt2, nullptr, nullptr, CH, 512);
    // 8. LN2 -> g_xT (reuse), transpose out
    k_ln<<<PTOT / 8, 256>>>(pt2, pxT, n2_w, n2_b);
    k_nhwc2nchw<<<dim3(HWSZ / 32, CH / 32, BATCH), dim3(32, 8)>>>((float*)d_out);
}

// round 7
// speedup vs baseline: 1.8190x; 1.1934x over previous
#include <cuda_runtime.h>
#include <cuda_bf16.h>
#include <math.h>
#include <stdint.h>

#define BATCH 2
#define CH    256
#define HH    128
#define WW    128
#define HWSZ  16384
#define PTOT  32768
#define LN_EPS 1e-6f

// ---------------- scratch ----------------
__device__ float g_xT  [(size_t)PTOT * CH];
__device__ float g_acc [(size_t)PTOT * CH];
__device__ float g_out1[(size_t)PTOT * CH];
__device__ float g_t2  [(size_t)PTOT * CH];
__device__ float g_offp[(size_t)3 * BATCH * 18 * HWSZ];   // [branch][b][18][HW]
__device__ __nv_bfloat16 g_xTh[(size_t)PTOT * CH];
__device__ __nv_bfloat16 g_xTl[(size_t)PTOT * CH];
__device__ __nv_bfloat16 g_o1h[(size_t)PTOT * CH];
__device__ __nv_bfloat16 g_o1l[(size_t)PTOT * CH];
__device__ __nv_bfloat16 g_hh [(size_t)PTOT * 512];
__device__ __nv_bfloat16 g_hl [(size_t)PTOT * 512];
__device__ __nv_bfloat16 g_wh[327680];
__device__ __nv_bfloat16 g_wl[327680];
// offset-conv weights reorganized: [3][32(padded o)][9*256 (k-major, c-minor)]
__device__ __nv_bfloat16 g_owh[3 * 32 * 2304];
__device__ __nv_bfloat16 g_owl[3 * 32 * 2304];

__device__ __forceinline__ float gelu_f(float v) {
    return 0.5f * v * (1.0f + erff(v * 0.70710678118654752440f));
}
__device__ __forceinline__ void split_bf16(float v, __nv_bfloat16& h, __nv_bfloat16& l) {
    h = __float2bfloat16(v);
    l = __float2bfloat16(v - __bfloat162float(h));
}
__device__ __forceinline__ uint32_t smem_u32(const void* p) {
    uint32_t a;
    asm("{ .reg .u64 t; cvta.to.shared.u64 t, %1; cvt.u32.u64 %0, t; }" : "=r"(a) : "l"(p));
    return a;
}
__device__ __forceinline__ void ldmx4(uint32_t* r, uint32_t addr) {
    asm volatile("ldmatrix.sync.aligned.m8n8.x4.shared.b16 {%0,%1,%2,%3}, [%4];"
                 : "=r"(r[0]), "=r"(r[1]), "=r"(r[2]), "=r"(r[3]) : "r"(addr));
}
__device__ __forceinline__ void mma16816(float* c, const uint32_t* a, const uint32_t* b) {
    asm volatile("mma.sync.aligned.m16n8k16.row.col.f32.bf16.bf16.f32 "
                 "{%0,%1,%2,%3}, {%4,%5,%6,%7}, {%8,%9}, {%0,%1,%2,%3};"
                 : "+f"(c[0]), "+f"(c[1]), "+f"(c[2]), "+f"(c[3])
                 : "r"(a[0]), "r"(a[1]), "r"(a[2]), "r"(a[3]), "r"(b[0]), "r"(b[1]));
}
__device__ __forceinline__ void cp16(uint32_t dst, const void* src) {
    asm volatile("cp.async.ca.shared.global [%0], [%1], 16;" :: "r"(dst), "l"(src));
}
__device__ __forceinline__ void cp16z(uint32_t dst, const void* src, bool valid) {
    int sz = valid ? 16 : 0;   // zero-fill when invalid
    asm volatile("cp.async.ca.shared.global [%0], [%1], 16, %2;"
                 :: "r"(dst), "l"(src), "r"(sz));
}
#define CP_COMMIT() asm volatile("cp.async.commit_group;" ::: "memory")
#define CP_WAIT0()  asm volatile("cp.async.wait_group 0;" ::: "memory")

// ---------------- NCHW -> NHWC transpose (+ bf16 hi/lo split) ----------------
__global__ void k_nchw2nhwc(const float* __restrict__ x) {
    __shared__ float t[32][33];
    int b  = blockIdx.z;
    int p0 = blockIdx.x * 32, c0 = blockIdx.y * 32;
    int tx = threadIdx.x, ty = threadIdx.y;
    const float* xb = x + (size_t)b * CH * HWSZ;
#pragma unroll
    for (int i = 0; i < 4; i++)
        t[ty + 8 * i][tx] = xb[(size_t)(c0 + ty + 8 * i) * HWSZ + p0 + tx];
    __syncthreads();
    size_t base = (size_t)b * HWSZ * CH;
#pragma unroll
    for (int i = 0; i < 4; i++) {
        float v = t[tx][ty + 8 * i];
        size_t idx = base + (size_t)(p0 + ty + 8 * i) * CH + c0 + tx;
        g_xT[idx] = v;
        __nv_bfloat16 h, l; split_bf16(v, h, l);
        g_xTh[idx] = h; g_xTl[idx] = l;
    }
}

// ---------------- NHWC -> NCHW transpose ----------------
__global__ void k_nhwc2nchw(float* __restrict__ out) {
    __shared__ float t[32][33];
    int b  = blockIdx.z;
    int p0 = blockIdx.x * 32, c0 = blockIdx.y * 32;
    int tx = threadIdx.x, ty = threadIdx.y;
    const float* in = g_xT + (size_t)b * HWSZ * CH;
#pragma unroll
    for (int i = 0; i < 4; i++)
        t[ty + 8 * i][tx] = in[(size_t)(p0 + ty + 8 * i) * CH + c0 + tx];
    __syncthreads();
    float* ob = out + (size_t)b * CH * HWSZ;
#pragma unroll
    for (int i = 0; i < 4; i++)
        ob[(size_t)(c0 + ty + 8 * i) * HWSZ + p0 + tx] = t[tx][ty + 8 * i];
}

// ---------------- fp32 -> bf16 hi/lo split (weights) ----------------
__global__ void k_split(const float* __restrict__ s, __nv_bfloat16* __restrict__ h,
                        __nv_bfloat16* __restrict__ l, int n4) {
    int i = blockIdx.x * blockDim.x + threadIdx.x;
    if (i >= n4) return;
    float4 v = ((const float4*)s)[i];
    __nv_bfloat16 ha, la, hb, lb, hc, lc, hd, ld;
    split_bf16(v.x, ha, la); split_bf16(v.y, hb, lb);
    split_bf16(v.z, hc, lc); split_bf16(v.w, hd, ld);
    ((__nv_bfloat162*)h)[2 * i + 0] = __nv_bfloat162(ha, hb);
    ((__nv_bfloat162*)h)[2 * i + 1] = __nv_bfloat162(hc, hd);
    ((__nv_bfloat162*)l)[2 * i + 0] = __nv_bfloat162(la, lb);
    ((__nv_bfloat162*)l)[2 * i + 1] = __nv_bfloat162(lc, ld);
}

// ---------------- offset-conv weight reorg: [18][256][9] -> [3][32][k*256+c] hi/lo ----------------
__global__ void k_owprep(const float* __restrict__ w0, const float* __restrict__ w1,
                         const float* __restrict__ w2) {
    int i = blockIdx.x * blockDim.x + threadIdx.x;
    if (i >= 3 * 32 * 2304) return;
    int br = i / (32 * 2304);
    int r  = i % (32 * 2304);
    int o  = r / 2304;
    int kk = r % 2304;
    int k  = kk / 256, c = kk % 256;
    const float* w = (br == 0) ? w0 : (br == 1) ? w1 : w2;
    float v = (o < 18) ? w[((size_t)o * 256 + c) * 9 + k] : 0.f;
    __nv_bfloat16 h, l; split_bf16(v, h, l);
    g_owh[i] = h; g_owl[i] = l;
}

// ---------------- offset conv via HMMA: block = one image row (128 px), N=32(18), K=2304 ----------------
// branch = blockIdx.y; dyn smem: 2 stages x (A hi/lo 128x40 + B hi/lo 32x40)
#define OFF_A_ARR (128 * 40)
#define OFF_B_ARR (32 * 40)
#define OFF_STG   (2 * OFF_A_ARR + 2 * OFF_B_ARR)
#define OFF_SMEM  (2 * OFF_STG * 2)   // bytes

__global__ void __launch_bounds__(256)
k_offmma() {
    extern __shared__ char dsm_[];
    __nv_bfloat16* sm = (__nv_bfloat16*)dsm_;

    int tid = threadIdx.x, wid = tid >> 5, lane = tid & 31;
    int bx = blockIdx.x, br = blockIdx.y;
    int h = bx & 127, b = bx >> 7;
    const int D = (br == 0) ? 1 : (br == 1) ? 9 : 12;

    const __nv_bfloat16* xh = g_xTh + (size_t)b * HWSZ * CH;
    const __nv_bfloat16* xl = g_xTl + (size_t)b * HWSZ * CH;
    const __nv_bfloat16* wbh = g_owh + (size_t)br * 32 * 2304;
    const __nv_bfloat16* wbl = g_owl + (size_t)br * 32 * 2304;

    float acc[4][4];
#pragma unroll
    for (int j = 0; j < 4; j++)
#pragma unroll
        for (int q = 0; q < 4; q++) acc[j][q] = 0.f;

    auto load_stage = [&](int kc, int s) {
        __nv_bfloat16* base = sm + s * OFF_STG;
        uint32_t sAh = smem_u32(base);
        uint32_t sAl = sAh + OFF_A_ARR * 2;
        uint32_t sBh = sAl + OFF_A_ARR * 2;
        uint32_t sBl = sBh + OFF_B_ARR * 2;
        int k  = kc >> 3;
        int cc = (kc & 7) * 32;
        int dy = (k / 3 - 1) * D, dx = (k % 3 - 1) * D;
        int srow = h + dy;
        bool vy = (srow >= 0) && (srow < HH);
        int srowc = vy ? srow : 0;
#pragma unroll
        for (int u = 0; u < 2; u++) {
            int idx = u * 256 + tid;
            int w = idx >> 2, ch = idx & 3;
            int wp = w + dx;
            bool v = vy && (wp >= 0) && (wp < WW);
            int wpc = v ? wp : 0;
            size_t goff = (size_t)(srowc * WW + wpc) * CH + cc + ch * 8;
            uint32_t soff = (uint32_t)(w * 40 + ch * 8) * 2;
            cp16z(sAh + soff, xh + goff, v);
            cp16z(sAl + soff, xl + goff, v);
        }
        if (tid < 128) {
            int o = tid >> 2, ch = tid & 3;
            size_t goff = (size_t)o * 2304 + k * 256 + cc + ch * 8;
            uint32_t soff = (uint32_t)(o * 40 + ch * 8) * 2;
            cp16(sBh + soff, wbh + goff);
            cp16(sBl + soff, wbl + goff);
        }
    };

    int a_row8 = ((lane >> 3) & 1) * 8 + (lane & 7);
    int a_col8 = ((lane >> 4) & 1) * 8;
    int b_row8 = ((lane >> 4) & 1) * 8 + (lane & 7);
    int b_col8 = ((lane >> 3) & 1) * 8;

    load_stage(0, 0); CP_COMMIT();
    CP_WAIT0(); __syncthreads();

    const int NK = 72;
    for (int kc = 0; kc < NK; kc++) {
        int cur = kc & 1;
        if (kc + 1 < NK) { load_stage(kc + 1, cur ^ 1); CP_COMMIT(); }

        __nv_bfloat16* base = sm + cur * OFF_STG;
        __nv_bfloat16* pAh = base;
        __nv_bfloat16* pAl = base + OFF_A_ARR;
        __nv_bfloat16* pBh = base + 2 * OFF_A_ARR;
        __nv_bfloat16* pBl = base + 2 * OFF_A_ARR + OFF_B_ARR;
#pragma unroll
        for (int ks = 0; ks < 2; ks++) {
            uint32_t af[2][4];
            ldmx4(af[0], smem_u32(pAh + (wid * 16 + a_row8) * 40 + ks * 16 + a_col8));
            ldmx4(af[1], smem_u32(pAl + (wid * 16 + a_row8) * 40 + ks * 16 + a_col8));
            uint32_t bfr[2][2][4];
#pragma unroll
            for (int jp = 0; jp < 2; jp++) {
                ldmx4(bfr[0][jp], smem_u32(pBh + (jp * 16 + b_row8) * 40 + ks * 16 + b_col8));
                ldmx4(bfr[1][jp], smem_u32(pBl + (jp * 16 + b_row8) * 40 + ks * 16 + b_col8));
            }
#pragma unroll
            for (int j = 0; j < 4; j++) {
                int jp = j >> 1, hB = (j & 1) * 2;
                uint32_t bh2[2] = {bfr[0][jp][hB], bfr[0][jp][hB + 1]};
                uint32_t bl2[2] = {bfr[1][jp][hB], bfr[1][jp][hB + 1]};
                mma16816(acc[j], af[0], bh2);
                mma16816(acc[j], af[0], bl2);
                mma16816(acc[j], af[1], bh2);
            }
        }
        if (kc + 1 < NK) CP_WAIT0();
        __syncthreads();
    }

    // store: offsets [br][b][18][HWSZ]
    float* op = g_offp + (size_t)(br * BATCH + b) * 18 * HWSZ;
    int g = lane >> 2, q = lane & 3;
#pragma unroll
    for (int half = 0; half < 2; half++) {
        int wcol = wid * 16 + g + half * 8;   // pixel column in this row
        int pimg = h * WW + wcol;
#pragma unroll
        for (int j = 0; j < 4; j++) {
#pragma unroll
            for (int e = 0; e < 2; e++) {
                int n = j * 8 + q * 2 + e;
                if (n < 18) op[(size_t)n * HWSZ + pimg] = acc[j][half * 2 + e];
            }
        }
    }
}

// ---------------- fused: 3 deform branches + conv-acc + LN1 + bf16 split ----------------
__global__ void __launch_bounds__(256)
k_deform3(const float* __restrict__ dw0, const float* __restrict__ dw1,
          const float* __restrict__ dw2,
          const float* __restrict__ lw0, const float* __restrict__ lb0,
          const float* __restrict__ lw1, const float* __restrict__ lb1,
          const float* __restrict__ lw2, const float* __restrict__ lb2,
          const float* __restrict__ n1w, const float* __restrict__ n1b) {
    __shared__ float sdefT[3][9 * CH];
    __shared__ int   sidx[8][36];
    __shared__ float swgt[8][36];

    int tid = threadIdx.x, wid = tid >> 5, lane = tid & 31;
    {
        const float* dws[3] = {dw0, dw1, dw2};
#pragma unroll
        for (int br = 0; br < 3; br++)
            for (int i = tid; i < 9 * CH; i += 256) {
                int c = i / 9, k = i % 9;
                sdefT[br][k * CH + c] = dws[br][i];
            }
    }
    __syncthreads();

    int pix = blockIdx.x * 8 + wid;
    int p = pix & (HWSZ - 1);
    int b = pix >> 14;
    int h = p >> 7, w = p & 127;
    int c0 = lane * 8;
    const float* xrow = g_xT + (size_t)b * HWSZ * CH;

    float sum[8];
    {
        const float4* ap = (const float4*)(g_acc + (size_t)pix * CH + c0);
        float4 a0 = ap[0], a1 = ap[1];
        sum[0] = a0.x; sum[1] = a0.y; sum[2] = a0.z; sum[3] = a0.w;
        sum[4] = a1.x; sum[5] = a1.y; sum[6] = a1.z; sum[7] = a1.w;
    }

    const int DS[3] = {1, 9, 12};
    const float* lws[3] = {lw0, lw1, lw2};
    const float* lbs[3] = {lb0, lb1, lb2};

#pragma unroll
    for (int br = 0; br < 3; br++) {
        int D = DS[br];
        if (lane < 9) {
            int k = lane, ky = k / 3, kx = k % 3;
            const float* op = g_offp + (size_t)(br * BATCH + b) * 18 * HWSZ;
            float oy = op[(size_t)(2 * k) * HWSZ + p];
            float ox = op[(size_t)(2 * k + 1) * HWSZ + p];
            float py = (float)h + (float)((ky - 1) * D) + oy;
            float px = (float)w + (float)((kx - 1) * D) + ox;
            float y0 = floorf(py), x0 = floorf(px);
#pragma unroll
            for (int dy = 0; dy < 2; dy++)
#pragma unroll
                for (int dx = 0; dx < 2; dx++) {
                    float yc = y0 + dy, xc = x0 + dx;
                    float wq = (1.f - fabsf(py - yc)) * (1.f - fabsf(px - xc));
                    bool valid = (yc >= 0.f) && (yc < 128.f) && (xc >= 0.f) && (xc < 128.f);
                    int iy = min(max((int)yc, 0), 127);
                    int ix = min(max((int)xc, 0), 127);
                    sidx[wid][k * 4 + dy * 2 + dx] = iy * WW + ix;
                    swgt[wid][k * 4 + dy * 2 + dx] = valid ? wq : 0.f;
                }
        }
        __syncwarp();

        float facc[8];
#pragma unroll
        for (int r = 0; r < 8; r++) facc[r] = 0.f;
#pragma unroll
        for (int k = 0; k < 9; k++) {
            float4 wk0 = *(const float4*)&sdefT[br][k * CH + c0];
            float4 wk1 = *(const float4*)&sdefT[br][k * CH + c0 + 4];
            float s[8];
#pragma unroll
            for (int r = 0; r < 8; r++) s[r] = 0.f;
#pragma unroll
            for (int j = 0; j < 4; j++) {
                float wq = swgt[wid][k * 4 + j];
                if (wq != 0.f) {
                    const float4* vp = (const float4*)(xrow + (size_t)sidx[wid][k * 4 + j] * CH + c0);
                    float4 v0 = vp[0], v1 = vp[1];
                    s[0] += wq * v0.x; s[1] += wq * v0.y; s[2] += wq * v0.z; s[3] += wq * v0.w;
                    s[4] += wq * v1.x; s[5] += wq * v1.y; s[6] += wq * v1.z; s[7] += wq * v1.w;
                }
            }
            facc[0] += wk0.x * s[0]; facc[1] += wk0.y * s[1];
            facc[2] += wk0.z * s[2]; facc[3] += wk0.w * s[3];
            facc[4] += wk1.x * s[4]; facc[5] += wk1.y * s[5];
            facc[6] += wk1.z * s[6]; facc[7] += wk1.w * s[7];
        }

        float ls = 0.f, lq = 0.f;
#pragma unroll
        for (int r = 0; r < 8; r++) { ls += facc[r]; lq += facc[r] * facc[r]; }
#pragma unroll
        for (int o = 16; o; o >>= 1) {
            ls += __shfl_xor_sync(0xffffffffu, ls, o);
            lq += __shfl_xor_sync(0xffffffffu, lq, o);
        }
        float mean = ls * (1.f / 256.f);
        float var  = lq * (1.f / 256.f) - mean * mean;
        float rstd = rsqrtf(var + LN_EPS);

        const float4* lwp = (const float4*)(lws[br] + c0);
        const float4* lbp = (const float4*)(lbs[br] + c0);
        float4 lw0v = lwp[0], lw1v = lwp[1], lb0v = lbp[0], lb1v = lbp[1];
        float lw[8] = {lw0v.x, lw0v.y, lw0v.z, lw0v.w, lw1v.x, lw1v.y, lw1v.z, lw1v.w};
        float lb[8] = {lb0v.x, lb0v.y, lb0v.z, lb0v.w, lb1v.x, lb1v.y, lb1v.z, lb1v.w};
#pragma unroll
        for (int r = 0; r < 8; r++)
            sum[r] += gelu_f(lw[r] * ((facc[r] - mean) * rstd) + lb[r]);
        __syncwarp();
    }

    float ls = 0.f, lq = 0.f;
#pragma unroll
    for (int r = 0; r < 8; r++) { ls += sum[r]; lq += sum[r] * sum[r]; }
#pragma unroll
    for (int o = 16; o; o >>= 1) {
        ls += __shfl_xor_sync(0xffffffffu, ls, o);
        lq += __shfl_xor_sync(0xffffffffu, lq, o);
    }
    float mean = ls * (1.f / 256.f);
    float var  = lq * (1.f / 256.f) - mean * mean;
    float rstd = rsqrtf(var + LN_EPS);

    const float4* wp = (const float4*)(n1w + c0);
    const float4* bp = (const float4*)(n1b + c0);
    float4 w0v = wp[0], w1v = wp[1], b0v = bp[0], b1v = bp[1];
    float gw[8] = {w0v.x, w0v.y, w0v.z, w0v.w, w1v.x, w1v.y, w1v.z, w1v.w};
    float gb[8] = {b0v.x, b0v.y, b0v.z, b0v.w, b1v.x, b1v.y, b1v.z, b1v.w};

    float o[8];
    uint32_t hp[4], lp[4];
#pragma unroll
    for (int r = 0; r < 8; r++) o[r] = gw[r] * ((sum[r] - mean) * rstd) + gb[r];
#pragma unroll
    for (int r = 0; r < 8; r += 2) {
        __nv_bfloat16 h0, l0, h1, l1;
        split_bf16(o[r], h0, l0); split_bf16(o[r + 1], h1, l1);
        hp[r >> 1] = (uint32_t)__bfloat16_as_ushort(h0) | ((uint32_t)__bfloat16_as_ushort(h1) << 16);
        lp[r >> 1] = (uint32_t)__bfloat16_as_ushort(l0) | ((uint32_t)__bfloat16_as_ushort(l1) << 16);
    }
    float4* fo = (float4*)(g_out1 + (size_t)pix * CH + c0);
    fo[0] = make_float4(o[0], o[1], o[2], o[3]);
    fo[1] = make_float4(o[4], o[5], o[6], o[7]);
    *(uint4*)(g_o1h + (size_t)pix * CH + c0) = make_uint4(hp[0], hp[1], hp[2], hp[3]);
    *(uint4*)(g_o1l + (size_t)pix * CH + c0) = make_uint4(lp[0], lp[1], lp[2], lp[3]);
}

// ---------------- split-bf16 GEMM via mma.sync, cp.async double-buffered ----------------
#define G_ARR (128 * 40)
#define G_STG (4 * G_ARR)
#define G_SMEM (2 * G_STG * 2)   // bytes = 81920

template <int ACT, bool RES, bool BF16OUT>
__global__ void __launch_bounds__(256)
k_mmagemm(const __nv_bfloat16* __restrict__ Ah, const __nv_bfloat16* __restrict__ Al,
          const __nv_bfloat16* __restrict__ Bh, const __nv_bfloat16* __restrict__ Bl,
          const float* __restrict__ bias, const float* __restrict__ res,
          float* __restrict__ Cf, __nv_bfloat16* __restrict__ Chi,
          __nv_bfloat16* __restrict__ Clo, int N, int K) {
    extern __shared__ char dsm_[];
    __nv_bfloat16* sm = (__nv_bfloat16*)dsm_;

    int tid  = threadIdx.x;
    int wid  = tid >> 5, lane = tid & 31;
    int m0   = blockIdx.x * 128, n0 = blockIdx.y * 128;
    int wm   = (wid & 3) * 32;
    int wn   = (wid >> 2) * 64;

    float acc[2][8][4];
#pragma unroll
    for (int i = 0; i < 2; i++)
#pragma unroll
        for (int j = 0; j < 8; j++)
#pragma unroll
            for (int q = 0; q < 4; q++) acc[i][j][q] = 0.f;

    const __nv_bfloat16* srcs[4] = {Ah + (size_t)m0 * K, Al + (size_t)m0 * K,
                                    Bh + (size_t)n0 * K, Bl + (size_t)n0 * K};

    auto load_stage = [&](int kc, int s) {
        __nv_bfloat16* base = sm + s * G_STG;
#pragma unroll
        for (int t = 0; t < 4; t++) {
            const __nv_bfloat16* src = srcs[t] + kc * 32;
            uint32_t dstb = smem_u32(base + t * G_ARR);
#pragma unroll
            for (int u = 0; u < 2; u++) {
                int idx = u * 256 + tid;
                int row = idx >> 2, ch = idx & 3;
                cp16(dstb + (uint32_t)(row * 40 + ch * 8) * 2,
                     src + (size_t)row * K + ch * 8);
            }
        }
    };

    int a_row8 = ((lane >> 3) & 1) * 8 + (lane & 7);
    int a_col8 = ((lane >> 4) & 1) * 8;
    int b_row8 = ((lane >> 4) & 1) * 8 + (lane & 7);
    int b_col8 = ((lane >> 3) & 1) * 8;

    load_stage(0, 0); CP_COMMIT();
    CP_WAIT0(); __syncthreads();

    int nk = K >> 5;
    for (int kc = 0; kc < nk; kc++) {
        int cur = kc & 1;
        if (kc + 1 < nk) { load_stage(kc + 1, cur ^ 1); CP_COMMIT(); }

        __nv_bfloat16* base = sm + cur * G_STG;
        __nv_bfloat16* pA[2] = {base, base + G_ARR};
        __nv_bfloat16* pB[2] = {base + 2 * G_ARR, base + 3 * G_ARR};
#pragma unroll
        for (int ks = 0; ks < 2; ks++) {
            uint32_t af[2][2][4];
#pragma unroll
            for (int hl = 0; hl < 2; hl++)
#pragma unroll
                for (int mi = 0; mi < 2; mi++)
                    ldmx4(af[hl][mi],
                          smem_u32(pA[hl] + (wm + mi * 16 + a_row8) * 40 + ks * 16 + a_col8));
            uint32_t bfr[2][4][4];
#pragma unroll
            for (int hl = 0; hl < 2; hl++)
#pragma unroll
                for (int jp = 0; jp < 4; jp++)
                    ldmx4(bfr[hl][jp],
                          smem_u32(pB[hl] + (wn + jp * 16 + b_row8) * 40 + ks * 16 + b_col8));
#pragma unroll
            for (int mi = 0; mi < 2; mi++)
#pragma unroll
                for (int j = 0; j < 8; j++) {
                    int jp = j >> 1, hB = (j & 1) * 2;
                    uint32_t bh2[2] = {bfr[0][jp][hB], bfr[0][jp][hB + 1]};
                    uint32_t bl2[2] = {bfr[1][jp][hB], bfr[1][jp][hB + 1]};
                    mma16816(acc[mi][j], af[0][mi], bh2);
                    mma16816(acc[mi][j], af[0][mi], bl2);
                    mma16816(acc[mi][j], af[1][mi], bh2);
                }
        }
        if (kc + 1 < nk) CP_WAIT0();
        __syncthreads();
    }

    int g = lane >> 2, q = lane & 3;
#pragma unroll
    for (int mi = 0; mi < 2; mi++) {
#pragma unroll
        for (int half = 0; half < 2; half++) {
            int m = m0 + wm + mi * 16 + g + half * 8;
#pragma unroll
            for (int j = 0; j < 8; j++) {
                int n = n0 + wn + j * 8 + q * 2;
                float v0 = acc[mi][j][half * 2 + 0] + __ldg(bias + n);
                float v1 = acc[mi][j][half * 2 + 1] + __ldg(bias + n + 1);
                if (ACT == 1) { v0 = gelu_f(v0); v1 = gelu_f(v1); }
                if (RES) {
                    const float2 rv = *(const float2*)(res + (size_t)m * N + n);
                    v0 += rv.x; v1 += rv.y;
                }
                if (BF16OUT) {
                    __nv_bfloat16 h0, l0, h1, l1;
                    split_bf16(v0, h0, l0); split_bf16(v1, h1, l1);
                    *(__nv_bfloat162*)(Chi + (size_t)m * N + n) = __nv_bfloat162(h0, h1);
                    *(__nv_bfloat162*)(Clo + (size_t)m * N + n) = __nv_bfloat162(l0, l1);
                } else {
                    *(float2*)(Cf + (size_t)m * N + n) = make_float2(v0, v1);
                }
            }
        }
    }
}

// ---------------- per-pixel LayerNorm (LN2) ----------------
__global__ void k_ln(const float* __restrict__ in, float* __restrict__ out,
                     const float* __restrict__ gw, const float* __restrict__ gb) {
    int lane = threadIdx.x & 31;
    size_t pix = (size_t)blockIdx.x * 8 + (threadIdx.x >> 5);
    const float4* r = (const float4*)(in + pix * CH) + lane * 2;
    float4 v0 = r[0], v1 = r[1];
    float s = v0.x + v0.y + v0.z + v0.w + v1.x + v1.y + v1.z + v1.w;
    float q = v0.x * v0.x + v0.y * v0.y + v0.z * v0.z + v0.w * v0.w +
              v1.x * v1.x + v1.y * v1.y + v1.z * v1.z + v1.w * v1.w;
#pragma unroll
    for (int o = 16; o; o >>= 1) {
        s += __shfl_xor_sync(0xffffffffu, s, o);
        q += __shfl_xor_sync(0xffffffffu, q, o);
    }
    float mean = s * (1.f / 256.f);
    float var  = q * (1.f / 256.f) - mean * mean;
    float rstd = rsqrtf(var + LN_EPS);
    int c = lane * 8;
    float4 o0, o1;
    o0.x = gw[c + 0] * ((v0.x - mean) * rstd) + gb[c + 0];
    o0.y = gw[c + 1] * ((v0.y - mean) * rstd) + gb[c + 1];
    o0.z = gw[c + 2] * ((v0.z - mean) * rstd) + gb[c + 2];
    o0.w = gw[c + 3] * ((v0.w - mean) * rstd) + gb[c + 3];
    o1.x = gw[c + 4] * ((v1.x - mean) * rstd) + gb[c + 4];
    o1.y = gw[c + 5] * ((v1.y - mean) * rstd) + gb[c + 5];
    o1.z = gw[c + 6] * ((v1.z - mean) * rstd) + gb[c + 6];
    o1.w = gw[c + 7] * ((v1.w - mean) * rstd) + gb[c + 7];
    float4* wptr = (float4*)(out + pix * CH) + lane * 2;
    wptr[0] = o0; wptr[1] = o1;
}

// ---------------- launch ----------------
extern "C" void kernel_launch(void* const* d_in, const int* in_sizes, int n_in,
                              void* d_out, int out_size) {
    const float* x       = (const float*)d_in[0];
    const float* off_w1  = (const float*)d_in[1];
    const float* def_w1  = (const float*)d_in[2];
    const float* bw1     = (const float*)d_in[3];
    const float* bb1     = (const float*)d_in[4];
    const float* off_w2  = (const float*)d_in[5];
    const float* def_w2  = (const float*)d_in[6];
    const float* bw2     = (const float*)d_in[7];
    const float* bb2     = (const float*)d_in[8];
    const float* off_w3  = (const float*)d_in[9];
    const float* def_w3  = (const float*)d_in[10];
    const float* bw3     = (const float*)d_in[11];
    const float* bb3     = (const float*)d_in[12];
    const float* conv_w  = (const float*)d_in[13];
    const float* conv_b  = (const float*)d_in[14];
    const float* n1_w    = (const float*)d_in[15];
    const float* n1_b    = (const float*)d_in[16];
    const float* n2_w    = (const float*)d_in[17];
    const float* n2_b    = (const float*)d_in[18];
    const float* mlp_w1  = (const float*)d_in[19];
    const float* mlp_b1  = (const float*)d_in[20];
    const float* mlp_w2  = (const float*)d_in[21];
    const float* mlp_b2  = (const float*)d_in[22];

    float *pxT, *pacc, *pout1, *pt2;
    __nv_bfloat16 *po1h, *po1l, *phh, *phl, *pwh, *pwl, *pxTh, *pxTl;
    cudaGetSymbolAddress((void**)&pxT,   g_xT);
    cudaGetSymbolAddress((void**)&pacc,  g_acc);
    cudaGetSymbolAddress((void**)&pout1, g_out1);
    cudaGetSymbolAddress((void**)&pt2,   g_t2);
    cudaGetSymbolAddress((void**)&pxTh,  g_xTh);
    cudaGetSymbolAddress((void**)&pxTl,  g_xTl);
    cudaGetSymbolAddress((void**)&po1h,  g_o1h);
    cudaGetSymbolAddress((void**)&po1l,  g_o1l);
    cudaGetSymbolAddress((void**)&phh,   g_hh);
    cudaGetSymbolAddress((void**)&phl,   g_hl);
    cudaGetSymbolAddress((void**)&pwh,   g_wh);
    cudaGetSymbolAddress((void**)&pwl,   g_wl);

    cudaFuncSetAttribute(k_mmagemm<0, false, false>,
                         cudaFuncAttributeMaxDynamicSharedMemorySize, G_SMEM);
    cudaFuncSetAttribute(k_mmagemm<1, false, true>,
                         cudaFuncAttributeMaxDynamicSharedMemorySize, G_SMEM);
    cudaFuncSetAttribute(k_mmagemm<0, true, false>,
                         cudaFuncAttributeMaxDynamicSharedMemorySize, G_SMEM);
    cudaFuncSetAttribute(k_offmma,
                         cudaFuncAttributeMaxDynamicSharedMemorySize, OFF_SMEM);

    // 1. x -> NHWC (+ hi/lo split)
    k_nchw2nhwc<<<dim3(HWSZ / 32, CH / 32, BATCH), dim3(32, 8)>>>(x);
    // 2. weight splits + offset-weight reorg
    k_split<<<(65536 / 4 + 255) / 256, 256>>>(conv_w, pwh, pwl, 65536 / 4);
    k_split<<<(131072 / 4 + 255) / 256, 256>>>(mlp_w1, pwh + 65536, pwl + 65536, 131072 / 4);
    k_split<<<(131072 / 4 + 255) / 256, 256>>>(mlp_w2, pwh + 196608, pwl + 196608, 131072 / 4);
    k_owprep<<<(3 * 32 * 2304 + 255) / 256, 256>>>(off_w1, off_w2, off_w3);
    // 3. conv1x1: acc = xT @ conv_w^T + conv_b
    k_mmagemm<0, false, false><<<dim3(PTOT / 128, CH / 128), 256, G_SMEM>>>(
        pxTh, pxTl, pwh, pwl, conv_b, nullptr, pacc, nullptr, nullptr, CH, CH);
    // 4. offset convs via HMMA (all 3 branches in one grid)
    k_offmma<<<dim3(PTOT / 128, 3), 256, OFF_SMEM>>>();
    // 5. fused deform x3 + LN1 + split
    k_deform3<<<PTOT / 8, 256>>>(def_w1, def_w2, def_w3,
                                 bw1, bb1, bw2, bb2, bw3, bb3, n1_w, n1_b);
    // 6. MLP1 (bias+GELU, bf16 hi/lo out)
    k_mmagemm<1, false, true><<<dim3(PTOT / 128, 512 / 128), 256, G_SMEM>>>(
        po1h, po1l, pwh + 65536, pwl + 65536, mlp_b1, nullptr,
        nullptr, phh, phl, 512, CH);
    // 7. MLP2 (bias + residual out1)
    k_mmagemm<0, true, false><<<dim3(PTOT / 128, CH / 128), 256, G_SMEM>>>(
        phh, phl, pwh + 196608, pwl + 196608, mlp_b2, pout1,
        pt2, nullptr, nullptr, CH, 512);
    // 8. LN2 -> g_xT (reuse), transpose out
    k_ln<<<PTOT / 8, 256>>>(pt2, pxT, n2_w, n2_b);
    k_nhwc2nchw<<<dim3(HWSZ / 32, CH / 32, BATCH), dim3(32, 8)>>>((float*)d_out);
}

// round 8
// speedup vs baseline: 1.8738x; 1.0301x over previous
#include <cuda_runtime.h>
#include <cuda_bf16.h>
#include <math.h>
#include <stdint.h>

#define BATCH 2
#define CH    256
#define HH    128
#define WW    128
#define HWSZ  16384
#define PTOT  32768
#define LN_EPS 1e-6f

// ---------------- scratch ----------------
__device__ float g_xT  [(size_t)PTOT * CH];
__device__ float g_acc [(size_t)PTOT * CH];
__device__ float g_t2  [(size_t)PTOT * CH];
__device__ float g_offp[(size_t)3 * BATCH * 18 * HWSZ];   // [branch][b][18][HW]
__device__ __nv_bfloat16 g_xTh[(size_t)PTOT * CH];
__device__ __nv_bfloat16 g_xTl[(size_t)PTOT * CH];
__device__ __nv_bfloat16 g_o1h[(size_t)PTOT * CH];
__device__ __nv_bfloat16 g_o1l[(size_t)PTOT * CH];
__device__ __nv_bfloat16 g_hh [(size_t)PTOT * 512];
__device__ __nv_bfloat16 g_hl [(size_t)PTOT * 512];
__device__ __nv_bfloat16 g_wh[327680];
__device__ __nv_bfloat16 g_wl[327680];
__device__ __nv_bfloat16 g_owh[3 * 32 * 2304];
__device__ __nv_bfloat16 g_owl[3 * 32 * 2304];

__device__ __forceinline__ float gelu_f(float v) {
    return 0.5f * v * (1.0f + erff(v * 0.70710678118654752440f));
}
__device__ __forceinline__ void split_bf16(float v, __nv_bfloat16& h, __nv_bfloat16& l) {
    h = __float2bfloat16(v);
    l = __float2bfloat16(v - __bfloat162float(h));
}
__device__ __forceinline__ uint32_t smem_u32(const void* p) {
    uint32_t a;
    asm("{ .reg .u64 t; cvta.to.shared.u64 t, %1; cvt.u32.u64 %0, t; }" : "=r"(a) : "l"(p));
    return a;
}
__device__ __forceinline__ void ldmx4(uint32_t* r, uint32_t addr) {
    asm volatile("ldmatrix.sync.aligned.m8n8.x4.shared.b16 {%0,%1,%2,%3}, [%4];"
                 : "=r"(r[0]), "=r"(r[1]), "=r"(r[2]), "=r"(r[3]) : "r"(addr));
}
__device__ __forceinline__ void mma16816(float* c, const uint32_t* a, const uint32_t* b) {
    asm volatile("mma.sync.aligned.m16n8k16.row.col.f32.bf16.bf16.f32 "
                 "{%0,%1,%2,%3}, {%4,%5,%6,%7}, {%8,%9}, {%0,%1,%2,%3};"
                 : "+f"(c[0]), "+f"(c[1]), "+f"(c[2]), "+f"(c[3])
                 : "r"(a[0]), "r"(a[1]), "r"(a[2]), "r"(a[3]), "r"(b[0]), "r"(b[1]));
}
__device__ __forceinline__ void cp16(uint32_t dst, const void* src) {
    asm volatile("cp.async.cg.shared.global [%0], [%1], 16;" :: "r"(dst), "l"(src));
}
__device__ __forceinline__ void cp16z(uint32_t dst, const void* src, bool valid) {
    int sz = valid ? 16 : 0;
    asm volatile("cp.async.cg.shared.global [%0], [%1], 16, %2;"
                 :: "r"(dst), "l"(src), "r"(sz));
}
#define CP_COMMIT() asm volatile("cp.async.commit_group;" ::: "memory")
#define CP_WAIT0()  asm volatile("cp.async.wait_group 0;" ::: "memory")

// ---------------- NCHW -> NHWC transpose (+ bf16 hi/lo split) ----------------
__global__ void k_nchw2nhwc(const float* __restrict__ x) {
    __shared__ float t[32][33];
    int b  = blockIdx.z;
    int p0 = blockIdx.x * 32, c0 = blockIdx.y * 32;
    int tx = threadIdx.x, ty = threadIdx.y;
    const float* xb = x + (size_t)b * CH * HWSZ;
#pragma unroll
    for (int i = 0; i < 4; i++)
        t[ty + 8 * i][tx] = xb[(size_t)(c0 + ty + 8 * i) * HWSZ + p0 + tx];
    __syncthreads();
    size_t base = (size_t)b * HWSZ * CH;
#pragma unroll
    for (int i = 0; i < 4; i++) {
        float v = t[tx][ty + 8 * i];
        size_t idx = base + (size_t)(p0 + ty + 8 * i) * CH + c0 + tx;
        g_xT[idx] = v;
        __nv_bfloat16 h, l; split_bf16(v, h, l);
        g_xTh[idx] = h; g_xTl[idx] = l;
    }
}

// ---------------- merged fp32 -> bf16 hi/lo split for all 3 weight mats ----------------
__global__ void k_prep(const float* __restrict__ cw, const float* __restrict__ w1,
                       const float* __restrict__ w2) {
    int i = blockIdx.x * blockDim.x + threadIdx.x;   // float4 index, 0..81919
    if (i >= 81920) return;
    const float* src; int dst;
    if (i < 16384)      { src = cw + i * 4;            dst = i * 4; }
    else if (i < 49152) { src = w1 + (i - 16384) * 4;  dst = 65536 + (i - 16384) * 4; }
    else                { src = w2 + (i - 49152) * 4;  dst = 196608 + (i - 49152) * 4; }
    float4 v = *(const float4*)src;
    __nv_bfloat16 ha, la, hb, lb, hc, lc, hd, ld;
    split_bf16(v.x, ha, la); split_bf16(v.y, hb, lb);
    split_bf16(v.z, hc, lc); split_bf16(v.w, hd, ld);
    ((__nv_bfloat162*)(g_wh + dst))[0] = __nv_bfloat162(ha, hb);
    ((__nv_bfloat162*)(g_wh + dst))[1] = __nv_bfloat162(hc, hd);
    ((__nv_bfloat162*)(g_wl + dst))[0] = __nv_bfloat162(la, lb);
    ((__nv_bfloat162*)(g_wl + dst))[1] = __nv_bfloat162(lc, ld);
}

// ---------------- offset-conv weight reorg ----------------
__global__ void k_owprep(const float* __restrict__ w0, const float* __restrict__ w1,
                         const float* __restrict__ w2) {
    int i = blockIdx.x * blockDim.x + threadIdx.x;
    if (i >= 3 * 32 * 2304) return;
    int br = i / (32 * 2304);
    int r  = i % (32 * 2304);
    int o  = r / 2304;
    int kk = r % 2304;
    int k  = kk / 256, c = kk % 256;
    const float* w = (br == 0) ? w0 : (br == 1) ? w1 : w2;
    float v = (o < 18) ? w[((size_t)o * 256 + c) * 9 + k] : 0.f;
    __nv_bfloat16 h, l; split_bf16(v, h, l);
    g_owh[i] = h; g_owl[i] = l;
}

// ---------------- offset conv via HMMA ----------------
#define OFF_A_ARR (128 * 40)
#define OFF_B_ARR (32 * 40)
#define OFF_STG   (2 * OFF_A_ARR + 2 * OFF_B_ARR)
#define OFF_SMEM  (2 * OFF_STG * 2)

__global__ void __launch_bounds__(256)
k_offmma() {
    extern __shared__ char dsm_[];
    __nv_bfloat16* sm = (__nv_bfloat16*)dsm_;

    int tid = threadIdx.x, wid = tid >> 5, lane = tid & 31;
    int bx = blockIdx.x, br = blockIdx.y;
    int h = bx & 127, b = bx >> 7;
    const int D = (br == 0) ? 1 : (br == 1) ? 9 : 12;

    const __nv_bfloat16* xh = g_xTh + (size_t)b * HWSZ * CH;
    const __nv_bfloat16* xl = g_xTl + (size_t)b * HWSZ * CH;
    const __nv_bfloat16* wbh = g_owh + (size_t)br * 32 * 2304;
    const __nv_bfloat16* wbl = g_owl + (size_t)br * 32 * 2304;

    float acc[4][4];
#pragma unroll
    for (int j = 0; j < 4; j++)
#pragma unroll
        for (int q = 0; q < 4; q++) acc[j][q] = 0.f;

    auto load_stage = [&](int kc, int s) {
        __nv_bfloat16* base = sm + s * OFF_STG;
        uint32_t sAh = smem_u32(base);
        uint32_t sAl = sAh + OFF_A_ARR * 2;
        uint32_t sBh = sAl + OFF_A_ARR * 2;
        uint32_t sBl = sBh + OFF_B_ARR * 2;
        int k  = kc >> 3;
        int cc = (kc & 7) * 32;
        int dy = (k / 3 - 1) * D, dx = (k % 3 - 1) * D;
        int srow = h + dy;
        bool vy = (srow >= 0) && (srow < HH);
        int srowc = vy ? srow : 0;
#pragma unroll
        for (int u = 0; u < 2; u++) {
            int idx = u * 256 + tid;
            int w = idx >> 2, ch = idx & 3;
            int wp = w + dx;
            bool v = vy && (wp >= 0) && (wp < WW);
            int wpc = v ? wp : 0;
            size_t goff = (size_t)(srowc * WW + wpc) * CH + cc + ch * 8;
            uint32_t soff = (uint32_t)(w * 40 + ch * 8) * 2;
            cp16z(sAh + soff, xh + goff, v);
            cp16z(sAl + soff, xl + goff, v);
        }
        if (tid < 128) {
            int o = tid >> 2, ch = tid & 3;
            size_t goff = (size_t)o * 2304 + k * 256 + cc + ch * 8;
            uint32_t soff = (uint32_t)(o * 40 + ch * 8) * 2;
            cp16(sBh + soff, wbh + goff);
            cp16(sBl + soff, wbl + goff);
        }
    };

    int a_row8 = ((lane >> 3) & 1) * 8 + (lane & 7);
    int a_col8 = ((lane >> 4) & 1) * 8;
    int b_row8 = ((lane >> 4) & 1) * 8 + (lane & 7);
    int b_col8 = ((lane >> 3) & 1) * 8;

    load_stage(0, 0); CP_COMMIT();
    CP_WAIT0(); __syncthreads();

    const int NK = 72;
    for (int kc = 0; kc < NK; kc++) {
        int cur = kc & 1;
        if (kc + 1 < NK) { load_stage(kc + 1, cur ^ 1); CP_COMMIT(); }

        __nv_bfloat16* base = sm + cur * OFF_STG;
        __nv_bfloat16* pAh = base;
        __nv_bfloat16* pAl = base + OFF_A_ARR;
        __nv_bfloat16* pBh = base + 2 * OFF_A_ARR;
        __nv_bfloat16* pBl = base + 2 * OFF_A_ARR + OFF_B_ARR;
#pragma unroll
        for (int ks = 0; ks < 2; ks++) {
            uint32_t af[2][4];
            ldmx4(af[0], smem_u32(pAh + (wid * 16 + a_row8) * 40 + ks * 16 + a_col8));
            ldmx4(af[1], smem_u32(pAl + (wid * 16 + a_row8) * 40 + ks * 16 + a_col8));
            uint32_t bfr[2][2][4];
#pragma unroll
            for (int jp = 0; jp < 2; jp++) {
                ldmx4(bfr[0][jp], smem_u32(pBh + (jp * 16 + b_row8) * 40 + ks * 16 + b_col8));
                ldmx4(bfr[1][jp], smem_u32(pBl + (jp * 16 + b_row8) * 40 + ks * 16 + b_col8));
            }
#pragma unroll
            for (int j = 0; j < 4; j++) {
                int jp = j >> 1, hB = (j & 1) * 2;
                uint32_t bh2[2] = {bfr[0][jp][hB], bfr[0][jp][hB + 1]};
                uint32_t bl2[2] = {bfr[1][jp][hB], bfr[1][jp][hB + 1]};
                mma16816(acc[j], af[0], bh2);
                mma16816(acc[j], af[0], bl2);
                mma16816(acc[j], af[1], bh2);
            }
        }
        if (kc + 1 < NK) CP_WAIT0();
        __syncthreads();
    }

    float* op = g_offp + (size_t)(br * BATCH + b) * 18 * HWSZ;
    int g = lane >> 2, q = lane & 3;
#pragma unroll
    for (int half = 0; half < 2; half++) {
        int wcol = wid * 16 + g + half * 8;
        int pimg = h * WW + wcol;
#pragma unroll
        for (int j = 0; j < 4; j++) {
#pragma unroll
            for (int e = 0; e < 2; e++) {
                int n = j * 8 + q * 2 + e;
                if (n < 18) op[(size_t)n * HWSZ + pimg] = acc[j][half * 2 + e];
            }
        }
    }
}

// ---------------- fused deform3 v2: 4 pixels/warp, k-outer weights in regs ----------------
__global__ void __launch_bounds__(256)
k_deform3(const float* __restrict__ dw0, const float* __restrict__ dw1,
          const float* __restrict__ dw2,
          const float* __restrict__ lw0, const float* __restrict__ lb0,
          const float* __restrict__ lw1, const float* __restrict__ lb1,
          const float* __restrict__ lw2, const float* __restrict__ lb2,
          const float* __restrict__ n1w, const float* __restrict__ n1b) {
    __shared__ float sdefT[3][9 * CH];
    __shared__ int   sidx[8][4][36];
    __shared__ float swgt[8][4][36];

    int tid = threadIdx.x, wid = tid >> 5, lane = tid & 31;
    {
        const float* dws[3] = {dw0, dw1, dw2};
#pragma unroll
        for (int br = 0; br < 3; br++)
            for (int i = tid; i < 9 * CH; i += 256) {
                int c = i / 9, k = i % 9;
                sdefT[br][k * CH + c] = dws[br][i];
            }
    }
    __syncthreads();

    int pix0 = blockIdx.x * 32 + wid * 4;
    int b = pix0 >> 14;
    int c0 = lane * 8;
    const float* xrow = g_xT + (size_t)b * HWSZ * CH;

    // seed with 1x1-conv result
    float sum[4][8];
#pragma unroll
    for (int e = 0; e < 4; e++) {
        const float4* ap = (const float4*)(g_acc + (size_t)(pix0 + e) * CH + c0);
        float4 a0 = ap[0], a1 = ap[1];
        sum[e][0] = a0.x; sum[e][1] = a0.y; sum[e][2] = a0.z; sum[e][3] = a0.w;
        sum[e][4] = a1.x; sum[e][5] = a1.y; sum[e][6] = a1.z; sum[e][7] = a1.w;
    }

    const int DS[3] = {1, 9, 12};
    const float* lws[3] = {lw0, lw1, lw2};
    const float* lbs[3] = {lb0, lb1, lb2};

#pragma unroll
    for (int br = 0; br < 3; br++) {
        int D = DS[br];
        // offsets for 4 pixels x 9 kernel points (36 tasks over 32 lanes)
        for (int t = lane; t < 36; t += 32) {
            int e = t / 9, k = t % 9;
            int pix = pix0 + e;
            int p = pix & (HWSZ - 1);
            int h = p >> 7, w = p & 127;
            int ky = k / 3, kx = k % 3;
            const float* op = g_offp + (size_t)(br * BATCH + b) * 18 * HWSZ;
            float oy = op[(size_t)(2 * k) * HWSZ + p];
            float ox = op[(size_t)(2 * k + 1) * HWSZ + p];
            float py = (float)h + (float)((ky - 1) * D) + oy;
            float px = (float)w + (float)((kx - 1) * D) + ox;
            float y0 = floorf(py), x0 = floorf(px);
#pragma unroll
            for (int dy = 0; dy < 2; dy++)
#pragma unroll
                for (int dx = 0; dx < 2; dx++) {
                    float yc = y0 + dy, xc = x0 + dx;
                    float wq = (1.f - fabsf(py - yc)) * (1.f - fabsf(px - xc));
                    bool valid = (yc >= 0.f) && (yc < 128.f) && (xc >= 0.f) && (xc < 128.f);
                    int iy = min(max((int)yc, 0), 127);
                    int ix = min(max((int)xc, 0), 127);
                    sidx[wid][e][k * 4 + dy * 2 + dx] = iy * WW + ix;
                    swgt[wid][e][k * 4 + dy * 2 + dx] = valid ? wq : 0.f;
                }
        }
        __syncwarp();

        float facc[4][8];
#pragma unroll
        for (int e = 0; e < 4; e++)
#pragma unroll
            for (int r = 0; r < 8; r++) facc[e][r] = 0.f;

#pragma unroll
        for (int k = 0; k < 9; k++) {
            float4 wk0 = *(const float4*)&sdefT[br][k * CH + c0];
            float4 wk1 = *(const float4*)&sdefT[br][k * CH + c0 + 4];
#pragma unroll
            for (int e = 0; e < 4; e++) {
                float s[8];
#pragma unroll
                for (int r = 0; r < 8; r++) s[r] = 0.f;
#pragma unroll
                for (int j = 0; j < 4; j++) {
                    float wq = swgt[wid][e][k * 4 + j];
                    if (wq != 0.f) {   // uniform across warp
                        const float4* vp =
                            (const float4*)(xrow + (size_t)sidx[wid][e][k * 4 + j] * CH + c0);
                        float4 v0 = vp[0], v1 = vp[1];
                        s[0] += wq * v0.x; s[1] += wq * v0.y; s[2] += wq * v0.z; s[3] += wq * v0.w;
                        s[4] += wq * v1.x; s[5] += wq * v1.y; s[6] += wq * v1.z; s[7] += wq * v1.w;
                    }
                }
                facc[e][0] += wk0.x * s[0]; facc[e][1] += wk0.y * s[1];
                facc[e][2] += wk0.z * s[2]; facc[e][3] += wk0.w * s[3];
                facc[e][4] += wk1.x * s[4]; facc[e][5] += wk1.y * s[5];
                facc[e][6] += wk1.z * s[6]; facc[e][7] += wk1.w * s[7];
            }
        }

        // per-branch LN + GELU, accumulate
        const float4* lwp = (const float4*)(lws[br] + c0);
        const float4* lbp = (const float4*)(lbs[br] + c0);
        float4 lw0v = lwp[0], lw1v = lwp[1], lb0v = lbp[0], lb1v = lbp[1];
        float lw[8] = {lw0v.x, lw0v.y, lw0v.z, lw0v.w, lw1v.x, lw1v.y, lw1v.z, lw1v.w};
        float lb[8] = {lb0v.x, lb0v.y, lb0v.z, lb0v.w, lb1v.x, lb1v.y, lb1v.z, lb1v.w};
#pragma unroll
        for (int e = 0; e < 4; e++) {
            float ls = 0.f, lq = 0.f;
#pragma unroll
            for (int r = 0; r < 8; r++) { ls += facc[e][r]; lq += facc[e][r] * facc[e][r]; }
#pragma unroll
            for (int o = 16; o; o >>= 1) {
                ls += __shfl_xor_sync(0xffffffffu, ls, o);
                lq += __shfl_xor_sync(0xffffffffu, lq, o);
            }
            float mean = ls * (1.f / 256.f);
            float var  = lq * (1.f / 256.f) - mean * mean;
            float rstd = rsqrtf(var + LN_EPS);
#pragma unroll
            for (int r = 0; r < 8; r++)
                sum[e][r] += gelu_f(lw[r] * ((facc[e][r] - mean) * rstd) + lb[r]);
        }
        __syncwarp();
    }

    // LN1 per pixel + bf16 hi/lo outputs
    const float4* wp = (const float4*)(n1w + c0);
    const float4* bp = (const float4*)(n1b + c0);
    float4 w0v = wp[0], w1v = wp[1], b0v = bp[0], b1v = bp[1];
    float gw[8] = {w0v.x, w0v.y, w0v.z, w0v.w, w1v.x, w1v.y, w1v.z, w1v.w};
    float gb[8] = {b0v.x, b0v.y, b0v.z, b0v.w, b1v.x, b1v.y, b1v.z, b1v.w};

#pragma unroll
    for (int e = 0; e < 4; e++) {
        float ls = 0.f, lq = 0.f;
#pragma unroll
        for (int r = 0; r < 8; r++) { ls += sum[e][r]; lq += sum[e][r] * sum[e][r]; }
#pragma unroll
        for (int o = 16; o; o >>= 1) {
            ls += __shfl_xor_sync(0xffffffffu, ls, o);
            lq += __shfl_xor_sync(0xffffffffu, lq, o);
        }
        float mean = ls * (1.f / 256.f);
        float var  = lq * (1.f / 256.f) - mean * mean;
        float rstd = rsqrtf(var + LN_EPS);

        uint32_t hp[4], lp[4];
#pragma unroll
        for (int r = 0; r < 8; r += 2) {
            float oa = gw[r] * ((sum[e][r] - mean) * rstd) + gb[r];
            float ob = gw[r + 1] * ((sum[e][r + 1] - mean) * rstd) + gb[r + 1];
            __nv_bfloat16 h0, l0, h1, l1;
            split_bf16(oa, h0, l0); split_bf16(ob, h1, l1);
            hp[r >> 1] = (uint32_t)__bfloat16_as_ushort(h0) |
                         ((uint32_t)__bfloat16_as_ushort(h1) << 16);
            lp[r >> 1] = (uint32_t)__bfloat16_as_ushort(l0) |
                         ((uint32_t)__bfloat16_as_ushort(l1) << 16);
        }
        *(uint4*)(g_o1h + (size_t)(pix0 + e) * CH + c0) = make_uint4(hp[0], hp[1], hp[2], hp[3]);
        *(uint4*)(g_o1l + (size_t)(pix0 + e) * CH + c0) = make_uint4(lp[0], lp[1], lp[2], lp[3]);
    }
}

// ---------------- split-bf16 GEMM via mma.sync, cp.async double-buffered ----------------
#define G_ARR (128 * 40)
#define G_STG (4 * G_ARR)
#define G_SMEM (2 * G_STG * 2)

template <int ACT, bool RES, bool BF16OUT>
__global__ void __launch_bounds__(256)
k_mmagemm(const __nv_bfloat16* __restrict__ Ah, const __nv_bfloat16* __restrict__ Al,
          const __nv_bfloat16* __restrict__ Bh, const __nv_bfloat16* __restrict__ Bl,
          const float* __restrict__ bias,
          const __nv_bfloat16* __restrict__ Resh, const __nv_bfloat16* __restrict__ Resl,
          float* __restrict__ Cf, __nv_bfloat16* __restrict__ Chi,
          __nv_bfloat16* __restrict__ Clo, int N, int K) {
    extern __shared__ char dsm_[];
    __nv_bfloat16* sm = (__nv_bfloat16*)dsm_;

    int tid  = threadIdx.x;
    int wid  = tid >> 5, lane = tid & 31;
    int m0   = blockIdx.x * 128, n0 = blockIdx.y * 128;
    int wm   = (wid & 3) * 32;
    int wn   = (wid >> 2) * 64;

    float acc[2][8][4];
#pragma unroll
    for (int i = 0; i < 2; i++)
#pragma unroll
        for (int j = 0; j < 8; j++)
#pragma unroll
            for (int q = 0; q < 4; q++) acc[i][j][q] = 0.f;

    const __nv_bfloat16* srcs[4] = {Ah + (size_t)m0 * K, Al + (size_t)m0 * K,
                                    Bh + (size_t)n0 * K, Bl + (size_t)n0 * K};

    auto load_stage = [&](int kc, int s) {
        __nv_bfloat16* base = sm + s * G_STG;
#pragma unroll
        for (int t = 0; t < 4; t++) {
            const __nv_bfloat16* src = srcs[t] + kc * 32;
            uint32_t dstb = smem_u32(base + t * G_ARR);
#pragma unroll
            for (int u = 0; u < 2; u++) {
                int idx = u * 256 + tid;
                int row = idx >> 2, ch = idx & 3;
                cp16(dstb + (uint32_t)(row * 40 + ch * 8) * 2,
                     src + (size_t)row * K + ch * 8);
            }
        }
    };

    int a_row8 = ((lane >> 3) & 1) * 8 + (lane & 7);
    int a_col8 = ((lane >> 4) & 1) * 8;
    int b_row8 = ((lane >> 4) & 1) * 8 + (lane & 7);
    int b_col8 = ((lane >> 3) & 1) * 8;

    load_stage(0, 0); CP_COMMIT();
    CP_WAIT0(); __syncthreads();

    int nk = K >> 5;
    for (int kc = 0; kc < nk; kc++) {
        int cur = kc & 1;
        if (kc + 1 < nk) { load_stage(kc + 1, cur ^ 1); CP_COMMIT(); }

        __nv_bfloat16* base = sm + cur * G_STG;
        __nv_bfloat16* pA[2] = {base, base + G_ARR};
        __nv_bfloat16* pB[2] = {base + 2 * G_ARR, base + 3 * G_ARR};
#pragma unroll
        for (int ks = 0; ks < 2; ks++) {
            uint32_t af[2][2][4];
#pragma unroll
            for (int hl = 0; hl < 2; hl++)
#pragma unroll
                for (int mi = 0; mi < 2; mi++)
                    ldmx4(af[hl][mi],
                          smem_u32(pA[hl] + (wm + mi * 16 + a_row8) * 40 + ks * 16 + a_col8));
            uint32_t bfr[2][4][4];
#pragma unroll
            for (int hl = 0; hl < 2; hl++)
#pragma unroll
                for (int jp = 0; jp < 4; jp++)
                    ldmx4(bfr[hl][jp],
                          smem_u32(pB[hl] + (wn + jp * 16 + b_row8) * 40 + ks * 16 + b_col8));
#pragma unroll
            for (int mi = 0; mi < 2; mi++)
#pragma unroll
                for (int j = 0; j < 8; j++) {
                    int jp = j >> 1, hB = (j & 1) * 2;
                    uint32_t bh2[2] = {bfr[0][jp][hB], bfr[0][jp][hB + 1]};
                    uint32_t bl2[2] = {bfr[1][jp][hB], bfr[1][jp][hB + 1]};
                    mma16816(acc[mi][j], af[0][mi], bh2);
                    mma16816(acc[mi][j], af[0][mi], bl2);
                    mma16816(acc[mi][j], af[1][mi], bh2);
                }
        }
        if (kc + 1 < nk) CP_WAIT0();
        __syncthreads();
    }

    int g = lane >> 2, q = lane & 3;
#pragma unroll
    for (int mi = 0; mi < 2; mi++) {
#pragma unroll
        for (int half = 0; half < 2; half++) {
            int m = m0 + wm + mi * 16 + g + half * 8;
#pragma unroll
            for (int j = 0; j < 8; j++) {
                int n = n0 + wn + j * 8 + q * 2;
                float v0 = acc[mi][j][half * 2 + 0] + __ldg(bias + n);
                float v1 = acc[mi][j][half * 2 + 1] + __ldg(bias + n + 1);
                if (ACT == 1) { v0 = gelu_f(v0); v1 = gelu_f(v1); }
                if (RES) {
                    __nv_bfloat162 rh = *(const __nv_bfloat162*)(Resh + (size_t)m * N + n);
                    __nv_bfloat162 rl = *(const __nv_bfloat162*)(Resl + (size_t)m * N + n);
                    v0 += __bfloat162float(rh.x) + __bfloat162float(rl.x);
                    v1 += __bfloat162float(rh.y) + __bfloat162float(rl.y);
                }
                if (BF16OUT) {
                    __nv_bfloat16 h0, l0, h1, l1;
                    split_bf16(v0, h0, l0); split_bf16(v1, h1, l1);
                    *(__nv_bfloat162*)(Chi + (size_t)m * N + n) = __nv_bfloat162(h0, h1);
                    *(__nv_bfloat162*)(Clo + (size_t)m * N + n) = __nv_bfloat162(l0, l1);
                } else {
                    *(float2*)(Cf + (size_t)m * N + n) = make_float2(v0, v1);
                }
            }
        }
    }
}

// ---------------- fused LN2 + NHWC->NCHW output ----------------
// block: 32 consecutive pixels x 256 ch; warp = pixel LN; coalesced NCHW stores
__global__ void __launch_bounds__(256)
k_ln2out(const float* __restrict__ in, float* __restrict__ out,
         const float* __restrict__ gwv, const float* __restrict__ gbv) {
    __shared__ float tr[256][33];
    int tid = threadIdx.x, wid = tid >> 5, lane = tid & 31;
    int p32 = blockIdx.x * 32;
    int b = p32 >> 14;
    int pimg = p32 & (HWSZ - 1);

#pragma unroll
    for (int i = 0; i < 4; i++) {
        int pxloc = wid + i * 8;
        const float4* row = (const float4*)(in + (size_t)(p32 + pxloc) * CH);
        float4 va = row[lane], vb = row[lane + 32];
        float s = va.x + va.y + va.z + va.w + vb.x + vb.y + vb.z + vb.w;
        float qq = va.x * va.x + va.y * va.y + va.z * va.z + va.w * va.w +
                   vb.x * vb.x + vb.y * vb.y + vb.z * vb.z + vb.w * vb.w;
#pragma unroll
        for (int o = 16; o; o >>= 1) {
            s  += __shfl_xor_sync(0xffffffffu, s, o);
            qq += __shfl_xor_sync(0xffffffffu, qq, o);
        }
        float mean = s * (1.f / 256.f);
        float var  = qq * (1.f / 256.f) - mean * mean;
        float rstd = rsqrtf(var + LN_EPS);
        int ca = lane * 4, cb = 128 + lane * 4;
        float4 ga = *(const float4*)(gwv + ca), gba = *(const float4*)(gbv + ca);
        float4 gb2 = *(const float4*)(gwv + cb), gbb = *(const float4*)(gbv + cb);
        tr[ca + 0][pxloc] = ga.x * ((va.x - mean) * rstd) + gba.x;
        tr[ca + 1][pxloc] = ga.y * ((va.y - mean) * rstd) + gba.y;
        tr[ca + 2][pxloc] = ga.z * ((va.z - mean) * rstd) + gba.z;
        tr[ca + 3][pxloc] = ga.w * ((va.w - mean) * rstd) + gba.w;
        tr[cb + 0][pxloc] = gb2.x * ((vb.x - mean) * rstd) + gbb.x;
        tr[cb + 1][pxloc] = gb2.y * ((vb.y - mean) * rstd) + gbb.y;
        tr[cb + 2][pxloc] = gb2.z * ((vb.z - mean) * rstd) + gbb.z;
        tr[cb + 3][pxloc] = gb2.w * ((vb.w - mean) * rstd) + gbb.w;
    }
    __syncthreads();

    float* ob = out + (size_t)b * CH * HWSZ + pimg;
#pragma unroll
    for (int it = 0; it < 32; it++) {
        int c = it * 8 + wid;
        ob[(size_t)c * HWSZ + lane] = tr[c][lane];
    }
}

// ---------------- launch ----------------
extern "C" void kernel_launch(void* const* d_in, const int* in_sizes, int n_in,
                              void* d_out, int out_size) {
    const float* x       = (const float*)d_in[0];
    const float* off_w1  = (const float*)d_in[1];
    const float* def_w1  = (const float*)d_in[2];
    const float* bw1     = (const float*)d_in[3];
    const float* bb1     = (const float*)d_in[4];
    const float* off_w2  = (const float*)d_in[5];
    const float* def_w2  = (const float*)d_in[6];
    const float* bw2     = (const float*)d_in[7];
    const float* bb2     = (const float*)d_in[8];
    const float* off_w3  = (const float*)d_in[9];
    const float* def_w3  = (const float*)d_in[10];
    const float* bw3     = (const float*)d_in[11];
    const float* bb3     = (const float*)d_in[12];
    const float* conv_w  = (const float*)d_in[13];
    const float* conv_b  = (const float*)d_in[14];
    const float* n1_w    = (const float*)d_in[15];
    const float* n1_b    = (const float*)d_in[16];
    const float* n2_w    = (const float*)d_in[17];
    const float* n2_b    = (const float*)d_in[18];
    const float* mlp_w1  = (const float*)d_in[19];
    const float* mlp_b1  = (const float*)d_in[20];
    const float* mlp_w2  = (const float*)d_in[21];
    const float* mlp_b2  = (const float*)d_in[22];

    float *pacc, *pt2;
    __nv_bfloat16 *po1h, *po1l, *phh, *phl, *pwh, *pwl, *pxTh, *pxTl;
    cudaGetSymbolAddress((void**)&pacc,  g_acc);
    cudaGetSymbolAddress((void**)&pt2,   g_t2);
    cudaGetSymbolAddress((void**)&pxTh,  g_xTh);
    cudaGetSymbolAddress((void**)&pxTl,  g_xTl);
    cudaGetSymbolAddress((void**)&po1h,  g_o1h);
    cudaGetSymbolAddress((void**)&po1l,  g_o1l);
    cudaGetSymbolAddress((void**)&phh,   g_hh);
    cudaGetSymbolAddress((void**)&phl,   g_hl);
    cudaGetSymbolAddress((void**)&pwh,   g_wh);
    cudaGetSymbolAddress((void**)&pwl,   g_wl);

    cudaFuncSetAttribute(k_mmagemm<0, false, false>,
                         cudaFuncAttributeMaxDynamicSharedMemorySize, G_SMEM);
    cudaFuncSetAttribute(k_mmagemm<1, false, true>,
                         cudaFuncAttributeMaxDynamicSharedMemorySize, G_SMEM);
    cudaFuncSetAttribute(k_mmagemm<0, true, false>,
                         cudaFuncAttributeMaxDynamicSharedMemorySize, G_SMEM);
    cudaFuncSetAttribute(k_offmma,
                         cudaFuncAttributeMaxDynamicSharedMemorySize, OFF_SMEM);

    // 1. x -> NHWC (+ hi/lo split)
    k_nchw2nhwc<<<dim3(HWSZ / 32, CH / 32, BATCH), dim3(32, 8)>>>(x);
    // 2. weight prep
    k_prep<<<(81920 + 255) / 256, 256>>>(conv_w, mlp_w1, mlp_w2);
    k_owprep<<<(3 * 32 * 2304 + 255) / 256, 256>>>(off_w1, off_w2, off_w3);
    // 3. conv1x1: acc = xT @ conv_w^T + conv_b
    k_mmagemm<0, false, false><<<dim3(PTOT / 128, CH / 128), 256, G_SMEM>>>(
        pxTh, pxTl, pwh, pwl, conv_b, nullptr, nullptr, pacc, nullptr, nullptr, CH, CH);
    // 4. offset convs via HMMA
    k_offmma<<<dim3(PTOT / 128, 3), 256, OFF_SMEM>>>();
    // 5. fused deform x3 + LN1 + split (4 px/warp)
    k_deform3<<<PTOT / 32, 256>>>(def_w1, def_w2, def_w3,
                                  bw1, bb1, bw2, bb2, bw3, bb3, n1_w, n1_b);
    // 6. MLP1 (bias+GELU, bf16 hi/lo out)
    k_mmagemm<1, false, true><<<dim3(PTOT / 128, 512 / 128), 256, G_SMEM>>>(
        po1h, po1l, pwh + 65536, pwl + 65536, mlp_b1, nullptr, nullptr,
        nullptr, phh, phl, 512, CH);
    // 7. MLP2 (bias + residual o1h+o1l)
    k_mmagemm<0, true, false><<<dim3(PTOT / 128, CH / 128), 256, G_SMEM>>>(
        phh, phl, pwh + 196608, pwl + 196608, mlp_b2, po1h, po1l,
        pt2, nullptr, nullptr, CH, 512);
    // 8. fused LN2 + transpose out
    k_ln2out<<<PTOT / 32, 256>>>(pt2, (float*)d_out, n2_w, n2_b);
}

// round 9
// speedup vs baseline: 1.9452x; 1.0381x over previous
#include <cuda_runtime.h>
#include <cuda_bf16.h>
#include <math.h>
#include <stdint.h>

#define BATCH 2
#define CH    256
#define HH    128
#define WW    128
#define HWSZ  16384
#define PTOT  32768
#define LN_EPS 1e-6f

// ---------------- scratch ----------------
__device__ float g_xT  [(size_t)PTOT * CH];
__device__ float g_acc [(size_t)PTOT * CH];
__device__ float g_t2  [(size_t)PTOT * CH];
__device__ float g_offp[(size_t)3 * BATCH * 18 * HWSZ];   // [branch][b][18][HW]
__device__ __nv_bfloat16 g_xTh[(size_t)PTOT * CH];
__device__ __nv_bfloat16 g_xTl[(size_t)PTOT * CH];
__device__ __nv_bfloat16 g_o1h[(size_t)PTOT * CH];
__device__ __nv_bfloat16 g_o1l[(size_t)PTOT * CH];
__device__ __nv_bfloat16 g_hh [(size_t)PTOT * 512];
__device__ __nv_bfloat16 g_hl [(size_t)PTOT * 512];
__device__ __nv_bfloat16 g_wh[327680];
__device__ __nv_bfloat16 g_wl[327680];
__device__ __nv_bfloat16 g_owh[3 * 32 * 2304];
__device__ __nv_bfloat16 g_owl[3 * 32 * 2304];

__device__ __forceinline__ float gelu_f(float v) {
    return 0.5f * v * (1.0f + erff(v * 0.70710678118654752440f));
}
__device__ __forceinline__ void split_bf16(float v, __nv_bfloat16& h, __nv_bfloat16& l) {
    h = __float2bfloat16(v);
    l = __float2bfloat16(v - __bfloat162float(h));
}
__device__ __forceinline__ uint32_t smem_u32(const void* p) {
    uint32_t a;
    asm("{ .reg .u64 t; cvta.to.shared.u64 t, %1; cvt.u32.u64 %0, t; }" : "=r"(a) : "l"(p));
    return a;
}
__device__ __forceinline__ void ldmx4(uint32_t* r, uint32_t addr) {
    asm volatile("ldmatrix.sync.aligned.m8n8.x4.shared.b16 {%0,%1,%2,%3}, [%4];"
                 : "=r"(r[0]), "=r"(r[1]), "=r"(r[2]), "=r"(r[3]) : "r"(addr));
}
__device__ __forceinline__ void mma16816(float* c, const uint32_t* a, const uint32_t* b) {
    asm volatile("mma.sync.aligned.m16n8k16.row.col.f32.bf16.bf16.f32 "
                 "{%0,%1,%2,%3}, {%4,%5,%6,%7}, {%8,%9}, {%0,%1,%2,%3};"
                 : "+f"(c[0]), "+f"(c[1]), "+f"(c[2]), "+f"(c[3])
                 : "r"(a[0]), "r"(a[1]), "r"(a[2]), "r"(a[3]), "r"(b[0]), "r"(b[1]));
}
__device__ __forceinline__ void cp16(uint32_t dst, const void* src) {
    asm volatile("cp.async.cg.shared.global [%0], [%1], 16;" :: "r"(dst), "l"(src));
}
__device__ __forceinline__ void cp16z(uint32_t dst, const void* src, bool valid) {
    int sz = valid ? 16 : 0;
    asm volatile("cp.async.cg.shared.global [%0], [%1], 16, %2;"
                 :: "r"(dst), "l"(src), "r"(sz));
}
#define CP_COMMIT() asm volatile("cp.async.commit_group;" ::: "memory")
#define CP_WAIT0()  asm volatile("cp.async.wait_group 0;" ::: "memory")

// ---------------- NCHW -> NHWC transpose (+ bf16 hi/lo split) ----------------
__global__ void k_nchw2nhwc(const float* __restrict__ x) {
    __shared__ float t[32][33];
    int b  = blockIdx.z;
    int p0 = blockIdx.x * 32, c0 = blockIdx.y * 32;
    int tx = threadIdx.x, ty = threadIdx.y;
    const float* xb = x + (size_t)b * CH * HWSZ;
#pragma unroll
    for (int i = 0; i < 4; i++)
        t[ty + 8 * i][tx] = xb[(size_t)(c0 + ty + 8 * i) * HWSZ + p0 + tx];
    __syncthreads();
    size_t base = (size_t)b * HWSZ * CH;
#pragma unroll
    for (int i = 0; i < 4; i++) {
        float v = t[tx][ty + 8 * i];
        size_t idx = base + (size_t)(p0 + ty + 8 * i) * CH + c0 + tx;
        g_xT[idx] = v;
        __nv_bfloat16 h, l; split_bf16(v, h, l);
        g_xTh[idx] = h; g_xTl[idx] = l;
    }
}

// ---------------- merged fp32 -> bf16 hi/lo split for all 3 weight mats ----------------
__global__ void k_prep(const float* __restrict__ cw, const float* __restrict__ w1,
                       const float* __restrict__ w2) {
    int i = blockIdx.x * blockDim.x + threadIdx.x;
    if (i >= 81920) return;
    const float* src; int dst;
    if (i < 16384)      { src = cw + i * 4;            dst = i * 4; }
    else if (i < 49152) { src = w1 + (i - 16384) * 4;  dst = 65536 + (i - 16384) * 4; }
    else                { src = w2 + (i - 49152) * 4;  dst = 196608 + (i - 49152) * 4; }
    float4 v = *(const float4*)src;
    __nv_bfloat16 ha, la, hb, lb, hc, lc, hd, ld;
    split_bf16(v.x, ha, la); split_bf16(v.y, hb, lb);
    split_bf16(v.z, hc, lc); split_bf16(v.w, hd, ld);
    ((__nv_bfloat162*)(g_wh + dst))[0] = __nv_bfloat162(ha, hb);
    ((__nv_bfloat162*)(g_wh + dst))[1] = __nv_bfloat162(hc, hd);
    ((__nv_bfloat162*)(g_wl + dst))[0] = __nv_bfloat162(la, lb);
    ((__nv_bfloat162*)(g_wl + dst))[1] = __nv_bfloat162(lc, ld);
}

// ---------------- offset-conv weight reorg ----------------
__global__ void k_owprep(const float* __restrict__ w0, const float* __restrict__ w1,
                         const float* __restrict__ w2) {
    int i = blockIdx.x * blockDim.x + threadIdx.x;
    if (i >= 3 * 32 * 2304) return;
    int br = i / (32 * 2304);
    int r  = i % (32 * 2304);
    int o  = r / 2304;
    int kk = r % 2304;
    int k  = kk / 256, c = kk % 256;
    const float* w = (br == 0) ? w0 : (br == 1) ? w1 : w2;
    float v = (o < 18) ? w[((size_t)o * 256 + c) * 9 + k] : 0.f;
    __nv_bfloat16 h, l; split_bf16(v, h, l);
    g_owh[i] = h; g_owl[i] = l;
}

// ---------------- offset conv via HMMA ----------------
#define OFF_A_ARR (128 * 40)
#define OFF_B_ARR (32 * 40)
#define OFF_STG   (2 * OFF_A_ARR + 2 * OFF_B_ARR)
#define OFF_SMEM  (2 * OFF_STG * 2)

__global__ void __launch_bounds__(256, 2)
k_offmma() {
    extern __shared__ char dsm_[];
    __nv_bfloat16* sm = (__nv_bfloat16*)dsm_;

    int tid = threadIdx.x, wid = tid >> 5, lane = tid & 31;
    int bx = blockIdx.x, br = blockIdx.y;
    int h = bx & 127, b = bx >> 7;
    const int D = (br == 0) ? 1 : (br == 1) ? 9 : 12;

    const __nv_bfloat16* xh = g_xTh + (size_t)b * HWSZ * CH;
    const __nv_bfloat16* xl = g_xTl + (size_t)b * HWSZ * CH;
    const __nv_bfloat16* wbh = g_owh + (size_t)br * 32 * 2304;
    const __nv_bfloat16* wbl = g_owl + (size_t)br * 32 * 2304;

    float acc[4][4];
#pragma unroll
    for (int j = 0; j < 4; j++)
#pragma unroll
        for (int q = 0; q < 4; q++) acc[j][q] = 0.f;

    auto load_stage = [&](int kc, int s) {
        __nv_bfloat16* base = sm + s * OFF_STG;
        uint32_t sAh = smem_u32(base);
        uint32_t sAl = sAh + OFF_A_ARR * 2;
        uint32_t sBh = sAl + OFF_A_ARR * 2;
        uint32_t sBl = sBh + OFF_B_ARR * 2;
        int k  = kc >> 3;
        int cc = (kc & 7) * 32;
        int dy = (k / 3 - 1) * D, dx = (k % 3 - 1) * D;
        int srow = h + dy;
        bool vy = (srow >= 0) && (srow < HH);
        int srowc = vy ? srow : 0;
#pragma unroll
        for (int u = 0; u < 2; u++) {
            int idx = u * 256 + tid;
            int w = idx >> 2, ch = idx & 3;
            int wp = w + dx;
            bool v = vy && (wp >= 0) && (wp < WW);
            int wpc = v ? wp : 0;
            size_t goff = (size_t)(srowc * WW + wpc) * CH + cc + ch * 8;
            uint32_t soff = (uint32_t)(w * 40 + ch * 8) * 2;
            cp16z(sAh + soff, xh + goff, v);
            cp16z(sAl + soff, xl + goff, v);
        }
        if (tid < 128) {
            int o = tid >> 2, ch = tid & 3;
            size_t goff = (size_t)o * 2304 + k * 256 + cc + ch * 8;
            uint32_t soff = (uint32_t)(o * 40 + ch * 8) * 2;
            cp16(sBh + soff, wbh + goff);
            cp16(sBl + soff, wbl + goff);
        }
    };

    int a_row8 = ((lane >> 3) & 1) * 8 + (lane & 7);
    int a_col8 = ((lane >> 4) & 1) * 8;
    int b_row8 = ((lane >> 4) & 1) * 8 + (lane & 7);
    int b_col8 = ((lane >> 3) & 1) * 8;

    load_stage(0, 0); CP_COMMIT();
    CP_WAIT0(); __syncthreads();

    const int NK = 72;
    for (int kc = 0; kc < NK; kc++) {
        int cur = kc & 1;
        if (kc + 1 < NK) { load_stage(kc + 1, cur ^ 1); CP_COMMIT(); }

        __nv_bfloat16* base = sm + cur * OFF_STG;
        __nv_bfloat16* pAh = base;
        __nv_bfloat16* pAl = base + OFF_A_ARR;
        __nv_bfloat16* pBh = base + 2 * OFF_A_ARR;
        __nv_bfloat16* pBl = base + 2 * OFF_A_ARR + OFF_B_ARR;
#pragma unroll
        for (int ks = 0; ks < 2; ks++) {
            uint32_t af[2][4];
            ldmx4(af[0], smem_u32(pAh + (wid * 16 + a_row8) * 40 + ks * 16 + a_col8));
            ldmx4(af[1], smem_u32(pAl + (wid * 16 + a_row8) * 40 + ks * 16 + a_col8));
#pragma unroll
            for (int jp = 0; jp < 2; jp++) {
                uint32_t bh[4], bl[4];
                ldmx4(bh, smem_u32(pBh + (jp * 16 + b_row8) * 40 + ks * 16 + b_col8));
                ldmx4(bl, smem_u32(pBl + (jp * 16 + b_row8) * 40 + ks * 16 + b_col8));
#pragma unroll
                for (int jj = 0; jj < 2; jj++) {
                    int j = jp * 2 + jj;
                    uint32_t bh2[2] = {bh[jj * 2], bh[jj * 2 + 1]};
                    uint32_t bl2[2] = {bl[jj * 2], bl[jj * 2 + 1]};
                    mma16816(acc[j], af[0], bh2);
                    mma16816(acc[j], af[0], bl2);
                    mma16816(acc[j], af[1], bh2);
                }
            }
        }
        if (kc + 1 < NK) CP_WAIT0();
        __syncthreads();
    }

    float* op = g_offp + (size_t)(br * BATCH + b) * 18 * HWSZ;
    int g = lane >> 2, q = lane & 3;
#pragma unroll
    for (int half = 0; half < 2; half++) {
        int wcol = wid * 16 + g + half * 8;
        int pimg = h * WW + wcol;
#pragma unroll
        for (int j = 0; j < 4; j++) {
#pragma unroll
            for (int e = 0; e < 2; e++) {
                int n = j * 8 + q * 2 + e;
                if (n < 18) op[(size_t)n * HWSZ + pimg] = acc[j][half * 2 + e];
            }
        }
    }
}

// ---------------- fused deform3: 4 pixels/warp, k-outer weights in regs ----------------
__global__ void __launch_bounds__(256)
k_deform3(const float* __restrict__ dw0, const float* __restrict__ dw1,
          const float* __restrict__ dw2,
          const float* __restrict__ lw0, const float* __restrict__ lb0,
          const float* __restrict__ lw1, const float* __restrict__ lb1,
          const float* __restrict__ lw2, const float* __restrict__ lb2,
          const float* __restrict__ n1w, const float* __restrict__ n1b) {
    __shared__ float sdefT[3][9 * CH];
    __shared__ int   sidx[8][4][36];
    __shared__ float swgt[8][4][36];

    int tid = threadIdx.x, wid = tid >> 5, lane = tid & 31;
    {
        const float* dws[3] = {dw0, dw1, dw2};
#pragma unroll
        for (int br = 0; br < 3; br++)
            for (int i = tid; i < 9 * CH; i += 256) {
                int c = i / 9, k = i % 9;
                sdefT[br][k * CH + c] = dws[br][i];
            }
    }
    __syncthreads();

    int pix0 = blockIdx.x * 32 + wid * 4;
    int b = pix0 >> 14;
    int c0 = lane * 8;
    const float* xrow = g_xT + (size_t)b * HWSZ * CH;

    float sum[4][8];
#pragma unroll
    for (int e = 0; e < 4; e++) {
        const float4* ap = (const float4*)(g_acc + (size_t)(pix0 + e) * CH + c0);
        float4 a0 = ap[0], a1 = ap[1];
        sum[e][0] = a0.x; sum[e][1] = a0.y; sum[e][2] = a0.z; sum[e][3] = a0.w;
        sum[e][4] = a1.x; sum[e][5] = a1.y; sum[e][6] = a1.z; sum[e][7] = a1.w;
    }

    const int DS[3] = {1, 9, 12};
    const float* lws[3] = {lw0, lw1, lw2};
    const float* lbs[3] = {lb0, lb1, lb2};

#pragma unroll
    for (int br = 0; br < 3; br++) {
        int D = DS[br];
        for (int t = lane; t < 36; t += 32) {
            int e = t / 9, k = t % 9;
            int pix = pix0 + e;
            int p = pix & (HWSZ - 1);
            int h = p >> 7, w = p & 127;
            int ky = k / 3, kx = k % 3;
            const float* op = g_offp + (size_t)(br * BATCH + b) * 18 * HWSZ;
            float oy = op[(size_t)(2 * k) * HWSZ + p];
            float ox = op[(size_t)(2 * k + 1) * HWSZ + p];
            float py = (float)h + (float)((ky - 1) * D) + oy;
            float px = (float)w + (float)((kx - 1) * D) + ox;
            float y0 = floorf(py), x0 = floorf(px);
#pragma unroll
            for (int dy = 0; dy < 2; dy++)
#pragma unroll
                for (int dx = 0; dx < 2; dx++) {
                    float yc = y0 + dy, xc = x0 + dx;
                    float wq = (1.f - fabsf(py - yc)) * (1.f - fabsf(px - xc));
                    bool valid = (yc >= 0.f) && (yc < 128.f) && (xc >= 0.f) && (xc < 128.f);
                    int iy = min(max((int)yc, 0), 127);
                    int ix = min(max((int)xc, 0), 127);
                    sidx[wid][e][k * 4 + dy * 2 + dx] = iy * WW + ix;
                    swgt[wid][e][k * 4 + dy * 2 + dx] = valid ? wq : 0.f;
                }
        }
        __syncwarp();

        float facc[4][8];
#pragma unroll
        for (int e = 0; e < 4; e++)
#pragma unroll
            for (int r = 0; r < 8; r++) facc[e][r] = 0.f;

#pragma unroll
        for (int k = 0; k < 9; k++) {
            float4 wk0 = *(const float4*)&sdefT[br][k * CH + c0];
            float4 wk1 = *(const float4*)&sdefT[br][k * CH + c0 + 4];
#pragma unroll
            for (int e = 0; e < 4; e++) {
                float s[8];
#pragma unroll
                for (int r = 0; r < 8; r++) s[r] = 0.f;
#pragma unroll
                for (int j = 0; j < 4; j++) {
                    float wq = swgt[wid][e][k * 4 + j];
                    if (wq != 0.f) {
                        const float4* vp =
                            (const float4*)(xrow + (size_t)sidx[wid][e][k * 4 + j] * CH + c0);
                        float4 v0 = vp[0], v1 = vp[1];
                        s[0] += wq * v0.x; s[1] += wq * v0.y; s[2] += wq * v0.z; s[3] += wq * v0.w;
                        s[4] += wq * v1.x; s[5] += wq * v1.y; s[6] += wq * v1.z; s[7] += wq * v1.w;
                    }
                }
                facc[e][0] += wk0.x * s[0]; facc[e][1] += wk0.y * s[1];
                facc[e][2] += wk0.z * s[2]; facc[e][3] += wk0.w * s[3];
                facc[e][4] += wk1.x * s[4]; facc[e][5] += wk1.y * s[5];
                facc[e][6] += wk1.z * s[6]; facc[e][7] += wk1.w * s[7];
            }
        }

        const float4* lwp = (const float4*)(lws[br] + c0);
        const float4* lbp = (const float4*)(lbs[br] + c0);
        float4 lw0v = lwp[0], lw1v = lwp[1], lb0v = lbp[0], lb1v = lbp[1];
        float lw[8] = {lw0v.x, lw0v.y, lw0v.z, lw0v.w, lw1v.x, lw1v.y, lw1v.z, lw1v.w};
        float lb[8] = {lb0v.x, lb0v.y, lb0v.z, lb0v.w, lb1v.x, lb1v.y, lb1v.z, lb1v.w};
#pragma unroll
        for (int e = 0; e < 4; e++) {
            float ls = 0.f, lq = 0.f;
#pragma unroll
            for (int r = 0; r < 8; r++) { ls += facc[e][r]; lq += facc[e][r] * facc[e][r]; }
#pragma unroll
            for (int o = 16; o; o >>= 1) {
                ls += __shfl_xor_sync(0xffffffffu, ls, o);
                lq += __shfl_xor_sync(0xffffffffu, lq, o);
            }
            float mean = ls * (1.f / 256.f);
            float var  = lq * (1.f / 256.f) - mean * mean;
            float rstd = rsqrtf(var + LN_EPS);
#pragma unroll
            for (int r = 0; r < 8; r++)
                sum[e][r] += gelu_f(lw[r] * ((facc[e][r] - mean) * rstd) + lb[r]);
        }
        __syncwarp();
    }

    const float4* wp = (const float4*)(n1w + c0);
    const float4* bp = (const float4*)(n1b + c0);
    float4 w0v = wp[0], w1v = wp[1], b0v = bp[0], b1v = bp[1];
    float gw[8] = {w0v.x, w0v.y, w0v.z, w0v.w, w1v.x, w1v.y, w1v.z, w1v.w};
    float gb[8] = {b0v.x, b0v.y, b0v.z, b0v.w, b1v.x, b1v.y, b1v.z, b1v.w};

#pragma unroll
    for (int e = 0; e < 4; e++) {
        float ls = 0.f, lq = 0.f;
#pragma unroll
        for (int r = 0; r < 8; r++) { ls += sum[e][r]; lq += sum[e][r] * sum[e][r]; }
#pragma unroll
        for (int o = 16; o; o >>= 1) {
            ls += __shfl_xor_sync(0xffffffffu, ls, o);
            lq += __shfl_xor_sync(0xffffffffu, lq, o);
        }
        float mean = ls * (1.f / 256.f);
        float var  = lq * (1.f / 256.f) - mean * mean;
        float rstd = rsqrtf(var + LN_EPS);

        uint32_t hp[4], lp[4];
#pragma unroll
        for (int r = 0; r < 8; r += 2) {
            float oa = gw[r] * ((sum[e][r] - mean) * rstd) + gb[r];
            float ob = gw[r + 1] * ((sum[e][r + 1] - mean) * rstd) + gb[r + 1];
            __nv_bfloat16 h0, l0, h1, l1;
            split_bf16(oa, h0, l0); split_bf16(ob, h1, l1);
            hp[r >> 1] = (uint32_t)__bfloat16_as_ushort(h0) |
                         ((uint32_t)__bfloat16_as_ushort(h1) << 16);
            lp[r >> 1] = (uint32_t)__bfloat16_as_ushort(l0) |
                         ((uint32_t)__bfloat16_as_ushort(l1) << 16);
        }
        *(uint4*)(g_o1h + (size_t)(pix0 + e) * CH + c0) = make_uint4(hp[0], hp[1], hp[2], hp[3]);
        *(uint4*)(g_o1l + (size_t)(pix0 + e) * CH + c0) = make_uint4(lp[0], lp[1], lp[2], lp[3]);
    }
}

// ---------------- split-bf16 GEMM via mma.sync, cp.async double-buffered, 2 blk/SM ----------------
#define G_ARR (128 * 40)
#define G_STG (4 * G_ARR)
#define G_SMEM (2 * G_STG * 2)

template <int ACT, bool RES, bool BF16OUT>
__global__ void __launch_bounds__(256, 2)
k_mmagemm(const __nv_bfloat16* __restrict__ Ah, const __nv_bfloat16* __restrict__ Al,
          const __nv_bfloat16* __restrict__ Bh, const __nv_bfloat16* __restrict__ Bl,
          const float* __restrict__ bias,
          const __nv_bfloat16* __restrict__ Resh, const __nv_bfloat16* __restrict__ Resl,
          float* __restrict__ Cf, __nv_bfloat16* __restrict__ Chi,
          __nv_bfloat16* __restrict__ Clo, int N, int K) {
    extern __shared__ char dsm_[];
    __nv_bfloat16* sm = (__nv_bfloat16*)dsm_;

    int tid  = threadIdx.x;
    int wid  = tid >> 5, lane = tid & 31;
    int m0   = blockIdx.x * 128, n0 = blockIdx.y * 128;
    int wm   = (wid & 3) * 32;
    int wn   = (wid >> 2) * 64;

    float acc[2][8][4];
#pragma unroll
    for (int i = 0; i < 2; i++)
#pragma unroll
        for (int j = 0; j < 8; j++)
#pragma unroll
            for (int q = 0; q < 4; q++) acc[i][j][q] = 0.f;

    const __nv_bfloat16* srcs[4] = {Ah + (size_t)m0 * K, Al + (size_t)m0 * K,
                                    Bh + (size_t)n0 * K, Bl + (size_t)n0 * K};

    auto load_stage = [&](int kc, int s) {
        __nv_bfloat16* base = sm + s * G_STG;
#pragma unroll
        for (int t = 0; t < 4; t++) {
            const __nv_bfloat16* src = srcs[t] + kc * 32;
            uint32_t dstb = smem_u32(base + t * G_ARR);
#pragma unroll
            for (int u = 0; u < 2; u++) {
                int idx = u * 256 + tid;
                int row = idx >> 2, ch = idx & 3;
                cp16(dstb + (uint32_t)(row * 40 + ch * 8) * 2,
                     src + (size_t)row * K + ch * 8);
            }
        }
    };

    int a_row8 = ((lane >> 3) & 1) * 8 + (lane & 7);
    int a_col8 = ((lane >> 4) & 1) * 8;
    int b_row8 = ((lane >> 4) & 1) * 8 + (lane & 7);
    int b_col8 = ((lane >> 3) & 1) * 8;

    load_stage(0, 0); CP_COMMIT();
    CP_WAIT0(); __syncthreads();

    int nk = K >> 5;
    for (int kc = 0; kc < nk; kc++) {
        int cur = kc & 1;
        if (kc + 1 < nk) { load_stage(kc + 1, cur ^ 1); CP_COMMIT(); }

        __nv_bfloat16* base = sm + cur * G_STG;
        __nv_bfloat16* pA[2] = {base, base + G_ARR};
        __nv_bfloat16* pB[2] = {base + 2 * G_ARR, base + 3 * G_ARR};
#pragma unroll
        for (int ks = 0; ks < 2; ks++) {
            uint32_t af[2][2][4];
#pragma unroll
            for (int hl = 0; hl < 2; hl++)
#pragma unroll
                for (int mi = 0; mi < 2; mi++)
                    ldmx4(af[hl][mi],
                          smem_u32(pA[hl] + (wm + mi * 16 + a_row8) * 40 + ks * 16 + a_col8));
            // B fragments loaded per-jp to cap register pressure (2 blk/SM)
#pragma unroll
            for (int jp = 0; jp < 4; jp++) {
                uint32_t bh[4], bl[4];
                ldmx4(bh, smem_u32(pB[0] + (wn + jp * 16 + b_row8) * 40 + ks * 16 + b_col8));
                ldmx4(bl, smem_u32(pB[1] + (wn + jp * 16 + b_row8) * 40 + ks * 16 + b_col8));
#pragma unroll
                for (int mi = 0; mi < 2; mi++)
#pragma unroll
                    for (int jj = 0; jj < 2; jj++) {
                        int j = jp * 2 + jj;
                        uint32_t bh2[2] = {bh[jj * 2], bh[jj * 2 + 1]};
                        uint32_t bl2[2] = {bl[jj * 2], bl[jj * 2 + 1]};
                        mma16816(acc[mi][j], af[0][mi], bh2);
                        mma16816(acc[mi][j], af[0][mi], bl2);
                        mma16816(acc[mi][j], af[1][mi], bh2);
                    }
            }
        }
        if (kc + 1 < nk) CP_WAIT0();
        __syncthreads();
    }

    int g = lane >> 2, q = lane & 3;
#pragma unroll
    for (int mi = 0; mi < 2; mi++) {
#pragma unroll
        for (int half = 0; half < 2; half++) {
            int m = m0 + wm + mi * 16 + g + half * 8;
#pragma unroll
            for (int j = 0; j < 8; j++) {
                int n = n0 + wn + j * 8 + q * 2;
                float v0 = acc[mi][j][half * 2 + 0] + __ldg(bias + n);
                float v1 = acc[mi][j][half * 2 + 1] + __ldg(bias + n + 1);
                if (ACT == 1) { v0 = gelu_f(v0); v1 = gelu_f(v1); }
                if (RES) {
                    __nv_bfloat162 rh = *(const __nv_bfloat162*)(Resh + (size_t)m * N + n);
                    __nv_bfloat162 rl = *(const __nv_bfloat162*)(Resl + (size_t)m * N + n);
                    v0 += __bfloat162float(rh.x) + __bfloat162float(rl.x);
                    v1 += __bfloat162float(rh.y) + __bfloat162float(rl.y);
                }
                if (BF16OUT) {
                    __nv_bfloat16 h0, l0, h1, l1;
                    split_bf16(v0, h0, l0); split_bf16(v1, h1, l1);
                    *(__nv_bfloat162*)(Chi + (size_t)m * N + n) = __nv_bfloat162(h0, h1);
                    *(__nv_bfloat162*)(Clo + (size_t)m * N + n) = __nv_bfloat162(l0, l1);
                } else {
                    *(float2*)(Cf + (size_t)m * N + n) = make_float2(v0, v1);
                }
            }
        }
    }
}

// ---------------- fused LN2 + NHWC->NCHW output ----------------
__global__ void __launch_bounds__(256)
k_ln2out(const float* __restrict__ in, float* __restrict__ out,
         const float* __restrict__ gwv, const float* __restrict__ gbv) {
    __shared__ float tr[256][33];
    int tid = threadIdx.x, wid = tid >> 5, lane = tid & 31;
    int p32 = blockIdx.x * 32;
    int b = p32 >> 14;
    int pimg = p32 & (HWSZ - 1);

#pragma unroll
    for (int i = 0; i < 4; i++) {
        int pxloc = wid + i * 8;
        const float4* row = (const float4*)(in + (size_t)(p32 + pxloc) * CH);
        float4 va = row[lane], vb = row[lane + 32];
        float s = va.x + va.y + va.z + va.w + vb.x + vb.y + vb.z + vb.w;
        float qq = va.x * va.x + va.y * va.y + va.z * va.z + va.w * va.w +
                   vb.x * vb.x + vb.y * vb.y + vb.z * vb.z + vb.w * vb.w;
#pragma unroll
        for (int o = 16; o; o >>= 1) {
            s  += __shfl_xor_sync(0xffffffffu, s, o);
            qq += __shfl_xor_sync(0xffffffffu, qq, o);
        }
        float mean = s * (1.f / 256.f);
        float var  = qq * (1.f / 256.f) - mean * mean;
        float rstd = rsqrtf(var + LN_EPS);
        int ca = lane * 4, cb = 128 + lane * 4;
        float4 ga = *(const float4*)(gwv + ca), gba = *(const float4*)(gbv + ca);
        float4 gb2 = *(const float4*)(gwv + cb), gbb = *(const float4*)(gbv + cb);
        tr[ca + 0][pxloc] = ga.x * ((va.x - mean) * rstd) + gba.x;
        tr[ca + 1][pxloc] = ga.y * ((va.y - mean) * rstd) + gba.y;
        tr[ca + 2][pxloc] = ga.z * ((va.z - mean) * rstd) + gba.z;
        tr[ca + 3][pxloc] = ga.w * ((va.w - mean) * rstd) + gba.w;
        tr[cb + 0][pxloc] = gb2.x * ((vb.x - mean) * rstd) + gbb.x;
        tr[cb + 1][pxloc] = gb2.y * ((vb.y - mean) * rstd) + gbb.y;
        tr[cb + 2][pxloc] = gb2.z * ((vb.z - mean) * rstd) + gbb.z;
        tr[cb + 3][pxloc] = gb2.w * ((vb.w - mean) * rstd) + gbb.w;
    }
    __syncthreads();

    float* ob = out + (size_t)b * CH * HWSZ + pimg;
#pragma unroll
    for (int it = 0; it < 32; it++) {
        int c = it * 8 + wid;
        ob[(size_t)c * HWSZ + lane] = tr[c][lane];
    }
}

// ---------------- launch ----------------
extern "C" void kernel_launch(void* const* d_in, const int* in_sizes, int n_in,
                              void* d_out, int out_size) {
    const float* x       = (const float*)d_in[0];
    const float* off_w1  = (const float*)d_in[1];
    const float* def_w1  = (const float*)d_in[2];
    const float* bw1     = (const float*)d_in[3];
    const float* bb1     = (const float*)d_in[4];
    const float* off_w2  = (const float*)d_in[5];
    const float* def_w2  = (const float*)d_in[6];
    const float* bw2     = (const float*)d_in[7];
    const float* bb2     = (const float*)d_in[8];
    const float* off_w3  = (const float*)d_in[9];
    const float* def_w3  = (const float*)d_in[10];
    const float* bw3     = (const float*)d_in[11];
    const float* bb3     = (const float*)d_in[12];
    const float* conv_w  = (const float*)d_in[13];
    const float* conv_b  = (const float*)d_in[14];
    const float* n1_w    = (const float*)d_in[15];
    const float* n1_b    = (const float*)d_in[16];
    const float* n2_w    = (const float*)d_in[17];
    const float* n2_b    = (const float*)d_in[18];
    const float* mlp_w1  = (const float*)d_in[19];
    const float* mlp_b1  = (const float*)d_in[20];
    const float* mlp_w2  = (const float*)d_in[21];
    const float* mlp_b2  = (const float*)d_in[22];

    float *pacc, *pt2;
    __nv_bfloat16 *po1h, *po1l, *phh, *phl, *pwh, *pwl, *pxTh, *pxTl;
    cudaGetSymbolAddress((void**)&pacc,  g_acc);
    cudaGetSymbolAddress((void**)&pt2,   g_t2);
    cudaGetSymbolAddress((void**)&pxTh,  g_xTh);
    cudaGetSymbolAddress((void**)&pxTl,  g_xTl);
    cudaGetSymbolAddress((void**)&po1h,  g_o1h);
    cudaGetSymbolAddress((void**)&po1l,  g_o1l);
    cudaGetSymbolAddress((void**)&phh,   g_hh);
    cudaGetSymbolAddress((void**)&phl,   g_hl);
    cudaGetSymbolAddress((void**)&pwh,   g_wh);
    cudaGetSymbolAddress((void**)&pwl,   g_wl);

    cudaFuncSetAttribute(k_mmagemm<0, false, false>,
                         cudaFuncAttributeMaxDynamicSharedMemorySize, G_SMEM);
    cudaFuncSetAttribute(k_mmagemm<1, false, true>,
                         cudaFuncAttributeMaxDynamicSharedMemorySize, G_SMEM);
    cudaFuncSetAttribute(k_mmagemm<0, true, false>,
                         cudaFuncAttributeMaxDynamicSharedMemorySize, G_SMEM);
    cudaFuncSetAttribute(k_offmma,
                         cudaFuncAttributeMaxDynamicSharedMemorySize, OFF_SMEM);

    // 1. x -> NHWC (+ hi/lo split)
    k_nchw2nhwc<<<dim3(HWSZ / 32, CH / 32, BATCH), dim3(32, 8)>>>(x);
    // 2. weight prep
    k_prep<<<(81920 + 255) / 256, 256>>>(conv_w, mlp_w1, mlp_w2);
    k_owprep<<<(3 * 32 * 2304 + 255) / 256, 256>>>(off_w1, off_w2, off_w3);
    // 3. conv1x1: acc = xT @ conv_w^T + conv_b
    k_mmagemm<0, false, false><<<dim3(PTOT / 128, CH / 128), 256, G_SMEM>>>(
        pxTh, pxTl, pwh, pwl, conv_b, nullptr, nullptr, pacc, nullptr, nullptr, CH, CH);
    // 4. offset convs via HMMA
    k_offmma<<<dim3(PTOT / 128, 3), 256, OFF_SMEM>>>();
    // 5. fused deform x3 + LN1 + split (4 px/warp)
    k_deform3<<<PTOT / 32, 256>>>(def_w1, def_w2, def_w3,
                                  bw1, bb1, bw2, bb2, bw3, bb3, n1_w, n1_b);
    // 6. MLP1 (bias+GELU, bf16 hi/lo out)
    k_mmagemm<1, false, true><<<dim3(PTOT / 128, 512 / 128), 256, G_SMEM>>>(
        po1h, po1l, pwh + 65536, pwl + 65536, mlp_b1, nullptr, nullptr,
        nullptr, phh, phl, 512, CH);
    // 7. MLP2 (bias + residual o1h+o1l)
    k_mmagemm<0, true, false><<<dim3(PTOT / 128, CH / 128), 256, G_SMEM>>>(
        phh, phl, pwh + 196608, pwl + 196608, mlp_b2, po1h, po1l,
        pt2, nullptr, nullptr, CH, 512);
    // 8. fused LN2 + transpose out
    k_ln2out<<<PTOT / 32, 256>>>(pt2, (float*)d_out, n2_w, n2_b);
}

// round 10
// speedup vs baseline: 1.9875x; 1.0218x over previous
#include <cuda_runtime.h>
#include <cuda_bf16.h>
#include <math.h>
#include <stdint.h>

#define BATCH 2
#define CH    256
#define HH    128
#define WW    128
#define HWSZ  16384
#define PTOT  32768
#define LN_EPS 1e-6f

// ---------------- scratch ----------------
__device__ float g_xT  [(size_t)PTOT * CH];
__device__ float g_acc [(size_t)PTOT * CH];
__device__ float g_t2  [(size_t)PTOT * CH];
__device__ float g_offp[(size_t)3 * BATCH * 18 * HWSZ];   // [branch][b][18][HW]
__device__ __nv_bfloat16 g_xTh[(size_t)PTOT * CH];
__device__ __nv_bfloat16 g_xTl[(size_t)PTOT * CH];
__device__ __nv_bfloat16 g_o1h[(size_t)PTOT * CH];
__device__ __nv_bfloat16 g_o1l[(size_t)PTOT * CH];
__device__ __nv_bfloat16 g_hh [(size_t)PTOT * 512];
__device__ __nv_bfloat16 g_hl [(size_t)PTOT * 512];
__device__ __nv_bfloat16 g_wh[327680];
__device__ __nv_bfloat16 g_wl[327680];
__device__ __nv_bfloat16 g_owh[3 * 32 * 2304];
__device__ __nv_bfloat16 g_owl[3 * 32 * 2304];

__device__ __forceinline__ float gelu_f(float v) {
    return 0.5f * v * (1.0f + erff(v * 0.70710678118654752440f));
}
__device__ __forceinline__ void split_bf16(float v, __nv_bfloat16& h, __nv_bfloat16& l) {
    h = __float2bfloat16(v);
    l = __float2bfloat16(v - __bfloat162float(h));
}
__device__ __forceinline__ uint32_t smem_u32(const void* p) {
    uint32_t a;
    asm("{ .reg .u64 t; cvta.to.shared.u64 t, %1; cvt.u32.u64 %0, t; }" : "=r"(a) : "l"(p));
    return a;
}
__device__ __forceinline__ void ldmx4(uint32_t* r, uint32_t addr) {
    asm volatile("ldmatrix.sync.aligned.m8n8.x4.shared.b16 {%0,%1,%2,%3}, [%4];"
                 : "=r"(r[0]), "=r"(r[1]), "=r"(r[2]), "=r"(r[3]) : "r"(addr));
}
__device__ __forceinline__ void mma16816(float* c, const uint32_t* a, const uint32_t* b) {
    asm volatile("mma.sync.aligned.m16n8k16.row.col.f32.bf16.bf16.f32 "
                 "{%0,%1,%2,%3}, {%4,%5,%6,%7}, {%8,%9}, {%0,%1,%2,%3};"
                 : "+f"(c[0]), "+f"(c[1]), "+f"(c[2]), "+f"(c[3])
                 : "r"(a[0]), "r"(a[1]), "r"(a[2]), "r"(a[3]), "r"(b[0]), "r"(b[1]));
}
__device__ __forceinline__ void cp16(uint32_t dst, const void* src) {
    asm volatile("cp.async.cg.shared.global [%0], [%1], 16;" :: "r"(dst), "l"(src));
}
__device__ __forceinline__ void cp16z(uint32_t dst, const void* src, bool valid) {
    int sz = valid ? 16 : 0;
    asm volatile("cp.async.cg.shared.global [%0], [%1], 16, %2;"
                 :: "r"(dst), "l"(src), "r"(sz));
}
#define CP_COMMIT() asm volatile("cp.async.commit_group;" ::: "memory")
#define CP_WAIT0()  asm volatile("cp.async.wait_group 0;" ::: "memory")

// =================== GEMM body (split-bf16 HMMA, cp.async double-buffered) ===================
#define G_ARR (128 * 40)
#define G_STG (4 * G_ARR)
#define G_SMEM (2 * G_STG * 2)   // 81920 bytes

template <int ACT, bool RES, bool BF16OUT>
__device__ __forceinline__ void gemm_body(
        char* dsm_, int mblk, int nblk,
        const __nv_bfloat16* __restrict__ Ah, const __nv_bfloat16* __restrict__ Al,
        const __nv_bfloat16* __restrict__ Bh, const __nv_bfloat16* __restrict__ Bl,
        const float* __restrict__ bias,
        const __nv_bfloat16* __restrict__ Resh, const __nv_bfloat16* __restrict__ Resl,
        float* __restrict__ Cf, __nv_bfloat16* __restrict__ Chi,
        __nv_bfloat16* __restrict__ Clo, int N, int K) {
    __nv_bfloat16* sm = (__nv_bfloat16*)dsm_;

    int tid  = threadIdx.x;
    int wid  = tid >> 5, lane = tid & 31;
    int m0   = mblk * 128, n0 = nblk * 128;
    int wm   = (wid & 3) * 32;
    int wn   = (wid >> 2) * 64;

    float acc[2][8][4];
#pragma unroll
    for (int i = 0; i < 2; i++)
#pragma unroll
        for (int j = 0; j < 8; j++)
#pragma unroll
            for (int q = 0; q < 4; q++) acc[i][j][q] = 0.f;

    const __nv_bfloat16* srcs[4] = {Ah + (size_t)m0 * K, Al + (size_t)m0 * K,
                                    Bh + (size_t)n0 * K, Bl + (size_t)n0 * K};

    auto load_stage = [&](int kc, int s) {
        __nv_bfloat16* base = sm + s * G_STG;
#pragma unroll
        for (int t = 0; t < 4; t++) {
            const __nv_bfloat16* src = srcs[t] + kc * 32;
            uint32_t dstb = smem_u32(base + t * G_ARR);
#pragma unroll
            for (int u = 0; u < 2; u++) {
                int idx = u * 256 + tid;
                int row = idx >> 2, ch = idx & 3;
                cp16(dstb + (uint32_t)(row * 40 + ch * 8) * 2,
                     src + (size_t)row * K + ch * 8);
            }
        }
    };

    int a_row8 = ((lane >> 3) & 1) * 8 + (lane & 7);
    int a_col8 = ((lane >> 4) & 1) * 8;
    int b_row8 = ((lane >> 4) & 1) * 8 + (lane & 7);
    int b_col8 = ((lane >> 3) & 1) * 8;

    load_stage(0, 0); CP_COMMIT();
    CP_WAIT0(); __syncthreads();

    int nk = K >> 5;
    for (int kc = 0; kc < nk; kc++) {
        int cur = kc & 1;
        if (kc + 1 < nk) { load_stage(kc + 1, cur ^ 1); CP_COMMIT(); }

        __nv_bfloat16* base = sm + cur * G_STG;
        __nv_bfloat16* pA[2] = {base, base + G_ARR};
        __nv_bfloat16* pB[2] = {base + 2 * G_ARR, base + 3 * G_ARR};
#pragma unroll
        for (int ks = 0; ks < 2; ks++) {
            uint32_t af[2][2][4];
#pragma unroll
            for (int hl = 0; hl < 2; hl++)
#pragma unroll
                for (int mi = 0; mi < 2; mi++)
                    ldmx4(af[hl][mi],
                          smem_u32(pA[hl] + (wm + mi * 16 + a_row8) * 40 + ks * 16 + a_col8));
#pragma unroll
            for (int jp = 0; jp < 4; jp++) {
                uint32_t bh[4], bl[4];
                ldmx4(bh, smem_u32(pB[0] + (wn + jp * 16 + b_row8) * 40 + ks * 16 + b_col8));
                ldmx4(bl, smem_u32(pB[1] + (wn + jp * 16 + b_row8) * 40 + ks * 16 + b_col8));
#pragma unroll
                for (int mi = 0; mi < 2; mi++)
#pragma unroll
                    for (int jj = 0; jj < 2; jj++) {
                        int j = jp * 2 + jj;
                        uint32_t bh2[2] = {bh[jj * 2], bh[jj * 2 + 1]};
                        uint32_t bl2[2] = {bl[jj * 2], bl[jj * 2 + 1]};
                        mma16816(acc[mi][j], af[0][mi], bh2);
                        mma16816(acc[mi][j], af[0][mi], bl2);
                        mma16816(acc[mi][j], af[1][mi], bh2);
                    }
            }
        }
        if (kc + 1 < nk) CP_WAIT0();
        __syncthreads();
    }

    int g = lane >> 2, q = lane & 3;
#pragma unroll
    for (int mi = 0; mi < 2; mi++) {
#pragma unroll
        for (int half = 0; half < 2; half++) {
            int m = m0 + wm + mi * 16 + g + half * 8;
#pragma unroll
            for (int j = 0; j < 8; j++) {
                int n = n0 + wn + j * 8 + q * 2;
                float v0 = acc[mi][j][half * 2 + 0] + __ldg(bias + n);
                float v1 = acc[mi][j][half * 2 + 1] + __ldg(bias + n + 1);
                if (ACT == 1) { v0 = gelu_f(v0); v1 = gelu_f(v1); }
                if (RES) {
                    __nv_bfloat162 rh = *(const __nv_bfloat162*)(Resh + (size_t)m * N + n);
                    __nv_bfloat162 rl = *(const __nv_bfloat162*)(Resl + (size_t)m * N + n);
                    v0 += __bfloat162float(rh.x) + __bfloat162float(rl.x);
                    v1 += __bfloat162float(rh.y) + __bfloat162float(rl.y);
                }
                if (BF16OUT) {
                    __nv_bfloat16 h0, l0, h1, l1;
                    split_bf16(v0, h0, l0); split_bf16(v1, h1, l1);
                    *(__nv_bfloat162*)(Chi + (size_t)m * N + n) = __nv_bfloat162(h0, h1);
                    *(__nv_bfloat162*)(Clo + (size_t)m * N + n) = __nv_bfloat162(l0, l1);
                } else {
                    *(float2*)(Cf + (size_t)m * N + n) = make_float2(v0, v1);
                }
            }
        }
    }
}

// =================== offmma body ===================
#define OFF_A_ARR (128 * 40)
#define OFF_B_ARR (32 * 40)
#define OFF_STG   (2 * OFF_A_ARR + 2 * OFF_B_ARR)

__device__ __forceinline__ void offmma_body(char* dsm_, int bx, int br) {
    __nv_bfloat16* sm = (__nv_bfloat16*)dsm_;

    int tid = threadIdx.x, wid = tid >> 5, lane = tid & 31;
    int h = bx & 127, b = bx >> 7;
    const int D = (br == 0) ? 1 : (br == 1) ? 9 : 12;

    const __nv_bfloat16* xh = g_xTh + (size_t)b * HWSZ * CH;
    const __nv_bfloat16* xl = g_xTl + (size_t)b * HWSZ * CH;
    const __nv_bfloat16* wbh = g_owh + (size_t)br * 32 * 2304;
    const __nv_bfloat16* wbl = g_owl + (size_t)br * 32 * 2304;

    float acc[4][4];
#pragma unroll
    for (int j = 0; j < 4; j++)
#pragma unroll
        for (int q = 0; q < 4; q++) acc[j][q] = 0.f;

    auto load_stage = [&](int kc, int s) {
        __nv_bfloat16* base = sm + s * OFF_STG;
        uint32_t sAh = smem_u32(base);
        uint32_t sAl = sAh + OFF_A_ARR * 2;
        uint32_t sBh = sAl + OFF_A_ARR * 2;
        uint32_t sBl = sBh + OFF_B_ARR * 2;
        int k  = kc >> 3;
        int cc = (kc & 7) * 32;
        int dy = (k / 3 - 1) * D, dx = (k % 3 - 1) * D;
        int srow = h + dy;
        bool vy = (srow >= 0) && (srow < HH);
        int srowc = vy ? srow : 0;
#pragma unroll
        for (int u = 0; u < 2; u++) {
            int idx = u * 256 + tid;
            int w = idx >> 2, ch = idx & 3;
            int wp = w + dx;
            bool v = vy && (wp >= 0) && (wp < WW);
            int wpc = v ? wp : 0;
            size_t goff = (size_t)(srowc * WW + wpc) * CH + cc + ch * 8;
            uint32_t soff = (uint32_t)(w * 40 + ch * 8) * 2;
            cp16z(sAh + soff, xh + goff, v);
            cp16z(sAl + soff, xl + goff, v);
        }
        if (tid < 128) {
            int o = tid >> 2, ch = tid & 3;
            size_t goff = (size_t)o * 2304 + k * 256 + cc + ch * 8;
            uint32_t soff = (uint32_t)(o * 40 + ch * 8) * 2;
            cp16(sBh + soff, wbh + goff);
            cp16(sBl + soff, wbl + goff);
        }
    };

    int a_row8 = ((lane >> 3) & 1) * 8 + (lane & 7);
    int a_col8 = ((lane >> 4) & 1) * 8;
    int b_row8 = ((lane >> 4) & 1) * 8 + (lane & 7);
    int b_col8 = ((lane >> 3) & 1) * 8;

    load_stage(0, 0); CP_COMMIT();
    CP_WAIT0(); __syncthreads();

    const int NK = 72;
    for (int kc = 0; kc < NK; kc++) {
        int cur = kc & 1;
        if (kc + 1 < NK) { load_stage(kc + 1, cur ^ 1); CP_COMMIT(); }

        __nv_bfloat16* base = sm + cur * OFF_STG;
        __nv_bfloat16* pAh = base;
        __nv_bfloat16* pAl = base + OFF_A_ARR;
        __nv_bfloat16* pBh = base + 2 * OFF_A_ARR;
        __nv_bfloat16* pBl = base + 2 * OFF_A_ARR + OFF_B_ARR;
#pragma unroll
        for (int ks = 0; ks < 2; ks++) {
            uint32_t af[2][4];
            ldmx4(af[0], smem_u32(pAh + (wid * 16 + a_row8) * 40 + ks * 16 + a_col8));
            ldmx4(af[1], smem_u32(pAl + (wid * 16 + a_row8) * 40 + ks * 16 + a_col8));
#pragma unroll
            for (int jp = 0; jp < 2; jp++) {
                uint32_t bh[4], bl[4];
                ldmx4(bh, smem_u32(pBh + (jp * 16 + b_row8) * 40 + ks * 16 + b_col8));
                ldmx4(bl, smem_u32(pBl + (jp * 16 + b_row8) * 40 + ks * 16 + b_col8));
#pragma unroll
                for (int jj = 0; jj < 2; jj++) {
                    int j = jp * 2 + jj;
                    uint32_t bh2[2] = {bh[jj * 2], bh[jj * 2 + 1]};
                    uint32_t bl2[2] = {bl[jj * 2], bl[jj * 2 + 1]};
                    mma16816(acc[j], af[0], bh2);
                    mma16816(acc[j], af[0], bl2);
                    mma16816(acc[j], af[1], bh2);
                }
            }
        }
        if (kc + 1 < NK) CP_WAIT0();
        __syncthreads();
    }

    float* op = g_offp + (size_t)(br * BATCH + b) * 18 * HWSZ;
    int g = lane >> 2, q = lane & 3;
#pragma unroll
    for (int half = 0; half < 2; half++) {
        int wcol = wid * 16 + g + half * 8;
        int pimg = h * WW + wcol;
#pragma unroll
        for (int j = 0; j < 4; j++) {
#pragma unroll
            for (int e = 0; e < 2; e++) {
                int n = j * 8 + q * 2 + e;
                if (n < 18) op[(size_t)n * HWSZ + pimg] = acc[j][half * 2 + e];
            }
        }
    }
}

// =================== stage 1: conv1x1 GEMM (blocks 0..511) + offmma (512..1279) ===================
__global__ void __launch_bounds__(256, 2)
k_stage1(const __nv_bfloat16* __restrict__ xTh, const __nv_bfloat16* __restrict__ xTl,
         const __nv_bfloat16* __restrict__ cwh, const __nv_bfloat16* __restrict__ cwl,
         const float* __restrict__ conv_b, float* __restrict__ accp) {
    extern __shared__ char dsm_[];
    int bid = blockIdx.x;
    if (bid < 512) {
        gemm_body<0, false, false>(dsm_, bid & 255, bid >> 8,
                                   xTh, xTl, cwh, cwl, conv_b,
                                   nullptr, nullptr, accp, nullptr, nullptr, CH, CH);
    } else {
        int obid = bid - 512;
        offmma_body(dsm_, obid & 255, obid >> 8);
    }
}

// =================== standalone MLP GEMMs ===================
template <int ACT, bool RES, bool BF16OUT>
__global__ void __launch_bounds__(256, 2)
k_mmagemm(const __nv_bfloat16* __restrict__ Ah, const __nv_bfloat16* __restrict__ Al,
          const __nv_bfloat16* __restrict__ Bh, const __nv_bfloat16* __restrict__ Bl,
          const float* __restrict__ bias,
          const __nv_bfloat16* __restrict__ Resh, const __nv_bfloat16* __restrict__ Resl,
          float* __restrict__ Cf, __nv_bfloat16* __restrict__ Chi,
          __nv_bfloat16* __restrict__ Clo, int N, int K) {
    extern __shared__ char dsm_[];
    gemm_body<ACT, RES, BF16OUT>(dsm_, blockIdx.x, blockIdx.y,
                                 Ah, Al, Bh, Bl, bias, Resh, Resl, Cf, Chi, Clo, N, K);
}

// =================== stage 0: transpose+split (0..8191) | prep (8192..8511) | owprep (8512..9375) ===================
__global__ void __launch_bounds__(256)
k_stage0(const float* __restrict__ x,
         const float* __restrict__ cw, const float* __restrict__ w1,
         const float* __restrict__ w2,
         const float* __restrict__ ow0, const float* __restrict__ ow1,
         const float* __restrict__ ow2) {
    int bid = blockIdx.x;
    int tid = threadIdx.x;
    if (bid < 8192) {
        // NCHW -> NHWC transpose + bf16 hi/lo split
        __shared__ float t[32][33];
        int tb = bid;
        int p0 = (tb & 511) * 32;
        int c0 = ((tb >> 9) & 7) * 32;
        int b  = tb >> 12;
        int tx = tid & 31, ty = tid >> 5;
        const float* xb = x + (size_t)b * CH * HWSZ;
#pragma unroll
        for (int i = 0; i < 4; i++)
            t[ty + 8 * i][tx] = xb[(size_t)(c0 + ty + 8 * i) * HWSZ + p0 + tx];
        __syncthreads();
        size_t base = (size_t)b * HWSZ * CH;
#pragma unroll
        for (int i = 0; i < 4; i++) {
            float v = t[tx][ty + 8 * i];
            size_t idx = base + (size_t)(p0 + ty + 8 * i) * CH + c0 + tx;
            g_xT[idx] = v;
            __nv_bfloat16 h, l; split_bf16(v, h, l);
            g_xTh[idx] = h; g_xTl[idx] = l;
        }
    } else if (bid < 8512) {
        // merged fp32 -> bf16 hi/lo split for conv_w / mlp_w1 / mlp_w2
        int i = (bid - 8192) * 256 + tid;
        if (i >= 81920) return;
        const float* src; int dst;
        if (i < 16384)      { src = cw + i * 4;            dst = i * 4; }
        else if (i < 49152) { src = w1 + (i - 16384) * 4;  dst = 65536 + (i - 16384) * 4; }
        else                { src = w2 + (i - 49152) * 4;  dst = 196608 + (i - 49152) * 4; }
        float4 v = *(const float4*)src;
        __nv_bfloat16 ha, la, hb, lb, hc, lc, hd, ld;
        split_bf16(v.x, ha, la); split_bf16(v.y, hb, lb);
        split_bf16(v.z, hc, lc); split_bf16(v.w, hd, ld);
        ((__nv_bfloat162*)(g_wh + dst))[0] = __nv_bfloat162(ha, hb);
        ((__nv_bfloat162*)(g_wh + dst))[1] = __nv_bfloat162(hc, hd);
        ((__nv_bfloat162*)(g_wl + dst))[0] = __nv_bfloat162(la, lb);
        ((__nv_bfloat162*)(g_wl + dst))[1] = __nv_bfloat162(lc, ld);
    } else {
        // offset-conv weight reorg: [18][256][9] -> [3][32][k*256+c] hi/lo
        int i = (bid - 8512) * 256 + tid;
        if (i >= 3 * 32 * 2304) return;
        int br = i / (32 * 2304);
        int r  = i % (32 * 2304);
        int o  = r / 2304;
        int kk = r % 2304;
        int k  = kk / 256, c = kk % 256;
        const float* w = (br == 0) ? ow0 : (br == 1) ? ow1 : ow2;
        float v = (o < 18) ? w[((size_t)o * 256 + c) * 9 + k] : 0.f;
        __nv_bfloat16 h, l; split_bf16(v, h, l);
        g_owh[i] = h; g_owl[i] = l;
    }
}

// =================== fused deform3: 4 pixels/warp ===================
__global__ void __launch_bounds__(256)
k_deform3(const float* __restrict__ dw0, const float* __restrict__ dw1,
          const float* __restrict__ dw2,
          const float* __restrict__ lw0, const float* __restrict__ lb0,
          const float* __restrict__ lw1, const float* __restrict__ lb1,
          const float* __restrict__ lw2, const float* __restrict__ lb2,
          const float* __restrict__ n1w, const float* __restrict__ n1b) {
    __shared__ float sdefT[3][9 * CH];
    __shared__ int   sidx[8][4][36];
    __shared__ float swgt[8][4][36];

    int tid = threadIdx.x, wid = tid >> 5, lane = tid & 31;
    {
        const float* dws[3] = {dw0, dw1, dw2};
#pragma unroll
        for (int br = 0; br < 3; br++)
            for (int i = tid; i < 9 * CH; i += 256) {
                int c = i / 9, k = i % 9;
                sdefT[br][k * CH + c] = dws[br][i];
            }
    }
    __syncthreads();

    int pix0 = blockIdx.x * 32 + wid * 4;
    int b = pix0 >> 14;
    int c0 = lane * 8;
    const float* xrow = g_xT + (size_t)b * HWSZ * CH;

    float sum[4][8];
#pragma unroll
    for (int e = 0; e < 4; e++) {
        const float4* ap = (const float4*)(g_acc + (size_t)(pix0 + e) * CH + c0);
        float4 a0 = ap[0], a1 = ap[1];
        sum[e][0] = a0.x; sum[e][1] = a0.y; sum[e][2] = a0.z; sum[e][3] = a0.w;
        sum[e][4] = a1.x; sum[e][5] = a1.y; sum[e][6] = a1.z; sum[e][7] = a1.w;
    }

    const int DS[3] = {1, 9, 12};
    const float* lws[3] = {lw0, lw1, lw2};
    const float* lbs[3] = {lb0, lb1, lb2};

#pragma unroll
    for (int br = 0; br < 3; br++) {
        int D = DS[br];
        for (int t = lane; t < 36; t += 32) {
            int e = t / 9, k = t % 9;
            int pix = pix0 + e;
            int p = pix & (HWSZ - 1);
            int h = p >> 7, w = p & 127;
            int ky = k / 3, kx = k % 3;
            const float* op = g_offp + (size_t)(br * BATCH + b) * 18 * HWSZ;
            float oy = op[(size_t)(2 * k) * HWSZ + p];
            float ox = op[(size_t)(2 * k + 1) * HWSZ + p];
            float py = (float)h + (float)((ky - 1) * D) + oy;
            float px = (float)w + (float)((kx - 1) * D) + ox;
            float y0 = floorf(py), x0 = floorf(px);
#pragma unroll
            for (int dy = 0; dy < 2; dy++)
#pragma unroll
                for (int dx = 0; dx < 2; dx++) {
                    float yc = y0 + dy, xc = x0 + dx;
                    float wq = (1.f - fabsf(py - yc)) * (1.f - fabsf(px - xc));
                    bool valid = (yc >= 0.f) && (yc < 128.f) && (xc >= 0.f) && (xc < 128.f);
                    int iy = min(max((int)yc, 0), 127);
                    int ix = min(max((int)xc, 0), 127);
                    sidx[wid][e][k * 4 + dy * 2 + dx] = iy * WW + ix;
                    swgt[wid][e][k * 4 + dy * 2 + dx] = valid ? wq : 0.f;
                }
        }
        __syncwarp();

        float facc[4][8];
#pragma unroll
        for (int e = 0; e < 4; e++)
#pragma unroll
            for (int r = 0; r < 8; r++) facc[e][r] = 0.f;

#pragma unroll
        for (int k = 0; k < 9; k++) {
            float4 wk0 = *(const float4*)&sdefT[br][k * CH + c0];
            float4 wk1 = *(const float4*)&sdefT[br][k * CH + c0 + 4];
#pragma unroll
            for (int e = 0; e < 4; e++) {
                float s[8];
#pragma unroll
                for (int r = 0; r < 8; r++) s[r] = 0.f;
#pragma unroll
                for (int j = 0; j < 4; j++) {
                    float wq = swgt[wid][e][k * 4 + j];
                    if (wq != 0.f) {
                        const float4* vp =
                            (const float4*)(xrow + (size_t)sidx[wid][e][k * 4 + j] * CH + c0);
                        float4 v0 = vp[0], v1 = vp[1];
                        s[0] += wq * v0.x; s[1] += wq * v0.y; s[2] += wq * v0.z; s[3] += wq * v0.w;
                        s[4] += wq * v1.x; s[5] += wq * v1.y; s[6] += wq * v1.z; s[7] += wq * v1.w;
                    }
                }
                facc[e][0] += wk0.x * s[0]; facc[e][1] += wk0.y * s[1];
                facc[e][2] += wk0.z * s[2]; facc[e][3] += wk0.w * s[3];
                facc[e][4] += wk1.x * s[4]; facc[e][5] += wk1.y * s[5];
                facc[e][6] += wk1.z * s[6]; facc[e][7] += wk1.w * s[7];
            }
        }

        const float4* lwp = (const float4*)(lws[br] + c0);
        const float4* lbp = (const float4*)(lbs[br] + c0);
        float4 lw0v = lwp[0], lw1v = lwp[1], lb0v = lbp[0], lb1v = lbp[1];
        float lw[8] = {lw0v.x, lw0v.y, lw0v.z, lw0v.w, lw1v.x, lw1v.y, lw1v.z, lw1v.w};
        float lb[8] = {lb0v.x, lb0v.y, lb0v.z, lb0v.w, lb1v.x, lb1v.y, lb1v.z, lb1v.w};
#pragma unroll
        for (int e = 0; e < 4; e++) {
            float ls = 0.f, lq = 0.f;
#pragma unroll
            for (int r = 0; r < 8; r++) { ls += facc[e][r]; lq += facc[e][r] * facc[e][r]; }
#pragma unroll
            for (int o = 16; o; o >>= 1) {
                ls += __shfl_xor_sync(0xffffffffu, ls, o);
                lq += __shfl_xor_sync(0xffffffffu, lq, o);
            }
            float mean = ls * (1.f / 256.f);
            float var  = lq * (1.f / 256.f) - mean * mean;
            float rstd = rsqrtf(var + LN_EPS);
#pragma unroll
            for (int r = 0; r < 8; r++)
                sum[e][r] += gelu_f(lw[r] * ((facc[e][r] - mean) * rstd) + lb[r]);
        }
        __syncwarp();
    }

    const float4* wp = (const float4*)(n1w + c0);
    const float4* bp = (const float4*)(n1b + c0);
    float4 w0v = wp[0], w1v = wp[1], b0v = bp[0], b1v = bp[1];
    float gw[8] = {w0v.x, w0v.y, w0v.z, w0v.w, w1v.x, w1v.y, w1v.z, w1v.w};
    float gb[8] = {b0v.x, b0v.y, b0v.z, b0v.w, b1v.x, b1v.y, b1v.z, b1v.w};

#pragma unroll
    for (int e = 0; e < 4; e++) {
        float ls = 0.f, lq = 0.f;
#pragma unroll
        for (int r = 0; r < 8; r++) { ls += sum[e][r]; lq += sum[e][r] * sum[e][r]; }
#pragma unroll
        for (int o = 16; o; o >>= 1) {
            ls += __shfl_xor_sync(0xffffffffu, ls, o);
            lq += __shfl_xor_sync(0xffffffffu, lq, o);
        }
        float mean = ls * (1.f / 256.f);
        float var  = lq * (1.f / 256.f) - mean * mean;
        float rstd = rsqrtf(var + LN_EPS);

        uint32_t hp[4], lp[4];
#pragma unroll
        for (int r = 0; r < 8; r += 2) {
            float oa = gw[r] * ((sum[e][r] - mean) * rstd) + gb[r];
            float ob = gw[r + 1] * ((sum[e][r + 1] - mean) * rstd) + gb[r + 1];
            __nv_bfloat16 h0, l0, h1, l1;
            split_bf16(oa, h0, l0); split_bf16(ob, h1, l1);
            hp[r >> 1] = (uint32_t)__bfloat16_as_ushort(h0) |
                         ((uint32_t)__bfloat16_as_ushort(h1) << 16);
            lp[r >> 1] = (uint32_t)__bfloat16_as_ushort(l0) |
                         ((uint32_t)__bfloat16_as_ushort(l1) << 16);
        }
        *(uint4*)(g_o1h + (size_t)(pix0 + e) * CH + c0) = make_uint4(hp[0], hp[1], hp[2], hp[3]);
        *(uint4*)(g_o1l + (size_t)(pix0 + e) * CH + c0) = make_uint4(lp[0], lp[1], lp[2], lp[3]);
    }
}

// =================== fused LN2 + NHWC->NCHW output ===================
__global__ void __launch_bounds__(256)
k_ln2out(const float* __restrict__ in, float* __restrict__ out,
         const float* __restrict__ gwv, const float* __restrict__ gbv) {
    __shared__ float tr[256][33];
    int tid = threadIdx.x, wid = tid >> 5, lane = tid & 31;
    int p32 = blockIdx.x * 32;
    int b = p32 >> 14;
    int pimg = p32 & (HWSZ - 1);

#pragma unroll
    for (int i = 0; i < 4; i++) {
        int pxloc = wid + i * 8;
        const float4* row = (const float4*)(in + (size_t)(p32 + pxloc) * CH);
        float4 va = row[lane], vb = row[lane + 32];
        float s = va.x + va.y + va.z + va.w + vb.x + vb.y + vb.z + vb.w;
        float qq = va.x * va.x + va.y * va.y + va.z * va.z + va.w * va.w +
                   vb.x * vb.x + vb.y * vb.y + vb.z * vb.z + vb.w * vb.w;
#pragma unroll
        for (int o = 16; o; o >>= 1) {
            s  += __shfl_xor_sync(0xffffffffu, s, o);
            qq += __shfl_xor_sync(0xffffffffu, qq, o);
        }
        float mean = s * (1.f / 256.f);
        float var  = qq * (1.f / 256.f) - mean * mean;
        float rstd = rsqrtf(var + LN_EPS);
        int ca = lane * 4, cb = 128 + lane * 4;
        float4 ga = *(const float4*)(gwv + ca), gba = *(const float4*)(gbv + ca);
        float4 gb2 = *(const float4*)(gwv + cb), gbb = *(const float4*)(gbv + cb);
        tr[ca + 0][pxloc] = ga.x * ((va.x - mean) * rstd) + gba.x;
        tr[ca + 1][pxloc] = ga.y * ((va.y - mean) * rstd) + gba.y;
        tr[ca + 2][pxloc] = ga.z * ((va.z - mean) * rstd) + gba.z;
        tr[ca + 3][pxloc] = ga.w * ((va.w - mean) * rstd) + gba.w;
        tr[cb + 0][pxloc] = gb2.x * ((vb.x - mean) * rstd) + gbb.x;
        tr[cb + 1][pxloc] = gb2.y * ((vb.y - mean) * rstd) + gbb.y;
        tr[cb + 2][pxloc] = gb2.z * ((vb.z - mean) * rstd) + gbb.z;
        tr[cb + 3][pxloc] = gb2.w * ((vb.w - mean) * rstd) + gbb.w;
    }
    __syncthreads();

    float* ob = out + (size_t)b * CH * HWSZ + pimg;
#pragma unroll
    for (int it = 0; it < 32; it++) {
        int c = it * 8 + wid;
        ob[(size_t)c * HWSZ + lane] = tr[c][lane];
    }
}

// =================== launch ===================
extern "C" void kernel_launch(void* const* d_in, const int* in_sizes, int n_in,
                              void* d_out, int out_size) {
    const float* x       = (const float*)d_in[0];
    const float* off_w1  = (const float*)d_in[1];
    const float* def_w1  = (const float*)d_in[2];
    const float* bw1     = (const float*)d_in[3];
    const float* bb1     = (const float*)d_in[4];
    const float* off_w2  = (const float*)d_in[5];
    const float* def_w2  = (const float*)d_in[6];
    const float* bw2     = (const float*)d_in[7];
    const float* bb2     = (const float*)d_in[8];
    const float* off_w3  = (const float*)d_in[9];
    const float* def_w3  = (const float*)d_in[10];
    const float* bw3     = (const float*)d_in[11];
    const float* bb3     = (const float*)d_in[12];
    const float* conv_w  = (const float*)d_in[13];
    const float* conv_b  = (const float*)d_in[14];
    const float* n1_w    = (const float*)d_in[15];
    const float* n1_b    = (const float*)d_in[16];
    const float* n2_w    = (const float*)d_in[17];
    const float* n2_b    = (const float*)d_in[18];
    const float* mlp_w1  = (const float*)d_in[19];
    const float* mlp_b1  = (const float*)d_in[20];
    const float* mlp_w2  = (const float*)d_in[21];
    const float* mlp_b2  = (const float*)d_in[22];

    float *pacc, *pt2;
    __nv_bfloat16 *po1h, *po1l, *phh, *phl, *pwh, *pwl, *pxTh, *pxTl;
    cudaGetSymbolAddress((void**)&pacc,  g_acc);
    cudaGetSymbolAddress((void**)&pt2,   g_t2);
    cudaGetSymbolAddress((void**)&pxTh,  g_xTh);
    cudaGetSymbolAddress((void**)&pxTl,  g_xTl);
    cudaGetSymbolAddress((void**)&po1h,  g_o1h);
    cudaGetSymbolAddress((void**)&po1l,  g_o1l);
    cudaGetSymbolAddress((void**)&phh,   g_hh);
    cudaGetSymbolAddress((void**)&phl,   g_hl);
    cudaGetSymbolAddress((void**)&pwh,   g_wh);
    cudaGetSymbolAddress((void**)&pwl,   g_wl);

    cudaFuncSetAttribute(k_stage1,
                         cudaFuncAttributeMaxDynamicSharedMemorySize, G_SMEM);
    cudaFuncSetAttribute(k_mmagemm<1, false, true>,
                         cudaFuncAttributeMaxDynamicSharedMemorySize, G_SMEM);
    cudaFuncSetAttribute(k_mmagemm<0, true, false>,
                         cudaFuncAttributeMaxDynamicSharedMemorySize, G_SMEM);

    // 1. transpose+split | weight prep | offset-weight reorg (one launch)
    k_stage0<<<9376, 256>>>(x, conv_w, mlp_w1, mlp_w2, off_w1, off_w2, off_w3);
    // 2. conv1x1 GEMM + offset convs, co-scheduled in one launch
    k_stage1<<<1280, 256, G_SMEM>>>(pxTh, pxTl, pwh, pwl, conv_b, pacc);
    // 3. fused deform x3 + LN1 + split (4 px/warp)
    k_deform3<<<PTOT / 32, 256>>>(def_w1, def_w2, def_w3,
                                  bw1, bb1, bw2, bb2, bw3, bb3, n1_w, n1_b);
    // 4. MLP1 (bias+GELU, bf16 hi/lo out)
    k_mmagemm<1, false, true><<<dim3(PTOT / 128, 512 / 128), 256, G_SMEM>>>(
        po1h, po1l, pwh + 65536, pwl + 65536, mlp_b1, nullptr, nullptr,
        nullptr, phh, phl, 512, CH);
    // 5. MLP2 (bias + residual o1h+o1l)
    k_mmagemm<0, true, false><<<dim3(PTOT / 128, CH / 128), 256, G_SMEM>>>(
        phh, phl, pwh + 196608, pwl + 196608, mlp_b2, po1h, po1l,
        pt2, nullptr, nullptr, CH, 512);
    // 6. fused LN2 + transpose out
    k_ln2out<<<PTOT / 32, 256>>>(pt2, (float*)d_out, n2_w, n2_b);
}

// round 11
// speedup vs baseline: 2.0888x; 1.0509x over previous
#include <cuda_runtime.h>
#include <cuda_bf16.h>
#include <math.h>
#include <stdint.h>

#define BATCH 2
#define CH    256
#define HH    128
#define WW    128
#define HWSZ  16384
#define PTOT  32768
#define LN_EPS 1e-6f

// ---------------- scratch ----------------
__device__ float g_xT  [(size_t)PTOT * CH];
__device__ float g_acc [(size_t)PTOT * CH];
__device__ float g_t2  [(size_t)PTOT * CH];
__device__ float g_offp[(size_t)3 * BATCH * 18 * HWSZ];   // [branch][b][18][HW]
__device__ __nv_bfloat16 g_xTh[(size_t)PTOT * CH];
__device__ __nv_bfloat16 g_xTl[(size_t)PTOT * CH];
__device__ __nv_bfloat16 g_o1h[(size_t)PTOT * CH];
__device__ __nv_bfloat16 g_o1l[(size_t)PTOT * CH];
__device__ __nv_bfloat16 g_hh [(size_t)PTOT * 512];
__device__ __nv_bfloat16 g_hl [(size_t)PTOT * 512];
__device__ __nv_bfloat16 g_wh[327680];
__device__ __nv_bfloat16 g_wl[327680];
__device__ __nv_bfloat16 g_owh[3 * 32 * 2304];
__device__ __nv_bfloat16 g_owl[3 * 32 * 2304];

__device__ __forceinline__ float gelu_f(float v) {
    return 0.5f * v * (1.0f + erff(v * 0.70710678118654752440f));
}
__device__ __forceinline__ void split_bf16(float v, __nv_bfloat16& h, __nv_bfloat16& l) {
    h = __float2bfloat16(v);
    l = __float2bfloat16(v - __bfloat162float(h));
}
__device__ __forceinline__ uint32_t smem_u32(const void* p) {
    uint32_t a;
    asm("{ .reg .u64 t; cvta.to.shared.u64 t, %1; cvt.u32.u64 %0, t; }" : "=r"(a) : "l"(p));
    return a;
}
__device__ __forceinline__ void ldmx4(uint32_t* r, uint32_t addr) {
    asm volatile("ldmatrix.sync.aligned.m8n8.x4.shared.b16 {%0,%1,%2,%3}, [%4];"
                 : "=r"(r[0]), "=r"(r[1]), "=r"(r[2]), "=r"(r[3]) : "r"(addr));
}
__device__ __forceinline__ void mma16816(float* c, const uint32_t* a, const uint32_t* b) {
    asm volatile("mma.sync.aligned.m16n8k16.row.col.f32.bf16.bf16.f32 "
                 "{%0,%1,%2,%3}, {%4,%5,%6,%7}, {%8,%9}, {%0,%1,%2,%3};"
                 : "+f"(c[0]), "+f"(c[1]), "+f"(c[2]), "+f"(c[3])
                 : "r"(a[0]), "r"(a[1]), "r"(a[2]), "r"(a[3]), "r"(b[0]), "r"(b[1]));
}
__device__ __forceinline__ void cp16(uint32_t dst, const void* src) {
    asm volatile("cp.async.cg.shared.global [%0], [%1], 16;" :: "r"(dst), "l"(src));
}
__device__ __forceinline__ void cp16z(uint32_t dst, const void* src, bool valid) {
    int sz = valid ? 16 : 0;
    asm volatile("cp.async.cg.shared.global [%0], [%1], 16, %2;"
                 :: "r"(dst), "l"(src), "r"(sz));
}
#define CP_COMMIT() asm volatile("cp.async.commit_group;" ::: "memory")
#define CP_WAIT0()  asm volatile("cp.async.wait_group 0;" ::: "memory")

// =================== GEMM body (split-bf16 HMMA, cp.async double-buffered) ===================
#define G_ARR (128 * 40)
#define G_STG (4 * G_ARR)
#define G_SMEM (2 * G_STG * 2)   // 81920 bytes

template <int ACT, bool RES, bool BF16OUT>
__device__ __forceinline__ void gemm_body(
        char* dsm_, int mblk, int nblk,
        const __nv_bfloat16* __restrict__ Ah, const __nv_bfloat16* __restrict__ Al,
        const __nv_bfloat16* __restrict__ Bh, const __nv_bfloat16* __restrict__ Bl,
        const float* __restrict__ bias,
        const __nv_bfloat16* __restrict__ Resh, const __nv_bfloat16* __restrict__ Resl,
        float* __restrict__ Cf, __nv_bfloat16* __restrict__ Chi,
        __nv_bfloat16* __restrict__ Clo, int N, int K) {
    __nv_bfloat16* sm = (__nv_bfloat16*)dsm_;

    int tid  = threadIdx.x;
    int wid  = tid >> 5, lane = tid & 31;
    int m0   = mblk * 128, n0 = nblk * 128;
    int wm   = (wid & 3) * 32;
    int wn   = (wid >> 2) * 64;

    float acc[2][8][4];
#pragma unroll
    for (int i = 0; i < 2; i++)
#pragma unroll
        for (int j = 0; j < 8; j++)
#pragma unroll
            for (int q = 0; q < 4; q++) acc[i][j][q] = 0.f;

    const __nv_bfloat16* srcs[4] = {Ah + (size_t)m0 * K, Al + (size_t)m0 * K,
                                    Bh + (size_t)n0 * K, Bl + (size_t)n0 * K};

    auto load_stage = [&](int kc, int s) {
        __nv_bfloat16* base = sm + s * G_STG;
#pragma unroll
        for (int t = 0; t < 4; t++) {
            const __nv_bfloat16* src = srcs[t] + kc * 32;
            uint32_t dstb = smem_u32(base + t * G_ARR);
#pragma unroll
            for (int u = 0; u < 2; u++) {
                int idx = u * 256 + tid;
                int row = idx >> 2, ch = idx & 3;
                cp16(dstb + (uint32_t)(row * 40 + ch * 8) * 2,
                     src + (size_t)row * K + ch * 8);
            }
        }
    };

    int a_row8 = ((lane >> 3) & 1) * 8 + (lane & 7);
    int a_col8 = ((lane >> 4) & 1) * 8;
    int b_row8 = ((lane >> 4) & 1) * 8 + (lane & 7);
    int b_col8 = ((lane >> 3) & 1) * 8;

    load_stage(0, 0); CP_COMMIT();
    CP_WAIT0(); __syncthreads();

    int nk = K >> 5;
    for (int kc = 0; kc < nk; kc++) {
        int cur = kc & 1;
        if (kc + 1 < nk) { load_stage(kc + 1, cur ^ 1); CP_COMMIT(); }

        __nv_bfloat16* base = sm + cur * G_STG;
        __nv_bfloat16* pA[2] = {base, base + G_ARR};
        __nv_bfloat16* pB[2] = {base + 2 * G_ARR, base + 3 * G_ARR};
#pragma unroll
        for (int ks = 0; ks < 2; ks++) {
            uint32_t af[2][2][4];
#pragma unroll
            for (int hl = 0; hl < 2; hl++)
#pragma unroll
                for (int mi = 0; mi < 2; mi++)
                    ldmx4(af[hl][mi],
                          smem_u32(pA[hl] + (wm + mi * 16 + a_row8) * 40 + ks * 16 + a_col8));
#pragma unroll
            for (int jp = 0; jp < 4; jp++) {
                uint32_t bh[4], bl[4];
                ldmx4(bh, smem_u32(pB[0] + (wn + jp * 16 + b_row8) * 40 + ks * 16 + b_col8));
                ldmx4(bl, smem_u32(pB[1] + (wn + jp * 16 + b_row8) * 40 + ks * 16 + b_col8));
#pragma unroll
                for (int mi = 0; mi < 2; mi++)
#pragma unroll
                    for (int jj = 0; jj < 2; jj++) {
                        int j = jp * 2 + jj;
                        uint32_t bh2[2] = {bh[jj * 2], bh[jj * 2 + 1]};
                        uint32_t bl2[2] = {bl[jj * 2], bl[jj * 2 + 1]};
                        mma16816(acc[mi][j], af[0][mi], bh2);
                        mma16816(acc[mi][j], af[0][mi], bl2);
                        mma16816(acc[mi][j], af[1][mi], bh2);
                    }
            }
        }
        if (kc + 1 < nk) CP_WAIT0();
        __syncthreads();
    }

    int g = lane >> 2, q = lane & 3;
#pragma unroll
    for (int mi = 0; mi < 2; mi++) {
#pragma unroll
        for (int half = 0; half < 2; half++) {
            int m = m0 + wm + mi * 16 + g + half * 8;
#pragma unroll
            for (int j = 0; j < 8; j++) {
                int n = n0 + wn + j * 8 + q * 2;
                float v0 = acc[mi][j][half * 2 + 0] + __ldg(bias + n);
                float v1 = acc[mi][j][half * 2 + 1] + __ldg(bias + n + 1);
                if (ACT == 1) { v0 = gelu_f(v0); v1 = gelu_f(v1); }
                if (RES) {
                    __nv_bfloat162 rh = *(const __nv_bfloat162*)(Resh + (size_t)m * N + n);
                    __nv_bfloat162 rl = *(const __nv_bfloat162*)(Resl + (size_t)m * N + n);
                    v0 += __bfloat162float(rh.x) + __bfloat162float(rl.x);
                    v1 += __bfloat162float(rh.y) + __bfloat162float(rl.y);
                }
                if (BF16OUT) {
                    __nv_bfloat16 h0, l0, h1, l1;
                    split_bf16(v0, h0, l0); split_bf16(v1, h1, l1);
                    *(__nv_bfloat162*)(Chi + (size_t)m * N + n) = __nv_bfloat162(h0, h1);
                    *(__nv_bfloat162*)(Clo + (size_t)m * N + n) = __nv_bfloat162(l0, l1);
                } else {
                    *(float2*)(Cf + (size_t)m * N + n) = make_float2(v0, v1);
                }
            }
        }
    }
}

// =================== offmma body ===================
#define OFF_A_ARR (128 * 40)
#define OFF_B_ARR (32 * 40)
#define OFF_STG   (2 * OFF_A_ARR + 2 * OFF_B_ARR)

__device__ __forceinline__ void offmma_body(char* dsm_, int bx, int br) {
    __nv_bfloat16* sm = (__nv_bfloat16*)dsm_;

    int tid = threadIdx.x, wid = tid >> 5, lane = tid & 31;
    int h = bx & 127, b = bx >> 7;
    const int D = (br == 0) ? 1 : (br == 1) ? 9 : 12;

    const __nv_bfloat16* xh = g_xTh + (size_t)b * HWSZ * CH;
    const __nv_bfloat16* xl = g_xTl + (size_t)b * HWSZ * CH;
    const __nv_bfloat16* wbh = g_owh + (size_t)br * 32 * 2304;
    const __nv_bfloat16* wbl = g_owl + (size_t)br * 32 * 2304;

    float acc[4][4];
#pragma unroll
    for (int j = 0; j < 4; j++)
#pragma unroll
        for (int q = 0; q < 4; q++) acc[j][q] = 0.f;

    auto load_stage = [&](int kc, int s) {
        __nv_bfloat16* base = sm + s * OFF_STG;
        uint32_t sAh = smem_u32(base);
        uint32_t sAl = sAh + OFF_A_ARR * 2;
        uint32_t sBh = sAl + OFF_A_ARR * 2;
        uint32_t sBl = sBh + OFF_B_ARR * 2;
        int k  = kc >> 3;
        int cc = (kc & 7) * 32;
        int dy = (k / 3 - 1) * D, dx = (k % 3 - 1) * D;
        int srow = h + dy;
        bool vy = (srow >= 0) && (srow < HH);
        int srowc = vy ? srow : 0;
#pragma unroll
        for (int u = 0; u < 2; u++) {
            int idx = u * 256 + tid;
            int w = idx >> 2, ch = idx & 3;
            int wp = w + dx;
            bool v = vy && (wp >= 0) && (wp < WW);
            int wpc = v ? wp : 0;
            size_t goff = (size_t)(srowc * WW + wpc) * CH + cc + ch * 8;
            uint32_t soff = (uint32_t)(w * 40 + ch * 8) * 2;
            cp16z(sAh + soff, xh + goff, v);
            cp16z(sAl + soff, xl + goff, v);
        }
        if (tid < 128) {
            int o = tid >> 2, ch = tid & 3;
            size_t goff = (size_t)o * 2304 + k * 256 + cc + ch * 8;
            uint32_t soff = (uint32_t)(o * 40 + ch * 8) * 2;
            cp16(sBh + soff, wbh + goff);
            cp16(sBl + soff, wbl + goff);
        }
    };

    int a_row8 = ((lane >> 3) & 1) * 8 + (lane & 7);
    int a_col8 = ((lane >> 4) & 1) * 8;
    int b_row8 = ((lane >> 4) & 1) * 8 + (lane & 7);
    int b_col8 = ((lane >> 3) & 1) * 8;

    load_stage(0, 0); CP_COMMIT();
    CP_WAIT0(); __syncthreads();

    const int NK = 72;
    for (int kc = 0; kc < NK; kc++) {
        int cur = kc & 1;
        if (kc + 1 < NK) { load_stage(kc + 1, cur ^ 1); CP_COMMIT(); }

        __nv_bfloat16* base = sm + cur * OFF_STG;
        __nv_bfloat16* pAh = base;
        __nv_bfloat16* pAl = base + OFF_A_ARR;
        __nv_bfloat16* pBh = base + 2 * OFF_A_ARR;
        __nv_bfloat16* pBl = base + 2 * OFF_A_ARR + OFF_B_ARR;
#pragma unroll
        for (int ks = 0; ks < 2; ks++) {
            uint32_t af[2][4];
            ldmx4(af[0], smem_u32(pAh + (wid * 16 + a_row8) * 40 + ks * 16 + a_col8));
            ldmx4(af[1], smem_u32(pAl + (wid * 16 + a_row8) * 40 + ks * 16 + a_col8));
#pragma unroll
            for (int jp = 0; jp < 2; jp++) {
                uint32_t bh[4], bl[4];
                ldmx4(bh, smem_u32(pBh + (jp * 16 + b_row8) * 40 + ks * 16 + b_col8));
                ldmx4(bl, smem_u32(pBl + (jp * 16 + b_row8) * 40 + ks * 16 + b_col8));
#pragma unroll
                for (int jj = 0; jj < 2; jj++) {
                    int j = jp * 2 + jj;
                    uint32_t bh2[2] = {bh[jj * 2], bh[jj * 2 + 1]};
                    uint32_t bl2[2] = {bl[jj * 2], bl[jj * 2 + 1]};
                    mma16816(acc[j], af[0], bh2);
                    mma16816(acc[j], af[0], bl2);
                    mma16816(acc[j], af[1], bh2);
                }
            }
        }
        if (kc + 1 < NK) CP_WAIT0();
        __syncthreads();
    }

    float* op = g_offp + (size_t)(br * BATCH + b) * 18 * HWSZ;
    int g = lane >> 2, q = lane & 3;
#pragma unroll
    for (int half = 0; half < 2; half++) {
        int wcol = wid * 16 + g + half * 8;
        int pimg = h * WW + wcol;
#pragma unroll
        for (int j = 0; j < 4; j++) {
#pragma unroll
            for (int e = 0; e < 2; e++) {
                int n = j * 8 + q * 2 + e;
                if (n < 18) op[(size_t)n * HWSZ + pimg] = acc[j][half * 2 + e];
            }
        }
    }
}

// =================== stage 1: conv1x1 GEMM (blocks 0..511) + offmma (512..1279) ===================
__global__ void __launch_bounds__(256, 2)
k_stage1(const __nv_bfloat16* __restrict__ xTh, const __nv_bfloat16* __restrict__ xTl,
         const __nv_bfloat16* __restrict__ cwh, const __nv_bfloat16* __restrict__ cwl,
         const float* __restrict__ conv_b, float* __restrict__ accp) {
    extern __shared__ char dsm_[];
    int bid = blockIdx.x;
    if (bid < 512) {
        gemm_body<0, false, false>(dsm_, bid & 255, bid >> 8,
                                   xTh, xTl, cwh, cwl, conv_b,
                                   nullptr, nullptr, accp, nullptr, nullptr, CH, CH);
    } else {
        int obid = bid - 512;
        offmma_body(dsm_, obid & 255, obid >> 8);
    }
}

// =================== standalone MLP GEMMs ===================
template <int ACT, bool RES, bool BF16OUT>
__global__ void __launch_bounds__(256, 2)
k_mmagemm(const __nv_bfloat16* __restrict__ Ah, const __nv_bfloat16* __restrict__ Al,
          const __nv_bfloat16* __restrict__ Bh, const __nv_bfloat16* __restrict__ Bl,
          const float* __restrict__ bias,
          const __nv_bfloat16* __restrict__ Resh, const __nv_bfloat16* __restrict__ Resl,
          float* __restrict__ Cf, __nv_bfloat16* __restrict__ Chi,
          __nv_bfloat16* __restrict__ Clo, int N, int K) {
    extern __shared__ char dsm_[];
    gemm_body<ACT, RES, BF16OUT>(dsm_, blockIdx.x, blockIdx.y,
                                 Ah, Al, Bh, Bl, bias, Resh, Resl, Cf, Chi, Clo, N, K);
}

// =================== stage 0: transpose+split | prep | owprep ===================
__global__ void __launch_bounds__(256)
k_stage0(const float* __restrict__ x,
         const float* __restrict__ cw, const float* __restrict__ w1,
         const float* __restrict__ w2,
         const float* __restrict__ ow0, const float* __restrict__ ow1,
         const float* __restrict__ ow2) {
    int bid = blockIdx.x;
    int tid = threadIdx.x;
    if (bid < 8192) {
        __shared__ float t[32][33];
        int tb = bid;
        int p0 = (tb & 511) * 32;
        int c0 = ((tb >> 9) & 7) * 32;
        int b  = tb >> 12;
        int tx = tid & 31, ty = tid >> 5;
        const float* xb = x + (size_t)b * CH * HWSZ;
#pragma unroll
        for (int i = 0; i < 4; i++)
            t[ty + 8 * i][tx] = xb[(size_t)(c0 + ty + 8 * i) * HWSZ + p0 + tx];
        __syncthreads();
        size_t base = (size_t)b * HWSZ * CH;
#pragma unroll
        for (int i = 0; i < 4; i++) {
            float v = t[tx][ty + 8 * i];
            size_t idx = base + (size_t)(p0 + ty + 8 * i) * CH + c0 + tx;
            g_xT[idx] = v;
            __nv_bfloat16 h, l; split_bf16(v, h, l);
            g_xTh[idx] = h; g_xTl[idx] = l;
        }
    } else if (bid < 8512) {
        int i = (bid - 8192) * 256 + tid;
        if (i >= 81920) return;
        const float* src; int dst;
        if (i < 16384)      { src = cw + i * 4;            dst = i * 4; }
        else if (i < 49152) { src = w1 + (i - 16384) * 4;  dst = 65536 + (i - 16384) * 4; }
        else                { src = w2 + (i - 49152) * 4;  dst = 196608 + (i - 49152) * 4; }
        float4 v = *(const float4*)src;
        __nv_bfloat16 ha, la, hb, lb, hc, lc, hd, ld;
        split_bf16(v.x, ha, la); split_bf16(v.y, hb, lb);
        split_bf16(v.z, hc, lc); split_bf16(v.w, hd, ld);
        ((__nv_bfloat162*)(g_wh + dst))[0] = __nv_bfloat162(ha, hb);
        ((__nv_bfloat162*)(g_wh + dst))[1] = __nv_bfloat162(hc, hd);
        ((__nv_bfloat162*)(g_wl + dst))[0] = __nv_bfloat162(la, lb);
        ((__nv_bfloat162*)(g_wl + dst))[1] = __nv_bfloat162(lc, ld);
    } else {
        int i = (bid - 8512) * 256 + tid;
        if (i >= 3 * 32 * 2304) return;
        int br = i / (32 * 2304);
        int r  = i % (32 * 2304);
        int o  = r / 2304;
        int kk = r % 2304;
        int k  = kk / 256, c = kk % 256;
        const float* w = (br == 0) ? ow0 : (br == 1) ? ow1 : ow2;
        float v = (o < 18) ? w[((size_t)o * 256 + c) * 9 + k] : 0.f;
        __nv_bfloat16 h, l; split_bf16(v, h, l);
        g_owh[i] = h; g_owl[i] = l;
    }
}

// =================== fused deform3: 4 pixels/warp ===================
// R11: force 2 blocks/SM (reg cap 128). Gather-latency-bound kernel was
// plausibly running at 1 block/SM (8 warps) with unbounded regs.
__global__ void __launch_bounds__(256, 2)
k_deform3(const float* __restrict__ dw0, const float* __restrict__ dw1,
          const float* __restrict__ dw2,
          const float* __restrict__ lw0, const float* __restrict__ lb0,
          const float* __restrict__ lw1, const float* __restrict__ lb1,
          const float* __restrict__ lw2, const float* __restrict__ lb2,
          const float* __restrict__ n1w, const float* __restrict__ n1b) {
    __shared__ float sdefT[3][9 * CH];
    __shared__ int   sidx[8][4][36];
    __shared__ float swgt[8][4][36];

    int tid = threadIdx.x, wid = tid >> 5, lane = tid & 31;
    {
        const float* dws[3] = {dw0, dw1, dw2};
#pragma unroll
        for (int br = 0; br < 3; br++)
            for (int i = tid; i < 9 * CH; i += 256) {
                int c = i / 9, k = i % 9;
                sdefT[br][k * CH + c] = dws[br][i];
            }
    }
    __syncthreads();

    int pix0 = blockIdx.x * 32 + wid * 4;
    int b = pix0 >> 14;
    int c0 = lane * 8;
    const float* xrow = g_xT + (size_t)b * HWSZ * CH;

    float sum[4][8];
#pragma unroll
    for (int e = 0; e < 4; e++) {
        const float4* ap = (const float4*)(g_acc + (size_t)(pix0 + e) * CH + c0);
        float4 a0 = ap[0], a1 = ap[1];
        sum[e][0] = a0.x; sum[e][1] = a0.y; sum[e][2] = a0.z; sum[e][3] = a0.w;
        sum[e][4] = a1.x; sum[e][5] = a1.y; sum[e][6] = a1.z; sum[e][7] = a1.w;
    }

    const int DS[3] = {1, 9, 12};
    const float* lws[3] = {lw0, lw1, lw2};
    const float* lbs[3] = {lb0, lb1, lb2};

#pragma unroll
    for (int br = 0; br < 3; br++) {
        int D = DS[br];
        for (int t = lane; t < 36; t += 32) {
            int e = t / 9, k = t % 9;
            int pix = pix0 + e;
            int p = pix & (HWSZ - 1);
            int h = p >> 7, w = p & 127;
            int ky = k / 3, kx = k % 3;
            const float* op = g_offp + (size_t)(br * BATCH + b) * 18 * HWSZ;
            float oy = op[(size_t)(2 * k) * HWSZ + p];
            float ox = op[(size_t)(2 * k + 1) * HWSZ + p];
            float py = (float)h + (float)((ky - 1) * D) + oy;
            float px = (float)w + (float)((kx - 1) * D) + ox;
            float y0 = floorf(py), x0 = floorf(px);
#pragma unroll
            for (int dy = 0; dy < 2; dy++)
#pragma unroll
                for (int dx = 0; dx < 2; dx++) {
                    float yc = y0 + dy, xc = x0 + dx;
                    float wq = (1.f - fabsf(py - yc)) * (1.f - fabsf(px - xc));
                    bool valid = (yc >= 0.f) && (yc < 128.f) && (xc >= 0.f) && (xc < 128.f);
                    int iy = min(max((int)yc, 0), 127);
                    int ix = min(max((int)xc, 0), 127);
                    sidx[wid][e][k * 4 + dy * 2 + dx] = iy * WW + ix;
                    swgt[wid][e][k * 4 + dy * 2 + dx] = valid ? wq : 0.f;
                }
        }
        __syncwarp();

        float facc[4][8];
#pragma unroll
        for (int e = 0; e < 4; e++)
#pragma unroll
            for (int r = 0; r < 8; r++) facc[e][r] = 0.f;

#pragma unroll
        for (int k = 0; k < 9; k++) {
            float4 wk0 = *(const float4*)&sdefT[br][k * CH + c0];
            float4 wk1 = *(const float4*)&sdefT[br][k * CH + c0 + 4];
#pragma unroll
            for (int e = 0; e < 4; e++) {
                float s[8];
#pragma unroll
                for (int r = 0; r < 8; r++) s[r] = 0.f;
#pragma unroll
                for (int j = 0; j < 4; j++) {
                    float wq = swgt[wid][e][k * 4 + j];
                    if (wq != 0.f) {
                        const float4* vp =
                            (const float4*)(xrow + (size_t)sidx[wid][e][k * 4 + j] * CH + c0);
                        float4 v0 = vp[0], v1 = vp[1];
                        s[0] += wq * v0.x; s[1] += wq * v0.y; s[2] += wq * v0.z; s[3] += wq * v0.w;
                        s[4] += wq * v1.x; s[5] += wq * v1.y; s[6] += wq * v1.z; s[7] += wq * v1.w;
                    }
                }
                facc[e][0] += wk0.x * s[0]; facc[e][1] += wk0.y * s[1];
                facc[e][2] += wk0.z * s[2]; facc[e][3] += wk0.w * s[3];
                facc[e][4] += wk1.x * s[4]; facc[e][5] += wk1.y * s[5];
                facc[e][6] += wk1.z * s[6]; facc[e][7] += wk1.w * s[7];
            }
        }

        const float4* lwp = (const float4*)(lws[br] + c0);
        const float4* lbp = (const float4*)(lbs[br] + c0);
        float4 lw0v = lwp[0], lw1v = lwp[1], lb0v = lbp[0], lb1v = lbp[1];
        float lw[8] = {lw0v.x, lw0v.y, lw0v.z, lw0v.w, lw1v.x, lw1v.y, lw1v.z, lw1v.w};
        float lb[8] = {lb0v.x, lb0v.y, lb0v.z, lb0v.w, lb1v.x, lb1v.y, lb1v.z, lb1v.w};
#pragma unroll
        for (int e = 0; e < 4; e++) {
            float ls = 0.f, lq = 0.f;
#pragma unroll
            for (int r = 0; r < 8; r++) { ls += facc[e][r]; lq += facc[e][r] * facc[e][r]; }
#pragma unroll
            for (int o = 16; o; o >>= 1) {
                ls += __shfl_xor_sync(0xffffffffu, ls, o);
                lq += __shfl_xor_sync(0xffffffffu, lq, o);
            }
            float mean = ls * (1.f / 256.f);
            float var  = lq * (1.f / 256.f) - mean * mean;
            float rstd = rsqrtf(var + LN_EPS);
#pragma unroll
            for (int r = 0; r < 8; r++)
                sum[e][r] += gelu_f(lw[r] * ((facc[e][r] - mean) * rstd) + lb[r]);
        }
        __syncwarp();
    }

    const float4* wp = (const float4*)(n1w + c0);
    const float4* bp = (const float4*)(n1b + c0);
    float4 w0v = wp[0], w1v = wp[1], b0v = bp[0], b1v = bp[1];
    float gw[8] = {w0v.x, w0v.y, w0v.z, w0v.w, w1v.x, w1v.y, w1v.z, w1v.w};
    float gb[8] = {b0v.x, b0v.y, b0v.z, b0v.w, b1v.x, b1v.y, b1v.z, b1v.w};

#pragma unroll
    for (int e = 0; e < 4; e++) {
        float ls = 0.f, lq = 0.f;
#pragma unroll
        for (int r = 0; r < 8; r++) { ls += sum[e][r]; lq += sum[e][r] * sum[e][r]; }
#pragma unroll
        for (int o = 16; o; o >>= 1) {
            ls += __shfl_xor_sync(0xffffffffu, ls, o);
            lq += __shfl_xor_sync(0xffffffffu, lq, o);
        }
        float mean = ls * (1.f / 256.f);
        float var  = lq * (1.f / 256.f) - mean * mean;
        float rstd = rsqrtf(var + LN_EPS);

        uint32_t hp[4], lp[4];
#pragma unroll
        for (int r = 0; r < 8; r += 2) {
            float oa = gw[r] * ((sum[e][r] - mean) * rstd) + gb[r];
            float ob = gw[r + 1] * ((sum[e][r + 1] - mean) * rstd) + gb[r + 1];
            __nv_bfloat16 h0, l0, h1, l1;
            split_bf16(oa, h0, l0); split_bf16(ob, h1, l1);
            hp[r >> 1] = (uint32_t)__bfloat16_as_ushort(h0) |
                         ((uint32_t)__bfloat16_as_ushort(h1) << 16);
            lp[r >> 1] = (uint32_t)__bfloat16_as_ushort(l0) |
                         ((uint32_t)__bfloat16_as_ushort(l1) << 16);
        }
        *(uint4*)(g_o1h + (size_t)(pix0 + e) * CH + c0) = make_uint4(hp[0], hp[1], hp[2], hp[3]);
        *(uint4*)(g_o1l + (size_t)(pix0 + e) * CH + c0) = make_uint4(lp[0], lp[1], lp[2], lp[3]);
    }
}

// =================== fused LN2 + NHWC->NCHW output ===================
__global__ void __launch_bounds__(256)
k_ln2out(const float* __restrict__ in, float* __restrict__ out,
         const float* __restrict__ gwv, const float* __restrict__ gbv) {
    __shared__ float tr[256][33];
    int tid = threadIdx.x, wid = tid >> 5, lane = tid & 31;
    int p32 = blockIdx.x * 32;
    int b = p32 >> 14;
    int pimg = p32 & (HWSZ - 1);

#pragma unroll
    for (int i = 0; i < 4; i++) {
        int pxloc = wid + i * 8;
        const float4* row = (const float4*)(in + (size_t)(p32 + pxloc) * CH);
        float4 va = row[lane], vb = row[lane + 32];
        float s = va.x + va.y + va.z + va.w + vb.x + vb.y + vb.z + vb.w;
        float qq = va.x * va.x + va.y * va.y + va.z * va.z + va.w * va.w +
                   vb.x * vb.x + vb.y * vb.y + vb.z * vb.z + vb.w * vb.w;
#pragma unroll
        for (int o = 16; o; o >>= 1) {
            s  += __shfl_xor_sync(0xffffffffu, s, o);
            qq += __shfl_xor_sync(0xffffffffu, qq, o);
        }
        float mean = s * (1.f / 256.f);
        float var  = qq * (1.f / 256.f) - mean * mean;
        float rstd = rsqrtf(var + LN_EPS);
        int ca = lane * 4, cb = 128 + lane * 4;
        float4 ga = *(const float4*)(gwv + ca), gba = *(const float4*)(gbv + ca);
        float4 gb2 = *(const float4*)(gwv + cb), gbb = *(const float4*)(gbv + cb);
        tr[ca + 0][pxloc] = ga.x * ((va.x - mean) * rstd) + gba.x;
        tr[ca + 1][pxloc] = ga.y * ((va.y - mean) * rstd) + gba.y;
        tr[ca + 2][pxloc] = ga.z * ((va.z - mean) * rstd) + gba.z;
        tr[ca + 3][pxloc] = ga.w * ((va.w - mean) * rstd) + gba.w;
        tr[cb + 0][pxloc] = gb2.x * ((vb.x - mean) * rstd) + gbb.x;
        tr[cb + 1][pxloc] = gb2.y * ((vb.y - mean) * rstd) + gbb.y;
        tr[cb + 2][pxloc] = gb2.z * ((vb.z - mean) * rstd) + gbb.z;
        tr[cb + 3][pxloc] = gb2.w * ((vb.w - mean) * rstd) + gbb.w;
    }
    __syncthreads();

    float* ob = out + (size_t)b * CH * HWSZ + pimg;
#pragma unroll
    for (int it = 0; it < 32; it++) {
        int c = it * 8 + wid;
        ob[(size_t)c * HWSZ + lane] = tr[c][lane];
    }
}

// =================== launch ===================
extern "C" void kernel_launch(void* const* d_in, const int* in_sizes, int n_in,
                              void* d_out, int out_size) {
    const float* x       = (const float*)d_in[0];
    const float* off_w1  = (const float*)d_in[1];
    const float* def_w1  = (const float*)d_in[2];
    const float* bw1     = (const float*)d_in[3];
    const float* bb1     = (const float*)d_in[4];
    const float* off_w2  = (const float*)d_in[5];
    const float* def_w2  = (const float*)d_in[6];
    const float* bw2     = (const float*)d_in[7];
    const float* bb2     = (const float*)d_in[8];
    const float* off_w3  = (const float*)d_in[9];
    const float* def_w3  = (const float*)d_in[10];
    const float* bw3     = (const float*)d_in[11];
    const float* bb3     = (const float*)d_in[12];
    const float* conv_w  = (const float*)d_in[13];
    const float* conv_b  = (const float*)d_in[14];
    const float* n1_w    = (const float*)d_in[15];
    const float* n1_b    = (const float*)d_in[16];
    const float* n2_w    = (const float*)d_in[17];
    const float* n2_b    = (const float*)d_in[18];
    const float* mlp_w1  = (const float*)d_in[19];
    const float* mlp_b1  = (const float*)d_in[20];
    const float* mlp_w2  = (const float*)d_in[21];
    const float* mlp_b2  = (const float*)d_in[22];

    float *pacc, *pt2;
    __nv_bfloat16 *po1h, *po1l, *phh, *phl, *pwh, *pwl, *pxTh, *pxTl;
    cudaGetSymbolAddress((void**)&pacc,  g_acc);
    cudaGetSymbolAddress((void**)&pt2,   g_t2);
    cudaGetSymbolAddress((void**)&pxTh,  g_xTh);
    cudaGetSymbolAddress((void**)&pxTl,  g_xTl);
    cudaGetSymbolAddress((void**)&po1h,  g_o1h);
    cudaGetSymbolAddress((void**)&po1l,  g_o1l);
    cudaGetSymbolAddress((void**)&phh,   g_hh);
    cudaGetSymbolAddress((void**)&phl,   g_hl);
    cudaGetSymbolAddress((void**)&pwh,   g_wh);
    cudaGetSymbolAddress((void**)&pwl,   g_wl);

    cudaFuncSetAttribute(k_stage1,
                         cudaFuncAttributeMaxDynamicSharedMemorySize, G_SMEM);
    cudaFuncSetAttribute(k_mmagemm<1, false, true>,
                         cudaFuncAttributeMaxDynamicSharedMemorySize, G_SMEM);
    cudaFuncSetAttribute(k_mmagemm<0, true, false>,
                         cudaFuncAttributeMaxDynamicSharedMemorySize, G_SMEM);

    // 1. transpose+split | weight prep | offset-weight reorg (one launch)
    k_stage0<<<9376, 256>>>(x, conv_w, mlp_w1, mlp_w2, off_w1, off_w2, off_w3);
    // 2. conv1x1 GEMM + offset convs, co-scheduled in one launch
    k_stage1<<<1280, 256, G_SMEM>>>(pxTh, pxTl, pwh, pwl, conv_b, pacc);
    // 3. fused deform x3 + LN1 + split (4 px/warp, now 2 blocks/SM)
    k_deform3<<<PTOT / 32, 256>>>(def_w1, def_w2, def_w3,
                                  bw1, bb1, bw2, bb2, bw3, bb3, n1_w, n1_b);
    // 4. MLP1 (bias+GELU, bf16 hi/lo out)
    k_mmagemm<1, false, true><<<dim3(PTOT / 128, 512 / 128), 256, G_SMEM>>>(
        po1h, po1l, pwh + 65536, pwl + 65536, mlp_b1, nullptr, nullptr,
        nullptr, phh, phl, 512, CH);
    // 5. MLP2 (bias + residual o1h+o1l)
    k_mmagemm<0, true, false><<<dim3(PTOT / 128, CH / 128), 256, G_SMEM>>>(
        phh, phl, pwh + 196608, pwl + 196608, mlp_b2, po1h, po1l,
        pt2, nullptr, nullptr, CH, 512);
    // 6. fused LN2 + transpose out
    k_ln2out<<<PTOT / 32, 256>>>(pt2, (float*)d_out, n2_w, n2_b);
}

// round 12
// speedup vs baseline: 2.1211x; 1.0155x over previous
#include <cuda_runtime.h>
#include <cuda_bf16.h>
#include <math.h>
#include <stdint.h>

#define BATCH 2
#define CH    256
#define HH    128
#define WW    128
#define HWSZ  16384
#define PTOT  32768
#define LN_EPS 1e-6f

// ---------------- scratch ----------------
__device__ float g_xT  [(size_t)PTOT * CH];
__device__ float g_acc [(size_t)PTOT * CH];
__device__ float g_t2  [(size_t)PTOT * CH];
__device__ float g_offp[(size_t)3 * BATCH * 18 * HWSZ];   // [branch][b][18][HW]
__device__ __nv_bfloat16 g_xTh[(size_t)PTOT * CH];
__device__ __nv_bfloat16 g_xTl[(size_t)PTOT * CH];
__device__ __nv_bfloat16 g_o1h[(size_t)PTOT * CH];
__device__ __nv_bfloat16 g_o1l[(size_t)PTOT * CH];
__device__ __nv_bfloat16 g_hh [(size_t)PTOT * 512];
__device__ __nv_bfloat16 g_hl [(size_t)PTOT * 512];
__device__ __nv_bfloat16 g_wh[327680];
__device__ __nv_bfloat16 g_wl[327680];
__device__ __nv_bfloat16 g_owh[3 * 32 * 2304];
__device__ __nv_bfloat16 g_owl[3 * 32 * 2304];

__device__ __forceinline__ float gelu_f(float v) {
    return 0.5f * v * (1.0f + erff(v * 0.70710678118654752440f));
}
__device__ __forceinline__ void split_bf16(float v, __nv_bfloat16& h, __nv_bfloat16& l) {
    h = __float2bfloat16(v);
    l = __float2bfloat16(v - __bfloat162float(h));
}
__device__ __forceinline__ uint32_t smem_u32(const void* p) {
    uint32_t a;
    asm("{ .reg .u64 t; cvta.to.shared.u64 t, %1; cvt.u32.u64 %0, t; }" : "=r"(a) : "l"(p));
    return a;
}
__device__ __forceinline__ void ldmx4(uint32_t* r, uint32_t addr) {
    asm volatile("ldmatrix.sync.aligned.m8n8.x4.shared.b16 {%0,%1,%2,%3}, [%4];"
                 : "=r"(r[0]), "=r"(r[1]), "=r"(r[2]), "=r"(r[3]) : "r"(addr));
}
__device__ __forceinline__ void mma16816(float* c, const uint32_t* a, const uint32_t* b) {
    asm volatile("mma.sync.aligned.m16n8k16.row.col.f32.bf16.bf16.f32 "
                 "{%0,%1,%2,%3}, {%4,%5,%6,%7}, {%8,%9}, {%0,%1,%2,%3};"
                 : "+f"(c[0]), "+f"(c[1]), "+f"(c[2]), "+f"(c[3])
                 : "r"(a[0]), "r"(a[1]), "r"(a[2]), "r"(a[3]), "r"(b[0]), "r"(b[1]));
}
__device__ __forceinline__ void cp16(uint32_t dst, const void* src) {
    asm volatile("cp.async.cg.shared.global [%0], [%1], 16;" :: "r"(dst), "l"(src));
}
__device__ __forceinline__ void cp16z(uint32_t dst, const void* src, bool valid) {
    int sz = valid ? 16 : 0;
    asm volatile("cp.async.cg.shared.global [%0], [%1], 16, %2;"
                 :: "r"(dst), "l"(src), "r"(sz));
}
#define CP_COMMIT() asm volatile("cp.async.commit_group;" ::: "memory")
#define CP_WAIT0()  asm volatile("cp.async.wait_group 0;" ::: "memory")

// =================== GEMM body (split-bf16 HMMA, cp.async double-buffered) ===================
#define G_ARR (128 * 40)
#define G_STG (4 * G_ARR)
#define G_SMEM (2 * G_STG * 2)   // 81920 bytes

template <int ACT, bool RES, bool BF16OUT>
__device__ __forceinline__ void gemm_body(
        char* dsm_, int mblk, int nblk,
        const __nv_bfloat16* __restrict__ Ah, const __nv_bfloat16* __restrict__ Al,
        const __nv_bfloat16* __restrict__ Bh, const __nv_bfloat16* __restrict__ Bl,
        const float* __restrict__ bias,
        const __nv_bfloat16* __restrict__ Resh, const __nv_bfloat16* __restrict__ Resl,
        float* __restrict__ Cf, __nv_bfloat16* __restrict__ Chi,
        __nv_bfloat16* __restrict__ Clo, int N, int K) {
    __nv_bfloat16* sm = (__nv_bfloat16*)dsm_;
    uint32_t smb = smem_u32(sm);

    int tid  = threadIdx.x;
    int wid  = tid >> 5, lane = tid & 31;
    int m0   = mblk * 128, n0 = nblk * 128;
    int wm   = (wid & 3) * 32;
    int wn   = (wid >> 2) * 64;

    float acc[2][8][4];
#pragma unroll
    for (int i = 0; i < 2; i++)
#pragma unroll
        for (int j = 0; j < 8; j++)
#pragma unroll
            for (int q = 0; q < 4; q++) acc[i][j][q] = 0.f;

    const __nv_bfloat16* srcs[4] = {Ah + (size_t)m0 * K, Al + (size_t)m0 * K,
                                    Bh + (size_t)n0 * K, Bl + (size_t)n0 * K};

    auto load_stage = [&](int kc, int s) {
        uint32_t stgoff = (uint32_t)s * (G_STG * 2);
#pragma unroll
        for (int t = 0; t < 4; t++) {
            const __nv_bfloat16* src = srcs[t] + kc * 32;
            uint32_t dstb = smb + stgoff + (uint32_t)t * (G_ARR * 2);
#pragma unroll
            for (int u = 0; u < 2; u++) {
                int idx = u * 256 + tid;
                int row = idx >> 2, ch = idx & 3;
                cp16(dstb + (uint32_t)(row * 40 + ch * 8) * 2,
                     src + (size_t)row * K + ch * 8);
            }
        }
    };

    int a_row8 = ((lane >> 3) & 1) * 8 + (lane & 7);
    int a_col8 = ((lane >> 4) & 1) * 8;
    int b_row8 = ((lane >> 4) & 1) * 8 + (lane & 7);
    int b_col8 = ((lane >> 3) & 1) * 8;

    // R12: hoisted ldmatrix base addresses (bytes); loop adds only so = cur*STG + ks*32
    uint32_t aB[2][2], bB[2][4];
#pragma unroll
    for (int hl = 0; hl < 2; hl++) {
#pragma unroll
        for (int mi = 0; mi < 2; mi++)
            aB[hl][mi] = smb + (uint32_t)(hl * (G_ARR * 2)) +
                         (uint32_t)((wm + mi * 16 + a_row8) * 80 + a_col8 * 2);
#pragma unroll
        for (int jp = 0; jp < 4; jp++)
            bB[hl][jp] = smb + (uint32_t)((2 + hl) * (G_ARR * 2)) +
                         (uint32_t)((wn + jp * 16 + b_row8) * 80 + b_col8 * 2);
    }

    load_stage(0, 0); CP_COMMIT();
    CP_WAIT0(); __syncthreads();

    int nk = K >> 5;
    for (int kc = 0; kc < nk; kc++) {
        int cur = kc & 1;
        if (kc + 1 < nk) { load_stage(kc + 1, cur ^ 1); CP_COMMIT(); }

        uint32_t stg = (uint32_t)cur * (G_STG * 2);
#pragma unroll
        for (int ks = 0; ks < 2; ks++) {
            uint32_t so = stg + (uint32_t)(ks * 32);
            uint32_t af[2][2][4];
#pragma unroll
            for (int hl = 0; hl < 2; hl++)
#pragma unroll
                for (int mi = 0; mi < 2; mi++)
                    ldmx4(af[hl][mi], aB[hl][mi] + so);
#pragma unroll
            for (int jp = 0; jp < 4; jp++) {
                uint32_t bh[4], bl[4];
                ldmx4(bh, bB[0][jp] + so);
                ldmx4(bl, bB[1][jp] + so);
#pragma unroll
                for (int mi = 0; mi < 2; mi++)
#pragma unroll
                    for (int jj = 0; jj < 2; jj++) {
                        int j = jp * 2 + jj;
                        uint32_t bh2[2] = {bh[jj * 2], bh[jj * 2 + 1]};
                        uint32_t bl2[2] = {bl[jj * 2], bl[jj * 2 + 1]};
                        mma16816(acc[mi][j], af[0][mi], bh2);
                        mma16816(acc[mi][j], af[0][mi], bl2);
                        mma16816(acc[mi][j], af[1][mi], bh2);
                    }
            }
        }
        if (kc + 1 < nk) CP_WAIT0();
        __syncthreads();
    }

    int g = lane >> 2, q = lane & 3;
#pragma unroll
    for (int mi = 0; mi < 2; mi++) {
#pragma unroll
        for (int half = 0; half < 2; half++) {
            int m = m0 + wm + mi * 16 + g + half * 8;
#pragma unroll
            for (int j = 0; j < 8; j++) {
                int n = n0 + wn + j * 8 + q * 2;
                float v0 = acc[mi][j][half * 2 + 0] + __ldg(bias + n);
                float v1 = acc[mi][j][half * 2 + 1] + __ldg(bias + n + 1);
                if (ACT == 1) { v0 = gelu_f(v0); v1 = gelu_f(v1); }
                if (RES) {
                    __nv_bfloat162 rh = *(const __nv_bfloat162*)(Resh + (size_t)m * N + n);
                    __nv_bfloat162 rl = *(const __nv_bfloat162*)(Resl + (size_t)m * N + n);
                    v0 += __bfloat162float(rh.x) + __bfloat162float(rl.x);
                    v1 += __bfloat162float(rh.y) + __bfloat162float(rl.y);
                }
                if (BF16OUT) {
                    __nv_bfloat16 h0, l0, h1, l1;
                    split_bf16(v0, h0, l0); split_bf16(v1, h1, l1);
                    *(__nv_bfloat162*)(Chi + (size_t)m * N + n) = __nv_bfloat162(h0, h1);
                    *(__nv_bfloat162*)(Clo + (size_t)m * N + n) = __nv_bfloat162(l0, l1);
                } else {
                    *(float2*)(Cf + (size_t)m * N + n) = make_float2(v0, v1);
                }
            }
        }
    }
}

// =================== offmma body ===================
#define OFF_A_ARR (128 * 40)
#define OFF_B_ARR (32 * 40)
#define OFF_STG   (2 * OFF_A_ARR + 2 * OFF_B_ARR)

__device__ __forceinline__ void offmma_body(char* dsm_, int bx, int br) {
    __nv_bfloat16* sm = (__nv_bfloat16*)dsm_;
    uint32_t smb = smem_u32(sm);

    int tid = threadIdx.x, wid = tid >> 5, lane = tid & 31;
    int h = bx & 127, b = bx >> 7;
    const int D = (br == 0) ? 1 : (br == 1) ? 9 : 12;

    const __nv_bfloat16* xh = g_xTh + (size_t)b * HWSZ * CH;
    const __nv_bfloat16* xl = g_xTl + (size_t)b * HWSZ * CH;
    const __nv_bfloat16* wbh = g_owh + (size_t)br * 32 * 2304;
    const __nv_bfloat16* wbl = g_owl + (size_t)br * 32 * 2304;

    float acc[4][4];
#pragma unroll
    for (int j = 0; j < 4; j++)
#pragma unroll
        for (int q = 0; q < 4; q++) acc[j][q] = 0.f;

    auto load_stage = [&](int kc, int s) {
        uint32_t base = smb + (uint32_t)s * (OFF_STG * 2);
        uint32_t sAh = base;
        uint32_t sAl = sAh + OFF_A_ARR * 2;
        uint32_t sBh = sAl + OFF_A_ARR * 2;
        uint32_t sBl = sBh + OFF_B_ARR * 2;
        int k  = kc >> 3;
        int cc = (kc & 7) * 32;
        int dy = (k / 3 - 1) * D, dx = (k % 3 - 1) * D;
        int srow = h + dy;
        bool vy = (srow >= 0) && (srow < HH);
        int srowc = vy ? srow : 0;
#pragma unroll
        for (int u = 0; u < 2; u++) {
            int idx = u * 256 + tid;
            int w = idx >> 2, ch = idx & 3;
            int wp = w + dx;
            bool v = vy && (wp >= 0) && (wp < WW);
            int wpc = v ? wp : 0;
            size_t goff = (size_t)(srowc * WW + wpc) * CH + cc + ch * 8;
            uint32_t soff = (uint32_t)(w * 40 + ch * 8) * 2;
            cp16z(sAh + soff, xh + goff, v);
            cp16z(sAl + soff, xl + goff, v);
        }
        if (tid < 128) {
            int o = tid >> 2, ch = tid & 3;
            size_t goff = (size_t)o * 2304 + k * 256 + cc + ch * 8;
            uint32_t soff = (uint32_t)(o * 40 + ch * 8) * 2;
            cp16(sBh + soff, wbh + goff);
            cp16(sBl + soff, wbl + goff);
        }
    };

    int a_row8 = ((lane >> 3) & 1) * 8 + (lane & 7);
    int a_col8 = ((lane >> 4) & 1) * 8;
    int b_row8 = ((lane >> 4) & 1) * 8 + (lane & 7);
    int b_col8 = ((lane >> 3) & 1) * 8;

    // hoisted ldmatrix bases
    uint32_t aB[2], bB[2][2];
#pragma unroll
    for (int hl = 0; hl < 2; hl++) {
        aB[hl] = smb + (uint32_t)(hl * (OFF_A_ARR * 2)) +
                 (uint32_t)((wid * 16 + a_row8) * 80 + a_col8 * 2);
#pragma unroll
        for (int jp = 0; jp < 2; jp++)
            bB[hl][jp] = smb + (uint32_t)(2 * OFF_A_ARR * 2 + hl * (OFF_B_ARR * 2)) +
                         (uint32_t)((jp * 16 + b_row8) * 80 + b_col8 * 2);
    }

    load_stage(0, 0); CP_COMMIT();
    CP_WAIT0(); __syncthreads();

    const int NK = 72;
    for (int kc = 0; kc < NK; kc++) {
        int cur = kc & 1;
        if (kc + 1 < NK) { load_stage(kc + 1, cur ^ 1); CP_COMMIT(); }

        uint32_t stg = (uint32_t)cur * (OFF_STG * 2);
#pragma unroll
        for (int ks = 0; ks < 2; ks++) {
            uint32_t so = stg + (uint32_t)(ks * 32);
            uint32_t af[2][4];
            ldmx4(af[0], aB[0] + so);
            ldmx4(af[1], aB[1] + so);
#pragma unroll
            for (int jp = 0; jp < 2; jp++) {
                uint32_t bh[4], bl[4];
                ldmx4(bh, bB[0][jp] + so);
                ldmx4(bl, bB[1][jp] + so);
#pragma unroll
                for (int jj = 0; jj < 2; jj++) {
                    int j = jp * 2 + jj;
                    uint32_t bh2[2] = {bh[jj * 2], bh[jj * 2 + 1]};
                    uint32_t bl2[2] = {bl[jj * 2], bl[jj * 2 + 1]};
                    mma16816(acc[j], af[0], bh2);
                    mma16816(acc[j], af[0], bl2);
                    mma16816(acc[j], af[1], bh2);
                }
            }
        }
        if (kc + 1 < NK) CP_WAIT0();
        __syncthreads();
    }

    float* op = g_offp + (size_t)(br * BATCH + b) * 18 * HWSZ;
    int g = lane >> 2, q = lane & 3;
#pragma unroll
    for (int half = 0; half < 2; half++) {
        int wcol = wid * 16 + g + half * 8;
        int pimg = h * WW + wcol;
#pragma unroll
        for (int j = 0; j < 4; j++) {
#pragma unroll
            for (int e = 0; e < 2; e++) {
                int n = j * 8 + q * 2 + e;
                if (n < 18) op[(size_t)n * HWSZ + pimg] = acc[j][half * 2 + e];
            }
        }
    }
}

// =================== stage 1: conv1x1 GEMM (blocks 0..511) + offmma (512..1279) ===================
__global__ void __launch_bounds__(256, 2)
k_stage1(const __nv_bfloat16* __restrict__ xTh, const __nv_bfloat16* __restrict__ xTl,
         const __nv_bfloat16* __restrict__ cwh, const __nv_bfloat16* __restrict__ cwl,
         const float* __restrict__ conv_b, float* __restrict__ accp) {
    extern __shared__ char dsm_[];
    int bid = blockIdx.x;
    if (bid < 512) {
        gemm_body<0, false, false>(dsm_, bid & 255, bid >> 8,
                                   xTh, xTl, cwh, cwl, conv_b,
                                   nullptr, nullptr, accp, nullptr, nullptr, CH, CH);
    } else {
        int obid = bid - 512;
        offmma_body(dsm_, obid & 255, obid >> 8);
    }
}

// =================== standalone MLP GEMMs ===================
template <int ACT, bool RES, bool BF16OUT>
__global__ void __launch_bounds__(256, 2)
k_mmagemm(const __nv_bfloat16* __restrict__ Ah, const __nv_bfloat16* __restrict__ Al,
          const __nv_bfloat16* __restrict__ Bh, const __nv_bfloat16* __restrict__ Bl,
          const float* __restrict__ bias,
          const __nv_bfloat16* __restrict__ Resh, const __nv_bfloat16* __restrict__ Resl,
          float* __restrict__ Cf, __nv_bfloat16* __restrict__ Chi,
          __nv_bfloat16* __restrict__ Clo, int N, int K) {
    extern __shared__ char dsm_[];
    gemm_body<ACT, RES, BF16OUT>(dsm_, blockIdx.x, blockIdx.y,
                                 Ah, Al, Bh, Bl, bias, Resh, Resl, Cf, Chi, Clo, N, K);
}

// =================== stage 0: transpose+split | prep | owprep ===================
__global__ void __launch_bounds__(256)
k_stage0(const float* __restrict__ x,
         const float* __restrict__ cw, const float* __restrict__ w1,
         const float* __restrict__ w2,
         const float* __restrict__ ow0, const float* __restrict__ ow1,
         const float* __restrict__ ow2) {
    int bid = blockIdx.x;
    int tid = threadIdx.x;
    if (bid < 8192) {
        __shared__ float t[32][33];
        int tb = bid;
        int p0 = (tb & 511) * 32;
        int c0 = ((tb >> 9) & 7) * 32;
        int b  = tb >> 12;
        int tx = tid & 31, ty = tid >> 5;
        const float* xb = x + (size_t)b * CH * HWSZ;
#pragma unroll
        for (int i = 0; i < 4; i++)
            t[ty + 8 * i][tx] = xb[(size_t)(c0 + ty + 8 * i) * HWSZ + p0 + tx];
        __syncthreads();
        size_t base = (size_t)b * HWSZ * CH;
#pragma unroll
        for (int i = 0; i < 4; i++) {
            float v = t[tx][ty + 8 * i];
            size_t idx = base + (size_t)(p0 + ty + 8 * i) * CH + c0 + tx;
            g_xT[idx] = v;
            __nv_bfloat16 h, l; split_bf16(v, h, l);
            g_xTh[idx] = h; g_xTl[idx] = l;
        }
    } else if (bid < 8512) {
        int i = (bid - 8192) * 256 + tid;
        if (i >= 81920) return;
        const float* src; int dst;
        if (i < 16384)      { src = cw + i * 4;            dst = i * 4; }
        else if (i < 49152) { src = w1 + (i - 16384) * 4;  dst = 65536 + (i - 16384) * 4; }
        else                { src = w2 + (i - 49152) * 4;  dst = 196608 + (i - 49152) * 4; }
        float4 v = *(const float4*)src;
        __nv_bfloat16 ha, la, hb, lb, hc, lc, hd, ld;
        split_bf16(v.x, ha, la); split_bf16(v.y, hb, lb);
        split_bf16(v.z, hc, lc); split_bf16(v.w, hd, ld);
        ((__nv_bfloat162*)(g_wh + dst))[0] = __nv_bfloat162(ha, hb);
        ((__nv_bfloat162*)(g_wh + dst))[1] = __nv_bfloat162(hc, hd);
        ((__nv_bfloat162*)(g_wl + dst))[0] = __nv_bfloat162(la, lb);
        ((__nv_bfloat162*)(g_wl + dst))[1] = __nv_bfloat162(lc, ld);
    } else {
        int i = (bid - 8512) * 256 + tid;
        if (i >= 3 * 32 * 2304) return;
        int br = i / (32 * 2304);
        int r  = i % (32 * 2304);
        int o  = r / 2304;
        int kk = r % 2304;
        int k  = kk / 256, c = kk % 256;
        const float* w = (br == 0) ? ow0 : (br == 1) ? ow1 : ow2;
        float v = (o < 18) ? w[((size_t)o * 256 + c) * 9 + k] : 0.f;
        __nv_bfloat16 h, l; split_bf16(v, h, l);
        g_owh[i] = h; g_owl[i] = l;
    }
}

// =================== fused deform3: 4 pixels/warp, 2 blocks/SM ===================
__global__ void __launch_bounds__(256, 2)
k_deform3(const float* __restrict__ dw0, const float* __restrict__ dw1,
          const float* __restrict__ dw2,
          const float* __restrict__ lw0, const float* __restrict__ lb0,
          const float* __restrict__ lw1, const float* __restrict__ lb1,
          const float* __restrict__ lw2, const float* __restrict__ lb2,
          const float* __restrict__ n1w, const float* __restrict__ n1b) {
    __shared__ float sdefT[3][9 * CH];
    __shared__ int   sidx[8][4][36];
    __shared__ float swgt[8][4][36];

    int tid = threadIdx.x, wid = tid >> 5, lane = tid & 31;
    {
        const float* dws[3] = {dw0, dw1, dw2};
#pragma unroll
        for (int br = 0; br < 3; br++)
            for (int i = tid; i < 9 * CH; i += 256) {
                int c = i / 9, k = i % 9;
                sdefT[br][k * CH + c] = dws[br][i];
            }
    }
    __syncthreads();

    int pix0 = blockIdx.x * 32 + wid * 4;
    int b = pix0 >> 14;
    int c0 = lane * 8;
    const float* xrow = g_xT + (size_t)b * HWSZ * CH;

    float sum[4][8];
#pragma unroll
    for (int e = 0; e < 4; e++) {
        const float4* ap = (const float4*)(g_acc + (size_t)(pix0 + e) * CH + c0);
        float4 a0 = ap[0], a1 = ap[1];
        sum[e][0] = a0.x; sum[e][1] = a0.y; sum[e][2] = a0.z; sum[e][3] = a0.w;
        sum[e][4] = a1.x; sum[e][5] = a1.y; sum[e][6] = a1.z; sum[e][7] = a1.w;
    }

    const int DS[3] = {1, 9, 12};
    const float* lws[3] = {lw0, lw1, lw2};
    const float* lbs[3] = {lb0, lb1, lb2};

#pragma unroll
    for (int br = 0; br < 3; br++) {
        int D = DS[br];
        for (int t = lane; t < 36; t += 32) {
            int e = t / 9, k = t % 9;
            int pix = pix0 + e;
            int p = pix & (HWSZ - 1);
            int h = p >> 7, w = p & 127;
            int ky = k / 3, kx = k % 3;
            const float* op = g_offp + (size_t)(br * BATCH + b) * 18 * HWSZ;
            float oy = op[(size_t)(2 * k) * HWSZ + p];
            float ox = op[(size_t)(2 * k + 1) * HWSZ + p];
            float py = (float)h + (float)((ky - 1) * D) + oy;
            float px = (float)w + (float)((kx - 1) * D) + ox;
            float y0 = floorf(py), x0 = floorf(px);
#pragma unroll
            for (int dy = 0; dy < 2; dy++)
#pragma unroll
                for (int dx = 0; dx < 2; dx++) {
                    float yc = y0 + dy, xc = x0 + dx;
                    float wq = (1.f - fabsf(py - yc)) * (1.f - fabsf(px - xc));
                    bool valid = (yc >= 0.f) && (yc < 128.f) && (xc >= 0.f) && (xc < 128.f);
                    int iy = min(max((int)yc, 0), 127);
                    int ix = min(max((int)xc, 0), 127);
                    sidx[wid][e][k * 4 + dy * 2 + dx] = iy * WW + ix;
                    swgt[wid][e][k * 4 + dy * 2 + dx] = valid ? wq : 0.f;
                }
        }
        __syncwarp();

        float facc[4][8];
#pragma unroll
        for (int e = 0; e < 4; e++)
#pragma unroll
            for (int r = 0; r < 8; r++) facc[e][r] = 0.f;

#pragma unroll
        for (int k = 0; k < 9; k++) {
            float4 wk0 = *(const float4*)&sdefT[br][k * CH + c0];
            float4 wk1 = *(const float4*)&sdefT[br][k * CH + c0 + 4];
#pragma unroll
            for (int e = 0; e < 4; e++) {
                float s[8];
#pragma unroll
                for (int r = 0; r < 8; r++) s[r] = 0.f;
#pragma unroll
                for (int j = 0; j < 4; j++) {
                    float wq = swgt[wid][e][k * 4 + j];
                    if (wq != 0.f) {
                        const float4* vp =
                            (const float4*)(xrow + (size_t)sidx[wid][e][k * 4 + j] * CH + c0);
                        float4 v0 = vp[0], v1 = vp[1];
                        s[0] += wq * v0.x; s[1] += wq * v0.y; s[2] += wq * v0.z; s[3] += wq * v0.w;
                        s[4] += wq * v1.x; s[5] += wq * v1.y; s[6] += wq * v1.z; s[7] += wq * v1.w;
                    }
                }
                facc[e][0] += wk0.x * s[0]; facc[e][1] += wk0.y * s[1];
                facc[e][2] += wk0.z * s[2]; facc[e][3] += wk0.w * s[3];
                facc[e][4] += wk1.x * s[4]; facc[e][5] += wk1.y * s[5];
                facc[e][6] += wk1.z * s[6]; facc[e][7] += wk1.w * s[7];
            }
        }

        const float4* lwp = (const float4*)(lws[br] + c0);
        const float4* lbp = (const float4*)(lbs[br] + c0);
        float4 lw0v = lwp[0], lw1v = lwp[1], lb0v = lbp[0], lb1v = lbp[1];
        float lw[8] = {lw0v.x, lw0v.y, lw0v.z, lw0v.w, lw1v.x, lw1v.y, lw1v.z, lw1v.w};
        float lb[8] = {lb0v.x, lb0v.y, lb0v.z, lb0v.w, lb1v.x, lb1v.y, lb1v.z, lb1v.w};
#pragma unroll
        for (int e = 0; e < 4; e++) {
            float ls = 0.f, lq = 0.f;
#pragma unroll
            for (int r = 0; r < 8; r++) { ls += facc[e][r]; lq += facc[e][r] * facc[e][r]; }
#pragma unroll
            for (int o = 16; o; o >>= 1) {
                ls += __shfl_xor_sync(0xffffffffu, ls, o);
                lq += __shfl_xor_sync(0xffffffffu, lq, o);
            }
            float mean = ls * (1.f / 256.f);
            float var  = lq * (1.f / 256.f) - mean * mean;
            float rstd = rsqrtf(var + LN_EPS);
#pragma unroll
            for (int r = 0; r < 8; r++)
                sum[e][r] += gelu_f(lw[r] * ((facc[e][r] - mean) * rstd) + lb[r]);
        }
        __syncwarp();
    }

    const float4* wp = (const float4*)(n1w + c0);
    const float4* bp = (const float4*)(n1b + c0);
    float4 w0v = wp[0], w1v = wp[1], b0v = bp[0], b1v = bp[1];
    float gw[8] = {w0v.x, w0v.y, w0v.z, w0v.w, w1v.x, w1v.y, w1v.z, w1v.w};
    float gb[8] = {b0v.x, b0v.y, b0v.z, b0v.w, b1v.x, b1v.y, b1v.z, b1v.w};

#pragma unroll
    for (int e = 0; e < 4; e++) {
        float ls = 0.f, lq = 0.f;
#pragma unroll
        for (int r = 0; r < 8; r++) { ls += sum[e][r]; lq += sum[e][r] * sum[e][r]; }
#pragma unroll
        for (int o = 16; o; o >>= 1) {
            ls += __shfl_xor_sync(0xffffffffu, ls, o);
            lq += __shfl_xor_sync(0xffffffffu, lq, o);
        }
        float mean = ls * (1.f / 256.f);
        float var  = lq * (1.f / 256.f) - mean * mean;
        float rstd = rsqrtf(var + LN_EPS);

        uint32_t hp[4], lp[4];
#pragma unroll
        for (int r = 0; r < 8; r += 2) {
            float oa = gw[r] * ((sum[e][r] - mean) * rstd) + gb[r];
            float ob = gw[r + 1] * ((sum[e][r + 1] - mean) * rstd) + gb[r + 1];
            __nv_bfloat16 h0, l0, h1, l1;
            split_bf16(oa, h0, l0); split_bf16(ob, h1, l1);
            hp[r >> 1] = (uint32_t)__bfloat16_as_ushort(h0) |
                         ((uint32_t)__bfloat16_as_ushort(h1) << 16);
            lp[r >> 1] = (uint32_t)__bfloat16_as_ushort(l0) |
                         ((uint32_t)__bfloat16_as_ushort(l1) << 16);
        }
        *(uint4*)(g_o1h + (size_t)(pix0 + e) * CH + c0) = make_uint4(hp[0], hp[1], hp[2], hp[3]);
        *(uint4*)(g_o1l + (size_t)(pix0 + e) * CH + c0) = make_uint4(lp[0], lp[1], lp[2], lp[3]);
    }
}

// =================== fused LN2 + NHWC->NCHW output ===================
__global__ void __launch_bounds__(256)
k_ln2out(const float* __restrict__ in, float* __restrict__ out,
         const float* __restrict__ gwv, const float* __restrict__ gbv) {
    __shared__ float tr[256][33];
    int tid = threadIdx.x, wid = tid >> 5, lane = tid & 31;
    int p32 = blockIdx.x * 32;
    int b = p32 >> 14;
    int pimg = p32 & (HWSZ - 1);

#pragma unroll
    for (int i = 0; i < 4; i++) {
        int pxloc = wid + i * 8;
        const float4* row = (const float4*)(in + (size_t)(p32 + pxloc) * CH);
        float4 va = row[lane], vb = row[lane + 32];
        float s = va.x + va.y + va.z + va.w + vb.x + vb.y + vb.z + vb.w;
        float qq = va.x * va.x + va.y * va.y + va.z * va.z + va.w * va.w +
                   vb.x * vb.x + vb.y * vb.y + vb.z * vb.z + vb.w * vb.w;
#pragma unroll
        for (int o = 16; o; o >>= 1) {
            s  += __shfl_xor_sync(0xffffffffu, s, o);
            qq += __shfl_xor_sync(0xffffffffu, qq, o);
        }
        float mean = s * (1.f / 256.f);
        float var  = qq * (1.f / 256.f) - mean * mean;
        float rstd = rsqrtf(var + LN_EPS);
        int ca = lane * 4, cb = 128 + lane * 4;
        float4 ga = *(const float4*)(gwv + ca), gba = *(const float4*)(gbv + ca);
        float4 gb2 = *(const float4*)(gwv + cb), gbb = *(const float4*)(gbv + cb);
        tr[ca + 0][pxloc] = ga.x * ((va.x - mean) * rstd) + gba.x;
        tr[ca + 1][pxloc] = ga.y * ((va.y - mean) * rstd) + gba.y;
        tr[ca + 2][pxloc] = ga.z * ((va.z - mean) * rstd) + gba.z;
        tr[ca + 3][pxloc] = ga.w * ((va.w - mean) * rstd) + gba.w;
        tr[cb + 0][pxloc] = gb2.x * ((vb.x - mean) * rstd) + gbb.x;
        tr[cb + 1][pxloc] = gb2.y * ((vb.y - mean) * rstd) + gbb.y;
        tr[cb + 2][pxloc] = gb2.z * ((vb.z - mean) * rstd) + gbb.z;
        tr[cb + 3][pxloc] = gb2.w * ((vb.w - mean) * rstd) + gbb.w;
    }
    __syncthreads();

    float* ob = out + (size_t)b * CH * HWSZ + pimg;
#pragma unroll
    for (int it = 0; it < 32; it++) {
        int c = it * 8 + wid;
        ob[(size_t)c * HWSZ + lane] = tr[c][lane];
    }
}

// =================== launch ===================
extern "C" void kernel_launch(void* const* d_in, const int* in_sizes, int n_in,
                              void* d_out, int out_size) {
    const float* x       = (const float*)d_in[0];
    const float* off_w1  = (const float*)d_in[1];
    const float* def_w1  = (const float*)d_in[2];
    const float* bw1     = (const float*)d_in[3];
    const float* bb1     = (const float*)d_in[4];
    const float* off_w2  = (const float*)d_in[5];
    const float* def_w2  = (const float*)d_in[6];
    const float* bw2     = (const float*)d_in[7];
    const float* bb2     = (const float*)d_in[8];
    const float* off_w3  = (const float*)d_in[9];
    const float* def_w3  = (const float*)d_in[10];
    const float* bw3     = (const float*)d_in[11];
    const float* bb3     = (const float*)d_in[12];
    const float* conv_w  = (const float*)d_in[13];
    const float* conv_b  = (const float*)d_in[14];
    const float* n1_w    = (const float*)d_in[15];
    const float* n1_b    = (const float*)d_in[16];
    const float* n2_w    = (const float*)d_in[17];
    const float* n2_b    = (const float*)d_in[18];
    const float* mlp_w1  = (const float*)d_in[19];
    const float* mlp_b1  = (const float*)d_in[20];
    const float* mlp_w2  = (const float*)d_in[21];
    const float* mlp_b2  = (const float*)d_in[22];

    float *pacc, *pt2;
    __nv_bfloat16 *po1h, *po1l, *phh, *phl, *pwh, *pwl, *pxTh, *pxTl;
    cudaGetSymbolAddress((void**)&pacc,  g_acc);
    cudaGetSymbolAddress((void**)&pt2,   g_t2);
    cudaGetSymbolAddress((void**)&pxTh,  g_xTh);
    cudaGetSymbolAddress((void**)&pxTl,  g_xTl);
    cudaGetSymbolAddress((void**)&po1h,  g_o1h);
    cudaGetSymbolAddress((void**)&po1l,  g_o1l);
    cudaGetSymbolAddress((void**)&phh,   g_hh);
    cudaGetSymbolAddress((void**)&phl,   g_hl);
    cudaGetSymbolAddress((void**)&pwh,   g_wh);
    cudaGetSymbolAddress((void**)&pwl,   g_wl);

    cudaFuncSetAttribute(k_stage1,
                         cudaFuncAttributeMaxDynamicSharedMemorySize, G_SMEM);
    cudaFuncSetAttribute(k_mmagemm<1, false, true>,
                         cudaFuncAttributeMaxDynamicSharedMemorySize, G_SMEM);
    cudaFuncSetAttribute(k_mmagemm<0, true, false>,
                         cudaFuncAttributeMaxDynamicSharedMemorySize, G_SMEM);

    // 1. transpose+split | weight prep | offset-weight reorg (one launch)
    k_stage0<<<9376, 256>>>(x, conv_w, mlp_w1, mlp_w2, off_w1, off_w2, off_w3);
    // 2. conv1x1 GEMM + offset convs, co-scheduled in one launch
    k_stage1<<<1280, 256, G_SMEM>>>(pxTh, pxTl, pwh, pwl, conv_b, pacc);
    // 3. fused deform x3 + LN1 + split (4 px/warp, 2 blocks/SM)
    k_deform3<<<PTOT / 32, 256>>>(def_w1, def_w2, def_w3,
                                  bw1, bb1, bw2, bb2, bw3, bb3, n1_w, n1_b);
    // 4. MLP1 (bias+GELU, bf16 hi/lo out)
    k_mmagemm<1, false, true><<<dim3(PTOT / 128, 512 / 128), 256, G_SMEM>>>(
        po1h, po1l, pwh + 65536, pwl + 65536, mlp_b1, nullptr, nullptr,
        nullptr, phh, phl, 512, CH);
    // 5. MLP2 (bias + residual o1h+o1l)
    k_mmagemm<0, true, false><<<dim3(PTOT / 128, CH / 128), 256, G_SMEM>>>(
        phh, phl, pwh + 196608, pwl + 196608, mlp_b2, po1h, po1l,
        pt2, nullptr, nullptr, CH, 512);
    // 6. fused LN2 + transpose out
    k_ln2out<<<PTOT / 32, 256>>>(pt2, (float*)d_out, n2_w, n2_b);
}

// round 13
// speedup vs baseline: 2.1378x; 1.0078x over previous
#include <cuda_runtime.h>
#include <cuda_bf16.h>
#include <math.h>
#include <stdint.h>

#define BATCH 2
#define CH    256
#define HH    128
#define WW    128
#define HWSZ  16384
#define PTOT  32768
#define LN_EPS 1e-6f

// ---------------- scratch ----------------
__device__ float g_xT  [(size_t)PTOT * CH];
__device__ float g_acc [(size_t)PTOT * CH];
__device__ float g_t2  [(size_t)PTOT * CH];
__device__ float g_offp[(size_t)3 * BATCH * 18 * HWSZ];   // [branch][b][18][HW]
__device__ __nv_bfloat16 g_xTh[(size_t)PTOT * CH];
__device__ __nv_bfloat16 g_xTl[(size_t)PTOT * CH];
__device__ __nv_bfloat16 g_o1h[(size_t)PTOT * CH];
__device__ __nv_bfloat16 g_o1l[(size_t)PTOT * CH];
__device__ __nv_bfloat16 g_hh [(size_t)PTOT * 512];
__device__ __nv_bfloat16 g_hl [(size_t)PTOT * 512];
__device__ __nv_bfloat16 g_wh[327680];
__device__ __nv_bfloat16 g_wl[327680];
__device__ __nv_bfloat16 g_owh[3 * 32 * 2304];
__device__ __nv_bfloat16 g_owl[3 * 32 * 2304];

__device__ __forceinline__ float gelu_f(float v) {
    return 0.5f * v * (1.0f + erff(v * 0.70710678118654752440f));
}
__device__ __forceinline__ void split_bf16(float v, __nv_bfloat16& h, __nv_bfloat16& l) {
    h = __float2bfloat16(v);
    l = __float2bfloat16(v - __bfloat162float(h));
}
__device__ __forceinline__ uint32_t smem_u32(const void* p) {
    uint32_t a;
    asm("{ .reg .u64 t; cvta.to.shared.u64 t, %1; cvt.u32.u64 %0, t; }" : "=r"(a) : "l"(p));
    return a;
}
__device__ __forceinline__ void ldmx4(uint32_t* r, uint32_t addr) {
    asm volatile("ldmatrix.sync.aligned.m8n8.x4.shared.b16 {%0,%1,%2,%3}, [%4];"
                 : "=r"(r[0]), "=r"(r[1]), "=r"(r[2]), "=r"(r[3]) : "r"(addr));
}
__device__ __forceinline__ void mma16816(float* c, const uint32_t* a, const uint32_t* b) {
    asm volatile("mma.sync.aligned.m16n8k16.row.col.f32.bf16.bf16.f32 "
                 "{%0,%1,%2,%3}, {%4,%5,%6,%7}, {%8,%9}, {%0,%1,%2,%3};"
                 : "+f"(c[0]), "+f"(c[1]), "+f"(c[2]), "+f"(c[3])
                 : "r"(a[0]), "r"(a[1]), "r"(a[2]), "r"(a[3]), "r"(b[0]), "r"(b[1]));
}
__device__ __forceinline__ void cp16(uint32_t dst, const void* src) {
    asm volatile("cp.async.cg.shared.global [%0], [%1], 16;" :: "r"(dst), "l"(src));
}
__device__ __forceinline__ void cp16z(uint32_t dst, const void* src, bool valid) {
    int sz = valid ? 16 : 0;
    asm volatile("cp.async.cg.shared.global [%0], [%1], 16, %2;"
                 :: "r"(dst), "l"(src), "r"(sz));
}
#define CP_COMMIT() asm volatile("cp.async.commit_group;" ::: "memory")
#define CP_WAIT0()  asm volatile("cp.async.wait_group 0;" ::: "memory")

// =================== GEMM body (split-bf16 HMMA, cp.async double-buffered) ===================
#define G_ARR (128 * 40)
#define G_STG (4 * G_ARR)
#define G_SMEM (2 * G_STG * 2)   // 81920 bytes

template <int ACT, bool RES, bool BF16OUT>
__device__ __forceinline__ void gemm_body(
        char* dsm_, int mblk, int nblk,
        const __nv_bfloat16* __restrict__ Ah, const __nv_bfloat16* __restrict__ Al,
        const __nv_bfloat16* __restrict__ Bh, const __nv_bfloat16* __restrict__ Bl,
        const float* __restrict__ bias,
        const __nv_bfloat16* __restrict__ Resh, const __nv_bfloat16* __restrict__ Resl,
        float* __restrict__ Cf, __nv_bfloat16* __restrict__ Chi,
        __nv_bfloat16* __restrict__ Clo, int N, int K) {
    __nv_bfloat16* sm = (__nv_bfloat16*)dsm_;
    uint32_t smb = smem_u32(sm);

    int tid  = threadIdx.x;
    int wid  = tid >> 5, lane = tid & 31;
    int m0   = mblk * 128, n0 = nblk * 128;
    int wm   = (wid & 3) * 32;
    int wn   = (wid >> 2) * 64;

    float acc[2][8][4];
#pragma unroll
    for (int i = 0; i < 2; i++)
#pragma unroll
        for (int j = 0; j < 8; j++)
#pragma unroll
            for (int q = 0; q < 4; q++) acc[i][j][q] = 0.f;

    const __nv_bfloat16* srcs[4] = {Ah + (size_t)m0 * K, Al + (size_t)m0 * K,
                                    Bh + (size_t)n0 * K, Bl + (size_t)n0 * K};

    auto load_stage = [&](int kc, int s) {
        uint32_t stgoff = (uint32_t)s * (G_STG * 2);
#pragma unroll
        for (int t = 0; t < 4; t++) {
            const __nv_bfloat16* src = srcs[t] + kc * 32;
            uint32_t dstb = smb + stgoff + (uint32_t)t * (G_ARR * 2);
#pragma unroll
            for (int u = 0; u < 2; u++) {
                int idx = u * 256 + tid;
                int row = idx >> 2, ch = idx & 3;
                cp16(dstb + (uint32_t)(row * 40 + ch * 8) * 2,
                     src + (size_t)row * K + ch * 8);
            }
        }
    };

    int a_row8 = ((lane >> 3) & 1) * 8 + (lane & 7);
    int a_col8 = ((lane >> 4) & 1) * 8;
    int b_row8 = ((lane >> 4) & 1) * 8 + (lane & 7);
    int b_col8 = ((lane >> 3) & 1) * 8;

    uint32_t aB[2][2], bB[2][4];
#pragma unroll
    for (int hl = 0; hl < 2; hl++) {
#pragma unroll
        for (int mi = 0; mi < 2; mi++)
            aB[hl][mi] = smb + (uint32_t)(hl * (G_ARR * 2)) +
                         (uint32_t)((wm + mi * 16 + a_row8) * 80 + a_col8 * 2);
#pragma unroll
        for (int jp = 0; jp < 4; jp++)
            bB[hl][jp] = smb + (uint32_t)((2 + hl) * (G_ARR * 2)) +
                         (uint32_t)((wn + jp * 16 + b_row8) * 80 + b_col8 * 2);
    }

    load_stage(0, 0); CP_COMMIT();
    CP_WAIT0(); __syncthreads();

    int nk = K >> 5;
    for (int kc = 0; kc < nk; kc++) {
        int cur = kc & 1;
        if (kc + 1 < nk) { load_stage(kc + 1, cur ^ 1); CP_COMMIT(); }

        uint32_t stg = (uint32_t)cur * (G_STG * 2);
#pragma unroll
        for (int ks = 0; ks < 2; ks++) {
            uint32_t so = stg + (uint32_t)(ks * 32);
            uint32_t af[2][2][4];
#pragma unroll
            for (int hl = 0; hl < 2; hl++)
#pragma unroll
                for (int mi = 0; mi < 2; mi++)
                    ldmx4(af[hl][mi], aB[hl][mi] + so);
#pragma unroll
            for (int jp = 0; jp < 4; jp++) {
                uint32_t bh[4], bl[4];
                ldmx4(bh, bB[0][jp] + so);
                ldmx4(bl, bB[1][jp] + so);
#pragma unroll
                for (int mi = 0; mi < 2; mi++)
#pragma unroll
                    for (int jj = 0; jj < 2; jj++) {
                        int j = jp * 2 + jj;
                        uint32_t bh2[2] = {bh[jj * 2], bh[jj * 2 + 1]};
                        uint32_t bl2[2] = {bl[jj * 2], bl[jj * 2 + 1]};
                        mma16816(acc[mi][j], af[0][mi], bh2);
                        mma16816(acc[mi][j], af[0][mi], bl2);
                        mma16816(acc[mi][j], af[1][mi], bh2);
                    }
            }
        }
        if (kc + 1 < nk) CP_WAIT0();
        __syncthreads();
    }

    int g = lane >> 2, q = lane & 3;
#pragma unroll
    for (int mi = 0; mi < 2; mi++) {
#pragma unroll
        for (int half = 0; half < 2; half++) {
            int m = m0 + wm + mi * 16 + g + half * 8;
#pragma unroll
            for (int j = 0; j < 8; j++) {
                int n = n0 + wn + j * 8 + q * 2;
                float v0 = acc[mi][j][half * 2 + 0] + __ldg(bias + n);
                float v1 = acc[mi][j][half * 2 + 1] + __ldg(bias + n + 1);
                if (ACT == 1) { v0 = gelu_f(v0); v1 = gelu_f(v1); }
                if (RES) {
                    __nv_bfloat162 rh = *(const __nv_bfloat162*)(Resh + (size_t)m * N + n);
                    __nv_bfloat162 rl = *(const __nv_bfloat162*)(Resl + (size_t)m * N + n);
                    v0 += __bfloat162float(rh.x) + __bfloat162float(rl.x);
                    v1 += __bfloat162float(rh.y) + __bfloat162float(rl.y);
                }
                if (BF16OUT) {
                    __nv_bfloat16 h0, l0, h1, l1;
                    split_bf16(v0, h0, l0); split_bf16(v1, h1, l1);
                    *(__nv_bfloat162*)(Chi + (size_t)m * N + n) = __nv_bfloat162(h0, h1);
                    *(__nv_bfloat162*)(Clo + (size_t)m * N + n) = __nv_bfloat162(l0, l1);
                } else {
                    *(float2*)(Cf + (size_t)m * N + n) = make_float2(v0, v1);
                }
            }
        }
    }
}

// =================== offmma body ===================
#define OFF_A_ARR (128 * 40)
#define OFF_B_ARR (32 * 40)
#define OFF_STG   (2 * OFF_A_ARR + 2 * OFF_B_ARR)

__device__ __forceinline__ void offmma_body(char* dsm_, int bx, int br) {
    __nv_bfloat16* sm = (__nv_bfloat16*)dsm_;
    uint32_t smb = smem_u32(sm);

    int tid = threadIdx.x, wid = tid >> 5, lane = tid & 31;
    int h = bx & 127, b = bx >> 7;
    const int D = (br == 0) ? 1 : (br == 1) ? 9 : 12;

    const __nv_bfloat16* xh = g_xTh + (size_t)b * HWSZ * CH;
    const __nv_bfloat16* xl = g_xTl + (size_t)b * HWSZ * CH;
    const __nv_bfloat16* wbh = g_owh + (size_t)br * 32 * 2304;
    const __nv_bfloat16* wbl = g_owl + (size_t)br * 32 * 2304;

    float acc[4][4];
#pragma unroll
    for (int j = 0; j < 4; j++)
#pragma unroll
        for (int q = 0; q < 4; q++) acc[j][q] = 0.f;

    auto load_stage = [&](int kc, int s) {
        uint32_t base = smb + (uint32_t)s * (OFF_STG * 2);
        uint32_t sAh = base;
        uint32_t sAl = sAh + OFF_A_ARR * 2;
        uint32_t sBh = sAl + OFF_A_ARR * 2;
        uint32_t sBl = sBh + OFF_B_ARR * 2;
        int k  = kc >> 3;
        int cc = (kc & 7) * 32;
        int dy = (k / 3 - 1) * D, dx = (k % 3 - 1) * D;
        int srow = h + dy;
        bool vy = (srow >= 0) && (srow < HH);
        int srowc = vy ? srow : 0;
#pragma unroll
        for (int u = 0; u < 2; u++) {
            int idx = u * 256 + tid;
            int w = idx >> 2, ch = idx & 3;
            int wp = w + dx;
            bool v = vy && (wp >= 0) && (wp < WW);
            int wpc = v ? wp : 0;
            size_t goff = (size_t)(srowc * WW + wpc) * CH + cc + ch * 8;
            uint32_t soff = (uint32_t)(w * 40 + ch * 8) * 2;
            cp16z(sAh + soff, xh + goff, v);
            cp16z(sAl + soff, xl + goff, v);
        }
        if (tid < 128) {
            int o = tid >> 2, ch = tid & 3;
            size_t goff = (size_t)o * 2304 + k * 256 + cc + ch * 8;
            uint32_t soff = (uint32_t)(o * 40 + ch * 8) * 2;
            cp16(sBh + soff, wbh + goff);
            cp16(sBl + soff, wbl + goff);
        }
    };

    int a_row8 = ((lane >> 3) & 1) * 8 + (lane & 7);
    int a_col8 = ((lane >> 4) & 1) * 8;
    int b_row8 = ((lane >> 4) & 1) * 8 + (lane & 7);
    int b_col8 = ((lane >> 3) & 1) * 8;

    uint32_t aB[2], bB[2][2];
#pragma unroll
    for (int hl = 0; hl < 2; hl++) {
        aB[hl] = smb + (uint32_t)(hl * (OFF_A_ARR * 2)) +
                 (uint32_t)((wid * 16 + a_row8) * 80 + a_col8 * 2);
#pragma unroll
        for (int jp = 0; jp < 2; jp++)
            bB[hl][jp] = smb + (uint32_t)(2 * OFF_A_ARR * 2 + hl * (OFF_B_ARR * 2)) +
                         (uint32_t)((jp * 16 + b_row8) * 80 + b_col8 * 2);
    }

    load_stage(0, 0); CP_COMMIT();
    CP_WAIT0(); __syncthreads();

    const int NK = 72;
    for (int kc = 0; kc < NK; kc++) {
        int cur = kc & 1;
        if (kc + 1 < NK) { load_stage(kc + 1, cur ^ 1); CP_COMMIT(); }

        uint32_t stg = (uint32_t)cur * (OFF_STG * 2);
#pragma unroll
        for (int ks = 0; ks < 2; ks++) {
            uint32_t so = stg + (uint32_t)(ks * 32);
            uint32_t af[2][4];
            ldmx4(af[0], aB[0] + so);
            ldmx4(af[1], aB[1] + so);
#pragma unroll
            for (int jp = 0; jp < 2; jp++) {
                uint32_t bh[4], bl[4];
                ldmx4(bh, bB[0][jp] + so);
                ldmx4(bl, bB[1][jp] + so);
#pragma unroll
                for (int jj = 0; jj < 2; jj++) {
                    int j = jp * 2 + jj;
                    uint32_t bh2[2] = {bh[jj * 2], bh[jj * 2 + 1]};
                    uint32_t bl2[2] = {bl[jj * 2], bl[jj * 2 + 1]};
                    mma16816(acc[j], af[0], bh2);
                    mma16816(acc[j], af[0], bl2);
                    mma16816(acc[j], af[1], bh2);
                }
            }
        }
        if (kc + 1 < NK) CP_WAIT0();
        __syncthreads();
    }

    float* op = g_offp + (size_t)(br * BATCH + b) * 18 * HWSZ;
    int g = lane >> 2, q = lane & 3;
#pragma unroll
    for (int half = 0; half < 2; half++) {
        int wcol = wid * 16 + g + half * 8;
        int pimg = h * WW + wcol;
#pragma unroll
        for (int j = 0; j < 4; j++) {
#pragma unroll
            for (int e = 0; e < 2; e++) {
                int n = j * 8 + q * 2 + e;
                if (n < 18) op[(size_t)n * HWSZ + pimg] = acc[j][half * 2 + e];
            }
        }
    }
}

// =================== stage 1: conv1x1 GEMM (blocks 0..511) + offmma (512..1279) ===================
__global__ void __launch_bounds__(256, 2)
k_stage1(const __nv_bfloat16* __restrict__ xTh, const __nv_bfloat16* __restrict__ xTl,
         const __nv_bfloat16* __restrict__ cwh, const __nv_bfloat16* __restrict__ cwl,
         const float* __restrict__ conv_b, float* __restrict__ accp) {
    extern __shared__ char dsm_[];
    int bid = blockIdx.x;
    if (bid < 512) {
        gemm_body<0, false, false>(dsm_, bid & 255, bid >> 8,
                                   xTh, xTl, cwh, cwl, conv_b,
                                   nullptr, nullptr, accp, nullptr, nullptr, CH, CH);
    } else {
        int obid = bid - 512;
        offmma_body(dsm_, obid & 255, obid >> 8);
    }
}

// =================== standalone MLP GEMMs ===================
template <int ACT, bool RES, bool BF16OUT>
__global__ void __launch_bounds__(256, 2)
k_mmagemm(const __nv_bfloat16* __restrict__ Ah, const __nv_bfloat16* __restrict__ Al,
          const __nv_bfloat16* __restrict__ Bh, const __nv_bfloat16* __restrict__ Bl,
          const float* __restrict__ bias,
          const __nv_bfloat16* __restrict__ Resh, const __nv_bfloat16* __restrict__ Resl,
          float* __restrict__ Cf, __nv_bfloat16* __restrict__ Chi,
          __nv_bfloat16* __restrict__ Clo, int N, int K) {
    extern __shared__ char dsm_[];
    gemm_body<ACT, RES, BF16OUT>(dsm_, blockIdx.x, blockIdx.y,
                                 Ah, Al, Bh, Bl, bias, Resh, Resl, Cf, Chi, Clo, N, K);
}

// =================== stage 0: transpose+split | prep | owprep ===================
__global__ void __launch_bounds__(256)
k_stage0(const float* __restrict__ x,
         const float* __restrict__ cw, const float* __restrict__ w1,
         const float* __restrict__ w2,
         const float* __restrict__ ow0, const float* __restrict__ ow1,
         const float* __restrict__ ow2) {
    int bid = blockIdx.x;
    int tid = threadIdx.x;
    if (bid < 8192) {
        __shared__ float t[32][33];
        int tb = bid;
        int p0 = (tb & 511) * 32;
        int c0 = ((tb >> 9) & 7) * 32;
        int b  = tb >> 12;
        int tx = tid & 31, ty = tid >> 5;
        const float* xb = x + (size_t)b * CH * HWSZ;
#pragma unroll
        for (int i = 0; i < 4; i++)
            t[ty + 8 * i][tx] = xb[(size_t)(c0 + ty + 8 * i) * HWSZ + p0 + tx];
        __syncthreads();
        size_t base = (size_t)b * HWSZ * CH;
#pragma unroll
        for (int i = 0; i < 4; i++) {
            float v = t[tx][ty + 8 * i];
            size_t idx = base + (size_t)(p0 + ty + 8 * i) * CH + c0 + tx;
            g_xT[idx] = v;
            __nv_bfloat16 h, l; split_bf16(v, h, l);
            g_xTh[idx] = h; g_xTl[idx] = l;
        }
    } else if (bid < 8512) {
        int i = (bid - 8192) * 256 + tid;
        if (i >= 81920) return;
        const float* src; int dst;
        if (i < 16384)      { src = cw + i * 4;            dst = i * 4; }
        else if (i < 49152) { src = w1 + (i - 16384) * 4;  dst = 65536 + (i - 16384) * 4; }
        else                { src = w2 + (i - 49152) * 4;  dst = 196608 + (i - 49152) * 4; }
        float4 v = *(const float4*)src;
        __nv_bfloat16 ha, la, hb, lb, hc, lc, hd, ld;
        split_bf16(v.x, ha, la); split_bf16(v.y, hb, lb);
        split_bf16(v.z, hc, lc); split_bf16(v.w, hd, ld);
        ((__nv_bfloat162*)(g_wh + dst))[0] = __nv_bfloat162(ha, hb);
        ((__nv_bfloat162*)(g_wh + dst))[1] = __nv_bfloat162(hc, hd);
        ((__nv_bfloat162*)(g_wl + dst))[0] = __nv_bfloat162(la, lb);
        ((__nv_bfloat162*)(g_wl + dst))[1] = __nv_bfloat162(lc, ld);
    } else {
        int i = (bid - 8512) * 256 + tid;
        if (i >= 3 * 32 * 2304) return;
        int br = i / (32 * 2304);
        int r  = i % (32 * 2304);
        int o  = r / 2304;
        int kk = r % 2304;
        int k  = kk / 256, c = kk % 256;
        const float* w = (br == 0) ? ow0 : (br == 1) ? ow1 : ow2;
        float v = (o < 18) ? w[((size_t)o * 256 + c) * 9 + k] : 0.f;
        __nv_bfloat16 h, l; split_bf16(v, h, l);
        g_owh[i] = h; g_owl[i] = l;
    }
}

// =================== fused deform3: 4 pixels/warp, 2 blocks/SM ===================
// R13: branchless gathers — wq==0 corners contribute exact zeros, so results
// are bitwise identical while the 32 loads per (k, 4px) batch freely (MLP up).
__global__ void __launch_bounds__(256, 2)
k_deform3(const float* __restrict__ dw0, const float* __restrict__ dw1,
          const float* __restrict__ dw2,
          const float* __restrict__ lw0, const float* __restrict__ lb0,
          const float* __restrict__ lw1, const float* __restrict__ lb1,
          const float* __restrict__ lw2, const float* __restrict__ lb2,
          const float* __restrict__ n1w, const float* __restrict__ n1b) {
    __shared__ float sdefT[3][9 * CH];
    __shared__ int   sidx[8][4][36];
    __shared__ float swgt[8][4][36];

    int tid = threadIdx.x, wid = tid >> 5, lane = tid & 31;
    {
        const float* dws[3] = {dw0, dw1, dw2};
#pragma unroll
        for (int br = 0; br < 3; br++)
            for (int i = tid; i < 9 * CH; i += 256) {
                int c = i / 9, k = i % 9;
                sdefT[br][k * CH + c] = dws[br][i];
            }
    }
    __syncthreads();

    int pix0 = blockIdx.x * 32 + wid * 4;
    int b = pix0 >> 14;
    int c0 = lane * 8;
    const float* xrow = g_xT + (size_t)b * HWSZ * CH;

    float sum[4][8];
#pragma unroll
    for (int e = 0; e < 4; e++) {
        const float4* ap = (const float4*)(g_acc + (size_t)(pix0 + e) * CH + c0);
        float4 a0 = ap[0], a1 = ap[1];
        sum[e][0] = a0.x; sum[e][1] = a0.y; sum[e][2] = a0.z; sum[e][3] = a0.w;
        sum[e][4] = a1.x; sum[e][5] = a1.y; sum[e][6] = a1.z; sum[e][7] = a1.w;
    }

    const int DS[3] = {1, 9, 12};
    const float* lws[3] = {lw0, lw1, lw2};
    const float* lbs[3] = {lb0, lb1, lb2};

#pragma unroll
    for (int br = 0; br < 3; br++) {
        int D = DS[br];
        for (int t = lane; t < 36; t += 32) {
            int e = t / 9, k = t % 9;
            int pix = pix0 + e;
            int p = pix & (HWSZ - 1);
            int h = p >> 7, w = p & 127;
            int ky = k / 3, kx = k % 3;
            const float* op = g_offp + (size_t)(br * BATCH + b) * 18 * HWSZ;
            float oy = op[(size_t)(2 * k) * HWSZ + p];
            float ox = op[(size_t)(2 * k + 1) * HWSZ + p];
            float py = (float)h + (float)((ky - 1) * D) + oy;
            float px = (float)w + (float)((kx - 1) * D) + ox;
            float y0 = floorf(py), x0 = floorf(px);
#pragma unroll
            for (int dy = 0; dy < 2; dy++)
#pragma unroll
                for (int dx = 0; dx < 2; dx++) {
                    float yc = y0 + dy, xc = x0 + dx;
                    float wq = (1.f - fabsf(py - yc)) * (1.f - fabsf(px - xc));
                    bool valid = (yc >= 0.f) && (yc < 128.f) && (xc >= 0.f) && (xc < 128.f);
                    int iy = min(max((int)yc, 0), 127);
                    int ix = min(max((int)xc, 0), 127);
                    sidx[wid][e][k * 4 + dy * 2 + dx] = iy * WW + ix;
                    swgt[wid][e][k * 4 + dy * 2 + dx] = valid ? wq : 0.f;
                }
        }
        __syncwarp();

        float facc[4][8];
#pragma unroll
        for (int e = 0; e < 4; e++)
#pragma unroll
            for (int r = 0; r < 8; r++) facc[e][r] = 0.f;

#pragma unroll
        for (int k = 0; k < 9; k++) {
            float4 wk0 = *(const float4*)&sdefT[br][k * CH + c0];
            float4 wk1 = *(const float4*)&sdefT[br][k * CH + c0 + 4];
#pragma unroll
            for (int e = 0; e < 4; e++) {
                float s[8];
#pragma unroll
                for (int r = 0; r < 8; r++) s[r] = 0.f;
#pragma unroll
                for (int j = 0; j < 4; j++) {
                    float wq = swgt[wid][e][k * 4 + j];
                    const float4* vp =
                        (const float4*)(xrow + (size_t)sidx[wid][e][k * 4 + j] * CH + c0);
                    float4 v0 = vp[0], v1 = vp[1];
                    s[0] += wq * v0.x; s[1] += wq * v0.y; s[2] += wq * v0.z; s[3] += wq * v0.w;
                    s[4] += wq * v1.x; s[5] += wq * v1.y; s[6] += wq * v1.z; s[7] += wq * v1.w;
                }
                facc[e][0] += wk0.x * s[0]; facc[e][1] += wk0.y * s[1];
                facc[e][2] += wk0.z * s[2]; facc[e][3] += wk0.w * s[3];
                facc[e][4] += wk1.x * s[4]; facc[e][5] += wk1.y * s[5];
                facc[e][6] += wk1.z * s[6]; facc[e][7] += wk1.w * s[7];
            }
        }

        const float4* lwp = (const float4*)(lws[br] + c0);
        const float4* lbp = (const float4*)(lbs[br] + c0);
        float4 lw0v = lwp[0], lw1v = lwp[1], lb0v = lbp[0], lb1v = lbp[1];
        float lw[8] = {lw0v.x, lw0v.y, lw0v.z, lw0v.w, lw1v.x, lw1v.y, lw1v.z, lw1v.w};
        float lb[8] = {lb0v.x, lb0v.y, lb0v.z, lb0v.w, lb1v.x, lb1v.y, lb1v.z, lb1v.w};
#pragma unroll
        for (int e = 0; e < 4; e++) {
            float ls = 0.f, lq = 0.f;
#pragma unroll
            for (int r = 0; r < 8; r++) { ls += facc[e][r]; lq += facc[e][r] * facc[e][r]; }
#pragma unroll
            for (int o = 16; o; o >>= 1) {
                ls += __shfl_xor_sync(0xffffffffu, ls, o);
                lq += __shfl_xor_sync(0xffffffffu, lq, o);
            }
            float mean = ls * (1.f / 256.f);
            float var  = lq * (1.f / 256.f) - mean * mean;
            float rstd = rsqrtf(var + LN_EPS);
#pragma unroll
            for (int r = 0; r < 8; r++)
                sum[e][r] += gelu_f(lw[r] * ((facc[e][r] - mean) * rstd) + lb[r]);
        }
        __syncwarp();
    }

    const float4* wp = (const float4*)(n1w + c0);
    const float4* bp = (const float4*)(n1b + c0);
    float4 w0v = wp[0], w1v = wp[1], b0v = bp[0], b1v = bp[1];
    float gw[8] = {w0v.x, w0v.y, w0v.z, w0v.w, w1v.x, w1v.y, w1v.z, w1v.w};
    float gb[8] = {b0v.x, b0v.y, b0v.z, b0v.w, b1v.x, b1v.y, b1v.z, b1v.w};

#pragma unroll
    for (int e = 0; e < 4; e++) {
        float ls = 0.f, lq = 0.f;
#pragma unroll
        for (int r = 0; r < 8; r++) { ls += sum[e][r]; lq += sum[e][r] * sum[e][r]; }
#pragma unroll
        for (int o = 16; o; o >>= 1) {
            ls += __shfl_xor_sync(0xffffffffu, ls, o);
            lq += __shfl_xor_sync(0xffffffffu, lq, o);
        }
        float mean = ls * (1.f / 256.f);
        float var  = lq * (1.f / 256.f) - mean * mean;
        float rstd = rsqrtf(var + LN_EPS);

        uint32_t hp[4], lp[4];
#pragma unroll
        for (int r = 0; r < 8; r += 2) {
            float oa = gw[r] * ((sum[e][r] - mean) * rstd) + gb[r];
            float ob = gw[r + 1] * ((sum[e][r + 1] - mean) * rstd) + gb[r + 1];
            __nv_bfloat16 h0, l0, h1, l1;
            split_bf16(oa, h0, l0); split_bf16(ob, h1, l1);
            hp[r >> 1] = (uint32_t)__bfloat16_as_ushort(h0) |
                         ((uint32_t)__bfloat16_as_ushort(h1) << 16);
            lp[r >> 1] = (uint32_t)__bfloat16_as_ushort(l0) |
                         ((uint32_t)__bfloat16_as_ushort(l1) << 16);
        }
        *(uint4*)(g_o1h + (size_t)(pix0 + e) * CH + c0) = make_uint4(hp[0], hp[1], hp[2], hp[3]);
        *(uint4*)(g_o1l + (size_t)(pix0 + e) * CH + c0) = make_uint4(lp[0], lp[1], lp[2], lp[3]);
    }
}

// =================== fused LN2 + NHWC->NCHW output ===================
__global__ void __launch_bounds__(256)
k_ln2out(const float* __restrict__ in, float* __restrict__ out,
         const float* __restrict__ gwv, const float* __restrict__ gbv) {
    __shared__ float tr[256][33];
    int tid = threadIdx.x, wid = tid >> 5, lane = tid & 31;
    int p32 = blockIdx.x * 32;
    int b = p32 >> 14;
    int pimg = p32 & (HWSZ - 1);

#pragma unroll
    for (int i = 0; i < 4; i++) {
        int pxloc = wid + i * 8;
        const float4* row = (const float4*)(in + (size_t)(p32 + pxloc) * CH);
        float4 va = row[lane], vb = row[lane + 32];
        float s = va.x + va.y + va.z + va.w + vb.x + vb.y + vb.z + vb.w;
        float qq = va.x * va.x + va.y * va.y + va.z * va.z + va.w * va.w +
                   vb.x * vb.x + vb.y * vb.y + vb.z * vb.z + vb.w * vb.w;
#pragma unroll
        for (int o = 16; o; o >>= 1) {
            s  += __shfl_xor_sync(0xffffffffu, s, o);
            qq += __shfl_xor_sync(0xffffffffu, qq, o);
        }
        float mean = s * (1.f / 256.f);
        float var  = qq * (1.f / 256.f) - mean * mean;
        float rstd = rsqrtf(var + LN_EPS);
        int ca = lane * 4, cb = 128 + lane * 4;
        float4 ga = *(const float4*)(gwv + ca), gba = *(const float4*)(gbv + ca);
        float4 gb2 = *(const float4*)(gwv + cb), gbb = *(const float4*)(gbv + cb);
        tr[ca + 0][pxloc] = ga.x * ((va.x - mean) * rstd) + gba.x;
        tr[ca + 1][pxloc] = ga.y * ((va.y - mean) * rstd) + gba.y;
        tr[ca + 2][pxloc] = ga.z * ((va.z - mean) * rstd) + gba.z;
        tr[ca + 3][pxloc] = ga.w * ((va.w - mean) * rstd) + gba.w;
        tr[cb + 0][pxloc] = gb2.x * ((vb.x - mean) * rstd) + gbb.x;
        tr[cb + 1][pxloc] = gb2.y * ((vb.y - mean) * rstd) + gbb.y;
        tr[cb + 2][pxloc] = gb2.z * ((vb.z - mean) * rstd) + gbb.z;
        tr[cb + 3][pxloc] = gb2.w * ((vb.w - mean) * rstd) + gbb.w;
    }
    __syncthreads();

    float* ob = out + (size_t)b * CH * HWSZ + pimg;
#pragma unroll
    for (int it = 0; it < 32; it++) {
        int c = it * 8 + wid;
        ob[(size_t)c * HWSZ + lane] = tr[c][lane];
    }
}

// =================== launch ===================
extern "C" void kernel_launch(void* const* d_in, const int* in_sizes, int n_in,
                              void* d_out, int out_size) {
    const float* x       = (const float*)d_in[0];
    const float* off_w1  = (const float*)d_in[1];
    const float* def_w1  = (const float*)d_in[2];
    const float* bw1     = (const float*)d_in[3];
    const float* bb1     = (const float*)d_in[4];
    const float* off_w2  = (const float*)d_in[5];
    const float* def_w2  = (const float*)d_in[6];
    const float* bw2     = (const float*)d_in[7];
    const float* bb2     = (const float*)d_in[8];
    const float* off_w3  = (const float*)d_in[9];
    const float* def_w3  = (const float*)d_in[10];
    const float* bw3     = (const float*)d_in[11];
    const float* bb3     = (const float*)d_in[12];
    const float* conv_w  = (const float*)d_in[13];
    const float* conv_b  = (const float*)d_in[14];
    const float* n1_w    = (const float*)d_in[15];
    const float* n1_b    = (const float*)d_in[16];
    const float* n2_w    = (const float*)d_in[17];
    const float* n2_b    = (const float*)d_in[18];
    const float* mlp_w1  = (const float*)d_in[19];
    const float* mlp_b1  = (const float*)d_in[20];
    const float* mlp_w2  = (const float*)d_in[21];
    const float* mlp_b2  = (const float*)d_in[22];

    float *pacc, *pt2;
    __nv_bfloat16 *po1h, *po1l, *phh, *phl, *pwh, *pwl, *pxTh, *pxTl;
    cudaGetSymbolAddress((void**)&pacc,  g_acc);
    cudaGetSymbolAddress((void**)&pt2,   g_t2);
    cudaGetSymbolAddress((void**)&pxTh,  g_xTh);
    cudaGetSymbolAddress((void**)&pxTl,  g_xTl);
    cudaGetSymbolAddress((void**)&po1h,  g_o1h);
    cudaGetSymbolAddress((void**)&po1l,  g_o1l);
    cudaGetSymbolAddress((void**)&phh,   g_hh);
    cudaGetSymbolAddress((void**)&phl,   g_hl);
    cudaGetSymbolAddress((void**)&pwh,   g_wh);
    cudaGetSymbolAddress((void**)&pwl,   g_wl);

    cudaFuncSetAttribute(k_stage1,
                         cudaFuncAttributeMaxDynamicSharedMemorySize, G_SMEM);
    cudaFuncSetAttribute(k_mmagemm<1, false, true>,
                         cudaFuncAttributeMaxDynamicSharedMemorySize, G_SMEM);
    cudaFuncSetAttribute(k_mmagemm<0, true, false>,
                         cudaFuncAttributeMaxDynamicSharedMemorySize, G_SMEM);

    // 1. transpose+split | weight prep | offset-weight reorg (one launch)
    k_stage0<<<9376, 256>>>(x, conv_w, mlp_w1, mlp_w2, off_w1, off_w2, off_w3);
    // 2. conv1x1 GEMM + offset convs, co-scheduled in one launch
    k_stage1<<<1280, 256, G_SMEM>>>(pxTh, pxTl, pwh, pwl, conv_b, pacc);
    // 3. fused deform x3 + LN1 + split (4 px/warp, 2 blocks/SM, branchless gathers)
    k_deform3<<<PTOT / 32, 256>>>(def_w1, def_w2, def_w3,
                                  bw1, bb1, bw2, bb2, bw3, bb3, n1_w, n1_b);
    // 4. MLP1 (bias+GELU, bf16 hi/lo out)
    k_mmagemm<1, false, true><<<dim3(PTOT / 128, 512 / 128), 256, G_SMEM>>>(
        po1h, po1l, pwh + 65536, pwl + 65536, mlp_b1, nullptr, nullptr,
        nullptr, phh, phl, 512, CH);
    // 5. MLP2 (bias + residual o1h+o1l)
    k_mmagemm<0, true, false><<<dim3(PTOT / 128, CH / 128), 256, G_SMEM>>>(
        phh, phl, pwh + 196608, pwl + 196608, mlp_b2, po1h, po1l,
        pt2, nullptr, nullptr, CH, 512);
    // 6. fused LN2 + transpose out
    k_ln2out<<<PTOT / 32, 256>>>(pt2, (float*)d_out, n2_w, n2_b);
}

// round 14
// speedup vs baseline: 2.1548x; 1.0080x over previous
#include <cuda_runtime.h>
#include <cuda_bf16.h>
#include <math.h>
#include <stdint.h>

#define BATCH 2
#define CH    256
#define HH    128
#define WW    128
#define HWSZ  16384
#define PTOT  32768
#define LN_EPS 1e-6f

// ---------------- scratch ----------------
__device__ float g_xT  [(size_t)PTOT * CH];
__device__ float g_acc [(size_t)PTOT * CH];
__device__ float g_offp[(size_t)3 * BATCH * 18 * HWSZ];   // [branch][b][18][HW]
__device__ __nv_bfloat16 g_xTh[(size_t)PTOT * CH];
__device__ __nv_bfloat16 g_xTl[(size_t)PTOT * CH];
__device__ __nv_bfloat16 g_o1h[(size_t)PTOT * CH];
__device__ __nv_bfloat16 g_o1l[(size_t)PTOT * CH];
__device__ __nv_bfloat16 g_hh [(size_t)PTOT * 512];
__device__ __nv_bfloat16 g_hl [(size_t)PTOT * 512];
__device__ __nv_bfloat16 g_wh[327680];
__device__ __nv_bfloat16 g_wl[327680];
__device__ __nv_bfloat16 g_owh[3 * 32 * 2304];
__device__ __nv_bfloat16 g_owl[3 * 32 * 2304];

__device__ __forceinline__ float gelu_f(float v) {
    return 0.5f * v * (1.0f + erff(v * 0.70710678118654752440f));
}
__device__ __forceinline__ void split_bf16(float v, __nv_bfloat16& h, __nv_bfloat16& l) {
    h = __float2bfloat16(v);
    l = __float2bfloat16(v - __bfloat162float(h));
}
__device__ __forceinline__ uint32_t smem_u32(const void* p) {
    uint32_t a;
    asm("{ .reg .u64 t; cvta.to.shared.u64 t, %1; cvt.u32.u64 %0, t; }" : "=r"(a) : "l"(p));
    return a;
}
__device__ __forceinline__ void ldmx4(uint32_t* r, uint32_t addr) {
    asm volatile("ldmatrix.sync.aligned.m8n8.x4.shared.b16 {%0,%1,%2,%3}, [%4];"
                 : "=r"(r[0]), "=r"(r[1]), "=r"(r[2]), "=r"(r[3]) : "r"(addr));
}
__device__ __forceinline__ void mma16816(float* c, const uint32_t* a, const uint32_t* b) {
    asm volatile("mma.sync.aligned.m16n8k16.row.col.f32.bf16.bf16.f32 "
                 "{%0,%1,%2,%3}, {%4,%5,%6,%7}, {%8,%9}, {%0,%1,%2,%3};"
                 : "+f"(c[0]), "+f"(c[1]), "+f"(c[2]), "+f"(c[3])
                 : "r"(a[0]), "r"(a[1]), "r"(a[2]), "r"(a[3]), "r"(b[0]), "r"(b[1]));
}
__device__ __forceinline__ void cp16(uint32_t dst, const void* src) {
    asm volatile("cp.async.cg.shared.global [%0], [%1], 16;" :: "r"(dst), "l"(src));
}
__device__ __forceinline__ void cp16z(uint32_t dst, const void* src, bool valid) {
    int sz = valid ? 16 : 0;
    asm volatile("cp.async.cg.shared.global [%0], [%1], 16, %2;"
                 :: "r"(dst), "l"(src), "r"(sz));
}
#define CP_COMMIT() asm volatile("cp.async.commit_group;" ::: "memory")
#define CP_WAIT0()  asm volatile("cp.async.wait_group 0;" ::: "memory")

// =================== GEMM body (split-bf16 HMMA, cp.async double-buffered) ===================
#define G_ARR (128 * 40)
#define G_STG (4 * G_ARR)
#define G_SMEM (2 * G_STG * 2)   // 81920 bytes

template <int ACT, bool RES, bool BF16OUT>
__device__ __forceinline__ void gemm_body(
        char* dsm_, int mblk, int nblk,
        const __nv_bfloat16* __restrict__ Ah, const __nv_bfloat16* __restrict__ Al,
        const __nv_bfloat16* __restrict__ Bh, const __nv_bfloat16* __restrict__ Bl,
        const float* __restrict__ bias,
        const __nv_bfloat16* __restrict__ Resh, const __nv_bfloat16* __restrict__ Resl,
        float* __restrict__ Cf, __nv_bfloat16* __restrict__ Chi,
        __nv_bfloat16* __restrict__ Clo, int N, int K) {
    __nv_bfloat16* sm = (__nv_bfloat16*)dsm_;
    uint32_t smb = smem_u32(sm);

    int tid  = threadIdx.x;
    int wid  = tid >> 5, lane = tid & 31;
    int m0   = mblk * 128, n0 = nblk * 128;
    int wm   = (wid & 3) * 32;
    int wn   = (wid >> 2) * 64;

    float acc[2][8][4];
#pragma unroll
    for (int i = 0; i < 2; i++)
#pragma unroll
        for (int j = 0; j < 8; j++)
#pragma unroll
            for (int q = 0; q < 4; q++) acc[i][j][q] = 0.f;

    const __nv_bfloat16* srcs[4] = {Ah + (size_t)m0 * K, Al + (size_t)m0 * K,
                                    Bh + (size_t)n0 * K, Bl + (size_t)n0 * K};

    auto load_stage = [&](int kc, int s) {
        uint32_t stgoff = (uint32_t)s * (G_STG * 2);
#pragma unroll
        for (int t = 0; t < 4; t++) {
            const __nv_bfloat16* src = srcs[t] + kc * 32;
            uint32_t dstb = smb + stgoff + (uint32_t)t * (G_ARR * 2);
#pragma unroll
            for (int u = 0; u < 2; u++) {
                int idx = u * 256 + tid;
                int row = idx >> 2, ch = idx & 3;
                cp16(dstb + (uint32_t)(row * 40 + ch * 8) * 2,
                     src + (size_t)row * K + ch * 8);
            }
        }
    };

    int a_row8 = ((lane >> 3) & 1) * 8 + (lane & 7);
    int a_col8 = ((lane >> 4) & 1) * 8;
    int b_row8 = ((lane >> 4) & 1) * 8 + (lane & 7);
    int b_col8 = ((lane >> 3) & 1) * 8;

    uint32_t aB[2][2], bB[2][4];
#pragma unroll
    for (int hl = 0; hl < 2; hl++) {
#pragma unroll
        for (int mi = 0; mi < 2; mi++)
            aB[hl][mi] = smb + (uint32_t)(hl * (G_ARR * 2)) +
                         (uint32_t)((wm + mi * 16 + a_row8) * 80 + a_col8 * 2);
#pragma unroll
        for (int jp = 0; jp < 4; jp++)
            bB[hl][jp] = smb + (uint32_t)((2 + hl) * (G_ARR * 2)) +
                         (uint32_t)((wn + jp * 16 + b_row8) * 80 + b_col8 * 2);
    }

    load_stage(0, 0); CP_COMMIT();
    CP_WAIT0(); __syncthreads();

    int nk = K >> 5;
    for (int kc = 0; kc < nk; kc++) {
        int cur = kc & 1;
        if (kc + 1 < nk) { load_stage(kc + 1, cur ^ 1); CP_COMMIT(); }

        uint32_t stg = (uint32_t)cur * (G_STG * 2);
#pragma unroll
        for (int ks = 0; ks < 2; ks++) {
            uint32_t so = stg + (uint32_t)(ks * 32);
            uint32_t af[2][2][4];
#pragma unroll
            for (int hl = 0; hl < 2; hl++)
#pragma unroll
                for (int mi = 0; mi < 2; mi++)
                    ldmx4(af[hl][mi], aB[hl][mi] + so);
#pragma unroll
            for (int jp = 0; jp < 4; jp++) {
                uint32_t bh[4], bl[4];
                ldmx4(bh, bB[0][jp] + so);
                ldmx4(bl, bB[1][jp] + so);
#pragma unroll
                for (int mi = 0; mi < 2; mi++)
#pragma unroll
                    for (int jj = 0; jj < 2; jj++) {
                        int j = jp * 2 + jj;
                        uint32_t bh2[2] = {bh[jj * 2], bh[jj * 2 + 1]};
                        uint32_t bl2[2] = {bl[jj * 2], bl[jj * 2 + 1]};
                        mma16816(acc[mi][j], af[0][mi], bh2);
                        mma16816(acc[mi][j], af[0][mi], bl2);
                        mma16816(acc[mi][j], af[1][mi], bh2);
                    }
            }
        }
        if (kc + 1 < nk) CP_WAIT0();
        __syncthreads();
    }

    int g = lane >> 2, q = lane & 3;
#pragma unroll
    for (int mi = 0; mi < 2; mi++) {
#pragma unroll
        for (int half = 0; half < 2; half++) {
            int m = m0 + wm + mi * 16 + g + half * 8;
#pragma unroll
            for (int j = 0; j < 8; j++) {
                int n = n0 + wn + j * 8 + q * 2;
                float v0 = acc[mi][j][half * 2 + 0] + __ldg(bias + n);
                float v1 = acc[mi][j][half * 2 + 1] + __ldg(bias + n + 1);
                if (ACT == 1) { v0 = gelu_f(v0); v1 = gelu_f(v1); }
                if (RES) {
                    __nv_bfloat162 rh = *(const __nv_bfloat162*)(Resh + (size_t)m * N + n);
                    __nv_bfloat162 rl = *(const __nv_bfloat162*)(Resl + (size_t)m * N + n);
                    v0 += __bfloat162float(rh.x) + __bfloat162float(rl.x);
                    v1 += __bfloat162float(rh.y) + __bfloat162float(rl.y);
                }
                if (BF16OUT) {
                    __nv_bfloat16 h0, l0, h1, l1;
                    split_bf16(v0, h0, l0); split_bf16(v1, h1, l1);
                    *(__nv_bfloat162*)(Chi + (size_t)m * N + n) = __nv_bfloat162(h0, h1);
                    *(__nv_bfloat162*)(Clo + (size_t)m * N + n) = __nv_bfloat162(l0, l1);
                } else {
                    *(float2*)(Cf + (size_t)m * N + n) = make_float2(v0, v1);
                }
            }
        }
    }
}

// =================== offmma body ===================
#define OFF_A_ARR (128 * 40)
#define OFF_B_ARR (32 * 40)
#define OFF_STG   (2 * OFF_A_ARR + 2 * OFF_B_ARR)

__device__ __forceinline__ void offmma_body(char* dsm_, int bx, int br) {
    __nv_bfloat16* sm = (__nv_bfloat16*)dsm_;
    uint32_t smb = smem_u32(sm);

    int tid = threadIdx.x, wid = tid >> 5, lane = tid & 31;
    int h = bx & 127, b = bx >> 7;
    const int D = (br == 0) ? 1 : (br == 1) ? 9 : 12;

    const __nv_bfloat16* xh = g_xTh + (size_t)b * HWSZ * CH;
    const __nv_bfloat16* xl = g_xTl + (size_t)b * HWSZ * CH;
    const __nv_bfloat16* wbh = g_owh + (size_t)br * 32 * 2304;
    const __nv_bfloat16* wbl = g_owl + (size_t)br * 32 * 2304;

    float acc[4][4];
#pragma unroll
    for (int j = 0; j < 4; j++)
#pragma unroll
        for (int q = 0; q < 4; q++) acc[j][q] = 0.f;

    auto load_stage = [&](int kc, int s) {
        uint32_t base = smb + (uint32_t)s * (OFF_STG * 2);
        uint32_t sAh = base;
        uint32_t sAl = sAh + OFF_A_ARR * 2;
        uint32_t sBh = sAl + OFF_A_ARR * 2;
        uint32_t sBl = sBh + OFF_B_ARR * 2;
        int k  = kc >> 3;
        int cc = (kc & 7) * 32;
        int dy = (k / 3 - 1) * D, dx = (k % 3 - 1) * D;
        int srow = h + dy;
        bool vy = (srow >= 0) && (srow < HH);
        int srowc = vy ? srow : 0;
#pragma unroll
        for (int u = 0; u < 2; u++) {
            int idx = u * 256 + tid;
            int w = idx >> 2, ch = idx & 3;
            int wp = w + dx;
            bool v = vy && (wp >= 0) && (wp < WW);
            int wpc = v ? wp : 0;
            size_t goff = (size_t)(srowc * WW + wpc) * CH + cc + ch * 8;
            uint32_t soff = (uint32_t)(w * 40 + ch * 8) * 2;
            cp16z(sAh + soff, xh + goff, v);
            cp16z(sAl + soff, xl + goff, v);
        }
        if (tid < 128) {
            int o = tid >> 2, ch = tid & 3;
            size_t goff = (size_t)o * 2304 + k * 256 + cc + ch * 8;
            uint32_t soff = (uint32_t)(o * 40 + ch * 8) * 2;
            cp16(sBh + soff, wbh + goff);
            cp16(sBl + soff, wbl + goff);
        }
    };

    int a_row8 = ((lane >> 3) & 1) * 8 + (lane & 7);
    int a_col8 = ((lane >> 4) & 1) * 8;
    int b_row8 = ((lane >> 4) & 1) * 8 + (lane & 7);
    int b_col8 = ((lane >> 3) & 1) * 8;

    uint32_t aB[2], bB[2][2];
#pragma unroll
    for (int hl = 0; hl < 2; hl++) {
        aB[hl] = smb + (uint32_t)(hl * (OFF_A_ARR * 2)) +
                 (uint32_t)((wid * 16 + a_row8) * 80 + a_col8 * 2);
#pragma unroll
        for (int jp = 0; jp < 2; jp++)
            bB[hl][jp] = smb + (uint32_t)(2 * OFF_A_ARR * 2 + hl * (OFF_B_ARR * 2)) +
                         (uint32_t)((jp * 16 + b_row8) * 80 + b_col8 * 2);
    }

    load_stage(0, 0); CP_COMMIT();
    CP_WAIT0(); __syncthreads();

    const int NK = 72;
    for (int kc = 0; kc < NK; kc++) {
        int cur = kc & 1;
        if (kc + 1 < NK) { load_stage(kc + 1, cur ^ 1); CP_COMMIT(); }

        uint32_t stg = (uint32_t)cur * (OFF_STG * 2);
#pragma unroll
        for (int ks = 0; ks < 2; ks++) {
            uint32_t so = stg + (uint32_t)(ks * 32);
            uint32_t af[2][4];
            ldmx4(af[0], aB[0] + so);
            ldmx4(af[1], aB[1] + so);
#pragma unroll
            for (int jp = 0; jp < 2; jp++) {
                uint32_t bh[4], bl[4];
                ldmx4(bh, bB[0][jp] + so);
                ldmx4(bl, bB[1][jp] + so);
#pragma unroll
                for (int jj = 0; jj < 2; jj++) {
                    int j = jp * 2 + jj;
                    uint32_t bh2[2] = {bh[jj * 2], bh[jj * 2 + 1]};
                    uint32_t bl2[2] = {bl[jj * 2], bl[jj * 2 + 1]};
                    mma16816(acc[j], af[0], bh2);
                    mma16816(acc[j], af[0], bl2);
                    mma16816(acc[j], af[1], bh2);
                }
            }
        }
        if (kc + 1 < NK) CP_WAIT0();
        __syncthreads();
    }

    float* op = g_offp + (size_t)(br * BATCH + b) * 18 * HWSZ;
    int g = lane >> 2, q = lane & 3;
#pragma unroll
    for (int half = 0; half < 2; half++) {
        int wcol = wid * 16 + g + half * 8;
        int pimg = h * WW + wcol;
#pragma unroll
        for (int j = 0; j < 4; j++) {
#pragma unroll
            for (int e = 0; e < 2; e++) {
                int n = j * 8 + q * 2 + e;
                if (n < 18) op[(size_t)n * HWSZ + pimg] = acc[j][half * 2 + e];
            }
        }
    }
}

// =================== stage 1: conv1x1 GEMM (blocks 0..511) + offmma (512..1279) ===================
__global__ void __launch_bounds__(256, 2)
k_stage1(const __nv_bfloat16* __restrict__ xTh, const __nv_bfloat16* __restrict__ xTl,
         const __nv_bfloat16* __restrict__ cwh, const __nv_bfloat16* __restrict__ cwl,
         const float* __restrict__ conv_b, float* __restrict__ accp) {
    extern __shared__ char dsm_[];
    int bid = blockIdx.x;
    if (bid < 512) {
        gemm_body<0, false, false>(dsm_, bid & 255, bid >> 8,
                                   xTh, xTl, cwh, cwl, conv_b,
                                   nullptr, nullptr, accp, nullptr, nullptr, CH, CH);
    } else {
        int obid = bid - 512;
        offmma_body(dsm_, obid & 255, obid >> 8);
    }
}

// =================== MLP1 GEMM ===================
template <int ACT, bool RES, bool BF16OUT>
__global__ void __launch_bounds__(256, 2)
k_mmagemm(const __nv_bfloat16* __restrict__ Ah, const __nv_bfloat16* __restrict__ Al,
          const __nv_bfloat16* __restrict__ Bh, const __nv_bfloat16* __restrict__ Bl,
          const float* __restrict__ bias,
          const __nv_bfloat16* __restrict__ Resh, const __nv_bfloat16* __restrict__ Resl,
          float* __restrict__ Cf, __nv_bfloat16* __restrict__ Chi,
          __nv_bfloat16* __restrict__ Clo, int N, int K) {
    extern __shared__ char dsm_[];
    gemm_body<ACT, RES, BF16OUT>(dsm_, blockIdx.x, blockIdx.y,
                                 Ah, Al, Bh, Bl, bias, Resh, Resl, Cf, Chi, Clo, N, K);
}

// =================== fused MLP2 + LN2 + NCHW output ===================
// block: 128 pixels (one image row) x 256 channels, 512 threads = 16 warps (4M x 4N)
#define F_A_ARR (128 * 40)
#define F_B_ARR (256 * 40)
#define F_STG   (2 * F_A_ARR + 2 * F_B_ARR)    // 30720 elems
#define F_PIPE  (2 * F_STG * 2)                // 122880 bytes
#define F_SMEM  (256 * 132 * 4)                // 135168 bytes (transpose stage, >= F_PIPE)

__global__ void __launch_bounds__(512, 1)
k_mlp2ln(const __nv_bfloat16* __restrict__ Ah, const __nv_bfloat16* __restrict__ Al,
         const __nv_bfloat16* __restrict__ Bh, const __nv_bfloat16* __restrict__ Bl,
         const float* __restrict__ bias,
         const __nv_bfloat16* __restrict__ Resh, const __nv_bfloat16* __restrict__ Resl,
         const float* __restrict__ n2w, const float* __restrict__ n2b,
         float* __restrict__ out) {
    extern __shared__ char dsm_[];
    uint32_t smb = smem_u32(dsm_);
    __shared__ float red_s[128][4];
    __shared__ float red_q[128][4];

    const int K = 512, N = 256;
    int tid = threadIdx.x, wid = tid >> 5, lane = tid & 31;
    int m0  = blockIdx.x * 128;
    int wm  = (wid & 3) * 32;
    int wn  = (wid >> 2) * 64;

    float acc[2][8][4];
#pragma unroll
    for (int i = 0; i < 2; i++)
#pragma unroll
        for (int j = 0; j < 8; j++)
#pragma unroll
            for (int q = 0; q < 4; q++) acc[i][j][q] = 0.f;

    const __nv_bfloat16* srcA[2] = {Ah + (size_t)m0 * K, Al + (size_t)m0 * K};
    const __nv_bfloat16* srcB[2] = {Bh, Bl};

    auto load_stage = [&](int kc, int s) {
        uint32_t stgoff = (uint32_t)s * (F_STG * 2);
#pragma unroll
        for (int t = 0; t < 2; t++) {      // A hi/lo: 128 rows, 1 cp16/thread
            const __nv_bfloat16* src = srcA[t] + kc * 32;
            uint32_t dstb = smb + stgoff + (uint32_t)t * (F_A_ARR * 2);
            int row = tid >> 2, ch = tid & 3;
            cp16(dstb + (uint32_t)(row * 40 + ch * 8) * 2,
                 src + (size_t)row * K + ch * 8);
        }
#pragma unroll
        for (int t = 0; t < 2; t++) {      // B hi/lo: 256 rows, 2 cp16/thread
            const __nv_bfloat16* src = srcB[t] + kc * 32;
            uint32_t dstb = smb + stgoff + (uint32_t)(2 * F_A_ARR * 2) +
                            (uint32_t)t * (F_B_ARR * 2);
#pragma unroll
            for (int u = 0; u < 2; u++) {
                int idx = u * 512 + tid;
                int row = idx >> 2, ch = idx & 3;
                cp16(dstb + (uint32_t)(row * 40 + ch * 8) * 2,
                     src + (size_t)row * K + ch * 8);
            }
        }
    };

    int a_row8 = ((lane >> 3) & 1) * 8 + (lane & 7);
    int a_col8 = ((lane >> 4) & 1) * 8;
    int b_row8 = ((lane >> 4) & 1) * 8 + (lane & 7);
    int b_col8 = ((lane >> 3) & 1) * 8;

    uint32_t aB[2][2], bB[2][4];
#pragma unroll
    for (int hl = 0; hl < 2; hl++) {
#pragma unroll
        for (int mi = 0; mi < 2; mi++)
            aB[hl][mi] = smb + (uint32_t)(hl * (F_A_ARR * 2)) +
                         (uint32_t)((wm + mi * 16 + a_row8) * 80 + a_col8 * 2);
#pragma unroll
        for (int jp = 0; jp < 4; jp++)
            bB[hl][jp] = smb + (uint32_t)(2 * F_A_ARR * 2 + hl * (F_B_ARR * 2)) +
                         (uint32_t)((wn + jp * 16 + b_row8) * 80 + b_col8 * 2);
    }

    load_stage(0, 0); CP_COMMIT();
    CP_WAIT0(); __syncthreads();

    const int nk = K >> 5;   // 16
    for (int kc = 0; kc < nk; kc++) {
        int cur = kc & 1;
        if (kc + 1 < nk) { load_stage(kc + 1, cur ^ 1); CP_COMMIT(); }

        uint32_t stg = (uint32_t)cur * (F_STG * 2);
#pragma unroll
        for (int ks = 0; ks < 2; ks++) {
            uint32_t so = stg + (uint32_t)(ks * 32);
            uint32_t af[2][2][4];
#pragma unroll
            for (int hl = 0; hl < 2; hl++)
#pragma unroll
                for (int mi = 0; mi < 2; mi++)
                    ldmx4(af[hl][mi], aB[hl][mi] + so);
#pragma unroll
            for (int jp = 0; jp < 4; jp++) {
                uint32_t bh[4], bl[4];
                ldmx4(bh, bB[0][jp] + so);
                ldmx4(bl, bB[1][jp] + so);
#pragma unroll
                for (int mi = 0; mi < 2; mi++)
#pragma unroll
                    for (int jj = 0; jj < 2; jj++) {
                        int j = jp * 2 + jj;
                        uint32_t bh2[2] = {bh[jj * 2], bh[jj * 2 + 1]};
                        uint32_t bl2[2] = {bl[jj * 2], bl[jj * 2 + 1]};
                        mma16816(acc[mi][j], af[0][mi], bh2);
                        mma16816(acc[mi][j], af[0][mi], bl2);
                        mma16816(acc[mi][j], af[1][mi], bh2);
                    }
            }
        }
        if (kc + 1 < nk) CP_WAIT0();
        __syncthreads();
    }

    // ---- epilogue: bias + residual, LN2 partials ----
    int g = lane >> 2, q = lane & 3;
    float ps[2][2], pq[2][2];
#pragma unroll
    for (int mi = 0; mi < 2; mi++) {
#pragma unroll
        for (int half = 0; half < 2; half++) {
            int m = m0 + wm + mi * 16 + g + half * 8;
            float s = 0.f, q2 = 0.f;
#pragma unroll
            for (int j = 0; j < 8; j++) {
                int n = wn + j * 8 + q * 2;
                __nv_bfloat162 rh = *(const __nv_bfloat162*)(Resh + (size_t)m * N + n);
                __nv_bfloat162 rl = *(const __nv_bfloat162*)(Resl + (size_t)m * N + n);
                float v0 = acc[mi][j][half * 2 + 0] + __ldg(bias + n) +
                           __bfloat162float(rh.x) + __bfloat162float(rl.x);
                float v1 = acc[mi][j][half * 2 + 1] + __ldg(bias + n + 1) +
                           __bfloat162float(rh.y) + __bfloat162float(rl.y);
                acc[mi][j][half * 2 + 0] = v0;
                acc[mi][j][half * 2 + 1] = v1;
                s += v0 + v1;
                q2 += v0 * v0 + v1 * v1;
            }
            // reduce across the 4-lane q-group (same rows, disjoint cols)
            s  += __shfl_xor_sync(0xffffffffu, s, 1);
            s  += __shfl_xor_sync(0xffffffffu, s, 2);
            q2 += __shfl_xor_sync(0xffffffffu, q2, 1);
            q2 += __shfl_xor_sync(0xffffffffu, q2, 2);
            ps[mi][half] = s; pq[mi][half] = q2;
        }
    }
    if (q == 0) {
        int wncol = wid >> 2;
#pragma unroll
        for (int mi = 0; mi < 2; mi++)
#pragma unroll
            for (int half = 0; half < 2; half++) {
                int ml = wm + mi * 16 + g + half * 8;
                red_s[ml][wncol] = ps[mi][half];
                red_q[ml][wncol] = pq[mi][half];
            }
    }
    __syncthreads();

    // ---- normalize + stage transpose into (dead) pipeline smem ----
    float* tr = (float*)dsm_;   // [256][132]
#pragma unroll
    for (int mi = 0; mi < 2; mi++) {
#pragma unroll
        for (int half = 0; half < 2; half++) {
            int ml = wm + mi * 16 + g + half * 8;
            float sm = red_s[ml][0] + red_s[ml][1] + red_s[ml][2] + red_s[ml][3];
            float sq = red_q[ml][0] + red_q[ml][1] + red_q[ml][2] + red_q[ml][3];
            float mean = sm * (1.f / 256.f);
            float var  = sq * (1.f / 256.f) - mean * mean;
            float rstd = rsqrtf(var + LN_EPS);
#pragma unroll
            for (int j = 0; j < 8; j++) {
#pragma unroll
                for (int e = 0; e < 2; e++) {
                    int n = wn + j * 8 + q * 2 + e;
                    float v = acc[mi][j][half * 2 + e];
                    tr[n * 132 + ml] = __ldg(n2w + n) * ((v - mean) * rstd) + __ldg(n2b + n);
                }
            }
        }
    }
    __syncthreads();

    // ---- coalesced NCHW output (128 px = one image row) ----
    int b = m0 >> 14;
    int pimg = m0 & (HWSZ - 1);
    float* ob = out + (size_t)b * CH * HWSZ + pimg;
#pragma unroll
    for (int it = 0; it < 16; it++) {
        int c = it * 16 + wid;
#pragma unroll
        for (int u = 0; u < 4; u++)
            ob[(size_t)c * HWSZ + u * 32 + lane] = tr[c * 132 + u * 32 + lane];
    }
}

// =================== stage 0: transpose+split | prep | owprep ===================
__global__ void __launch_bounds__(256)
k_stage0(const float* __restrict__ x,
         const float* __restrict__ cw, const float* __restrict__ w1,
         const float* __restrict__ w2,
         const float* __restrict__ ow0, const float* __restrict__ ow1,
         const float* __restrict__ ow2) {
    int bid = blockIdx.x;
    int tid = threadIdx.x;
    if (bid < 8192) {
        __shared__ float t[32][33];
        int tb = bid;
        int p0 = (tb & 511) * 32;
        int c0 = ((tb >> 9) & 7) * 32;
        int b  = tb >> 12;
        int tx = tid & 31, ty = tid >> 5;
        const float* xb = x + (size_t)b * CH * HWSZ;
#pragma unroll
        for (int i = 0; i < 4; i++)
            t[ty + 8 * i][tx] = xb[(size_t)(c0 + ty + 8 * i) * HWSZ + p0 + tx];
        __syncthreads();
        size_t base = (size_t)b * HWSZ * CH;
#pragma unroll
        for (int i = 0; i < 4; i++) {
            float v = t[tx][ty + 8 * i];
            size_t idx = base + (size_t)(p0 + ty + 8 * i) * CH + c0 + tx;
            g_xT[idx] = v;
            __nv_bfloat16 h, l; split_bf16(v, h, l);
            g_xTh[idx] = h; g_xTl[idx] = l;
        }
    } else if (bid < 8512) {
        int i = (bid - 8192) * 256 + tid;
        if (i >= 81920) return;
        const float* src; int dst;
        if (i < 16384)      { src = cw + i * 4;            dst = i * 4; }
        else if (i < 49152) { src = w1 + (i - 16384) * 4;  dst = 65536 + (i - 16384) * 4; }
        else                { src = w2 + (i - 49152) * 4;  dst = 196608 + (i - 49152) * 4; }
        float4 v = *(const float4*)src;
        __nv_bfloat16 ha, la, hb, lb, hc, lc, hd, ld;
        split_bf16(v.x, ha, la); split_bf16(v.y, hb, lb);
        split_bf16(v.z, hc, lc); split_bf16(v.w, hd, ld);
        ((__nv_bfloat162*)(g_wh + dst))[0] = __nv_bfloat162(ha, hb);
        ((__nv_bfloat162*)(g_wh + dst))[1] = __nv_bfloat162(hc, hd);
        ((__nv_bfloat162*)(g_wl + dst))[0] = __nv_bfloat162(la, lb);
        ((__nv_bfloat162*)(g_wl + dst))[1] = __nv_bfloat162(lc, ld);
    } else {
        int i = (bid - 8512) * 256 + tid;
        if (i >= 3 * 32 * 2304) return;
        int br = i / (32 * 2304);
        int r  = i % (32 * 2304);
        int o  = r / 2304;
        int kk = r % 2304;
        int k  = kk / 256, c = kk % 256;
        const float* w = (br == 0) ? ow0 : (br == 1) ? ow1 : ow2;
        float v = (o < 18) ? w[((size_t)o * 256 + c) * 9 + k] : 0.f;
        __nv_bfloat16 h, l; split_bf16(v, h, l);
        g_owh[i] = h; g_owl[i] = l;
    }
}

// =================== fused deform3: 4 pixels/warp, 2 blocks/SM ===================
__global__ void __launch_bounds__(256, 2)
k_deform3(const float* __restrict__ dw0, const float* __restrict__ dw1,
          const float* __restrict__ dw2,
          const float* __restrict__ lw0, const float* __restrict__ lb0,
          const float* __restrict__ lw1, const float* __restrict__ lb1,
          const float* __restrict__ lw2, const float* __restrict__ lb2,
          const float* __restrict__ n1w, const float* __restrict__ n1b) {
    __shared__ float sdefT[3][9 * CH];
    __shared__ int   sidx[8][4][36];
    __shared__ float swgt[8][4][36];

    int tid = threadIdx.x, wid = tid >> 5, lane = tid & 31;
    {
        const float* dws[3] = {dw0, dw1, dw2};
#pragma unroll
        for (int br = 0; br < 3; br++)
            for (int i = tid; i < 9 * CH; i += 256) {
                int c = i / 9, k = i % 9;
                sdefT[br][k * CH + c] = dws[br][i];
            }
    }
    __syncthreads();

    int pix0 = blockIdx.x * 32 + wid * 4;
    int b = pix0 >> 14;
    int c0 = lane * 8;
    const float* xrow = g_xT + (size_t)b * HWSZ * CH;

    float sum[4][8];
#pragma unroll
    for (int e = 0; e < 4; e++) {
        const float4* ap = (const float4*)(g_acc + (size_t)(pix0 + e) * CH + c0);
        float4 a0 = ap[0], a1 = ap[1];
        sum[e][0] = a0.x; sum[e][1] = a0.y; sum[e][2] = a0.z; sum[e][3] = a0.w;
        sum[e][4] = a1.x; sum[e][5] = a1.y; sum[e][6] = a1.z; sum[e][7] = a1.w;
    }

    const int DS[3] = {1, 9, 12};
    const float* lws[3] = {lw0, lw1, lw2};
    const float* lbs[3] = {lb0, lb1, lb2};

#pragma unroll
    for (int br = 0; br < 3; br++) {
        int D = DS[br];
        for (int t = lane; t < 36; t += 32) {
            int e = t / 9, k = t % 9;
            int pix = pix0 + e;
            int p = pix & (HWSZ - 1);
            int h = p >> 7, w = p & 127;
            int ky = k / 3, kx = k % 3;
            const float* op = g_offp + (size_t)(br * BATCH + b) * 18 * HWSZ;
            float oy = op[(size_t)(2 * k) * HWSZ + p];
            float ox = op[(size_t)(2 * k + 1) * HWSZ + p];
            float py = (float)h + (float)((ky - 1) * D) + oy;
            float px = (float)w + (float)((kx - 1) * D) + ox;
            float y0 = floorf(py), x0 = floorf(px);
#pragma unroll
            for (int dy = 0; dy < 2; dy++)
#pragma unroll
                for (int dx = 0; dx < 2; dx++) {
                    float yc = y0 + dy, xc = x0 + dx;
                    float wq = (1.f - fabsf(py - yc)) * (1.f - fabsf(px - xc));
                    bool valid = (yc >= 0.f) && (yc < 128.f) && (xc >= 0.f) && (xc < 128.f);
                    int iy = min(max((int)yc, 0), 127);
                    int ix = min(max((int)xc, 0), 127);
                    sidx[wid][e][k * 4 + dy * 2 + dx] = iy * WW + ix;
                    swgt[wid][e][k * 4 + dy * 2 + dx] = valid ? wq : 0.f;
                }
        }
        __syncwarp();

        float facc[4][8];
#pragma unroll
        for (int e = 0; e < 4; e++)
#pragma unroll
            for (int r = 0; r < 8; r++) facc[e][r] = 0.f;

#pragma unroll
        for (int k = 0; k < 9; k++) {
            float4 wk0 = *(const float4*)&sdefT[br][k * CH + c0];
            float4 wk1 = *(const float4*)&sdefT[br][k * CH + c0 + 4];
#pragma unroll
            for (int e = 0; e < 4; e++) {
                float s[8];
#pragma unroll
                for (int r = 0; r < 8; r++) s[r] = 0.f;
#pragma unroll
                for (int j = 0; j < 4; j++) {
                    float wq = swgt[wid][e][k * 4 + j];
                    const float4* vp =
                        (const float4*)(xrow + (size_t)sidx[wid][e][k * 4 + j] * CH + c0);
                    float4 v0 = vp[0], v1 = vp[1];
                    s[0] += wq * v0.x; s[1] += wq * v0.y; s[2] += wq * v0.z; s[3] += wq * v0.w;
                    s[4] += wq * v1.x; s[5] += wq * v1.y; s[6] += wq * v1.z; s[7] += wq * v1.w;
                }
                facc[e][0] += wk0.x * s[0]; facc[e][1] += wk0.y * s[1];
                facc[e][2] += wk0.z * s[2]; facc[e][3] += wk0.w * s[3];
                facc[e][4] += wk1.x * s[4]; facc[e][5] += wk1.y * s[5];
                facc[e][6] += wk1.z * s[6]; facc[e][7] += wk1.w * s[7];
            }
        }

        const float4* lwp = (const float4*)(lws[br] + c0);
        const float4* lbp = (const float4*)(lbs[br] + c0);
        float4 lw0v = lwp[0], lw1v = lwp[1], lb0v = lbp[0], lb1v = lbp[1];
        float lw[8] = {lw0v.x, lw0v.y, lw0v.z, lw0v.w, lw1v.x, lw1v.y, lw1v.z, lw1v.w};
        float lb[8] = {lb0v.x, lb0v.y, lb0v.z, lb0v.w, lb1v.x, lb1v.y, lb1v.z, lb1v.w};
#pragma unroll
        for (int e = 0; e < 4; e++) {
            float ls = 0.f, lq = 0.f;
#pragma unroll
            for (int r = 0; r < 8; r++) { ls += facc[e][r]; lq += facc[e][r] * facc[e][r]; }
#pragma unroll
            for (int o = 16; o; o >>= 1) {
                ls += __shfl_xor_sync(0xffffffffu, ls, o);
                lq += __shfl_xor_sync(0xffffffffu, lq, o);
            }
            float mean = ls * (1.f / 256.f);
            float var  = lq * (1.f / 256.f) - mean * mean;
            float rstd = rsqrtf(var + LN_EPS);
#pragma unroll
            for (int r = 0; r < 8; r++)
                sum[e][r] += gelu_f(lw[r] * ((facc[e][r] - mean) * rstd) + lb[r]);
        }
        __syncwarp();
    }

    const float4* wp = (const float4*)(n1w + c0);
    const float4* bp = (const float4*)(n1b + c0);
    float4 w0v = wp[0], w1v = wp[1], b0v = bp[0], b1v = bp[1];
    float gw[8] = {w0v.x, w0v.y, w0v.z, w0v.w, w1v.x, w1v.y, w1v.z, w1v.w};
    float gb[8] = {b0v.x, b0v.y, b0v.z, b0v.w, b1v.x, b1v.y, b1v.z, b1v.w};

#pragma unroll
    for (int e = 0; e < 4; e++) {
        float ls = 0.f, lq = 0.f;
#pragma unroll
        for (int r = 0; r < 8; r++) { ls += sum[e][r]; lq += sum[e][r] * sum[e][r]; }
#pragma unroll
        for (int o = 16; o; o >>= 1) {
            ls += __shfl_xor_sync(0xffffffffu, ls, o);
            lq += __shfl_xor_sync(0xffffffffu, lq, o);
        }
        float mean = ls * (1.f / 256.f);
        float var  = lq * (1.f / 256.f) - mean * mean;
        float rstd = rsqrtf(var + LN_EPS);

        uint32_t hp[4], lp[4];
#pragma unroll
        for (int r = 0; r < 8; r += 2) {
            float oa = gw[r] * ((sum[e][r] - mean) * rstd) + gb[r];
            float ob = gw[r + 1] * ((sum[e][r + 1] - mean) * rstd) + gb[r + 1];
            __nv_bfloat16 h0, l0, h1, l1;
            split_bf16(oa, h0, l0); split_bf16(ob, h1, l1);
            hp[r >> 1] = (uint32_t)__bfloat16_as_ushort(h0) |
                         ((uint32_t)__bfloat16_as_ushort(h1) << 16);
            lp[r >> 1] = (uint32_t)__bfloat16_as_ushort(l0) |
                         ((uint32_t)__bfloat16_as_ushort(l1) << 16);
        }
        *(uint4*)(g_o1h + (size_t)(pix0 + e) * CH + c0) = make_uint4(hp[0], hp[1], hp[2], hp[3]);
        *(uint4*)(g_o1l + (size_t)(pix0 + e) * CH + c0) = make_uint4(lp[0], lp[1], lp[2], lp[3]);
    }
}

// =================== launch ===================
extern "C" void kernel_launch(void* const* d_in, const int* in_sizes, int n_in,
                              void* d_out, int out_size) {
    const float* x       = (const float*)d_in[0];
    const float* off_w1  = (const float*)d_in[1];
    const float* def_w1  = (const float*)d_in[2];
    const float* bw1     = (const float*)d_in[3];
    const float* bb1     = (const float*)d_in[4];
    const float* off_w2  = (const float*)d_in[5];
    const float* def_w2  = (const float*)d_in[6];
    const float* bw2     = (const float*)d_in[7];
    const float* bb2     = (const float*)d_in[8];
    const float* off_w3  = (const float*)d_in[9];
    const float* def_w3  = (const float*)d_in[10];
    const float* bw3     = (const float*)d_in[11];
    const float* bb3     = (const float*)d_in[12];
    const float* conv_w  = (const float*)d_in[13];
    const float* conv_b  = (const float*)d_in[14];
    const float* n1_w    = (const float*)d_in[15];
    const float* n1_b    = (const float*)d_in[16];
    const float* n2_w    = (const float*)d_in[17];
    const float* n2_b    = (const float*)d_in[18];
    const float* mlp_w1  = (const float*)d_in[19];
    const float* mlp_b1  = (const float*)d_in[20];
    const float* mlp_w2  = (const float*)d_in[21];
    const float* mlp_b2  = (const float*)d_in[22];

    float* pacc;
    __nv_bfloat16 *po1h, *po1l, *phh, *phl, *pwh, *pwl, *pxTh, *pxTl;
    cudaGetSymbolAddress((void**)&pacc,  g_acc);
    cudaGetSymbolAddress((void**)&pxTh,  g_xTh);
    cudaGetSymbolAddress((void**)&pxTl,  g_xTl);
    cudaGetSymbolAddress((void**)&po1h,  g_o1h);
    cudaGetSymbolAddress((void**)&po1l,  g_o1l);
    cudaGetSymbolAddress((void**)&phh,   g_hh);
    cudaGetSymbolAddress((void**)&phl,   g_hl);
    cudaGetSymbolAddress((void**)&pwh,   g_wh);
    cudaGetSymbolAddress((void**)&pwl,   g_wl);

    cudaFuncSetAttribute(k_stage1,
                         cudaFuncAttributeMaxDynamicSharedMemorySize, G_SMEM);
    cudaFuncSetAttribute(k_mmagemm<1, false, true>,
                         cudaFuncAttributeMaxDynamicSharedMemorySize, G_SMEM);
    cudaFuncSetAttribute(k_mlp2ln,
                         cudaFuncAttributeMaxDynamicSharedMemorySize, F_SMEM);

    // 1. transpose+split | weight prep | offset-weight reorg (one launch)
    k_stage0<<<9376, 256>>>(x, conv_w, mlp_w1, mlp_w2, off_w1, off_w2, off_w3);
    // 2. conv1x1 GEMM + offset convs, co-scheduled
    k_stage1<<<1280, 256, G_SMEM>>>(pxTh, pxTl, pwh, pwl, conv_b, pacc);
    // 3. fused deform x3 + LN1 + split
    k_deform3<<<PTOT / 32, 256>>>(def_w1, def_w2, def_w3,
                                  bw1, bb1, bw2, bb2, bw3, bb3, n1_w, n1_b);
    // 4. MLP1 (bias+GELU, bf16 hi/lo out)
    k_mmagemm<1, false, true><<<dim3(PTOT / 128, 512 / 128), 256, G_SMEM>>>(
        po1h, po1l, pwh + 65536, pwl + 65536, mlp_b1, nullptr, nullptr,
        nullptr, phh, phl, 512, CH);
    // 5. fused MLP2 + residual + LN2 + NCHW output
    k_mlp2ln<<<PTOT / 128, 512, F_SMEM>>>(
        phh, phl, pwh + 196608, pwl + 196608, mlp_b2, po1h, po1l,
        n2_w, n2_b, (float*)d_out);
}

// round 15
// speedup vs baseline: 2.4270x; 1.1263x over previous
#include <cuda_runtime.h>
#include <cuda_fp16.h>
#include <math.h>
#include <stdint.h>

#define BATCH 2
#define CH    256
#define HH    128
#define WW    128
#define HWSZ  16384
#define PTOT  32768
#define LN_EPS 1e-6f

// ---------------- scratch ----------------
__device__ float g_xT  [(size_t)PTOT * CH];
__device__ float g_acc [(size_t)PTOT * CH];
__device__ float g_offp[(size_t)3 * BATCH * 18 * HWSZ];   // [branch][b][18][HW]
__device__ __half g_xTh[(size_t)PTOT * CH];
__device__ __half g_xTl[(size_t)PTOT * CH];
__device__ __half g_o1h[(size_t)PTOT * CH];
__device__ __half g_o1l[(size_t)PTOT * CH];
__device__ __half g_hh [(size_t)PTOT * 512];
__device__ __half g_hl [(size_t)PTOT * 512];
__device__ __half g_wh[327680];            // fp16 weights: conv(65536)|w1(131072)|w2(131072)
__device__ __half g_owh[3 * 32 * 2304];    // offset-conv weights, fp16

__device__ __forceinline__ float gelu_f(float v) {
    return 0.5f * v * (1.0f + erff(v * 0.70710678118654752440f));
}
__device__ __forceinline__ void split_f16(float v, __half& h, __half& l) {
    h = __float2half_rn(v);
    l = __float2half_rn(v - __half2float(h));
}
__device__ __forceinline__ uint32_t smem_u32(const void* p) {
    uint32_t a;
    asm("{ .reg .u64 t; cvta.to.shared.u64 t, %1; cvt.u32.u64 %0, t; }" : "=r"(a) : "l"(p));
    return a;
}
__device__ __forceinline__ void ldmx4(uint32_t* r, uint32_t addr) {
    asm volatile("ldmatrix.sync.aligned.m8n8.x4.shared.b16 {%0,%1,%2,%3}, [%4];"
                 : "=r"(r[0]), "=r"(r[1]), "=r"(r[2]), "=r"(r[3]) : "r"(addr));
}
__device__ __forceinline__ void mma16816(float* c, const uint32_t* a, const uint32_t* b) {
    asm volatile("mma.sync.aligned.m16n8k16.row.col.f32.f16.f16.f32 "
                 "{%0,%1,%2,%3}, {%4,%5,%6,%7}, {%8,%9}, {%0,%1,%2,%3};"
                 : "+f"(c[0]), "+f"(c[1]), "+f"(c[2]), "+f"(c[3])
                 : "r"(a[0]), "r"(a[1]), "r"(a[2]), "r"(a[3]), "r"(b[0]), "r"(b[1]));
}
__device__ __forceinline__ void cp16(uint32_t dst, const void* src) {
    asm volatile("cp.async.cg.shared.global [%0], [%1], 16;" :: "r"(dst), "l"(src));
}
__device__ __forceinline__ void cp16z(uint32_t dst, const void* src, bool valid) {
    int sz = valid ? 16 : 0;
    asm volatile("cp.async.cg.shared.global [%0], [%1], 16, %2;"
                 :: "r"(dst), "l"(src), "r"(sz));
}
#define CP_COMMIT() asm volatile("cp.async.commit_group;" ::: "memory")
#define CP_WAIT0()  asm volatile("cp.async.wait_group 0;" ::: "memory")

// =================== GEMM body (fp16 2-term, cp.async double-buffered) ===================
// D = Ah*B + Al*B, A = Ah+Al (fp16 hi/lo), B = fp16 weights
#define G_ARR (128 * 40)
#define G_STG (3 * G_ARR)
#define G_SMEM (2 * G_STG * 2)   // 61440 bytes

template <int ACT, bool RES, bool F16OUT>
__device__ __forceinline__ void gemm_body(
        char* dsm_, int mblk, int nblk,
        const __half* __restrict__ Ah, const __half* __restrict__ Al,
        const __half* __restrict__ Bw,
        const float* __restrict__ bias,
        const __half* __restrict__ Resh, const __half* __restrict__ Resl,
        float* __restrict__ Cf, __half* __restrict__ Chi,
        __half* __restrict__ Clo, int N, int K) {
    uint32_t smb = smem_u32(dsm_);

    int tid  = threadIdx.x;
    int wid  = tid >> 5, lane = tid & 31;
    int m0   = mblk * 128, n0 = nblk * 128;
    int wm   = (wid & 3) * 32;
    int wn   = (wid >> 2) * 64;

    float acc[2][8][4];
#pragma unroll
    for (int i = 0; i < 2; i++)
#pragma unroll
        for (int j = 0; j < 8; j++)
#pragma unroll
            for (int q = 0; q < 4; q++) acc[i][j][q] = 0.f;

    const __half* srcs[3] = {Ah + (size_t)m0 * K, Al + (size_t)m0 * K,
                             Bw + (size_t)n0 * K};

    auto load_stage = [&](int kc, int s) {
        uint32_t stgoff = (uint32_t)s * (G_STG * 2);
#pragma unroll
        for (int t = 0; t < 3; t++) {
            const __half* src = srcs[t] + kc * 32;
            uint32_t dstb = smb + stgoff + (uint32_t)t * (G_ARR * 2);
#pragma unroll
            for (int u = 0; u < 2; u++) {
                int idx = u * 256 + tid;
                int row = idx >> 2, ch = idx & 3;
                cp16(dstb + (uint32_t)(row * 40 + ch * 8) * 2,
                     src + (size_t)row * K + ch * 8);
            }
        }
    };

    int a_row8 = ((lane >> 3) & 1) * 8 + (lane & 7);
    int a_col8 = ((lane >> 4) & 1) * 8;
    int b_row8 = ((lane >> 4) & 1) * 8 + (lane & 7);
    int b_col8 = ((lane >> 3) & 1) * 8;

    uint32_t aB[2][2], bB[4];
#pragma unroll
    for (int hl = 0; hl < 2; hl++)
#pragma unroll
        for (int mi = 0; mi < 2; mi++)
            aB[hl][mi] = smb + (uint32_t)(hl * (G_ARR * 2)) +
                         (uint32_t)((wm + mi * 16 + a_row8) * 80 + a_col8 * 2);
#pragma unroll
    for (int jp = 0; jp < 4; jp++)
        bB[jp] = smb + (uint32_t)(2 * (G_ARR * 2)) +
                 (uint32_t)((wn + jp * 16 + b_row8) * 80 + b_col8 * 2);

    load_stage(0, 0); CP_COMMIT();
    CP_WAIT0(); __syncthreads();

    int nk = K >> 5;
    for (int kc = 0; kc < nk; kc++) {
        int cur = kc & 1;
        if (kc + 1 < nk) { load_stage(kc + 1, cur ^ 1); CP_COMMIT(); }

        uint32_t stg = (uint32_t)cur * (G_STG * 2);
#pragma unroll
        for (int ks = 0; ks < 2; ks++) {
            uint32_t so = stg + (uint32_t)(ks * 32);
            uint32_t af[2][2][4];
#pragma unroll
            for (int hl = 0; hl < 2; hl++)
#pragma unroll
                for (int mi = 0; mi < 2; mi++)
                    ldmx4(af[hl][mi], aB[hl][mi] + so);
#pragma unroll
            for (int jp = 0; jp < 4; jp++) {
                uint32_t bf[4];
                ldmx4(bf, bB[jp] + so);
#pragma unroll
                for (int mi = 0; mi < 2; mi++)
#pragma unroll
                    for (int jj = 0; jj < 2; jj++) {
                        int j = jp * 2 + jj;
                        uint32_t b2[2] = {bf[jj * 2], bf[jj * 2 + 1]};
                        mma16816(acc[mi][j], af[0][mi], b2);
                        mma16816(acc[mi][j], af[1][mi], b2);
                    }
            }
        }
        if (kc + 1 < nk) CP_WAIT0();
        __syncthreads();
    }

    int g = lane >> 2, q = lane & 3;
#pragma unroll
    for (int mi = 0; mi < 2; mi++) {
#pragma unroll
        for (int half = 0; half < 2; half++) {
            int m = m0 + wm + mi * 16 + g + half * 8;
#pragma unroll
            for (int j = 0; j < 8; j++) {
                int n = n0 + wn + j * 8 + q * 2;
                float v0 = acc[mi][j][half * 2 + 0] + __ldg(bias + n);
                float v1 = acc[mi][j][half * 2 + 1] + __ldg(bias + n + 1);
                if (ACT == 1) { v0 = gelu_f(v0); v1 = gelu_f(v1); }
                if (RES) {
                    __half2 rh = *(const __half2*)(Resh + (size_t)m * N + n);
                    __half2 rl = *(const __half2*)(Resl + (size_t)m * N + n);
                    v0 += __half2float(rh.x) + __half2float(rl.x);
                    v1 += __half2float(rh.y) + __half2float(rl.y);
                }
                if (F16OUT) {
                    __half h0, l0, h1, l1;
                    split_f16(v0, h0, l0); split_f16(v1, h1, l1);
                    *(__half2*)(Chi + (size_t)m * N + n) = __halves2half2(h0, h1);
                    *(__half2*)(Clo + (size_t)m * N + n) = __halves2half2(l0, l1);
                } else {
                    *(float2*)(Cf + (size_t)m * N + n) = make_float2(v0, v1);
                }
            }
        }
    }
}

// =================== offmma body (fp16 2-term) ===================
#define OFF_A_ARR (128 * 40)
#define OFF_B_ARR (32 * 40)
#define OFF_STG   (2 * OFF_A_ARR + OFF_B_ARR)

__device__ __forceinline__ void offmma_body(char* dsm_, int bx, int br) {
    uint32_t smb = smem_u32(dsm_);

    int tid = threadIdx.x, wid = tid >> 5, lane = tid & 31;
    int h = bx & 127, b = bx >> 7;
    const int D = (br == 0) ? 1 : (br == 1) ? 9 : 12;

    const __half* xh = g_xTh + (size_t)b * HWSZ * CH;
    const __half* xl = g_xTl + (size_t)b * HWSZ * CH;
    const __half* wbh = g_owh + (size_t)br * 32 * 2304;

    float acc[4][4];
#pragma unroll
    for (int j = 0; j < 4; j++)
#pragma unroll
        for (int q = 0; q < 4; q++) acc[j][q] = 0.f;

    auto load_stage = [&](int kc, int s) {
        uint32_t base = smb + (uint32_t)s * (OFF_STG * 2);
        uint32_t sAh = base;
        uint32_t sAl = sAh + OFF_A_ARR * 2;
        uint32_t sBh = sAl + OFF_A_ARR * 2;
        int k  = kc >> 3;
        int cc = (kc & 7) * 32;
        int dy = (k / 3 - 1) * D, dx = (k % 3 - 1) * D;
        int srow = h + dy;
        bool vy = (srow >= 0) && (srow < HH);
        int srowc = vy ? srow : 0;
#pragma unroll
        for (int u = 0; u < 2; u++) {
            int idx = u * 256 + tid;
            int w = idx >> 2, ch = idx & 3;
            int wp = w + dx;
            bool v = vy && (wp >= 0) && (wp < WW);
            int wpc = v ? wp : 0;
            size_t goff = (size_t)(srowc * WW + wpc) * CH + cc + ch * 8;
            uint32_t soff = (uint32_t)(w * 40 + ch * 8) * 2;
            cp16z(sAh + soff, xh + goff, v);
            cp16z(sAl + soff, xl + goff, v);
        }
        if (tid < 128) {
            int o = tid >> 2, ch = tid & 3;
            size_t goff = (size_t)o * 2304 + k * 256 + cc + ch * 8;
            uint32_t soff = (uint32_t)(o * 40 + ch * 8) * 2;
            cp16(sBh + soff, wbh + goff);
        }
    };

    int a_row8 = ((lane >> 3) & 1) * 8 + (lane & 7);
    int a_col8 = ((lane >> 4) & 1) * 8;
    int b_row8 = ((lane >> 4) & 1) * 8 + (lane & 7);
    int b_col8 = ((lane >> 3) & 1) * 8;

    uint32_t aB[2], bB[2];
#pragma unroll
    for (int hl = 0; hl < 2; hl++)
        aB[hl] = smb + (uint32_t)(hl * (OFF_A_ARR * 2)) +
                 (uint32_t)((wid * 16 + a_row8) * 80 + a_col8 * 2);
#pragma unroll
    for (int jp = 0; jp < 2; jp++)
        bB[jp] = smb + (uint32_t)(2 * OFF_A_ARR * 2) +
                 (uint32_t)((jp * 16 + b_row8) * 80 + b_col8 * 2);

    load_stage(0, 0); CP_COMMIT();
    CP_WAIT0(); __syncthreads();

    const int NK = 72;
    for (int kc = 0; kc < NK; kc++) {
        int cur = kc & 1;
        if (kc + 1 < NK) { load_stage(kc + 1, cur ^ 1); CP_COMMIT(); }

        uint32_t stg = (uint32_t)cur * (OFF_STG * 2);
#pragma unroll
        for (int ks = 0; ks < 2; ks++) {
            uint32_t so = stg + (uint32_t)(ks * 32);
            uint32_t af[2][4];
            ldmx4(af[0], aB[0] + so);
            ldmx4(af[1], aB[1] + so);
#pragma unroll
            for (int jp = 0; jp < 2; jp++) {
                uint32_t bf[4];
                ldmx4(bf, bB[jp] + so);
#pragma unroll
                for (int jj = 0; jj < 2; jj++) {
                    int j = jp * 2 + jj;
                    uint32_t b2[2] = {bf[jj * 2], bf[jj * 2 + 1]};
                    mma16816(acc[j], af[0], b2);
                    mma16816(acc[j], af[1], b2);
                }
            }
        }
        if (kc + 1 < NK) CP_WAIT0();
        __syncthreads();
    }

    float* op = g_offp + (size_t)(br * BATCH + b) * 18 * HWSZ;
    int g = lane >> 2, q = lane & 3;
#pragma unroll
    for (int half = 0; half < 2; half++) {
        int wcol = wid * 16 + g + half * 8;
        int pimg = h * WW + wcol;
#pragma unroll
        for (int j = 0; j < 4; j++) {
#pragma unroll
            for (int e = 0; e < 2; e++) {
                int n = j * 8 + q * 2 + e;
                if (n < 18) op[(size_t)n * HWSZ + pimg] = acc[j][half * 2 + e];
            }
        }
    }
}

// =================== stage 1: conv1x1 GEMM (0..511) + offmma (512..1279) ===================
__global__ void __launch_bounds__(256, 2)
k_stage1(const __half* __restrict__ xTh, const __half* __restrict__ xTl,
         const __half* __restrict__ cwh,
         const float* __restrict__ conv_b, float* __restrict__ accp) {
    extern __shared__ char dsm_[];
    int bid = blockIdx.x;
    if (bid < 512) {
        gemm_body<0, false, false>(dsm_, bid & 255, bid >> 8,
                                   xTh, xTl, cwh, conv_b,
                                   nullptr, nullptr, accp, nullptr, nullptr, CH, CH);
    } else {
        int obid = bid - 512;
        offmma_body(dsm_, obid & 255, obid >> 8);
    }
}

// =================== MLP1 GEMM ===================
template <int ACT, bool RES, bool F16OUT>
__global__ void __launch_bounds__(256, 2)
k_mmagemm(const __half* __restrict__ Ah, const __half* __restrict__ Al,
          const __half* __restrict__ Bw,
          const float* __restrict__ bias,
          const __half* __restrict__ Resh, const __half* __restrict__ Resl,
          float* __restrict__ Cf, __half* __restrict__ Chi,
          __half* __restrict__ Clo, int N, int K) {
    extern __shared__ char dsm_[];
    gemm_body<ACT, RES, F16OUT>(dsm_, blockIdx.x, blockIdx.y,
                                Ah, Al, Bw, bias, Resh, Resl, Cf, Chi, Clo, N, K);
}

// =================== fused MLP2 + LN2 + NCHW output (fp16 2-term) ===================
#define F_A_ARR (128 * 40)
#define F_B_ARR (256 * 40)
#define F_STG   (2 * F_A_ARR + F_B_ARR)        // 20480 elems
#define F_SMEM  (256 * 132 * 4)                // 135168 bytes (transpose stage dominates)

__global__ void __launch_bounds__(512, 1)
k_mlp2ln(const __half* __restrict__ Ah, const __half* __restrict__ Al,
         const __half* __restrict__ Bw,
         const float* __restrict__ bias,
         const __half* __restrict__ Resh, const __half* __restrict__ Resl,
         const float* __restrict__ n2w, const float* __restrict__ n2b,
         float* __restrict__ out) {
    extern __shared__ char dsm_[];
    uint32_t smb = smem_u32(dsm_);
    __shared__ float red_s[128][4];
    __shared__ float red_q[128][4];

    const int K = 512, N = 256;
    int tid = threadIdx.x, wid = tid >> 5, lane = tid & 31;
    int m0  = blockIdx.x * 128;
    int wm  = (wid & 3) * 32;
    int wn  = (wid >> 2) * 64;

    float acc[2][8][4];
#pragma unroll
    for (int i = 0; i < 2; i++)
#pragma unroll
        for (int j = 0; j < 8; j++)
#pragma unroll
            for (int q = 0; q < 4; q++) acc[i][j][q] = 0.f;

    const __half* srcA[2] = {Ah + (size_t)m0 * K, Al + (size_t)m0 * K};

    auto load_stage = [&](int kc, int s) {
        uint32_t stgoff = (uint32_t)s * (F_STG * 2);
#pragma unroll
        for (int t = 0; t < 2; t++) {      // A hi/lo: 128 rows, 1 cp16/thread
            const __half* src = srcA[t] + kc * 32;
            uint32_t dstb = smb + stgoff + (uint32_t)t * (F_A_ARR * 2);
            int row = tid >> 2, ch = tid & 3;
            cp16(dstb + (uint32_t)(row * 40 + ch * 8) * 2,
                 src + (size_t)row * K + ch * 8);
        }
        {                                   // B: 256 rows, 2 cp16/thread
            const __half* src = Bw + kc * 32;
            uint32_t dstb = smb + stgoff + (uint32_t)(2 * F_A_ARR * 2);
#pragma unroll
            for (int u = 0; u < 2; u++) {
                int idx = u * 512 + tid;
                int row = idx >> 2, ch = idx & 3;
                cp16(dstb + (uint32_t)(row * 40 + ch * 8) * 2,
                     src + (size_t)row * K + ch * 8);
            }
        }
    };

    int a_row8 = ((lane >> 3) & 1) * 8 + (lane & 7);
    int a_col8 = ((lane >> 4) & 1) * 8;
    int b_row8 = ((lane >> 4) & 1) * 8 + (lane & 7);
    int b_col8 = ((lane >> 3) & 1) * 8;

    uint32_t aB[2][2], bB[4];
#pragma unroll
    for (int hl = 0; hl < 2; hl++)
#pragma unroll
        for (int mi = 0; mi < 2; mi++)
            aB[hl][mi] = smb + (uint32_t)(hl * (F_A_ARR * 2)) +
                         (uint32_t)((wm + mi * 16 + a_row8) * 80 + a_col8 * 2);
#pragma unroll
    for (int jp = 0; jp < 4; jp++)
        bB[jp] = smb + (uint32_t)(2 * F_A_ARR * 2) +
                 (uint32_t)((wn + jp * 16 + b_row8) * 80 + b_col8 * 2);

    load_stage(0, 0); CP_COMMIT();
    CP_WAIT0(); __syncthreads();

    const int nk = K >> 5;   // 16
    for (int kc = 0; kc < nk; kc++) {
        int cur = kc & 1;
        if (kc + 1 < nk) { load_stage(kc + 1, cur ^ 1); CP_COMMIT(); }

        uint32_t stg = (uint32_t)cur * (F_STG * 2);
#pragma unroll
        for (int ks = 0; ks < 2; ks++) {
            uint32_t so = stg + (uint32_t)(ks * 32);
            uint32_t af[2][2][4];
#pragma unroll
            for (int hl = 0; hl < 2; hl++)
#pragma unroll
                for (int mi = 0; mi < 2; mi++)
                    ldmx4(af[hl][mi], aB[hl][mi] + so);
#pragma unroll
            for (int jp = 0; jp < 4; jp++) {
                uint32_t bf[4];
                ldmx4(bf, bB[jp] + so);
#pragma unroll
                for (int mi = 0; mi < 2; mi++)
#pragma unroll
                    for (int jj = 0; jj < 2; jj++) {
                        int j = jp * 2 + jj;
                        uint32_t b2[2] = {bf[jj * 2], bf[jj * 2 + 1]};
                        mma16816(acc[mi][j], af[0][mi], b2);
                        mma16816(acc[mi][j], af[1][mi], b2);
                    }
            }
        }
        if (kc + 1 < nk) CP_WAIT0();
        __syncthreads();
    }

    // ---- epilogue: bias + residual, LN2 partials ----
    int g = lane >> 2, q = lane & 3;
    float ps[2][2], pq[2][2];
#pragma unroll
    for (int mi = 0; mi < 2; mi++) {
#pragma unroll
        for (int half = 0; half < 2; half++) {
            int m = m0 + wm + mi * 16 + g + half * 8;
            float s = 0.f, q2 = 0.f;
#pragma unroll
            for (int j = 0; j < 8; j++) {
                int n = wn + j * 8 + q * 2;
                __half2 rh = *(const __half2*)(Resh + (size_t)m * N + n);
                __half2 rl = *(const __half2*)(Resl + (size_t)m * N + n);
                float v0 = acc[mi][j][half * 2 + 0] + __ldg(bias + n) +
                           __half2float(rh.x) + __half2float(rl.x);
                float v1 = acc[mi][j][half * 2 + 1] + __ldg(bias + n + 1) +
                           __half2float(rh.y) + __half2float(rl.y);
                acc[mi][j][half * 2 + 0] = v0;
                acc[mi][j][half * 2 + 1] = v1;
                s += v0 + v1;
                q2 += v0 * v0 + v1 * v1;
            }
            s  += __shfl_xor_sync(0xffffffffu, s, 1);
            s  += __shfl_xor_sync(0xffffffffu, s, 2);
            q2 += __shfl_xor_sync(0xffffffffu, q2, 1);
            q2 += __shfl_xor_sync(0xffffffffu, q2, 2);
            ps[mi][half] = s; pq[mi][half] = q2;
        }
    }
    if (q == 0) {
        int wncol = wid >> 2;
#pragma unroll
        for (int mi = 0; mi < 2; mi++)
#pragma unroll
            for (int half = 0; half < 2; half++) {
                int ml = wm + mi * 16 + g + half * 8;
                red_s[ml][wncol] = ps[mi][half];
                red_q[ml][wncol] = pq[mi][half];
            }
    }
    __syncthreads();

    // ---- normalize + stage transpose into (dead) pipeline smem ----
    float* tr = (float*)dsm_;   // [256][132]
#pragma unroll
    for (int mi = 0; mi < 2; mi++) {
#pragma unroll
        for (int half = 0; half < 2; half++) {
            int ml = wm + mi * 16 + g + half * 8;
            float sm = red_s[ml][0] + red_s[ml][1] + red_s[ml][2] + red_s[ml][3];
            float sq = red_q[ml][0] + red_q[ml][1] + red_q[ml][2] + red_q[ml][3];
            float mean = sm * (1.f / 256.f);
            float var  = sq * (1.f / 256.f) - mean * mean;
            float rstd = rsqrtf(var + LN_EPS);
#pragma unroll
            for (int j = 0; j < 8; j++) {
#pragma unroll
                for (int e = 0; e < 2; e++) {
                    int n = wn + j * 8 + q * 2 + e;
                    float v = acc[mi][j][half * 2 + e];
                    tr[n * 132 + ml] = __ldg(n2w + n) * ((v - mean) * rstd) + __ldg(n2b + n);
                }
            }
        }
    }
    __syncthreads();

    // ---- coalesced NCHW output ----
    int b = m0 >> 14;
    int pimg = m0 & (HWSZ - 1);
    float* ob = out + (size_t)b * CH * HWSZ + pimg;
#pragma unroll
    for (int it = 0; it < 16; it++) {
        int c = it * 16 + wid;
#pragma unroll
        for (int u = 0; u < 4; u++)
            ob[(size_t)c * HWSZ + u * 32 + lane] = tr[c * 132 + u * 32 + lane];
    }
}

// =================== stage 0: transpose+split | prep | owprep ===================
__global__ void __launch_bounds__(256)
k_stage0(const float* __restrict__ x,
         const float* __restrict__ cw, const float* __restrict__ w1,
         const float* __restrict__ w2,
         const float* __restrict__ ow0, const float* __restrict__ ow1,
         const float* __restrict__ ow2) {
    int bid = blockIdx.x;
    int tid = threadIdx.x;
    if (bid < 8192) {
        __shared__ float t[32][33];
        int tb = bid;
        int p0 = (tb & 511) * 32;
        int c0 = ((tb >> 9) & 7) * 32;
        int b  = tb >> 12;
        int tx = tid & 31, ty = tid >> 5;
        const float* xb = x + (size_t)b * CH * HWSZ;
#pragma unroll
        for (int i = 0; i < 4; i++)
            t[ty + 8 * i][tx] = xb[(size_t)(c0 + ty + 8 * i) * HWSZ + p0 + tx];
        __syncthreads();
        size_t base = (size_t)b * HWSZ * CH;
#pragma unroll
        for (int i = 0; i < 4; i++) {
            float v = t[tx][ty + 8 * i];
            size_t idx = base + (size_t)(p0 + ty + 8 * i) * CH + c0 + tx;
            g_xT[idx] = v;
            __half h, l; split_f16(v, h, l);
            g_xTh[idx] = h; g_xTl[idx] = l;
        }
    } else if (bid < 8512) {
        int i = (bid - 8192) * 256 + tid;
        if (i >= 81920) return;
        const float* src; int dst;
        if (i < 16384)      { src = cw + i * 4;            dst = i * 4; }
        else if (i < 49152) { src = w1 + (i - 16384) * 4;  dst = 65536 + (i - 16384) * 4; }
        else                { src = w2 + (i - 49152) * 4;  dst = 196608 + (i - 49152) * 4; }
        float4 v = *(const float4*)src;
        ((__half2*)(g_wh + dst))[0] = __floats2half2_rn(v.x, v.y);
        ((__half2*)(g_wh + dst))[1] = __floats2half2_rn(v.z, v.w);
    } else {
        int i = (bid - 8512) * 256 + tid;
        if (i >= 3 * 32 * 2304) return;
        int br = i / (32 * 2304);
        int r  = i % (32 * 2304);
        int o  = r / 2304;
        int kk = r % 2304;
        int k  = kk / 256, c = kk % 256;
        const float* w = (br == 0) ? ow0 : (br == 1) ? ow1 : ow2;
        float v = (o < 18) ? w[((size_t)o * 256 + c) * 9 + k] : 0.f;
        g_owh[i] = __float2half_rn(v);
    }
}

// =================== fused deform3: 4 pixels/warp, 2 blocks/SM ===================
__global__ void __launch_bounds__(256, 2)
k_deform3(const float* __restrict__ dw0, const float* __restrict__ dw1,
          const float* __restrict__ dw2,
          const float* __restrict__ lw0, const float* __restrict__ lb0,
          const float* __restrict__ lw1, const float* __restrict__ lb1,
          const float* __restrict__ lw2, const float* __restrict__ lb2,
          const float* __restrict__ n1w, const float* __restrict__ n1b) {
    __shared__ float sdefT[3][9 * CH];
    __shared__ int   sidx[8][4][36];
    __shared__ float swgt[8][4][36];

    int tid = threadIdx.x, wid = tid >> 5, lane = tid & 31;
    {
        const float* dws[3] = {dw0, dw1, dw2};
#pragma unroll
        for (int br = 0; br < 3; br++)
            for (int i = tid; i < 9 * CH; i += 256) {
                int c = i / 9, k = i % 9;
                sdefT[br][k * CH + c] = dws[br][i];
            }
    }
    __syncthreads();

    int pix0 = blockIdx.x * 32 + wid * 4;
    int b = pix0 >> 14;
    int c0 = lane * 8;
    const float* xrow = g_xT + (size_t)b * HWSZ * CH;

    float sum[4][8];
#pragma unroll
    for (int e = 0; e < 4; e++) {
        const float4* ap = (const float4*)(g_acc + (size_t)(pix0 + e) * CH + c0);
        float4 a0 = ap[0], a1 = ap[1];
        sum[e][0] = a0.x; sum[e][1] = a0.y; sum[e][2] = a0.z; sum[e][3] = a0.w;
        sum[e][4] = a1.x; sum[e][5] = a1.y; sum[e][6] = a1.z; sum[e][7] = a1.w;
    }

    const int DS[3] = {1, 9, 12};
    const float* lws[3] = {lw0, lw1, lw2};
    const float* lbs[3] = {lb0, lb1, lb2};

#pragma unroll
    for (int br = 0; br < 3; br++) {
        int D = DS[br];
        for (int t = lane; t < 36; t += 32) {
            int e = t / 9, k = t % 9;
            int pix = pix0 + e;
            int p = pix & (HWSZ - 1);
            int h = p >> 7, w = p & 127;
            int ky = k / 3, kx = k % 3;
            const float* op = g_offp + (size_t)(br * BATCH + b) * 18 * HWSZ;
            float oy = op[(size_t)(2 * k) * HWSZ + p];
            float ox = op[(size_t)(2 * k + 1) * HWSZ + p];
            float py = (float)h + (float)((ky - 1) * D) + oy;
            float px = (float)w + (float)((kx - 1) * D) + ox;
            float y0 = floorf(py), x0 = floorf(px);
#pragma unroll
            for (int dy = 0; dy < 2; dy++)
#pragma unroll
                for (int dx = 0; dx < 2; dx++) {
                    float yc = y0 + dy, xc = x0 + dx;
                    float wq = (1.f - fabsf(py - yc)) * (1.f - fabsf(px - xc));
                    bool valid = (yc >= 0.f) && (yc < 128.f) && (xc >= 0.f) && (xc < 128.f);
                    int iy = min(max((int)yc, 0), 127);
                    int ix = min(max((int)xc, 0), 127);
                    sidx[wid][e][k * 4 + dy * 2 + dx] = iy * WW + ix;
                    swgt[wid][e][k * 4 + dy * 2 + dx] = valid ? wq : 0.f;
                }
        }
        __syncwarp();

        float facc[4][8];
#pragma unroll
        for (int e = 0; e < 4; e++)
#pragma unroll
            for (int r = 0; r < 8; r++) facc[e][r] = 0.f;

#pragma unroll
        for (int k = 0; k < 9; k++) {
            float4 wk0 = *(const float4*)&sdefT[br][k * CH + c0];
            float4 wk1 = *(const float4*)&sdefT[br][k * CH + c0 + 4];
#pragma unroll
            for (int e = 0; e < 4; e++) {
                float s[8];
#pragma unroll
                for (int r = 0; r < 8; r++) s[r] = 0.f;
#pragma unroll
                for (int j = 0; j < 4; j++) {
                    float wq = swgt[wid][e][k * 4 + j];
                    const float4* vp =
                        (const float4*)(xrow + (size_t)sidx[wid][e][k * 4 + j] * CH + c0);
                    float4 v0 = vp[0], v1 = vp[1];
                    s[0] += wq * v0.x; s[1] += wq * v0.y; s[2] += wq * v0.z; s[3] += wq * v0.w;
                    s[4] += wq * v1.x; s[5] += wq * v1.y; s[6] += wq * v1.z; s[7] += wq * v1.w;
                }
                facc[e][0] += wk0.x * s[0]; facc[e][1] += wk0.y * s[1];
                facc[e][2] += wk0.z * s[2]; facc[e][3] += wk0.w * s[3];
                facc[e][4] += wk1.x * s[4]; facc[e][5] += wk1.y * s[5];
                facc[e][6] += wk1.z * s[6]; facc[e][7] += wk1.w * s[7];
            }
        }

        const float4* lwp = (const float4*)(lws[br] + c0);
        const float4* lbp = (const float4*)(lbs[br] + c0);
        float4 lw0v = lwp[0], lw1v = lwp[1], lb0v = lbp[0], lb1v = lbp[1];
        float lw[8] = {lw0v.x, lw0v.y, lw0v.z, lw0v.w, lw1v.x, lw1v.y, lw1v.z, lw1v.w};
        float lb[8] = {lb0v.x, lb0v.y, lb0v.z, lb0v.w, lb1v.x, lb1v.y, lb1v.z, lb1v.w};
#pragma unroll
        for (int e = 0; e < 4; e++) {
            float ls = 0.f, lq = 0.f;
#pragma unroll
            for (int r = 0; r < 8; r++) { ls += facc[e][r]; lq += facc[e][r] * facc[e][r]; }
#pragma unroll
            for (int o = 16; o; o >>= 1) {
                ls += __shfl_xor_sync(0xffffffffu, ls, o);
                lq += __shfl_xor_sync(0xffffffffu, lq, o);
            }
            float mean = ls * (1.f / 256.f);
            float var  = lq * (1.f / 256.f) - mean * mean;
            float rstd = rsqrtf(var + LN_EPS);
#pragma unroll
            for (int r = 0; r < 8; r++)
                sum[e][r] += gelu_f(lw[r] * ((facc[e][r] - mean) * rstd) + lb[r]);
        }
        __syncwarp();
    }

    const float4* wp = (const float4*)(n1w + c0);
    const float4* bp = (const float4*)(n1b + c0);
    float4 w0v = wp[0], w1v = wp[1], b0v = bp[0], b1v = bp[1];
    float gw[8] = {w0v.x, w0v.y, w0v.z, w0v.w, w1v.x, w1v.y, w1v.z, w1v.w};
    float gb[8] = {b0v.x, b0v.y, b0v.z, b0v.w, b1v.x, b1v.y, b1v.z, b1v.w};

#pragma unroll
    for (int e = 0; e < 4; e++) {
        float ls = 0.f, lq = 0.f;
#pragma unroll
        for (int r = 0; r < 8; r++) { ls += sum[e][r]; lq += sum[e][r] * sum[e][r]; }
#pragma unroll
        for (int o = 16; o; o >>= 1) {
            ls += __shfl_xor_sync(0xffffffffu, ls, o);
            lq += __shfl_xor_sync(0xffffffffu, lq, o);
        }
        float mean = ls * (1.f / 256.f);
        float var  = lq * (1.f / 256.f) - mean * mean;
        float rstd = rsqrtf(var + LN_EPS);

        uint32_t hp[4], lp[4];
#pragma unroll
        for (int r = 0; r < 8; r += 2) {
            float oa = gw[r] * ((sum[e][r] - mean) * rstd) + gb[r];
            float ob = gw[r + 1] * ((sum[e][r + 1] - mean) * rstd) + gb[r + 1];
            __half h0, l0, h1, l1;
            split_f16(oa, h0, l0); split_f16(ob, h1, l1);
            hp[r >> 1] = (uint32_t)__half_as_ushort(h0) |
                         ((uint32_t)__half_as_ushort(h1) << 16);
            lp[r >> 1] = (uint32_t)__half_as_ushort(l0) |
                         ((uint32_t)__half_as_ushort(l1) << 16);
        }
        *(uint4*)(g_o1h + (size_t)(pix0 + e) * CH + c0) = make_uint4(hp[0], hp[1], hp[2], hp[3]);
        *(uint4*)(g_o1l + (size_t)(pix0 + e) * CH + c0) = make_uint4(lp[0], lp[1], lp[2], lp[3]);
    }
}

// =================== launch ===================
extern "C" void kernel_launch(void* const* d_in, const int* in_sizes, int n_in,
                              void* d_out, int out_size) {
    const float* x       = (const float*)d_in[0];
    const float* off_w1  = (const float*)d_in[1];
    const float* def_w1  = (const float*)d_in[2];
    const float* bw1     = (const float*)d_in[3];
    const float* bb1     = (const float*)d_in[4];
    const float* off_w2  = (const float*)d_in[5];
    const float* def_w2  = (const float*)d_in[6];
    const float* bw2     = (const float*)d_in[7];
    const float* bb2     = (const float*)d_in[8];
    const float* off_w3  = (const float*)d_in[9];
    const float* def_w3  = (const float*)d_in[10];
    const float* bw3     = (const float*)d_in[11];
    const float* bb3     = (const float*)d_in[12];
    const float* conv_w  = (const float*)d_in[13];
    const float* conv_b  = (const float*)d_in[14];
    const float* n1_w    = (const float*)d_in[15];
    const float* n1_b    = (const float*)d_in[16];
    const float* n2_w    = (const float*)d_in[17];
    const float* n2_b    = (const float*)d_in[18];
    const float* mlp_w1  = (const float*)d_in[19];
    const float* mlp_b1  = (const float*)d_in[20];
    const float* mlp_w2  = (const float*)d_in[21];
    const float* mlp_b2  = (const float*)d_in[22];

    float* pacc;
    __half *po1h, *po1l, *phh, *phl, *pwh, *pxTh, *pxTl;
    cudaGetSymbolAddress((void**)&pacc,  g_acc);
    cudaGetSymbolAddress((void**)&pxTh,  g_xTh);
    cudaGetSymbolAddress((void**)&pxTl,  g_xTl);
    cudaGetSymbolAddress((void**)&po1h,  g_o1h);
    cudaGetSymbolAddress((void**)&po1l,  g_o1l);
    cudaGetSymbolAddress((void**)&phh,   g_hh);
    cudaGetSymbolAddress((void**)&phl,   g_hl);
    cudaGetSymbolAddress((void**)&pwh,   g_wh);

    cudaFuncSetAttribute(k_stage1,
                         cudaFuncAttributeMaxDynamicSharedMemorySize, G_SMEM);
    cudaFuncSetAttribute(k_mmagemm<1, false, true>,
                         cudaFuncAttributeMaxDynamicSharedMemorySize, G_SMEM);
    cudaFuncSetAttribute(k_mlp2ln,
                         cudaFuncAttributeMaxDynamicSharedMemorySize, F_SMEM);

    // 1. transpose+split | weight prep | offset-weight reorg (one launch)
    k_stage0<<<9376, 256>>>(x, conv_w, mlp_w1, mlp_w2, off_w1, off_w2, off_w3);
    // 2. conv1x1 GEMM + offset convs, co-scheduled
    k_stage1<<<1280, 256, G_SMEM>>>(pxTh, pxTl, pwh, conv_b, pacc);
    // 3. fused deform x3 + LN1 + split
    k_deform3<<<PTOT / 32, 256>>>(def_w1, def_w2, def_w3,
                                  bw1, bb1, bw2, bb2, bw3, bb3, n1_w, n1_b);
    // 4. MLP1 (bias+GELU, fp16 hi/lo out)
    k_mmagemm<1, false, true><<<dim3(PTOT / 128, 512 / 128), 256, G_SMEM>>>(
        po1h, po1l, pwh + 65536, mlp_b1, nullptr, nullptr,
        nullptr, phh, phl, 512, CH);
    // 5. fused MLP2 + residual + LN2 + NCHW output
    k_mlp2ln<<<PTOT / 128, 512, F_SMEM>>>(
        phh, phl, pwh + 196608, mlp_b2, po1h, po1l,
        n2_w, n2_b, (float*)d_out);
}

// round 16
// speedup vs baseline: 2.4306x; 1.0015x over previous
#include <cuda_runtime.h>
#include <cuda_fp16.h>
#include <math.h>
#include <stdint.h>

#define BATCH 2
#define CH    256
#define HH    128
#define WW    128
#define HWSZ  16384
#define PTOT  32768
#define LN_EPS 1e-6f

// ---------------- scratch ----------------
__device__ float g_xT  [(size_t)PTOT * CH];
__device__ float g_acc [(size_t)PTOT * CH];
__device__ float g_offp[(size_t)3 * BATCH * 18 * HWSZ];   // [branch][b][18][HW]
__device__ __half g_xTh[(size_t)PTOT * CH];
__device__ __half g_xTl[(size_t)PTOT * CH];
__device__ __half g_o1h[(size_t)PTOT * CH];
__device__ __half g_o1l[(size_t)PTOT * CH];
__device__ __half g_hh [(size_t)PTOT * 512];
__device__ __half g_hl [(size_t)PTOT * 512];
__device__ __half g_wh[327680];            // fp16 weights: conv(65536)|w1(131072)|w2(131072)
__device__ __half g_owh[3 * 32 * 2304];    // offset-conv weights, fp16

__device__ __forceinline__ float gelu_f(float v) {
    return 0.5f * v * (1.0f + erff(v * 0.70710678118654752440f));
}
__device__ __forceinline__ void split_f16(float v, __half& h, __half& l) {
    h = __float2half_rn(v);
    l = __float2half_rn(v - __half2float(h));
}
__device__ __forceinline__ uint32_t smem_u32(const void* p) {
    uint32_t a;
    asm("{ .reg .u64 t; cvta.to.shared.u64 t, %1; cvt.u32.u64 %0, t; }" : "=r"(a) : "l"(p));
    return a;
}
__device__ __forceinline__ void ldmx4(uint32_t* r, uint32_t addr) {
    asm volatile("ldmatrix.sync.aligned.m8n8.x4.shared.b16 {%0,%1,%2,%3}, [%4];"
                 : "=r"(r[0]), "=r"(r[1]), "=r"(r[2]), "=r"(r[3]) : "r"(addr));
}
__device__ __forceinline__ void mma16816(float* c, const uint32_t* a, const uint32_t* b) {
    asm volatile("mma.sync.aligned.m16n8k16.row.col.f32.f16.f16.f32 "
                 "{%0,%1,%2,%3}, {%4,%5,%6,%7}, {%8,%9}, {%0,%1,%2,%3};"
                 : "+f"(c[0]), "+f"(c[1]), "+f"(c[2]), "+f"(c[3])
                 : "r"(a[0]), "r"(a[1]), "r"(a[2]), "r"(a[3]), "r"(b[0]), "r"(b[1]));
}
__device__ __forceinline__ void cp16(uint32_t dst, const void* src) {
    asm volatile("cp.async.cg.shared.global [%0], [%1], 16;" :: "r"(dst), "l"(src));
}
__device__ __forceinline__ void cp16z(uint32_t dst, const void* src, bool valid) {
    int sz = valid ? 16 : 0;
    asm volatile("cp.async.cg.shared.global [%0], [%1], 16, %2;"
                 :: "r"(dst), "l"(src), "r"(sz));
}
#define CP_COMMIT() asm volatile("cp.async.commit_group;" ::: "memory")
#define CP_WAIT0()  asm volatile("cp.async.wait_group 0;" ::: "memory")

// =================== GEMM body (fp16 2-term, cp.async double-buffered) ===================
#define G_ARR (128 * 40)
#define G_STG (3 * G_ARR)
#define G_SMEM (2 * G_STG * 2)   // 61440 bytes

template <int ACT, bool RES, bool F16OUT>
__device__ __forceinline__ void gemm_body(
        char* dsm_, int mblk, int nblk,
        const __half* __restrict__ Ah, const __half* __restrict__ Al,
        const __half* __restrict__ Bw,
        const float* __restrict__ bias,
        const __half* __restrict__ Resh, const __half* __restrict__ Resl,
        float* __restrict__ Cf, __half* __restrict__ Chi,
        __half* __restrict__ Clo, int N, int K) {
    uint32_t smb = smem_u32(dsm_);

    int tid  = threadIdx.x;
    int wid  = tid >> 5, lane = tid & 31;
    int m0   = mblk * 128, n0 = nblk * 128;
    int wm   = (wid & 3) * 32;
    int wn   = (wid >> 2) * 64;

    float acc[2][8][4];
#pragma unroll
    for (int i = 0; i < 2; i++)
#pragma unroll
        for (int j = 0; j < 8; j++)
#pragma unroll
            for (int q = 0; q < 4; q++) acc[i][j][q] = 0.f;

    const __half* srcs[3] = {Ah + (size_t)m0 * K, Al + (size_t)m0 * K,
                             Bw + (size_t)n0 * K};

    auto load_stage = [&](int kc, int s) {
        uint32_t stgoff = (uint32_t)s * (G_STG * 2);
#pragma unroll
        for (int t = 0; t < 3; t++) {
            const __half* src = srcs[t] + kc * 32;
            uint32_t dstb = smb + stgoff + (uint32_t)t * (G_ARR * 2);
#pragma unroll
            for (int u = 0; u < 2; u++) {
                int idx = u * 256 + tid;
                int row = idx >> 2, ch = idx & 3;
                cp16(dstb + (uint32_t)(row * 40 + ch * 8) * 2,
                     src + (size_t)row * K + ch * 8);
            }
        }
    };

    int a_row8 = ((lane >> 3) & 1) * 8 + (lane & 7);
    int a_col8 = ((lane >> 4) & 1) * 8;
    int b_row8 = ((lane >> 4) & 1) * 8 + (lane & 7);
    int b_col8 = ((lane >> 3) & 1) * 8;

    uint32_t aB[2][2], bB[4];
#pragma unroll
    for (int hl = 0; hl < 2; hl++)
#pragma unroll
        for (int mi = 0; mi < 2; mi++)
            aB[hl][mi] = smb + (uint32_t)(hl * (G_ARR * 2)) +
                         (uint32_t)((wm + mi * 16 + a_row8) * 80 + a_col8 * 2);
#pragma unroll
    for (int jp = 0; jp < 4; jp++)
        bB[jp] = smb + (uint32_t)(2 * (G_ARR * 2)) +
                 (uint32_t)((wn + jp * 16 + b_row8) * 80 + b_col8 * 2);

    load_stage(0, 0); CP_COMMIT();
    CP_WAIT0(); __syncthreads();

    int nk = K >> 5;
    for (int kc = 0; kc < nk; kc++) {
        int cur = kc & 1;
        if (kc + 1 < nk) { load_stage(kc + 1, cur ^ 1); CP_COMMIT(); }

        uint32_t stg = (uint32_t)cur * (G_STG * 2);
#pragma unroll
        for (int ks = 0; ks < 2; ks++) {
            uint32_t so = stg + (uint32_t)(ks * 32);
            uint32_t af[2][2][4];
#pragma unroll
            for (int hl = 0; hl < 2; hl++)
#pragma unroll
                for (int mi = 0; mi < 2; mi++)
                    ldmx4(af[hl][mi], aB[hl][mi] + so);
#pragma unroll
            for (int jp = 0; jp < 4; jp++) {
                uint32_t bf[4];
                ldmx4(bf, bB[jp] + so);
#pragma unroll
                for (int mi = 0; mi < 2; mi++)
#pragma unroll
                    for (int jj = 0; jj < 2; jj++) {
                        int j = jp * 2 + jj;
                        uint32_t b2[2] = {bf[jj * 2], bf[jj * 2 + 1]};
                        mma16816(acc[mi][j], af[0][mi], b2);
                        mma16816(acc[mi][j], af[1][mi], b2);
                    }
            }
        }
        if (kc + 1 < nk) CP_WAIT0();
        __syncthreads();
    }

    int g = lane >> 2, q = lane & 3;
#pragma unroll
    for (int mi = 0; mi < 2; mi++) {
#pragma unroll
        for (int half = 0; half < 2; half++) {
            int m = m0 + wm + mi * 16 + g + half * 8;
#pragma unroll
            for (int j = 0; j < 8; j++) {
                int n = n0 + wn + j * 8 + q * 2;
                float v0 = acc[mi][j][half * 2 + 0] + __ldg(bias + n);
                float v1 = acc[mi][j][half * 2 + 1] + __ldg(bias + n + 1);
                if (ACT == 1) { v0 = gelu_f(v0); v1 = gelu_f(v1); }
                if (RES) {
                    __half2 rh = *(const __half2*)(Resh + (size_t)m * N + n);
                    __half2 rl = *(const __half2*)(Resl + (size_t)m * N + n);
                    v0 += __half2float(rh.x) + __half2float(rl.x);
                    v1 += __half2float(rh.y) + __half2float(rl.y);
                }
                if (F16OUT) {
                    __half h0, l0, h1, l1;
                    split_f16(v0, h0, l0); split_f16(v1, h1, l1);
                    *(__half2*)(Chi + (size_t)m * N + n) = __halves2half2(h0, h1);
                    *(__half2*)(Clo + (size_t)m * N + n) = __halves2half2(l0, l1);
                } else {
                    *(float2*)(Cf + (size_t)m * N + n) = make_float2(v0, v1);
                }
            }
        }
    }
}

// =================== offmma body (fp16 2-term) ===================
#define OFF_A_ARR (128 * 40)
#define OFF_B_ARR (32 * 40)
#define OFF_STG   (2 * OFF_A_ARR + OFF_B_ARR)

__device__ __forceinline__ void offmma_body(char* dsm_, int bx, int br) {
    uint32_t smb = smem_u32(dsm_);

    int tid = threadIdx.x, wid = tid >> 5, lane = tid & 31;
    int h = bx & 127, b = bx >> 7;
    const int D = (br == 0) ? 1 : (br == 1) ? 9 : 12;

    const __half* xh = g_xTh + (size_t)b * HWSZ * CH;
    const __half* xl = g_xTl + (size_t)b * HWSZ * CH;
    const __half* wbh = g_owh + (size_t)br * 32 * 2304;

    float acc[4][4];
#pragma unroll
    for (int j = 0; j < 4; j++)
#pragma unroll
        for (int q = 0; q < 4; q++) acc[j][q] = 0.f;

    auto load_stage = [&](int kc, int s) {
        uint32_t base = smb + (uint32_t)s * (OFF_STG * 2);
        uint32_t sAh = base;
        uint32_t sAl = sAh + OFF_A_ARR * 2;
        uint32_t sBh = sAl + OFF_A_ARR * 2;
        int k  = kc >> 3;
        int cc = (kc & 7) * 32;
        int dy = (k / 3 - 1) * D, dx = (k % 3 - 1) * D;
        int srow = h + dy;
        bool vy = (srow >= 0) && (srow < HH);
        int srowc = vy ? srow : 0;
#pragma unroll
        for (int u = 0; u < 2; u++) {
            int idx = u * 256 + tid;
            int w = idx >> 2, ch = idx & 3;
            int wp = w + dx;
            bool v = vy && (wp >= 0) && (wp < WW);
            int wpc = v ? wp : 0;
            size_t goff = (size_t)(srowc * WW + wpc) * CH + cc + ch * 8;
            uint32_t soff = (uint32_t)(w * 40 + ch * 8) * 2;
            cp16z(sAh + soff, xh + goff, v);
            cp16z(sAl + soff, xl + goff, v);
        }
        if (tid < 128) {
            int o = tid >> 2, ch = tid & 3;
            size_t goff = (size_t)o * 2304 + k * 256 + cc + ch * 8;
            uint32_t soff = (uint32_t)(o * 40 + ch * 8) * 2;
            cp16(sBh + soff, wbh + goff);
        }
    };

    int a_row8 = ((lane >> 3) & 1) * 8 + (lane & 7);
    int a_col8 = ((lane >> 4) & 1) * 8;
    int b_row8 = ((lane >> 4) & 1) * 8 + (lane & 7);
    int b_col8 = ((lane >> 3) & 1) * 8;

    uint32_t aB[2], bB[2];
#pragma unroll
    for (int hl = 0; hl < 2; hl++)
        aB[hl] = smb + (uint32_t)(hl * (OFF_A_ARR * 2)) +
                 (uint32_t)((wid * 16 + a_row8) * 80 + a_col8 * 2);
#pragma unroll
    for (int jp = 0; jp < 2; jp++)
        bB[jp] = smb + (uint32_t)(2 * OFF_A_ARR * 2) +
                 (uint32_t)((jp * 16 + b_row8) * 80 + b_col8 * 2);

    load_stage(0, 0); CP_COMMIT();
    CP_WAIT0(); __syncthreads();

    const int NK = 72;
    for (int kc = 0; kc < NK; kc++) {
        int cur = kc & 1;
        if (kc + 1 < NK) { load_stage(kc + 1, cur ^ 1); CP_COMMIT(); }

        uint32_t stg = (uint32_t)cur * (OFF_STG * 2);
#pragma unroll
        for (int ks = 0; ks < 2; ks++) {
            uint32_t so = stg + (uint32_t)(ks * 32);
            uint32_t af[2][4];
            ldmx4(af[0], aB[0] + so);
            ldmx4(af[1], aB[1] + so);
#pragma unroll
            for (int jp = 0; jp < 2; jp++) {
                uint32_t bf[4];
                ldmx4(bf, bB[jp] + so);
#pragma unroll
                for (int jj = 0; jj < 2; jj++) {
                    int j = jp * 2 + jj;
                    uint32_t b2[2] = {bf[jj * 2], bf[jj * 2 + 1]};
                    mma16816(acc[j], af[0], b2);
                    mma16816(acc[j], af[1], b2);
                }
            }
        }
        if (kc + 1 < NK) CP_WAIT0();
        __syncthreads();
    }

    float* op = g_offp + (size_t)(br * BATCH + b) * 18 * HWSZ;
    int g = lane >> 2, q = lane & 3;
#pragma unroll
    for (int half = 0; half < 2; half++) {
        int wcol = wid * 16 + g + half * 8;
        int pimg = h * WW + wcol;
#pragma unroll
        for (int j = 0; j < 4; j++) {
#pragma unroll
            for (int e = 0; e < 2; e++) {
                int n = j * 8 + q * 2 + e;
                if (n < 18) op[(size_t)n * HWSZ + pimg] = acc[j][half * 2 + e];
            }
        }
    }
}

// =================== stage 1: conv1x1 GEMM (0..511) + offmma (512..1279) ===================
__global__ void __launch_bounds__(256, 2)
k_stage1(const __half* __restrict__ xTh, const __half* __restrict__ xTl,
         const __half* __restrict__ cwh,
         const float* __restrict__ conv_b, float* __restrict__ accp) {
    extern __shared__ char dsm_[];
    int bid = blockIdx.x;
    if (bid < 512) {
        gemm_body<0, false, false>(dsm_, bid & 255, bid >> 8,
                                   xTh, xTl, cwh, conv_b,
                                   nullptr, nullptr, accp, nullptr, nullptr, CH, CH);
    } else {
        int obid = bid - 512;
        offmma_body(dsm_, obid & 255, obid >> 8);
    }
}

// =================== MLP1 GEMM ===================
template <int ACT, bool RES, bool F16OUT>
__global__ void __launch_bounds__(256, 2)
k_mmagemm(const __half* __restrict__ Ah, const __half* __restrict__ Al,
          const __half* __restrict__ Bw,
          const float* __restrict__ bias,
          const __half* __restrict__ Resh, const __half* __restrict__ Resl,
          float* __restrict__ Cf, __half* __restrict__ Chi,
          __half* __restrict__ Clo, int N, int K) {
    extern __shared__ char dsm_[];
    gemm_body<ACT, RES, F16OUT>(dsm_, blockIdx.x, blockIdx.y,
                                Ah, Al, Bw, bias, Resh, Resl, Cf, Chi, Clo, N, K);
}

// =================== fused MLP2 + LN2 + NCHW output (fp16 2-term, 64px blocks, 2/SM) ===================
#define F_A_ARR (64 * 40)
#define F_B_ARR (256 * 40)
#define F_STG   (2 * F_A_ARR + F_B_ARR)        // 15360 elems
#define F_PIPE  (2 * F_STG * 2)                // 61440 bytes
#define F_SMEM  (256 * 68 * 4)                 // 69632 bytes (transpose stage dominates)

__global__ void __launch_bounds__(256, 2)
k_mlp2ln(const __half* __restrict__ Ah, const __half* __restrict__ Al,
         const __half* __restrict__ Bw,
         const float* __restrict__ bias,
         const __half* __restrict__ Resh, const __half* __restrict__ Resl,
         const float* __restrict__ n2w, const float* __restrict__ n2b,
         float* __restrict__ out) {
    extern __shared__ char dsm_[];
    uint32_t smb = smem_u32(dsm_);
    __shared__ float red_s[64][4];
    __shared__ float red_q[64][4];

    const int K = 512, N = 256;
    int tid = threadIdx.x, wid = tid >> 5, lane = tid & 31;
    int m0  = blockIdx.x * 64;
    int wm  = (wid & 1) * 32;      // 2 M-warps
    int wn  = (wid >> 1) * 64;     // 4 N-warps

    float acc[2][8][4];
#pragma unroll
    for (int i = 0; i < 2; i++)
#pragma unroll
        for (int j = 0; j < 8; j++)
#pragma unroll
            for (int q = 0; q < 4; q++) acc[i][j][q] = 0.f;

    const __half* srcA[2] = {Ah + (size_t)m0 * K, Al + (size_t)m0 * K};

    auto load_stage = [&](int kc, int s) {
        uint32_t stgoff = (uint32_t)s * (F_STG * 2);
#pragma unroll
        for (int t = 0; t < 2; t++) {      // A hi/lo: 64 rows, 1 cp16/thread
            const __half* src = srcA[t] + kc * 32;
            uint32_t dstb = smb + stgoff + (uint32_t)t * (F_A_ARR * 2);
            int row = tid >> 2, ch = tid & 3;
            cp16(dstb + (uint32_t)(row * 40 + ch * 8) * 2,
                 src + (size_t)row * K + ch * 8);
        }
        {                                   // B: 256 rows, 4 cp16/thread
            const __half* src = Bw + kc * 32;
            uint32_t dstb = smb + stgoff + (uint32_t)(2 * F_A_ARR * 2);
#pragma unroll
            for (int u = 0; u < 4; u++) {
                int idx = u * 256 + tid;
                int row = idx >> 2, ch = idx & 3;
                cp16(dstb + (uint32_t)(row * 40 + ch * 8) * 2,
                     src + (size_t)row * K + ch * 8);
            }
        }
    };

    int a_row8 = ((lane >> 3) & 1) * 8 + (lane & 7);
    int a_col8 = ((lane >> 4) & 1) * 8;
    int b_row8 = ((lane >> 4) & 1) * 8 + (lane & 7);
    int b_col8 = ((lane >> 3) & 1) * 8;

    uint32_t aB[2][2], bB[4];
#pragma unroll
    for (int hl = 0; hl < 2; hl++)
#pragma unroll
        for (int mi = 0; mi < 2; mi++)
            aB[hl][mi] = smb + (uint32_t)(hl * (F_A_ARR * 2)) +
                         (uint32_t)((wm + mi * 16 + a_row8) * 80 + a_col8 * 2);
#pragma unroll
    for (int jp = 0; jp < 4; jp++)
        bB[jp] = smb + (uint32_t)(2 * F_A_ARR * 2) +
                 (uint32_t)((wn + jp * 16 + b_row8) * 80 + b_col8 * 2);

    load_stage(0, 0); CP_COMMIT();
    CP_WAIT0(); __syncthreads();

    const int nk = K >> 5;   // 16
    for (int kc = 0; kc < nk; kc++) {
        int cur = kc & 1;
        if (kc + 1 < nk) { load_stage(kc + 1, cur ^ 1); CP_COMMIT(); }

        uint32_t stg = (uint32_t)cur * (F_STG * 2);
#pragma unroll
        for (int ks = 0; ks < 2; ks++) {
            uint32_t so = stg + (uint32_t)(ks * 32);
            uint32_t af[2][2][4];
#pragma unroll
            for (int hl = 0; hl < 2; hl++)
#pragma unroll
                for (int mi = 0; mi < 2; mi++)
                    ldmx4(af[hl][mi], aB[hl][mi] + so);
#pragma unroll
            for (int jp = 0; jp < 4; jp++) {
                uint32_t bf[4];
                ldmx4(bf, bB[jp] + so);
#pragma unroll
                for (int mi = 0; mi < 2; mi++)
#pragma unroll
                    for (int jj = 0; jj < 2; jj++) {
                        int j = jp * 2 + jj;
                        uint32_t b2[2] = {bf[jj * 2], bf[jj * 2 + 1]};
                        mma16816(acc[mi][j], af[0][mi], b2);
                        mma16816(acc[mi][j], af[1][mi], b2);
                    }
            }
        }
        if (kc + 1 < nk) CP_WAIT0();
        __syncthreads();
    }

    // ---- epilogue: bias + residual, LN2 partials ----
    int g = lane >> 2, q = lane & 3;
    float ps[2][2], pq[2][2];
#pragma unroll
    for (int mi = 0; mi < 2; mi++) {
#pragma unroll
        for (int half = 0; half < 2; half++) {
            int m = m0 + wm + mi * 16 + g + half * 8;
            float s = 0.f, q2 = 0.f;
#pragma unroll
            for (int j = 0; j < 8; j++) {
                int n = wn + j * 8 + q * 2;
                __half2 rh = *(const __half2*)(Resh + (size_t)m * N + n);
                __half2 rl = *(const __half2*)(Resl + (size_t)m * N + n);
                float v0 = acc[mi][j][half * 2 + 0] + __ldg(bias + n) +
                           __half2float(rh.x) + __half2float(rl.x);
                float v1 = acc[mi][j][half * 2 + 1] + __ldg(bias + n + 1) +
                           __half2float(rh.y) + __half2float(rl.y);
                acc[mi][j][half * 2 + 0] = v0;
                acc[mi][j][half * 2 + 1] = v1;
                s += v0 + v1;
                q2 += v0 * v0 + v1 * v1;
            }
            s  += __shfl_xor_sync(0xffffffffu, s, 1);
            s  += __shfl_xor_sync(0xffffffffu, s, 2);
            q2 += __shfl_xor_sync(0xffffffffu, q2, 1);
            q2 += __shfl_xor_sync(0xffffffffu, q2, 2);
            ps[mi][half] = s; pq[mi][half] = q2;
        }
    }
    if (q == 0) {
        int wncol = wid >> 1;
#pragma unroll
        for (int mi = 0; mi < 2; mi++)
#pragma unroll
            for (int half = 0; half < 2; half++) {
                int ml = wm + mi * 16 + g + half * 8;
                red_s[ml][wncol] = ps[mi][half];
                red_q[ml][wncol] = pq[mi][half];
            }
    }
    __syncthreads();

    // ---- normalize + stage transpose into (dead) pipeline smem ----
    float* tr = (float*)dsm_;   // [256][68]
#pragma unroll
    for (int mi = 0; mi < 2; mi++) {
#pragma unroll
        for (int half = 0; half < 2; half++) {
            int ml = wm + mi * 16 + g + half * 8;
            float sm = red_s[ml][0] + red_s[ml][1] + red_s[ml][2] + red_s[ml][3];
            float sq = red_q[ml][0] + red_q[ml][1] + red_q[ml][2] + red_q[ml][3];
            float mean = sm * (1.f / 256.f);
            float var  = sq * (1.f / 256.f) - mean * mean;
            float rstd = rsqrtf(var + LN_EPS);
#pragma unroll
            for (int j = 0; j < 8; j++) {
#pragma unroll
                for (int e = 0; e < 2; e++) {
                    int n = wn + j * 8 + q * 2 + e;
                    float v = acc[mi][j][half * 2 + e];
                    tr[n * 68 + ml] = __ldg(n2w + n) * ((v - mean) * rstd) + __ldg(n2b + n);
                }
            }
        }
    }
    __syncthreads();

    // ---- coalesced NCHW output (64 consecutive pixels per channel) ----
    int b = m0 >> 14;
    int pimg = m0 & (HWSZ - 1);
    float* ob = out + (size_t)b * CH * HWSZ + pimg;
#pragma unroll
    for (int it = 0; it < 32; it++) {
        int c = it * 8 + wid;
#pragma unroll
        for (int u = 0; u < 2; u++)
            ob[(size_t)c * HWSZ + u * 32 + lane] = tr[c * 68 + u * 32 + lane];
    }
}

// =================== stage 0: transpose+split | prep | owprep ===================
__global__ void __launch_bounds__(256)
k_stage0(const float* __restrict__ x,
         const float* __restrict__ cw, const float* __restrict__ w1,
         const float* __restrict__ w2,
         const float* __restrict__ ow0, const float* __restrict__ ow1,
         const float* __restrict__ ow2) {
    int bid = blockIdx.x;
    int tid = threadIdx.x;
    if (bid < 8192) {
        __shared__ float t[32][33];
        int tb = bid;
        int p0 = (tb & 511) * 32;
        int c0 = ((tb >> 9) & 7) * 32;
        int b  = tb >> 12;
        int tx = tid & 31, ty = tid >> 5;
        const float* xb = x + (size_t)b * CH * HWSZ;
#pragma unroll
        for (int i = 0; i < 4; i++)
            t[ty + 8 * i][tx] = xb[(size_t)(c0 + ty + 8 * i) * HWSZ + p0 + tx];
        __syncthreads();
        size_t base = (size_t)b * HWSZ * CH;
#pragma unroll
        for (int i = 0; i < 4; i++) {
            float v = t[tx][ty + 8 * i];
            size_t idx = base + (size_t)(p0 + ty + 8 * i) * CH + c0 + tx;
            g_xT[idx] = v;
            __half h, l; split_f16(v, h, l);
            g_xTh[idx] = h; g_xTl[idx] = l;
        }
    } else if (bid < 8512) {
        int i = (bid - 8192) * 256 + tid;
        if (i >= 81920) return;
        const float* src; int dst;
        if (i < 16384)      { src = cw + i * 4;            dst = i * 4; }
        else if (i < 49152) { src = w1 + (i - 16384) * 4;  dst = 65536 + (i - 16384) * 4; }
        else                { src = w2 + (i - 49152) * 4;  dst = 196608 + (i - 49152) * 4; }
        float4 v = *(const float4*)src;
        ((__half2*)(g_wh + dst))[0] = __floats2half2_rn(v.x, v.y);
        ((__half2*)(g_wh + dst))[1] = __floats2half2_rn(v.z, v.w);
    } else {
        int i = (bid - 8512) * 256 + tid;
        if (i >= 3 * 32 * 2304) return;
        int br = i / (32 * 2304);
        int r  = i % (32 * 2304);
        int o  = r / 2304;
        int kk = r % 2304;
        int k  = kk / 256, c = kk % 256;
        const float* w = (br == 0) ? ow0 : (br == 1) ? ow1 : ow2;
        float v = (o < 18) ? w[((size_t)o * 256 + c) * 9 + k] : 0.f;
        g_owh[i] = __float2half_rn(v);
    }
}

// =================== fused deform3: 4 pixels/warp, 2 blocks/SM ===================
__global__ void __launch_bounds__(256, 2)
k_deform3(const float* __restrict__ dw0, const float* __restrict__ dw1,
          const float* __restrict__ dw2,
          const float* __restrict__ lw0, const float* __restrict__ lb0,
          const float* __restrict__ lw1, const float* __restrict__ lb1,
          const float* __restrict__ lw2, const float* __restrict__ lb2,
          const float* __restrict__ n1w, const float* __restrict__ n1b) {
    __shared__ float sdefT[3][9 * CH];
    __shared__ int   sidx[8][4][36];
    __shared__ float swgt[8][4][36];

    int tid = threadIdx.x, wid = tid >> 5, lane = tid & 31;
    {
        const float* dws[3] = {dw0, dw1, dw2};
#pragma unroll
        for (int br = 0; br < 3; br++)
            for (int i = tid; i < 9 * CH; i += 256) {
                int c = i / 9, k = i % 9;
                sdefT[br][k * CH + c] = dws[br][i];
            }
    }
    __syncthreads();

    int pix0 = blockIdx.x * 32 + wid * 4;
    int b = pix0 >> 14;
    int c0 = lane * 8;
    const float* xrow = g_xT + (size_t)b * HWSZ * CH;

    float sum[4][8];
#pragma unroll
    for (int e = 0; e < 4; e++) {
        const float4* ap = (const float4*)(g_acc + (size_t)(pix0 + e) * CH + c0);
        float4 a0 = ap[0], a1 = ap[1];
        sum[e][0] = a0.x; sum[e][1] = a0.y; sum[e][2] = a0.z; sum[e][3] = a0.w;
        sum[e][4] = a1.x; sum[e][5] = a1.y; sum[e][6] = a1.z; sum[e][7] = a1.w;
    }

    const int DS[3] = {1, 9, 12};
    const float* lws[3] = {lw0, lw1, lw2};
    const float* lbs[3] = {lb0, lb1, lb2};

#pragma unroll
    for (int br = 0; br < 3; br++) {
        int D = DS[br];
        for (int t = lane; t < 36; t += 32) {
            int e = t / 9, k = t % 9;
            int pix = pix0 + e;
            int p = pix & (HWSZ - 1);
            int h = p >> 7, w = p & 127;
            int ky = k / 3, kx = k % 3;
            const float* op = g_offp + (size_t)(br * BATCH + b) * 18 * HWSZ;
            float oy = op[(size_t)(2 * k) * HWSZ + p];
            float ox = op[(size_t)(2 * k + 1) * HWSZ + p];
            float py = (float)h + (float)((ky - 1) * D) + oy;
            float px = (float)w + (float)((kx - 1) * D) + ox;
            float y0 = floorf(py), x0 = floorf(px);
#pragma unroll
            for (int dy = 0; dy < 2; dy++)
#pragma unroll
                for (int dx = 0; dx < 2; dx++) {
                    float yc = y0 + dy, xc = x0 + dx;
                    float wq = (1.f - fabsf(py - yc)) * (1.f - fabsf(px - xc));
                    bool valid = (yc >= 0.f) && (yc < 128.f) && (xc >= 0.f) && (xc < 128.f);
                    int iy = min(max((int)yc, 0), 127);
                    int ix = min(max((int)xc, 0), 127);
                    sidx[wid][e][k * 4 + dy * 2 + dx] = iy * WW + ix;
                    swgt[wid][e][k * 4 + dy * 2 + dx] = valid ? wq : 0.f;
                }
        }
        __syncwarp();

        float facc[4][8];
#pragma unroll
        for (int e = 0; e < 4; e++)
#pragma unroll
            for (int r = 0; r < 8; r++) facc[e][r] = 0.f;

#pragma unroll
        for (int k = 0; k < 9; k++) {
            float4 wk0 = *(const float4*)&sdefT[br][k * CH + c0];
            float4 wk1 = *(const float4*)&sdefT[br][k * CH + c0 + 4];
#pragma unroll
            for (int e = 0; e < 4; e++) {
                float s[8];
#pragma unroll
                for (int r = 0; r < 8; r++) s[r] = 0.f;
#pragma unroll
                for (int j = 0; j < 4; j++) {
                    float wq = swgt[wid][e][k * 4 + j];
                    const float4* vp =
                        (const float4*)(xrow + (size_t)sidx[wid][e][k * 4 + j] * CH + c0);
                    float4 v0 = vp[0], v1 = vp[1];
                    s[0] += wq * v0.x; s[1] += wq * v0.y; s[2] += wq * v0.z; s[3] += wq * v0.w;
                    s[4] += wq * v1.x; s[5] += wq * v1.y; s[6] += wq * v1.z; s[7] += wq * v1.w;
                }
                facc[e][0] += wk0.x * s[0]; facc[e][1] += wk0.y * s[1];
                facc[e][2] += wk0.z * s[2]; facc[e][3] += wk0.w * s[3];
                facc[e][4] += wk1.x * s[4]; facc[e][5] += wk1.y * s[5];
                facc[e][6] += wk1.z * s[6]; facc[e][7] += wk1.w * s[7];
            }
        }

        const float4* lwp = (const float4*)(lws[br] + c0);
        const float4* lbp = (const float4*)(lbs[br] + c0);
        float4 lw0v = lwp[0], lw1v = lwp[1], lb0v = lbp[0], lb1v = lbp[1];
        float lw[8] = {lw0v.x, lw0v.y, lw0v.z, lw0v.w, lw1v.x, lw1v.y, lw1v.z, lw1v.w};
        float lb[8] = {lb0v.x, lb0v.y, lb0v.z, lb0v.w, lb1v.x, lb1v.y, lb1v.z, lb1v.w};
#pragma unroll
        for (int e = 0; e < 4; e++) {
            float ls = 0.f, lq = 0.f;
#pragma unroll
            for (int r = 0; r < 8; r++) { ls += facc[e][r]; lq += facc[e][r] * facc[e][r]; }
#pragma unroll
            for (int o = 16; o; o >>= 1) {
                ls += __shfl_xor_sync(0xffffffffu, ls, o);
                lq += __shfl_xor_sync(0xffffffffu, lq, o);
            }
            float mean = ls * (1.f / 256.f);
            float var  = lq * (1.f / 256.f) - mean * mean;
            float rstd = rsqrtf(var + LN_EPS);
#pragma unroll
            for (int r = 0; r < 8; r++)
                sum[e][r] += gelu_f(lw[r] * ((facc[e][r] - mean) * rstd) + lb[r]);
        }
        __syncwarp();
    }

    const float4* wp = (const float4*)(n1w + c0);
    const float4* bp = (const float4*)(n1b + c0);
    float4 w0v = wp[0], w1v = wp[1], b0v = bp[0], b1v = bp[1];
    float gw[8] = {w0v.x, w0v.y, w0v.z, w0v.w, w1v.x, w1v.y, w1v.z, w1v.w};
    float gb[8] = {b0v.x, b0v.y, b0v.z, b0v.w, b1v.x, b1v.y, b1v.z, b1v.w};

#pragma unroll
    for (int e = 0; e < 4; e++) {
        float ls = 0.f, lq = 0.f;
#pragma unroll
        for (int r = 0; r < 8; r++) { ls += sum[e][r]; lq += sum[e][r] * sum[e][r]; }
#pragma unroll
        for (int o = 16; o; o >>= 1) {
            ls += __shfl_xor_sync(0xffffffffu, ls, o);
            lq += __shfl_xor_sync(0xffffffffu, lq, o);
        }
        float mean = ls * (1.f / 256.f);
        float var  = lq * (1.f / 256.f) - mean * mean;
        float rstd = rsqrtf(var + LN_EPS);

        uint32_t hp[4], lp[4];
#pragma unroll
        for (int r = 0; r < 8; r += 2) {
            float oa = gw[r] * ((sum[e][r] - mean) * rstd) + gb[r];
            float ob = gw[r + 1] * ((sum[e][r + 1] - mean) * rstd) + gb[r + 1];
            __half h0, l0, h1, l1;
            split_f16(oa, h0, l0); split_f16(ob, h1, l1);
            hp[r >> 1] = (uint32_t)__half_as_ushort(h0) |
                         ((uint32_t)__half_as_ushort(h1) << 16);
            lp[r >> 1] = (uint32_t)__half_as_ushort(l0) |
                         ((uint32_t)__half_as_ushort(l1) << 16);
        }
        *(uint4*)(g_o1h + (size_t)(pix0 + e) * CH + c0) = make_uint4(hp[0], hp[1], hp[2], hp[3]);
        *(uint4*)(g_o1l + (size_t)(pix0 + e) * CH + c0) = make_uint4(lp[0], lp[1], lp[2], lp[3]);
    }
}

// =================== launch ===================
extern "C" void kernel_launch(void* const* d_in, const int* in_sizes, int n_in,
                              void* d_out, int out_size) {
    const float* x       = (const float*)d_in[0];
    const float* off_w1  = (const float*)d_in[1];
    const float* def_w1  = (const float*)d_in[2];
    const float* bw1     = (const float*)d_in[3];
    const float* bb1     = (const float*)d_in[4];
    const float* off_w2  = (const float*)d_in[5];
    const float* def_w2  = (const float*)d_in[6];
    const float* bw2     = (const float*)d_in[7];
    const float* bb2     = (const float*)d_in[8];
    const float* off_w3  = (const float*)d_in[9];
    const float* def_w3  = (const float*)d_in[10];
    const float* bw3     = (const float*)d_in[11];
    const float* bb3     = (const float*)d_in[12];
    const float* conv_w  = (const float*)d_in[13];
    const float* conv_b  = (const float*)d_in[14];
    const float* n1_w    = (const float*)d_in[15];
    const float* n1_b    = (const float*)d_in[16];
    const float* n2_w    = (const float*)d_in[17];
    const float* n2_b    = (const float*)d_in[18];
    const float* mlp_w1  = (const float*)d_in[19];
    const float* mlp_b1  = (const float*)d_in[20];
    const float* mlp_w2  = (const float*)d_in[21];
    const float* mlp_b2  = (const float*)d_in[22];

    float* pacc;
    __half *po1h, *po1l, *phh, *phl, *pwh, *pxTh, *pxTl;
    cudaGetSymbolAddress((void**)&pacc,  g_acc);
    cudaGetSymbolAddress((void**)&pxTh,  g_xTh);
    cudaGetSymbolAddress((void**)&pxTl,  g_xTl);
    cudaGetSymbolAddress((void**)&po1h,  g_o1h);
    cudaGetSymbolAddress((void**)&po1l,  g_o1l);
    cudaGetSymbolAddress((void**)&phh,   g_hh);
    cudaGetSymbolAddress((void**)&phl,   g_hl);
    cudaGetSymbolAddress((void**)&pwh,   g_wh);

    cudaFuncSetAttribute(k_stage1,
                         cudaFuncAttributeMaxDynamicSharedMemorySize, G_SMEM);
    cudaFuncSetAttribute(k_mmagemm<1, false, true>,
                         cudaFuncAttributeMaxDynamicSharedMemorySize, G_SMEM);
    cudaFuncSetAttribute(k_mlp2ln,
                         cudaFuncAttributeMaxDynamicSharedMemorySize, F_SMEM);

    // 1. transpose+split | weight prep | offset-weight reorg (one launch)
    k_stage0<<<9376, 256>>>(x, conv_w, mlp_w1, mlp_w2, off_w1, off_w2, off_w3);
    // 2. conv1x1 GEMM + offset convs, co-scheduled
    k_stage1<<<1280, 256, G_SMEM>>>(pxTh, pxTl, pwh, conv_b, pacc);
    // 3. fused deform x3 + LN1 + split
    k_deform3<<<PTOT / 32, 256>>>(def_w1, def_w2, def_w3,
                                  bw1, bb1, bw2, bb2, bw3, bb3, n1_w, n1_b);
    // 4. MLP1 (bias+GELU, fp16 hi/lo out)
    k_mmagemm<1, false, true><<<dim3(PTOT / 128, 512 / 128), 256, G_SMEM>>>(
        po1h, po1l, pwh + 65536, mlp_b1, nullptr, nullptr,
        nullptr, phh, phl, 512, CH);
    // 5. fused MLP2 + residual + LN2 + NCHW output (64px blocks, 2 blocks/SM)
    k_mlp2ln<<<PTOT / 64, 256, F_SMEM>>>(
        phh, phl, pwh + 196608, mlp_b2, po1h, po1l,
        n2_w, n2_b, (float*)d_out);
}

// round 17
// speedup vs baseline: 2.7683x; 1.1389x over previous
#include <cuda_runtime.h>
#include <cuda_fp16.h>
#include <math.h>
#include <stdint.h>

#define BATCH 2
#define CH    256
#define HH    128
#define WW    128
#define HWSZ  16384
#define PTOT  32768
#define LN_EPS 1e-6f

// ---------------- scratch ----------------
__device__ float g_acc [(size_t)PTOT * CH];
__device__ float g_offp[(size_t)3 * BATCH * 18 * HWSZ];   // [branch][b][18][HW]
__device__ __half g_xTh[(size_t)PTOT * CH];
__device__ __half g_xTl[(size_t)PTOT * CH];
__device__ __half g_o1h[(size_t)PTOT * CH];
__device__ __half g_o1l[(size_t)PTOT * CH];
__device__ __half g_hh [(size_t)PTOT * 512];
__device__ __half g_hl [(size_t)PTOT * 512];
__device__ __half g_wh[327680];            // fp16 weights: conv(65536)|w1(131072)|w2(131072)
__device__ __half g_owh[3 * 32 * 2304];    // offset-conv weights, fp16

__device__ __forceinline__ float gelu_f(float v) {
    return 0.5f * v * (1.0f + erff(v * 0.70710678118654752440f));
}
__device__ __forceinline__ void split_f16(float v, __half& h, __half& l) {
    h = __float2half_rn(v);
    l = __float2half_rn(v - __half2float(h));
}
__device__ __forceinline__ uint32_t smem_u32(const void* p) {
    uint32_t a;
    asm("{ .reg .u64 t; cvta.to.shared.u64 t, %1; cvt.u32.u64 %0, t; }" : "=r"(a) : "l"(p));
    return a;
}
__device__ __forceinline__ void ldmx4(uint32_t* r, uint32_t addr) {
    asm volatile("ldmatrix.sync.aligned.m8n8.x4.shared.b16 {%0,%1,%2,%3}, [%4];"
                 : "=r"(r[0]), "=r"(r[1]), "=r"(r[2]), "=r"(r[3]) : "r"(addr));
}
__device__ __forceinline__ void mma16816(float* c, const uint32_t* a, const uint32_t* b) {
    asm volatile("mma.sync.aligned.m16n8k16.row.col.f32.f16.f16.f32 "
                 "{%0,%1,%2,%3}, {%4,%5,%6,%7}, {%8,%9}, {%0,%1,%2,%3};"
                 : "+f"(c[0]), "+f"(c[1]), "+f"(c[2]), "+f"(c[3])
                 : "r"(a[0]), "r"(a[1]), "r"(a[2]), "r"(a[3]), "r"(b[0]), "r"(b[1]));
}
__device__ __forceinline__ void cp16(uint32_t dst, const void* src) {
    asm volatile("cp.async.cg.shared.global [%0], [%1], 16;" :: "r"(dst), "l"(src));
}
__device__ __forceinline__ void cp16z(uint32_t dst, const void* src, bool valid) {
    int sz = valid ? 16 : 0;
    asm volatile("cp.async.cg.shared.global [%0], [%1], 16, %2;"
                 :: "r"(dst), "l"(src), "r"(sz));
}
#define CP_COMMIT() asm volatile("cp.async.commit_group;" ::: "memory")
#define CP_WAIT0()  asm volatile("cp.async.wait_group 0;" ::: "memory")

// =================== GEMM body (fp16 2-term, cp.async double-buffered) ===================
#define G_ARR (128 * 40)
#define G_STG (3 * G_ARR)
#define G_SMEM (2 * G_STG * 2)   // 61440 bytes

template <int ACT, bool RES, bool F16OUT>
__device__ __forceinline__ void gemm_body(
        char* dsm_, int mblk, int nblk,
        const __half* __restrict__ Ah, const __half* __restrict__ Al,
        const __half* __restrict__ Bw,
        const float* __restrict__ bias,
        const __half* __restrict__ Resh, const __half* __restrict__ Resl,
        float* __restrict__ Cf, __half* __restrict__ Chi,
        __half* __restrict__ Clo, int N, int K) {
    uint32_t smb = smem_u32(dsm_);

    int tid  = threadIdx.x;
    int wid  = tid >> 5, lane = tid & 31;
    int m0   = mblk * 128, n0 = nblk * 128;
    int wm   = (wid & 3) * 32;
    int wn   = (wid >> 2) * 64;

    float acc[2][8][4];
#pragma unroll
    for (int i = 0; i < 2; i++)
#pragma unroll
        for (int j = 0; j < 8; j++)
#pragma unroll
            for (int q = 0; q < 4; q++) acc[i][j][q] = 0.f;

    const __half* srcs[3] = {Ah + (size_t)m0 * K, Al + (size_t)m0 * K,
                             Bw + (size_t)n0 * K};

    auto load_stage = [&](int kc, int s) {
        uint32_t stgoff = (uint32_t)s * (G_STG * 2);
#pragma unroll
        for (int t = 0; t < 3; t++) {
            const __half* src = srcs[t] + kc * 32;
            uint32_t dstb = smb + stgoff + (uint32_t)t * (G_ARR * 2);
#pragma unroll
            for (int u = 0; u < 2; u++) {
                int idx = u * 256 + tid;
                int row = idx >> 2, ch = idx & 3;
                cp16(dstb + (uint32_t)(row * 40 + ch * 8) * 2,
                     src + (size_t)row * K + ch * 8);
            }
        }
    };

    int a_row8 = ((lane >> 3) & 1) * 8 + (lane & 7);
    int a_col8 = ((lane >> 4) & 1) * 8;
    int b_row8 = ((lane >> 4) & 1) * 8 + (lane & 7);
    int b_col8 = ((lane >> 3) & 1) * 8;

    uint32_t aB[2][2], bB[4];
#pragma unroll
    for (int hl = 0; hl < 2; hl++)
#pragma unroll
        for (int mi = 0; mi < 2; mi++)
            aB[hl][mi] = smb + (uint32_t)(hl * (G_ARR * 2)) +
                         (uint32_t)((wm + mi * 16 + a_row8) * 80 + a_col8 * 2);
#pragma unroll
    for (int jp = 0; jp < 4; jp++)
        bB[jp] = smb + (uint32_t)(2 * (G_ARR * 2)) +
                 (uint32_t)((wn + jp * 16 + b_row8) * 80 + b_col8 * 2);

    load_stage(0, 0); CP_COMMIT();
    CP_WAIT0(); __syncthreads();

    int nk = K >> 5;
    for (int kc = 0; kc < nk; kc++) {
        int cur = kc & 1;
        if (kc + 1 < nk) { load_stage(kc + 1, cur ^ 1); CP_COMMIT(); }

        uint32_t stg = (uint32_t)cur * (G_STG * 2);
#pragma unroll
        for (int ks = 0; ks < 2; ks++) {
            uint32_t so = stg + (uint32_t)(ks * 32);
            uint32_t af[2][2][4];
#pragma unroll
            for (int hl = 0; hl < 2; hl++)
#pragma unroll
                for (int mi = 0; mi < 2; mi++)
                    ldmx4(af[hl][mi], aB[hl][mi] + so);
#pragma unroll
            for (int jp = 0; jp < 4; jp++) {
                uint32_t bf[4];
                ldmx4(bf, bB[jp] + so);
#pragma unroll
                for (int mi = 0; mi < 2; mi++)
#pragma unroll
                    for (int jj = 0; jj < 2; jj++) {
                        int j = jp * 2 + jj;
                        uint32_t b2[2] = {bf[jj * 2], bf[jj * 2 + 1]};
                        mma16816(acc[mi][j], af[0][mi], b2);
                        mma16816(acc[mi][j], af[1][mi], b2);
                    }
            }
        }
        if (kc + 1 < nk) CP_WAIT0();
        __syncthreads();
    }

    int g = lane >> 2, q = lane & 3;
#pragma unroll
    for (int mi = 0; mi < 2; mi++) {
#pragma unroll
        for (int half = 0; half < 2; half++) {
            int m = m0 + wm + mi * 16 + g + half * 8;
#pragma unroll
            for (int j = 0; j < 8; j++) {
                int n = n0 + wn + j * 8 + q * 2;
                float v0 = acc[mi][j][half * 2 + 0] + __ldg(bias + n);
                float v1 = acc[mi][j][half * 2 + 1] + __ldg(bias + n + 1);
                if (ACT == 1) { v0 = gelu_f(v0); v1 = gelu_f(v1); }
                if (RES) {
                    __half2 rh = *(const __half2*)(Resh + (size_t)m * N + n);
                    __half2 rl = *(const __half2*)(Resl + (size_t)m * N + n);
                    v0 += __half2float(rh.x) + __half2float(rl.x);
                    v1 += __half2float(rh.y) + __half2float(rl.y);
                }
                if (F16OUT) {
                    __half h0, l0, h1, l1;
                    split_f16(v0, h0, l0); split_f16(v1, h1, l1);
                    *(__half2*)(Chi + (size_t)m * N + n) = __halves2half2(h0, h1);
                    *(__half2*)(Clo + (size_t)m * N + n) = __halves2half2(l0, l1);
                } else {
                    *(float2*)(Cf + (size_t)m * N + n) = make_float2(v0, v1);
                }
            }
        }
    }
}

// =================== offmma body (fp16 2-term) ===================
#define OFF_A_ARR (128 * 40)
#define OFF_B_ARR (32 * 40)
#define OFF_STG   (2 * OFF_A_ARR + OFF_B_ARR)

__device__ __forceinline__ void offmma_body(char* dsm_, int bx, int br) {
    uint32_t smb = smem_u32(dsm_);

    int tid = threadIdx.x, wid = tid >> 5, lane = tid & 31;
    int h = bx & 127, b = bx >> 7;
    const int D = (br == 0) ? 1 : (br == 1) ? 9 : 12;

    const __half* xh = g_xTh + (size_t)b * HWSZ * CH;
    const __half* xl = g_xTl + (size_t)b * HWSZ * CH;
    const __half* wbh = g_owh + (size_t)br * 32 * 2304;

    float acc[4][4];
#pragma unroll
    for (int j = 0; j < 4; j++)
#pragma unroll
        for (int q = 0; q < 4; q++) acc[j][q] = 0.f;

    auto load_stage = [&](int kc, int s) {
        uint32_t base = smb + (uint32_t)s * (OFF_STG * 2);
        uint32_t sAh = base;
        uint32_t sAl = sAh + OFF_A_ARR * 2;
        uint32_t sBh = sAl + OFF_A_ARR * 2;
        int k  = kc >> 3;
        int cc = (kc & 7) * 32;
        int dy = (k / 3 - 1) * D, dx = (k % 3 - 1) * D;
        int srow = h + dy;
        bool vy = (srow >= 0) && (srow < HH);
        int srowc = vy ? srow : 0;
#pragma unroll
        for (int u = 0; u < 2; u++) {
            int idx = u * 256 + tid;
            int w = idx >> 2, ch = idx & 3;
            int wp = w + dx;
            bool v = vy && (wp >= 0) && (wp < WW);
            int wpc = v ? wp : 0;
            size_t goff = (size_t)(srowc * WW + wpc) * CH + cc + ch * 8;
            uint32_t soff = (uint32_t)(w * 40 + ch * 8) * 2;
            cp16z(sAh + soff, xh + goff, v);
            cp16z(sAl + soff, xl + goff, v);
        }
        if (tid < 128) {
            int o = tid >> 2, ch = tid & 3;
            size_t goff = (size_t)o * 2304 + k * 256 + cc + ch * 8;
            uint32_t soff = (uint32_t)(o * 40 + ch * 8) * 2;
            cp16(sBh + soff, wbh + goff);
        }
    };

    int a_row8 = ((lane >> 3) & 1) * 8 + (lane & 7);
    int a_col8 = ((lane >> 4) & 1) * 8;
    int b_row8 = ((lane >> 4) & 1) * 8 + (lane & 7);
    int b_col8 = ((lane >> 3) & 1) * 8;

    uint32_t aB[2], bB[2];
#pragma unroll
    for (int hl = 0; hl < 2; hl++)
        aB[hl] = smb + (uint32_t)(hl * (OFF_A_ARR * 2)) +
                 (uint32_t)((wid * 16 + a_row8) * 80 + a_col8 * 2);
#pragma unroll
    for (int jp = 0; jp < 2; jp++)
        bB[jp] = smb + (uint32_t)(2 * OFF_A_ARR * 2) +
                 (uint32_t)((jp * 16 + b_row8) * 80 + b_col8 * 2);

    load_stage(0, 0); CP_COMMIT();
    CP_WAIT0(); __syncthreads();

    const int NK = 72;
    for (int kc = 0; kc < NK; kc++) {
        int cur = kc & 1;
        if (kc + 1 < NK) { load_stage(kc + 1, cur ^ 1); CP_COMMIT(); }

        uint32_t stg = (uint32_t)cur * (OFF_STG * 2);
#pragma unroll
        for (int ks = 0; ks < 2; ks++) {
            uint32_t so = stg + (uint32_t)(ks * 32);
            uint32_t af[2][4];
            ldmx4(af[0], aB[0] + so);
            ldmx4(af[1], aB[1] + so);
#pragma unroll
            for (int jp = 0; jp < 2; jp++) {
                uint32_t bf[4];
                ldmx4(bf, bB[jp] + so);
#pragma unroll
                for (int jj = 0; jj < 2; jj++) {
                    int j = jp * 2 + jj;
                    uint32_t b2[2] = {bf[jj * 2], bf[jj * 2 + 1]};
                    mma16816(acc[j], af[0], b2);
                    mma16816(acc[j], af[1], b2);
                }
            }
        }
        if (kc + 1 < NK) CP_WAIT0();
        __syncthreads();
    }

    float* op = g_offp + (size_t)(br * BATCH + b) * 18 * HWSZ;
    int g = lane >> 2, q = lane & 3;
#pragma unroll
    for (int half = 0; half < 2; half++) {
        int wcol = wid * 16 + g + half * 8;
        int pimg = h * WW + wcol;
#pragma unroll
        for (int j = 0; j < 4; j++) {
#pragma unroll
            for (int e = 0; e < 2; e++) {
                int n = j * 8 + q * 2 + e;
                if (n < 18) op[(size_t)n * HWSZ + pimg] = acc[j][half * 2 + e];
            }
        }
    }
}

// =================== stage 1: conv1x1 GEMM (0..511) + offmma (512..1279) ===================
__global__ void __launch_bounds__(256, 2)
k_stage1(const __half* __restrict__ xTh, const __half* __restrict__ xTl,
         const __half* __restrict__ cwh,
         const float* __restrict__ conv_b, float* __restrict__ accp) {
    extern __shared__ char dsm_[];
    int bid = blockIdx.x;
    if (bid < 512) {
        gemm_body<0, false, false>(dsm_, bid & 255, bid >> 8,
                                   xTh, xTl, cwh, conv_b,
                                   nullptr, nullptr, accp, nullptr, nullptr, CH, CH);
    } else {
        int obid = bid - 512;
        offmma_body(dsm_, obid & 255, obid >> 8);
    }
}

// =================== MLP1 GEMM ===================
template <int ACT, bool RES, bool F16OUT>
__global__ void __launch_bounds__(256, 2)
k_mmagemm(const __half* __restrict__ Ah, const __half* __restrict__ Al,
          const __half* __restrict__ Bw,
          const float* __restrict__ bias,
          const __half* __restrict__ Resh, const __half* __restrict__ Resl,
          float* __restrict__ Cf, __half* __restrict__ Chi,
          __half* __restrict__ Clo, int N, int K) {
    extern __shared__ char dsm_[];
    gemm_body<ACT, RES, F16OUT>(dsm_, blockIdx.x, blockIdx.y,
                                Ah, Al, Bw, bias, Resh, Resl, Cf, Chi, Clo, N, K);
}

// =================== fused MLP2 + LN2 + NCHW output (64px blocks, 2/SM) ===================
#define F_A_ARR (64 * 40)
#define F_B_ARR (256 * 40)
#define F_STG   (2 * F_A_ARR + F_B_ARR)
#define F_SMEM  (256 * 68 * 4)

__global__ void __launch_bounds__(256, 2)
k_mlp2ln(const __half* __restrict__ Ah, const __half* __restrict__ Al,
         const __half* __restrict__ Bw,
         const float* __restrict__ bias,
         const __half* __restrict__ Resh, const __half* __restrict__ Resl,
         const float* __restrict__ n2w, const float* __restrict__ n2b,
         float* __restrict__ out) {
    extern __shared__ char dsm_[];
    uint32_t smb = smem_u32(dsm_);
    __shared__ float red_s[64][4];
    __shared__ float red_q[64][4];

    const int K = 512, N = 256;
    int tid = threadIdx.x, wid = tid >> 5, lane = tid & 31;
    int m0  = blockIdx.x * 64;
    int wm  = (wid & 1) * 32;
    int wn  = (wid >> 1) * 64;

    float acc[2][8][4];
#pragma unroll
    for (int i = 0; i < 2; i++)
#pragma unroll
        for (int j = 0; j < 8; j++)
#pragma unroll
            for (int q = 0; q < 4; q++) acc[i][j][q] = 0.f;

    const __half* srcA[2] = {Ah + (size_t)m0 * K, Al + (size_t)m0 * K};

    auto load_stage = [&](int kc, int s) {
        uint32_t stgoff = (uint32_t)s * (F_STG * 2);
#pragma unroll
        for (int t = 0; t < 2; t++) {
            const __half* src = srcA[t] + kc * 32;
            uint32_t dstb = smb + stgoff + (uint32_t)t * (F_A_ARR * 2);
            int row = tid >> 2, ch = tid & 3;
            cp16(dstb + (uint32_t)(row * 40 + ch * 8) * 2,
                 src + (size_t)row * K + ch * 8);
        }
        {
            const __half* src = Bw + kc * 32;
            uint32_t dstb = smb + stgoff + (uint32_t)(2 * F_A_ARR * 2);
#pragma unroll
            for (int u = 0; u < 4; u++) {
                int idx = u * 256 + tid;
                int row = idx >> 2, ch = idx & 3;
                cp16(dstb + (uint32_t)(row * 40 + ch * 8) * 2,
                     src + (size_t)row * K + ch * 8);
            }
        }
    };

    int a_row8 = ((lane >> 3) & 1) * 8 + (lane & 7);
    int a_col8 = ((lane >> 4) & 1) * 8;
    int b_row8 = ((lane >> 4) & 1) * 8 + (lane & 7);
    int b_col8 = ((lane >> 3) & 1) * 8;

    uint32_t aB[2][2], bB[4];
#pragma unroll
    for (int hl = 0; hl < 2; hl++)
#pragma unroll
        for (int mi = 0; mi < 2; mi++)
            aB[hl][mi] = smb + (uint32_t)(hl * (F_A_ARR * 2)) +
                         (uint32_t)((wm + mi * 16 + a_row8) * 80 + a_col8 * 2);
#pragma unroll
    for (int jp = 0; jp < 4; jp++)
        bB[jp] = smb + (uint32_t)(2 * F_A_ARR * 2) +
                 (uint32_t)((wn + jp * 16 + b_row8) * 80 + b_col8 * 2);

    load_stage(0, 0); CP_COMMIT();
    CP_WAIT0(); __syncthreads();

    const int nk = K >> 5;
    for (int kc = 0; kc < nk; kc++) {
        int cur = kc & 1;
        if (kc + 1 < nk) { load_stage(kc + 1, cur ^ 1); CP_COMMIT(); }

        uint32_t stg = (uint32_t)cur * (F_STG * 2);
#pragma unroll
        for (int ks = 0; ks < 2; ks++) {
            uint32_t so = stg + (uint32_t)(ks * 32);
            uint32_t af[2][2][4];
#pragma unroll
            for (int hl = 0; hl < 2; hl++)
#pragma unroll
                for (int mi = 0; mi < 2; mi++)
                    ldmx4(af[hl][mi], aB[hl][mi] + so);
#pragma unroll
            for (int jp = 0; jp < 4; jp++) {
                uint32_t bf[4];
                ldmx4(bf, bB[jp] + so);
#pragma unroll
                for (int mi = 0; mi < 2; mi++)
#pragma unroll
                    for (int jj = 0; jj < 2; jj++) {
                        int j = jp * 2 + jj;
                        uint32_t b2[2] = {bf[jj * 2], bf[jj * 2 + 1]};
                        mma16816(acc[mi][j], af[0][mi], b2);
                        mma16816(acc[mi][j], af[1][mi], b2);
                    }
            }
        }
        if (kc + 1 < nk) CP_WAIT0();
        __syncthreads();
    }

    int g = lane >> 2, q = lane & 3;
    float ps[2][2], pq[2][2];
#pragma unroll
    for (int mi = 0; mi < 2; mi++) {
#pragma unroll
        for (int half = 0; half < 2; half++) {
            int m = m0 + wm + mi * 16 + g + half * 8;
            float s = 0.f, q2 = 0.f;
#pragma unroll
            for (int j = 0; j < 8; j++) {
                int n = wn + j * 8 + q * 2;
                __half2 rh = *(const __half2*)(Resh + (size_t)m * N + n);
                __half2 rl = *(const __half2*)(Resl + (size_t)m * N + n);
                float v0 = acc[mi][j][half * 2 + 0] + __ldg(bias + n) +
                           __half2float(rh.x) + __half2float(rl.x);
                float v1 = acc[mi][j][half * 2 + 1] + __ldg(bias + n + 1) +
                           __half2float(rh.y) + __half2float(rl.y);
                acc[mi][j][half * 2 + 0] = v0;
                acc[mi][j][half * 2 + 1] = v1;
                s += v0 + v1;
                q2 += v0 * v0 + v1 * v1;
            }
            s  += __shfl_xor_sync(0xffffffffu, s, 1);
            s  += __shfl_xor_sync(0xffffffffu, s, 2);
            q2 += __shfl_xor_sync(0xffffffffu, q2, 1);
            q2 += __shfl_xor_sync(0xffffffffu, q2, 2);
            ps[mi][half] = s; pq[mi][half] = q2;
        }
    }
    if (q == 0) {
        int wncol = wid >> 1;
#pragma unroll
        for (int mi = 0; mi < 2; mi++)
#pragma unroll
            for (int half = 0; half < 2; half++) {
                int ml = wm + mi * 16 + g + half * 8;
                red_s[ml][wncol] = ps[mi][half];
                red_q[ml][wncol] = pq[mi][half];
            }
    }
    __syncthreads();

    float* tr = (float*)dsm_;   // [256][68]
#pragma unroll
    for (int mi = 0; mi < 2; mi++) {
#pragma unroll
        for (int half = 0; half < 2; half++) {
            int ml = wm + mi * 16 + g + half * 8;
            float sm = red_s[ml][0] + red_s[ml][1] + red_s[ml][2] + red_s[ml][3];
            float sq = red_q[ml][0] + red_q[ml][1] + red_q[ml][2] + red_q[ml][3];
            float mean = sm * (1.f / 256.f);
            float var  = sq * (1.f / 256.f) - mean * mean;
            float rstd = rsqrtf(var + LN_EPS);
#pragma unroll
            for (int j = 0; j < 8; j++) {
#pragma unroll
                for (int e = 0; e < 2; e++) {
                    int n = wn + j * 8 + q * 2 + e;
                    float v = acc[mi][j][half * 2 + e];
                    tr[n * 68 + ml] = __ldg(n2w + n) * ((v - mean) * rstd) + __ldg(n2b + n);
                }
            }
        }
    }
    __syncthreads();

    int b = m0 >> 14;
    int pimg = m0 & (HWSZ - 1);
    float* ob = out + (size_t)b * CH * HWSZ + pimg;
#pragma unroll
    for (int it = 0; it < 32; it++) {
        int c = it * 8 + wid;
#pragma unroll
        for (int u = 0; u < 2; u++)
            ob[(size_t)c * HWSZ + u * 32 + lane] = tr[c * 68 + u * 32 + lane];
    }
}

// =================== stage 0: transpose+split | prep | owprep ===================
__global__ void __launch_bounds__(256)
k_stage0(const float* __restrict__ x,
         const float* __restrict__ cw, const float* __restrict__ w1,
         const float* __restrict__ w2,
         const float* __restrict__ ow0, const float* __restrict__ ow1,
         const float* __restrict__ ow2) {
    int bid = blockIdx.x;
    int tid = threadIdx.x;
    if (bid < 8192) {
        __shared__ float t[32][33];
        int tb = bid;
        int p0 = (tb & 511) * 32;
        int c0 = ((tb >> 9) & 7) * 32;
        int b  = tb >> 12;
        int tx = tid & 31, ty = tid >> 5;
        const float* xb = x + (size_t)b * CH * HWSZ;
#pragma unroll
        for (int i = 0; i < 4; i++)
            t[ty + 8 * i][tx] = xb[(size_t)(c0 + ty + 8 * i) * HWSZ + p0 + tx];
        __syncthreads();
        size_t base = (size_t)b * HWSZ * CH;
#pragma unroll
        for (int i = 0; i < 4; i++) {
            float v = t[tx][ty + 8 * i];
            size_t idx = base + (size_t)(p0 + ty + 8 * i) * CH + c0 + tx;
            __half h, l; split_f16(v, h, l);
            g_xTh[idx] = h; g_xTl[idx] = l;
        }
    } else if (bid < 8512) {
        int i = (bid - 8192) * 256 + tid;
        if (i >= 81920) return;
        const float* src; int dst;
        if (i < 16384)      { src = cw + i * 4;            dst = i * 4; }
        else if (i < 49152) { src = w1 + (i - 16384) * 4;  dst = 65536 + (i - 16384) * 4; }
        else                { src = w2 + (i - 49152) * 4;  dst = 196608 + (i - 49152) * 4; }
        float4 v = *(const float4*)src;
        ((__half2*)(g_wh + dst))[0] = __floats2half2_rn(v.x, v.y);
        ((__half2*)(g_wh + dst))[1] = __floats2half2_rn(v.z, v.w);
    } else {
        int i = (bid - 8512) * 256 + tid;
        if (i >= 3 * 32 * 2304) return;
        int br = i / (32 * 2304);
        int r  = i % (32 * 2304);
        int o  = r / 2304;
        int kk = r % 2304;
        int k  = kk / 256, c = kk % 256;
        const float* w = (br == 0) ? ow0 : (br == 1) ? ow1 : ow2;
        float v = (o < 18) ? w[((size_t)o * 256 + c) * 9 + k] : 0.f;
        g_owh[i] = __float2half_rn(v);
    }
}

// =================== fused deform3: 4 pixels/warp, fp16 gathers (R17) ===================
__global__ void __launch_bounds__(256, 2)
k_deform3(const float* __restrict__ dw0, const float* __restrict__ dw1,
          const float* __restrict__ dw2,
          const float* __restrict__ lw0, const float* __restrict__ lb0,
          const float* __restrict__ lw1, const float* __restrict__ lb1,
          const float* __restrict__ lw2, const float* __restrict__ lb2,
          const float* __restrict__ n1w, const float* __restrict__ n1b) {
    __shared__ float sdefT[3][9 * CH];
    __shared__ int   sidx[8][4][36];
    __shared__ float swgt[8][4][36];

    int tid = threadIdx.x, wid = tid >> 5, lane = tid & 31;
    {
        const float* dws[3] = {dw0, dw1, dw2};
#pragma unroll
        for (int br = 0; br < 3; br++)
            for (int i = tid; i < 9 * CH; i += 256) {
                int c = i / 9, k = i % 9;
                sdefT[br][k * CH + c] = dws[br][i];
            }
    }
    __syncthreads();

    int pix0 = blockIdx.x * 32 + wid * 4;
    int b = pix0 >> 14;
    int c0 = lane * 8;
    const __half* xrow = g_xTh + (size_t)b * HWSZ * CH;   // fp16 gathers: half the bytes

    float sum[4][8];
#pragma unroll
    for (int e = 0; e < 4; e++) {
        const float4* ap = (const float4*)(g_acc + (size_t)(pix0 + e) * CH + c0);
        float4 a0 = ap[0], a1 = ap[1];
        sum[e][0] = a0.x; sum[e][1] = a0.y; sum[e][2] = a0.z; sum[e][3] = a0.w;
        sum[e][4] = a1.x; sum[e][5] = a1.y; sum[e][6] = a1.z; sum[e][7] = a1.w;
    }

    const int DS[3] = {1, 9, 12};
    const float* lws[3] = {lw0, lw1, lw2};
    const float* lbs[3] = {lb0, lb1, lb2};

#pragma unroll
    for (int br = 0; br < 3; br++) {
        int D = DS[br];
        for (int t = lane; t < 36; t += 32) {
            int e = t / 9, k = t % 9;
            int pix = pix0 + e;
            int p = pix & (HWSZ - 1);
            int h = p >> 7, w = p & 127;
            int ky = k / 3, kx = k % 3;
            const float* op = g_offp + (size_t)(br * BATCH + b) * 18 * HWSZ;
            float oy = op[(size_t)(2 * k) * HWSZ + p];
            float ox = op[(size_t)(2 * k + 1) * HWSZ + p];
            float py = (float)h + (float)((ky - 1) * D) + oy;
            float px = (float)w + (float)((kx - 1) * D) + ox;
            float y0 = floorf(py), x0 = floorf(px);
#pragma unroll
            for (int dy = 0; dy < 2; dy++)
#pragma unroll
                for (int dx = 0; dx < 2; dx++) {
                    float yc = y0 + dy, xc = x0 + dx;
                    float wq = (1.f - fabsf(py - yc)) * (1.f - fabsf(px - xc));
                    bool valid = (yc >= 0.f) && (yc < 128.f) && (xc >= 0.f) && (xc < 128.f);
                    int iy = min(max((int)yc, 0), 127);
                    int ix = min(max((int)xc, 0), 127);
                    sidx[wid][e][k * 4 + dy * 2 + dx] = iy * WW + ix;
                    swgt[wid][e][k * 4 + dy * 2 + dx] = valid ? wq : 0.f;
                }
        }
        __syncwarp();

        float facc[4][8];
#pragma unroll
        for (int e = 0; e < 4; e++)
#pragma unroll
            for (int r = 0; r < 8; r++) facc[e][r] = 0.f;

#pragma unroll
        for (int k = 0; k < 9; k++) {
            float4 wk0 = *(const float4*)&sdefT[br][k * CH + c0];
            float4 wk1 = *(const float4*)&sdefT[br][k * CH + c0 + 4];
#pragma unroll
            for (int e = 0; e < 4; e++) {
                float s[8];
#pragma unroll
                for (int r = 0; r < 8; r++) s[r] = 0.f;
#pragma unroll
                for (int j = 0; j < 4; j++) {
                    float wq = swgt[wid][e][k * 4 + j];
                    uint4 raw = *(const uint4*)(xrow +
                                (size_t)sidx[wid][e][k * 4 + j] * CH + c0);
                    const __half2* hp = (const __half2*)&raw;
                    float2 f0 = __half22float2(hp[0]);
                    float2 f1 = __half22float2(hp[1]);
                    float2 f2 = __half22float2(hp[2]);
                    float2 f3 = __half22float2(hp[3]);
                    s[0] += wq * f0.x; s[1] += wq * f0.y;
                    s[2] += wq * f1.x; s[3] += wq * f1.y;
                    s[4] += wq * f2.x; s[5] += wq * f2.y;
                    s[6] += wq * f3.x; s[7] += wq * f3.y;
                }
                facc[e][0] += wk0.x * s[0]; facc[e][1] += wk0.y * s[1];
                facc[e][2] += wk0.z * s[2]; facc[e][3] += wk0.w * s[3];
                facc[e][4] += wk1.x * s[4]; facc[e][5] += wk1.y * s[5];
                facc[e][6] += wk1.z * s[6]; facc[e][7] += wk1.w * s[7];
            }
        }

        const float4* lwp = (const float4*)(lws[br] + c0);
        const float4* lbp = (const float4*)(lbs[br] + c0);
        float4 lw0v = lwp[0], lw1v = lwp[1], lb0v = lbp[0], lb1v = lbp[1];
        float lw[8] = {lw0v.x, lw0v.y, lw0v.z, lw0v.w, lw1v.x, lw1v.y, lw1v.z, lw1v.w};
        float lb[8] = {lb0v.x, lb0v.y, lb0v.z, lb0v.w, lb1v.x, lb1v.y, lb1v.z, lb1v.w};
#pragma unroll
        for (int e = 0; e < 4; e++) {
            float ls = 0.f, lq = 0.f;
#pragma unroll
            for (int r = 0; r < 8; r++) { ls += facc[e][r]; lq += facc[e][r] * facc[e][r]; }
#pragma unroll
            for (int o = 16; o; o >>= 1) {
                ls += __shfl_xor_sync(0xffffffffu, ls, o);
                lq += __shfl_xor_sync(0xffffffffu, lq, o);
            }
            float mean = ls * (1.f / 256.f);
            float var  = lq * (1.f / 256.f) - mean * mean;
            float rstd = rsqrtf(var + LN_EPS);
#pragma unroll
            for (int r = 0; r < 8; r++)
                sum[e][r] += gelu_f(lw[r] * ((facc[e][r] - mean) * rstd) + lb[r]);
        }
        __syncwarp();
    }

    const float4* wp = (const float4*)(n1w + c0);
    const float4* bp = (const float4*)(n1b + c0);
    float4 w0v = wp[0], w1v = wp[1], b0v = bp[0], b1v = bp[1];
    float gw[8] = {w0v.x, w0v.y, w0v.z, w0v.w, w1v.x, w1v.y, w1v.z, w1v.w};
    float gb[8] = {b0v.x, b0v.y, b0v.z, b0v.w, b1v.x, b1v.y, b1v.z, b1v.w};

#pragma unroll
    for (int e = 0; e < 4; e++) {
        float ls = 0.f, lq = 0.f;
#pragma unroll
        for (int r = 0; r < 8; r++) { ls += sum[e][r]; lq += sum[e][r] * sum[e][r]; }
#pragma unroll
        for (int o = 16; o; o >>= 1) {
            ls += __shfl_xor_sync(0xffffffffu, ls, o);
            lq += __shfl_xor_sync(0xffffffffu, lq, o);
        }
        float mean = ls * (1.f / 256.f);
        float var  = lq * (1.f / 256.f) - mean * mean;
        float rstd = rsqrtf(var + LN_EPS);

        uint32_t hp[4], lp[4];
#pragma unroll
        for (int r = 0; r < 8; r += 2) {
            float oa = gw[r] * ((sum[e][r] - mean) * rstd) + gb[r];
            float ob = gw[r + 1] * ((sum[e][r + 1] - mean) * rstd) + gb[r + 1];
            __half h0, l0, h1, l1;
            split_f16(oa, h0, l0); split_f16(ob, h1, l1);
            hp[r >> 1] = (uint32_t)__half_as_ushort(h0) |
                         ((uint32_t)__half_as_ushort(h1) << 16);
            lp[r >> 1] = (uint32_t)__half_as_ushort(l0) |
                         ((uint32_t)__half_as_ushort(l1) << 16);
        }
        *(uint4*)(g_o1h + (size_t)(pix0 + e) * CH + c0) = make_uint4(hp[0], hp[1], hp[2], hp[3]);
        *(uint4*)(g_o1l + (size_t)(pix0 + e) * CH + c0) = make_uint4(lp[0], lp[1], lp[2], lp[3]);
    }
}

// =================== launch ===================
extern "C" void kernel_launch(void* const* d_in, const int* in_sizes, int n_in,
                              void* d_out, int out_size) {
    const float* x       = (const float*)d_in[0];
    const float* off_w1  = (const float*)d_in[1];
    const float* def_w1  = (const float*)d_in[2];
    const float* bw1     = (const float*)d_in[3];
    const float* bb1     = (const float*)d_in[4];
    const float* off_w2  = (const float*)d_in[5];
    const float* def_w2  = (const float*)d_in[6];
    const float* bw2     = (const float*)d_in[7];
    const float* bb2     = (const float*)d_in[8];
    const float* off_w3  = (const float*)d_in[9];
    const float* def_w3  = (const float*)d_in[10];
    const float* bw3     = (const float*)d_in[11];
    const float* bb3     = (const float*)d_in[12];
    const float* conv_w  = (const float*)d_in[13];
    const float* conv_b  = (const float*)d_in[14];
    const float* n1_w    = (const float*)d_in[15];
    const float* n1_b    = (const float*)d_in[16];
    const float* n2_w    = (const float*)d_in[17];
    const float* n2_b    = (const float*)d_in[18];
    const float* mlp_w1  = (const float*)d_in[19];
    const float* mlp_b1  = (const float*)d_in[20];
    const float* mlp_w2  = (const float*)d_in[21];
    const float* mlp_b2  = (const float*)d_in[22];

    float* pacc;
    __half *po1h, *po1l, *phh, *phl, *pwh, *pxTh, *pxTl;
    cudaGetSymbolAddress((void**)&pacc,  g_acc);
    cudaGetSymbolAddress((void**)&pxTh,  g_xTh);
    cudaGetSymbolAddress((void**)&pxTl,  g_xTl);
    cudaGetSymbolAddress((void**)&po1h,  g_o1h);
    cudaGetSymbolAddress((void**)&po1l,  g_o1l);
    cudaGetSymbolAddress((void**)&phh,   g_hh);
    cudaGetSymbolAddress((void**)&phl,   g_hl);
    cudaGetSymbolAddress((void**)&pwh,   g_wh);

    cudaFuncSetAttribute(k_stage1,
                         cudaFuncAttributeMaxDynamicSharedMemorySize, G_SMEM);
    cudaFuncSetAttribute(k_mmagemm<1, false, true>,
                         cudaFuncAttributeMaxDynamicSharedMemorySize, G_SMEM);
    cudaFuncSetAttribute(k_mlp2ln,
                         cudaFuncAttributeMaxDynamicSharedMemorySize, F_SMEM);

    // 1. transpose+split | weight prep | offset-weight reorg (one launch)
    k_stage0<<<9376, 256>>>(x, conv_w, mlp_w1, mlp_w2, off_w1, off_w2, off_w3);
    // 2. conv1x1 GEMM + offset convs, co-scheduled
    k_stage1<<<1280, 256, G_SMEM>>>(pxTh, pxTl, pwh, conv_b, pacc);
    // 3. fused deform x3 + LN1 + split (fp16 gathers)
    k_deform3<<<PTOT / 32, 256>>>(def_w1, def_w2, def_w3,
                                  bw1, bb1, bw2, bb2, bw3, bb3, n1_w, n1_b);
    // 4. MLP1 (bias+GELU, fp16 hi/lo out)
    k_mmagemm<1, false, true><<<dim3(PTOT / 128, 512 / 128), 256, G_SMEM>>>(
        po1h, po1l, pwh + 65536, mlp_b1, nullptr, nullptr,
        nullptr, phh, phl, 512, CH);
    // 5. fused MLP2 + residual + LN2 + NCHW output
    k_mlp2ln<<<PTOT / 64, 256, F_SMEM>>>(
        phh, phl, pwh + 196608, mlp_b2, po1h, po1l,
        n2_w, n2_b, (float*)d_out);
}